// round 1
// baseline (speedup 1.0000x reference)
#include <cuda_runtime.h>
#include <math.h>
#include <stdint.h>

// ---------------------------------------------------------------------------
// Problem constants
// ---------------------------------------------------------------------------
constexpr int B_   = 16;
constexpr int C_   = 512;
constexpr int Hh   = 64;
constexpr int Wd   = 64;
constexpr int Qn   = 1024;
constexpr int C2_  = 256;
constexpr int N1_  = 256;    // 16x16 after stride-4 conv
constexpr int N2_  = 1024;   // 32x32 after stride-2 conv

// ---------------------------------------------------------------------------
// Device scratch (no allocations allowed anywhere)
// ---------------------------------------------------------------------------
__device__ float g_qproj[(size_t)Qn * B_ * C_];          //  8.4M
__device__ float g_imgK [(size_t)B_ * C_ * Hh * Wd];     // 33.5M
__device__ float g_imgV [(size_t)B_ * C_ * Hh * Wd];     // 33.5M
__device__ float g_k1n  [(size_t)B_ * N1_ * C_];
__device__ float g_v1n  [(size_t)B_ * N1_ * C_];
__device__ float g_k2n  [(size_t)B_ * N2_ * C_];
__device__ float g_v2n  [(size_t)B_ * N2_ * C_];
__device__ float g_k1   [(size_t)B_ * N1_ * C2_];
__device__ float g_v1   [(size_t)B_ * N1_ * C2_];
__device__ float g_k2   [(size_t)B_ * N2_ * C2_];
__device__ float g_v2   [(size_t)B_ * N2_ * C2_];
__device__ float g_v1r  [(size_t)B_ * N1_ * C2_];
__device__ float g_v2r  [(size_t)B_ * N2_ * C2_];
__device__ float g_attn [(size_t)B_ * 4 * Qn * N2_];     // 67M floats (reused both branches)
__device__ float g_xcat [(size_t)B_ * Qn * C_];

// ---------------------------------------------------------------------------
// (N,B,C) -> "(B,C,H,W)" raw-reshape image materialization.
// key.transpose(0,2,1).reshape(B,C,H,W) flat index F corresponds to source
// element key[n = F>>13, b = r&15, c = r>>4] with r = F & 8191.
// This is a 512x16 transpose inside each 8192-float chunk -> smem tiled.
// ---------------------------------------------------------------------------
__global__ void to_image_kernel(const float* __restrict__ src, float* __restrict__ dst) {
    __shared__ float sm[16][513];
    size_t base = (size_t)blockIdx.x * 8192;
    for (int j = threadIdx.x; j < 8192; j += 256) {
        sm[j >> 9][j & 511] = src[base + j];     // sm[b][c] = key[n,b,c]
    }
    __syncthreads();
    for (int r = threadIdx.x; r < 8192; r += 256) {
        dst[base + r] = sm[r & 15][r >> 4];
    }
}

// ---------------------------------------------------------------------------
// SGEMM:  C[m,n] = sum_k A[m,k] * W[n,k] (+ bias[n])
// A row-major M*K, W row-major N*K.  128x128 tile, BK=8, 256 threads, 8x8 micro.
// LOADER 0: plain row-major A.
// LOADER 1: implicit im2col from NCHW image, 4x4 conv stride 4 (K = 512*16).
// LOADER 2: implicit im2col from NCHW image, 2x2 conv stride 2 (K = 512*4).
// Requires M%128==0, N%128==0, K%8==0 (all shapes here satisfy this).
// ---------------------------------------------------------------------------
template <int LOADER>
__global__ __launch_bounds__(256) void sgemm_kernel(
    const float* __restrict__ A, const float* __restrict__ W,
    const float* __restrict__ bias, float* __restrict__ Cmat,
    int M, int N, int K)
{
    __shared__ float As[8][128];
    __shared__ float Ws[8][128];

    const int bm = blockIdx.y << 7;
    const int bn = blockIdx.x << 7;
    const int tid = threadIdx.x;
    const int lr = tid >> 1;            // 0..127
    const int lc = (tid & 1) << 2;      // 0 or 4
    const int tx = tid & 15, ty = tid >> 4;

    float acc[8][8];
#pragma unroll
    for (int i = 0; i < 8; i++)
#pragma unroll
        for (int j = 0; j < 8; j++) acc[i][j] = 0.f;

    const int m = bm + lr;

    for (int k0 = 0; k0 < K; k0 += 8) {
        const int k = k0 + lc;
        float4 av;
        if (LOADER == 0) {
            av = *(const float4*)(A + (size_t)m * K + k);
        } else if (LOADER == 1) {
            // m = b*256 + oy*16 + ox ; k = ic*16 + ky*4 + kx (kx = 0..3 contiguous)
            int b  = m >> 8, oy = (m >> 4) & 15, ox = m & 15;
            int ic = k >> 4, ky = (k >> 2) & 3;
            av = *(const float4*)(A + (((size_t)(b * 512 + ic) * 64) + oy * 4 + ky) * 64 + ox * 4);
        } else {
            // m = b*1024 + oy*32 + ox ; k = ic*4 + ky*2 + kx
            int b  = m >> 10, oy = (m >> 5) & 31, ox = m & 31;
            int ic = k >> 2;
            const float* p = A + (((size_t)(b * 512 + ic) * 64) + oy * 2) * 64 + ox * 2;
            float2 r0 = *(const float2*)p;
            float2 r1 = *(const float2*)(p + 64);
            av = make_float4(r0.x, r0.y, r1.x, r1.y);
        }
        float4 wv = *(const float4*)(W + (size_t)(bn + lr) * K + k);

        As[lc + 0][lr] = av.x; As[lc + 1][lr] = av.y; As[lc + 2][lr] = av.z; As[lc + 3][lr] = av.w;
        Ws[lc + 0][lr] = wv.x; Ws[lc + 1][lr] = wv.y; Ws[lc + 2][lr] = wv.z; Ws[lc + 3][lr] = wv.w;
        __syncthreads();

#pragma unroll
        for (int kk = 0; kk < 8; kk++) {
            float4 a0 = *(const float4*)&As[kk][ty << 3];
            float4 a1 = *(const float4*)&As[kk][(ty << 3) + 4];
            float4 b0 = *(const float4*)&Ws[kk][tx << 3];
            float4 b1 = *(const float4*)&Ws[kk][(tx << 3) + 4];
            float a[8] = {a0.x, a0.y, a0.z, a0.w, a1.x, a1.y, a1.z, a1.w};
            float bv[8] = {b0.x, b0.y, b0.z, b0.w, b1.x, b1.y, b1.z, b1.w};
#pragma unroll
            for (int i = 0; i < 8; i++)
#pragma unroll
                for (int j = 0; j < 8; j++) acc[i][j] += a[i] * bv[j];
        }
        __syncthreads();
    }

#pragma unroll
    for (int i = 0; i < 8; i++) {
        int mo = bm + (ty << 3) + i;
        float* crow = Cmat + (size_t)mo * N + bn + (tx << 3);
        float b0 = 0.f, b1 = 0.f, b2 = 0.f, b3 = 0.f, b4 = 0.f, b5 = 0.f, b6 = 0.f, b7 = 0.f;
        if (bias) {
            const float* bp = bias + bn + (tx << 3);
            b0 = bp[0]; b1 = bp[1]; b2 = bp[2]; b3 = bp[3];
            b4 = bp[4]; b5 = bp[5]; b6 = bp[6]; b7 = bp[7];
        }
        float4 o0 = make_float4(acc[i][0] + b0, acc[i][1] + b1, acc[i][2] + b2, acc[i][3] + b3);
        float4 o1 = make_float4(acc[i][4] + b4, acc[i][5] + b5, acc[i][6] + b6, acc[i][7] + b7);
        *(float4*)(crow + 0) = o0;
        *(float4*)(crow + 4) = o1;
    }
}

// ---------------------------------------------------------------------------
// Fused LayerNorm (over 512) + exact GELU, in place. One block per row.
// ---------------------------------------------------------------------------
__global__ void ln_gelu_kernel(float* __restrict__ x,
                               const float* __restrict__ w,
                               const float* __restrict__ b)
{
    __shared__ float sh[8];
    float* row = x + (size_t)blockIdx.x * 512;
    int t = threadIdx.x;
    float v0 = row[t], v1 = row[t + 256];

    float s = v0 + v1;
#pragma unroll
    for (int o = 16; o; o >>= 1) s += __shfl_xor_sync(0xffffffffu, s, o);
    if ((t & 31) == 0) sh[t >> 5] = s;
    __syncthreads();
    float tot = 0.f;
#pragma unroll
    for (int i = 0; i < 8; i++) tot += sh[i];
    float mu = tot * (1.f / 512.f);
    float d0 = v0 - mu, d1 = v1 - mu;
    __syncthreads();

    float ss = d0 * d0 + d1 * d1;
#pragma unroll
    for (int o = 16; o; o >>= 1) ss += __shfl_xor_sync(0xffffffffu, ss, o);
    if ((t & 31) == 0) sh[t >> 5] = ss;
    __syncthreads();
    float tot2 = 0.f;
#pragma unroll
    for (int i = 0; i < 8; i++) tot2 += sh[i];
    float inv = rsqrtf(tot2 * (1.f / 512.f) + 1e-5f);

    float y0 = d0 * inv * w[t]       + b[t];
    float y1 = d1 * inv * w[t + 256] + b[t + 256];
    row[t]       = 0.5f * y0 * (1.f + erff(y0 * 0.7071067811865476f));
    row[t + 256] = 0.5f * y1 * (1.f + erff(y1 * 0.7071067811865476f));
}

// ---------------------------------------------------------------------------
// Depthwise 3x3 (pad 1) residual:  out = v + lb + dwconv3x3(v)
// Layout [ (b*Nn + y*ww + x) * 256 + c ]  (c coalesced)
// ---------------------------------------------------------------------------
__global__ void dwconv_res_kernel(const float* __restrict__ v,
                                  const float* __restrict__ lw,
                                  const float* __restrict__ lb,
                                  float* __restrict__ out,
                                  int hh, int ww)
{
    int idx = blockIdx.x * 256 + threadIdx.x;
    int c = idx & 255;
    int sp = idx >> 8;          // b*Nn + n
    int Nn = hh * ww;
    int bb = sp / Nn;
    int n = sp - bb * Nn;
    int y = n / ww;
    int x = n - y * ww;

    float acc = lb[c];
#pragma unroll
    for (int dy = -1; dy <= 1; dy++) {
        int yy = y + dy;
        if (yy < 0 || yy >= hh) continue;
#pragma unroll
        for (int dx = -1; dx <= 1; dx++) {
            int xx = x + dx;
            if (xx < 0 || xx >= ww) continue;
            acc += v[((size_t)(bb * Nn + yy * ww + xx) << 8) + c] * lw[c * 9 + (dy + 1) * 3 + (dx + 1)];
        }
    }
    out[idx] = v[idx] + acc;
}

// ---------------------------------------------------------------------------
// Scores: S[b,h,q,k] = 0.125 * sum_d q(b,hoff+h,q,d) * K(b,h,k,d)
// q read through raw-reshape view of qproj; K from [b*Nk+k, h*64+d] buffer.
// One block: 64q x 64k output tile (d = 64 fully unrolled).
// ---------------------------------------------------------------------------
__global__ __launch_bounds__(256) void scores_kernel(
    const float* __restrict__ qp, const float* __restrict__ kb,
    float* __restrict__ attn, int Nk, int hoff)
{
    __shared__ float Qs[64][65];
    __shared__ float Ks[64][65];
    int bz = blockIdx.z;
    int b = bz >> 2, h = bz & 3;
    int q0 = blockIdx.y << 6, k0 = blockIdx.x << 6;
    int tid = threadIdx.x;

    for (int i = tid; i < 1024; i += 256) {
        int row = i >> 4;
        int d4 = (i & 15) << 2;
        float4 qv = *(const float4*)(qp + ((size_t)(b * Qn + q0 + row)) * 512 + (hoff + h) * 64 + d4);
        Qs[row][d4] = qv.x; Qs[row][d4 + 1] = qv.y; Qs[row][d4 + 2] = qv.z; Qs[row][d4 + 3] = qv.w;
        float4 kv = *(const float4*)(kb + ((size_t)(b * Nk + k0 + row)) * 256 + h * 64 + d4);
        Ks[row][d4] = kv.x; Ks[row][d4 + 1] = kv.y; Ks[row][d4 + 2] = kv.z; Ks[row][d4 + 3] = kv.w;
    }
    __syncthreads();

    int tx = tid & 15, ty = tid >> 4;
    float acc[4][4];
#pragma unroll
    for (int i = 0; i < 4; i++)
#pragma unroll
        for (int j = 0; j < 4; j++) acc[i][j] = 0.f;

#pragma unroll 8
    for (int d = 0; d < 64; d++) {
        float a0 = Qs[(ty << 2) + 0][d], a1 = Qs[(ty << 2) + 1][d];
        float a2 = Qs[(ty << 2) + 2][d], a3 = Qs[(ty << 2) + 3][d];
        float c0 = Ks[(tx << 2) + 0][d], c1 = Ks[(tx << 2) + 1][d];
        float c2 = Ks[(tx << 2) + 2][d], c3 = Ks[(tx << 2) + 3][d];
        acc[0][0] += a0 * c0; acc[0][1] += a0 * c1; acc[0][2] += a0 * c2; acc[0][3] += a0 * c3;
        acc[1][0] += a1 * c0; acc[1][1] += a1 * c1; acc[1][2] += a1 * c2; acc[1][3] += a1 * c3;
        acc[2][0] += a2 * c0; acc[2][1] += a2 * c1; acc[2][2] += a2 * c2; acc[2][3] += a2 * c3;
        acc[3][0] += a3 * c0; acc[3][1] += a3 * c1; acc[3][2] += a3 * c2; acc[3][3] += a3 * c3;
    }

    const float scale = 0.125f;
#pragma unroll
    for (int i = 0; i < 4; i++) {
        float4 o = make_float4(acc[i][0] * scale, acc[i][1] * scale, acc[i][2] * scale, acc[i][3] * scale);
        *(float4*)(attn + ((size_t)bz * Qn + q0 + (ty << 2) + i) * Nk + k0 + (tx << 2)) = o;
    }
}

// ---------------------------------------------------------------------------
// Row softmax, row length L (256 or 1024), one block (256 thr) per row.
// ---------------------------------------------------------------------------
__global__ void softmax_kernel(float* __restrict__ attn, int L) {
    __shared__ float sh[8];
    float* row = attn + (size_t)blockIdx.x * L;
    int t = threadIdx.x;

    float m = -1e30f;
    for (int i = t; i < L; i += 256) m = fmaxf(m, row[i]);
#pragma unroll
    for (int o = 16; o; o >>= 1) m = fmaxf(m, __shfl_xor_sync(0xffffffffu, m, o));
    if ((t & 31) == 0) sh[t >> 5] = m;
    __syncthreads();
    float mm = sh[0];
#pragma unroll
    for (int i = 1; i < 8; i++) mm = fmaxf(mm, sh[i]);
    __syncthreads();

    float s = 0.f;
    for (int i = t; i < L; i += 256) {
        float e = __expf(row[i] - mm);
        row[i] = e;
        s += e;
    }
#pragma unroll
    for (int o = 16; o; o >>= 1) s += __shfl_xor_sync(0xffffffffu, s, o);
    if ((t & 31) == 0) sh[t >> 5] = s;
    __syncthreads();
    float tot = 0.f;
#pragma unroll
    for (int i = 0; i < 8; i++) tot += sh[i];
    float inv = 1.f / tot;
    for (int i = t; i < L; i += 256) row[i] *= inv;
}

// ---------------------------------------------------------------------------
// PV: out(b,h,q,d) = sum_k attn(b,h,q,k) * V(b,h,k,d); written into xcat at
// column offset coloff + h*64.  One block: 64q x 64d, looping K in 64 chunks.
// ---------------------------------------------------------------------------
__global__ __launch_bounds__(256) void pv_kernel(
    const float* __restrict__ attn, const float* __restrict__ vb,
    float* __restrict__ xcat, int Nk, int coloff)
{
    __shared__ float As[64][65];
    __shared__ float Vs[64][65];
    int bz = blockIdx.z;
    int b = bz >> 2, h = bz & 3;
    int q0 = blockIdx.y << 6;
    int tid = threadIdx.x;
    int tx = tid & 15, ty = tid >> 4;

    float acc[4][4];
#pragma unroll
    for (int i = 0; i < 4; i++)
#pragma unroll
        for (int j = 0; j < 4; j++) acc[i][j] = 0.f;

    for (int kc = 0; kc < Nk; kc += 64) {
        __syncthreads();
        for (int i = tid; i < 1024; i += 256) {
            int row = i >> 4;
            int c4 = (i & 15) << 2;
            float4 av = *(const float4*)(attn + ((size_t)bz * Qn + q0 + row) * Nk + kc + c4);
            As[row][c4] = av.x; As[row][c4 + 1] = av.y; As[row][c4 + 2] = av.z; As[row][c4 + 3] = av.w;
            float4 vv = *(const float4*)(vb + ((size_t)(b * Nk + kc + row)) * 256 + h * 64 + c4);
            Vs[row][c4] = vv.x; Vs[row][c4 + 1] = vv.y; Vs[row][c4 + 2] = vv.z; Vs[row][c4 + 3] = vv.w;
        }
        __syncthreads();
#pragma unroll 4
        for (int kk = 0; kk < 64; kk++) {
            float a0 = As[(ty << 2) + 0][kk], a1 = As[(ty << 2) + 1][kk];
            float a2 = As[(ty << 2) + 2][kk], a3 = As[(ty << 2) + 3][kk];
            float c0 = Vs[kk][(tx << 2) + 0], c1 = Vs[kk][(tx << 2) + 1];
            float c2 = Vs[kk][(tx << 2) + 2], c3 = Vs[kk][(tx << 2) + 3];
            acc[0][0] += a0 * c0; acc[0][1] += a0 * c1; acc[0][2] += a0 * c2; acc[0][3] += a0 * c3;
            acc[1][0] += a1 * c0; acc[1][1] += a1 * c1; acc[1][2] += a1 * c2; acc[1][3] += a1 * c3;
            acc[2][0] += a2 * c0; acc[2][1] += a2 * c1; acc[2][2] += a2 * c2; acc[2][3] += a2 * c3;
            acc[3][0] += a3 * c0; acc[3][1] += a3 * c1; acc[3][2] += a3 * c2; acc[3][3] += a3 * c3;
        }
    }

#pragma unroll
    for (int i = 0; i < 4; i++) {
        float4 o = make_float4(acc[i][0], acc[i][1], acc[i][2], acc[i][3]);
        *(float4*)(xcat + ((size_t)(b * Qn + q0 + (ty << 2) + i)) * 512 + coloff + h * 64 + (tx << 2)) = o;
    }
}

// ---------------------------------------------------------------------------
// Host-side launch sequence (graph-capturable: kernels only, default stream)
// ---------------------------------------------------------------------------
extern "C" void kernel_launch(void* const* d_in, const int* in_sizes, int n_in,
                              void* d_out, int out_size)
{
    (void)in_sizes; (void)out_size;
    // H and W scalars may or may not appear as inputs 3,4.
    const int s = (n_in >= 24) ? 2 : 0;

    const float* query   = (const float*)d_in[0];
    const float* key     = (const float*)d_in[1];
    const float* value   = (const float*)d_in[2];
    const float* q_w     = (const float*)d_in[3 + s];
    const float* sr1_w   = (const float*)d_in[4 + s];
    const float* sr1_b   = (const float*)d_in[5 + s];
    const float* norm1_w = (const float*)d_in[6 + s];
    const float* norm1_b = (const float*)d_in[7 + s];
    const float* sr2_w   = (const float*)d_in[8 + s];
    const float* sr2_b   = (const float*)d_in[9 + s];
    const float* norm2_w = (const float*)d_in[10 + s];
    const float* norm2_b = (const float*)d_in[11 + s];
    const float* k1_w    = (const float*)d_in[12 + s];
    /* v1_w (13+s) is intentionally unused: reference uses k1_w for v1 */
    const float* k2_w    = (const float*)d_in[14 + s];
    const float* v2_w    = (const float*)d_in[15 + s];
    const float* lc1_w   = (const float*)d_in[16 + s];
    const float* lc1_b   = (const float*)d_in[17 + s];
    const float* lc2_w   = (const float*)d_in[18 + s];
    const float* lc2_b   = (const float*)d_in[19 + s];
    const float* proj_w  = (const float*)d_in[20 + s];
    const float* proj_b  = (const float*)d_in[21 + s];
    float* out = (float*)d_out;

    float *qproj, *imgK, *imgV, *k1n, *v1n, *k2n, *v2n;
    float *k1, *v1, *k2, *v2, *v1r, *v2r, *attn, *xcat;
    cudaGetSymbolAddress((void**)&qproj, g_qproj);
    cudaGetSymbolAddress((void**)&imgK,  g_imgK);
    cudaGetSymbolAddress((void**)&imgV,  g_imgV);
    cudaGetSymbolAddress((void**)&k1n,   g_k1n);
    cudaGetSymbolAddress((void**)&v1n,   g_v1n);
    cudaGetSymbolAddress((void**)&k2n,   g_k2n);
    cudaGetSymbolAddress((void**)&v2n,   g_v2n);
    cudaGetSymbolAddress((void**)&k1,    g_k1);
    cudaGetSymbolAddress((void**)&v1,    g_v1);
    cudaGetSymbolAddress((void**)&k2,    g_k2);
    cudaGetSymbolAddress((void**)&v2,    g_v2);
    cudaGetSymbolAddress((void**)&v1r,   g_v1r);
    cudaGetSymbolAddress((void**)&v2r,   g_v2r);
    cudaGetSymbolAddress((void**)&attn,  g_attn);
    cudaGetSymbolAddress((void**)&xcat,  g_xcat);

    dim3 blk(256);

    // q projection: (16384,512) @ (512,512)^T
    sgemm_kernel<0><<<dim3(4, 128), blk>>>(query, q_w, nullptr, qproj, 16384, 512, 512);

    // (N,B,C) -> NCHW images
    to_image_kernel<<<4096, 256>>>(key, imgK);
    to_image_kernel<<<4096, 256>>>(value, imgV);

    // SR branch 1: 4x4 stride-4 conv as implicit-im2col GEMM (M=4096,K=8192,N=512)
    sgemm_kernel<1><<<dim3(4, 32), blk>>>(imgK, sr1_w, sr1_b, k1n, 4096, 512, 8192);
    sgemm_kernel<1><<<dim3(4, 32), blk>>>(imgV, sr1_w, sr1_b, v1n, 4096, 512, 8192);
    // SR branch 2: 2x2 stride-2 conv (M=16384,K=2048,N=512)
    sgemm_kernel<2><<<dim3(4, 128), blk>>>(imgK, sr2_w, sr2_b, k2n, 16384, 512, 2048);
    sgemm_kernel<2><<<dim3(4, 128), blk>>>(imgV, sr2_w, sr2_b, v2n, 16384, 512, 2048);

    // LayerNorm + GELU (in place)
    ln_gelu_kernel<<<4096, 256>>>(k1n, norm1_w, norm1_b);
    ln_gelu_kernel<<<4096, 256>>>(v1n, norm1_w, norm1_b);
    ln_gelu_kernel<<<16384, 256>>>(k2n, norm2_w, norm2_b);
    ln_gelu_kernel<<<16384, 256>>>(v2n, norm2_w, norm2_b);

    // K/V head projections (v1 uses k1_w — faithful to reference)
    sgemm_kernel<0><<<dim3(2, 32), blk>>>(k1n, k1_w, nullptr, k1, 4096, 256, 512);
    sgemm_kernel<0><<<dim3(2, 32), blk>>>(v1n, k1_w, nullptr, v1, 4096, 256, 512);
    sgemm_kernel<0><<<dim3(2, 128), blk>>>(k2n, k2_w, nullptr, k2, 16384, 256, 512);
    sgemm_kernel<0><<<dim3(2, 128), blk>>>(v2n, v2_w, nullptr, v2, 16384, 256, 512);

    // local depthwise 3x3 residual on V
    dwconv_res_kernel<<<(B_ * N1_ * C2_) / 256, 256>>>(v1, lc1_w, lc1_b, v1r, 16, 16);
    dwconv_res_kernel<<<(B_ * N2_ * C2_) / 256, 256>>>(v2, lc2_w, lc2_b, v2r, 32, 32);

    // attention branch 1 (heads 0..3, Nk=256)
    scores_kernel<<<dim3(N1_ / 64, Qn / 64, B_ * 4), blk>>>(qproj, k1, attn, N1_, 0);
    softmax_kernel<<<B_ * 4 * Qn, 256>>>(attn, N1_);
    pv_kernel<<<dim3(1, Qn / 64, B_ * 4), blk>>>(attn, v1r, xcat, N1_, 0);

    // attention branch 2 (q heads 4..7, Nk=1024)
    scores_kernel<<<dim3(N2_ / 64, Qn / 64, B_ * 4), blk>>>(qproj, k2, attn, N2_, 4);
    softmax_kernel<<<B_ * 4 * Qn, 256>>>(attn, N2_);
    pv_kernel<<<dim3(1, Qn / 64, B_ * 4), blk>>>(attn, v2r, xcat, N2_, 256);

    // output projection (writes d_out)
    sgemm_kernel<0><<<dim3(4, 128), blk>>>(xcat, proj_w, proj_b, out, 16384, 512, 512);
}

// round 3
// speedup vs baseline: 1.7669x; 1.7669x over previous
#include <cuda_runtime.h>
#include <cuda_bf16.h>
#include <math.h>
#include <stdint.h>

// ---------------------------------------------------------------------------
// Problem constants
// ---------------------------------------------------------------------------
constexpr int B_   = 16;
constexpr int C_   = 512;
constexpr int Qn   = 1024;
constexpr int C2_  = 256;
constexpr int N1_  = 256;    // 16x16 after stride-4 conv
constexpr int N2_  = 1024;   // 32x32 after stride-2 conv

// ---------------------------------------------------------------------------
// Device scratch
// ---------------------------------------------------------------------------
__device__ float g_qproj[(size_t)Qn * B_ * C_];
__device__ float g_img  [(size_t)2 * B_ * C_ * 64 * 64];        // K then V
__device__ float g_kv1n [(size_t)2 * B_ * N1_ * C_];
__device__ float g_kv2n [(size_t)2 * B_ * N2_ * C_];
__device__ float g_kv1  [(size_t)2 * B_ * N1_ * C2_];
__device__ float g_k2   [(size_t)B_ * N2_ * C2_];
__device__ float g_v2   [(size_t)B_ * N2_ * C2_];
__device__ float g_v1r  [(size_t)B_ * N1_ * C2_];
__device__ float g_v2r  [(size_t)B_ * N2_ * C2_];
__device__ float g_attn [(size_t)B_ * 4 * Qn * N2_];
__device__ float g_xcat [(size_t)B_ * Qn * C_];

// ---------------------------------------------------------------------------
// warp-MMA helpers (base-ISA: sm_80+, compiles under compute_103)
// ---------------------------------------------------------------------------
__device__ __forceinline__ uint32_t smem_u32(const void* p) {
    uint32_t a;
    asm("{ .reg .u64 t; cvta.to.shared.u64 t, %1; cvt.u32.u64 %0, t; }" : "=r"(a) : "l"(p));
    return a;
}
__device__ __forceinline__ void ldsm_x4(uint32_t& r0, uint32_t& r1, uint32_t& r2, uint32_t& r3,
                                        uint32_t addr) {
    asm volatile("ldmatrix.sync.aligned.m8n8.x4.shared.b16 {%0,%1,%2,%3}, [%4];"
                 : "=r"(r0), "=r"(r1), "=r"(r2), "=r"(r3) : "r"(addr));
}
__device__ __forceinline__ void mma_bf16(float* d,
                                         uint32_t a0, uint32_t a1, uint32_t a2, uint32_t a3,
                                         uint32_t b0, uint32_t b1) {
    asm volatile(
        "mma.sync.aligned.m16n8k16.row.col.f32.bf16.bf16.f32 "
        "{%0,%1,%2,%3}, {%4,%5,%6,%7}, {%8,%9}, {%0,%1,%2,%3};"
        : "+f"(d[0]), "+f"(d[1]), "+f"(d[2]), "+f"(d[3])
        : "r"(a0), "r"(a1), "r"(a2), "r"(a3), "r"(b0), "r"(b1));
}
__device__ __forceinline__ uint32_t pack_hi(float x, float y) {
    __nv_bfloat162 p(__float2bfloat16(x), __float2bfloat16(y));
    return *(uint32_t*)&p;
}
__device__ __forceinline__ uint32_t pack_lo(float x, float y) {
    float hx = __bfloat162float(__float2bfloat16(x));
    float hy = __bfloat162float(__float2bfloat16(y));
    __nv_bfloat162 p(__float2bfloat16(x - hx), __float2bfloat16(y - hy));
    return *(uint32_t*)&p;
}

// ---------------------------------------------------------------------------
// (N,B,C) -> raw-reshape "(B,C,H,W)" image
// ---------------------------------------------------------------------------
__global__ void to_image_kernel(const float* __restrict__ src, float* __restrict__ dst) {
    __shared__ float sm[16][513];
    size_t base = (size_t)blockIdx.x * 8192;
    for (int j = threadIdx.x; j < 8192; j += 256) sm[j >> 9][j & 511] = src[base + j];
    __syncthreads();
    for (int r = threadIdx.x; r < 8192; r += 256) dst[base + r] = sm[r & 15][r >> 4];
}

// ---------------------------------------------------------------------------
// Split-bf16 HMMA GEMM:  C[m,n] = sum_k A[m,k]*W[n,k] (+bias[n])
// Block tile 128x128, K-chunk 32 fp32. 8 warps (4M x 2N), warp tile 32x64.
// Per chunk: 3 split passes (hh, hl, lh) x 2 k16 steps of m16n8k16 MMA.
// LOADER 0: row-major A. LOADER 1: 4x4/s4 conv im2col. LOADER 2: 2x2/s2.
// ---------------------------------------------------------------------------
template <int LOADER>
__global__ __launch_bounds__(256) void hgemm_kernel(
    const float* __restrict__ A, const float* __restrict__ W,
    const float* __restrict__ bias, float* __restrict__ Cmat,
    int M, int N, int K)
{
    // stride 40 bf16 = 80B rows: ldmatrix phase banks row*20 mod 32 -> conflict-free
    __shared__ __align__(16) __nv_bfloat16 Ah[128][40];
    __shared__ __align__(16) __nv_bfloat16 Al[128][40];
    __shared__ __align__(16) __nv_bfloat16 Wh[128][40];
    __shared__ __align__(16) __nv_bfloat16 Wl[128][40];

    const int tid  = threadIdx.x;
    const int wid  = tid >> 5;
    const int lane = tid & 31;
    const int bm = blockIdx.y << 7;
    const int bn = blockIdx.x << 7;

    const int m0 = (wid & 3) << 5;   // warp M offset (32 rows)
    const int n0 = (wid >> 2) << 6;  // warp N offset (64 cols)

    const uint32_t AhB = smem_u32(Ah), AlB = smem_u32(Al);
    const uint32_t WhB = smem_u32(Wh), WlB = smem_u32(Wl);

    // ldmatrix row/quad offsets (bytes)
    const uint32_t lrow = (uint32_t)(lane & 15);
    const uint32_t lkq  = (uint32_t)(lane >> 4) * 16;   // 8 bf16 = 16B
    const uint32_t aOff0 = (m0 + lrow) * 80 + lkq;
    const uint32_t aOff1 = aOff0 + 16 * 80;
    uint32_t bOff[4];
#pragma unroll
    for (int nt = 0; nt < 4; nt++) bOff[nt] = (n0 + nt * 16 + lrow) * 80 + lkq;

    float acc[2][8][4];
#pragma unroll
    for (int i = 0; i < 2; i++)
#pragma unroll
        for (int j = 0; j < 8; j++)
#pragma unroll
            for (int l = 0; l < 4; l++) acc[i][j][l] = 0.f;

    const int nchunks = K >> 5;
    for (int c = 0; c < nchunks; c++) {
        const int k0 = c << 5;
        // ---- load 128x32 A and 128x32 W, split hi/lo into smem ----
#pragma unroll
        for (int it = 0; it < 4; it++) {
            const int i = tid + (it << 8);      // 0..1023 float4 slots
            const int r = i >> 3;
            const int kc = (i & 7) << 2;
            const int k = k0 + kc;

            float4 av;
            if (LOADER == 0) {
                av = *(const float4*)(A + (size_t)(bm + r) * K + k);
            } else if (LOADER == 1) {
                int m = bm + r;
                int b = m >> 8, oy = (m >> 4) & 15, ox = m & 15;
                int ic = k >> 4, ky = (k >> 2) & 3;
                av = *(const float4*)(A + (((size_t)(b * 512 + ic) * 64) + oy * 4 + ky) * 64 + ox * 4);
            } else {
                int m = bm + r;
                int b = m >> 10, oy = (m >> 5) & 31, ox = m & 31;
                int ic = k >> 2;
                const float* p = A + (((size_t)(b * 512 + ic) * 64) + oy * 2) * 64 + ox * 2;
                float2 r0 = *(const float2*)p;
                float2 r1 = *(const float2*)(p + 64);
                av = make_float4(r0.x, r0.y, r1.x, r1.y);
            }
            float4 wv = *(const float4*)(W + (size_t)(bn + r) * K + k);

            *(uint2*)&Ah[r][kc] = make_uint2(pack_hi(av.x, av.y), pack_hi(av.z, av.w));
            *(uint2*)&Al[r][kc] = make_uint2(pack_lo(av.x, av.y), pack_lo(av.z, av.w));
            *(uint2*)&Wh[r][kc] = make_uint2(pack_hi(wv.x, wv.y), pack_hi(wv.z, wv.w));
            *(uint2*)&Wl[r][kc] = make_uint2(pack_lo(wv.x, wv.y), pack_lo(wv.z, wv.w));
        }
        __syncthreads();

        // ---- 3 split passes x 2 k16 steps ----
#pragma unroll
        for (int s = 0; s < 3; s++) {
            const uint32_t ab = (s == 2) ? AlB : AhB;
            const uint32_t bb = (s == 1) ? WlB : WhB;
#pragma unroll
            for (int kh = 0; kh < 2; kh++) {
                const uint32_t ko = (uint32_t)kh * 32;  // 16 bf16 = 32B
                uint32_t a0, a1, a2, a3, a4, a5, a6, a7;
                ldsm_x4(a0, a1, a2, a3, ab + aOff0 + ko);
                ldsm_x4(a4, a5, a6, a7, ab + aOff1 + ko);
#pragma unroll
                for (int nt = 0; nt < 4; nt++) {
                    uint32_t b0, b1, b2, b3;
                    ldsm_x4(b0, b1, b2, b3, bb + bOff[nt] + ko);
                    mma_bf16(acc[0][nt * 2 + 0], a0, a1, a2, a3, b0, b2);
                    mma_bf16(acc[0][nt * 2 + 1], a0, a1, a2, a3, b1, b3);
                    mma_bf16(acc[1][nt * 2 + 0], a4, a5, a6, a7, b0, b2);
                    mma_bf16(acc[1][nt * 2 + 1], a4, a5, a6, a7, b1, b3);
                }
            }
        }
        __syncthreads();
    }

    // ---- epilogue ----
    const int gr = lane >> 2;      // 0..7
    const int gc = (lane & 3) * 2; // 0,2,4,6
#pragma unroll
    for (int mt = 0; mt < 2; mt++) {
        const int row0 = bm + m0 + mt * 16 + gr;
#pragma unroll
        for (int nt = 0; nt < 8; nt++) {
            const int col = bn + n0 + nt * 8 + gc;
            float b0 = bias ? bias[col] : 0.f;
            float b1 = bias ? bias[col + 1] : 0.f;
            *(float2*)(Cmat + (size_t)row0 * N + col) =
                make_float2(acc[mt][nt][0] + b0, acc[mt][nt][1] + b1);
            *(float2*)(Cmat + (size_t)(row0 + 8) * N + col) =
                make_float2(acc[mt][nt][2] + b0, acc[mt][nt][3] + b1);
        }
    }
}

// ---------------------------------------------------------------------------
// Fused LayerNorm(512) + exact GELU, in place
// ---------------------------------------------------------------------------
__global__ void ln_gelu_kernel(float* __restrict__ x,
                               const float* __restrict__ w,
                               const float* __restrict__ b)
{
    __shared__ float sh[8];
    float* row = x + (size_t)blockIdx.x * 512;
    int t = threadIdx.x;
    float v0 = row[t], v1 = row[t + 256];

    float s = v0 + v1;
#pragma unroll
    for (int o = 16; o; o >>= 1) s += __shfl_xor_sync(0xffffffffu, s, o);
    if ((t & 31) == 0) sh[t >> 5] = s;
    __syncthreads();
    float tot = 0.f;
#pragma unroll
    for (int i = 0; i < 8; i++) tot += sh[i];
    float mu = tot * (1.f / 512.f);
    float d0 = v0 - mu, d1 = v1 - mu;
    __syncthreads();

    float ss = d0 * d0 + d1 * d1;
#pragma unroll
    for (int o = 16; o; o >>= 1) ss += __shfl_xor_sync(0xffffffffu, ss, o);
    if ((t & 31) == 0) sh[t >> 5] = ss;
    __syncthreads();
    float tot2 = 0.f;
#pragma unroll
    for (int i = 0; i < 8; i++) tot2 += sh[i];
    float inv = rsqrtf(tot2 * (1.f / 512.f) + 1e-5f);

    float y0 = d0 * inv * w[t]       + b[t];
    float y1 = d1 * inv * w[t + 256] + b[t + 256];
    row[t]       = 0.5f * y0 * (1.f + erff(y0 * 0.7071067811865476f));
    row[t + 256] = 0.5f * y1 * (1.f + erff(y1 * 0.7071067811865476f));
}

// ---------------------------------------------------------------------------
// Depthwise 3x3 (pad 1) residual
// ---------------------------------------------------------------------------
__global__ void dwconv_res_kernel(const float* __restrict__ v,
                                  const float* __restrict__ lw,
                                  const float* __restrict__ lb,
                                  float* __restrict__ out,
                                  int hh, int ww)
{
    int idx = blockIdx.x * 256 + threadIdx.x;
    int c = idx & 255;
    int sp = idx >> 8;
    int Nn = hh * ww;
    int bb = sp / Nn;
    int n = sp - bb * Nn;
    int y = n / ww;
    int x = n - y * ww;

    float acc = lb[c];
#pragma unroll
    for (int dy = -1; dy <= 1; dy++) {
        int yy = y + dy;
        if (yy < 0 || yy >= hh) continue;
#pragma unroll
        for (int dx = -1; dx <= 1; dx++) {
            int xx = x + dx;
            if (xx < 0 || xx >= ww) continue;
            acc += v[((size_t)(bb * Nn + yy * ww + xx) << 8) + c] * lw[c * 9 + (dy + 1) * 3 + (dx + 1)];
        }
    }
    out[idx] = v[idx] + acc;
}

// ---------------------------------------------------------------------------
// Scores (fp32)
// ---------------------------------------------------------------------------
__global__ __launch_bounds__(256) void scores_kernel(
    const float* __restrict__ qp, const float* __restrict__ kb,
    float* __restrict__ attn, int Nk, int hoff)
{
    __shared__ float Qs[64][65];
    __shared__ float Ks[64][65];
    int bz = blockIdx.z;
    int b = bz >> 2, h = bz & 3;
    int q0 = blockIdx.y << 6, k0 = blockIdx.x << 6;
    int tid = threadIdx.x;

    for (int i = tid; i < 1024; i += 256) {
        int row = i >> 4;
        int d4 = (i & 15) << 2;
        float4 qv = *(const float4*)(qp + ((size_t)(b * Qn + q0 + row)) * 512 + (hoff + h) * 64 + d4);
        Qs[row][d4] = qv.x; Qs[row][d4 + 1] = qv.y; Qs[row][d4 + 2] = qv.z; Qs[row][d4 + 3] = qv.w;
        float4 kv = *(const float4*)(kb + ((size_t)(b * Nk + k0 + row)) * 256 + h * 64 + d4);
        Ks[row][d4] = kv.x; Ks[row][d4 + 1] = kv.y; Ks[row][d4 + 2] = kv.z; Ks[row][d4 + 3] = kv.w;
    }
    __syncthreads();

    int tx = tid & 15, ty = tid >> 4;
    float acc[4][4];
#pragma unroll
    for (int i = 0; i < 4; i++)
#pragma unroll
        for (int j = 0; j < 4; j++) acc[i][j] = 0.f;

#pragma unroll 8
    for (int d = 0; d < 64; d++) {
        float a0 = Qs[(ty << 2) + 0][d], a1 = Qs[(ty << 2) + 1][d];
        float a2 = Qs[(ty << 2) + 2][d], a3 = Qs[(ty << 2) + 3][d];
        float c0 = Ks[(tx << 2) + 0][d], c1 = Ks[(tx << 2) + 1][d];
        float c2 = Ks[(tx << 2) + 2][d], c3 = Ks[(tx << 2) + 3][d];
        acc[0][0] += a0 * c0; acc[0][1] += a0 * c1; acc[0][2] += a0 * c2; acc[0][3] += a0 * c3;
        acc[1][0] += a1 * c0; acc[1][1] += a1 * c1; acc[1][2] += a1 * c2; acc[1][3] += a1 * c3;
        acc[2][0] += a2 * c0; acc[2][1] += a2 * c1; acc[2][2] += a2 * c2; acc[2][3] += a2 * c3;
        acc[3][0] += a3 * c0; acc[3][1] += a3 * c1; acc[3][2] += a3 * c2; acc[3][3] += a3 * c3;
    }

    const float scale = 0.125f;
#pragma unroll
    for (int i = 0; i < 4; i++) {
        float4 o = make_float4(acc[i][0] * scale, acc[i][1] * scale, acc[i][2] * scale, acc[i][3] * scale);
        *(float4*)(attn + ((size_t)bz * Qn + q0 + (ty << 2) + i) * Nk + k0 + (tx << 2)) = o;
    }
}

// ---------------------------------------------------------------------------
// Row softmax
// ---------------------------------------------------------------------------
__global__ void softmax_kernel(float* __restrict__ attn, int L) {
    __shared__ float sh[8];
    float* row = attn + (size_t)blockIdx.x * L;
    int t = threadIdx.x;

    float m = -1e30f;
    for (int i = t; i < L; i += 256) m = fmaxf(m, row[i]);
#pragma unroll
    for (int o = 16; o; o >>= 1) m = fmaxf(m, __shfl_xor_sync(0xffffffffu, m, o));
    if ((t & 31) == 0) sh[t >> 5] = m;
    __syncthreads();
    float mm = sh[0];
#pragma unroll
    for (int i = 1; i < 8; i++) mm = fmaxf(mm, sh[i]);
    __syncthreads();

    float s = 0.f;
    for (int i = t; i < L; i += 256) {
        float e = __expf(row[i] - mm);
        row[i] = e;
        s += e;
    }
#pragma unroll
    for (int o = 16; o; o >>= 1) s += __shfl_xor_sync(0xffffffffu, s, o);
    if ((t & 31) == 0) sh[t >> 5] = s;
    __syncthreads();
    float tot = 0.f;
#pragma unroll
    for (int i = 0; i < 8; i++) tot += sh[i];
    float inv = 1.f / tot;
    for (int i = t; i < L; i += 256) row[i] *= inv;
}

// ---------------------------------------------------------------------------
// PV (fp32)
// ---------------------------------------------------------------------------
__global__ __launch_bounds__(256) void pv_kernel(
    const float* __restrict__ attn, const float* __restrict__ vb,
    float* __restrict__ xcat, int Nk, int coloff)
{
    __shared__ float As[64][65];
    __shared__ float Vs[64][65];
    int bz = blockIdx.z;
    int b = bz >> 2, h = bz & 3;
    int q0 = blockIdx.y << 6;
    int tid = threadIdx.x;
    int tx = tid & 15, ty = tid >> 4;

    float acc[4][4];
#pragma unroll
    for (int i = 0; i < 4; i++)
#pragma unroll
        for (int j = 0; j < 4; j++) acc[i][j] = 0.f;

    for (int kc = 0; kc < Nk; kc += 64) {
        __syncthreads();
        for (int i = tid; i < 1024; i += 256) {
            int row = i >> 4;
            int c4 = (i & 15) << 2;
            float4 av = *(const float4*)(attn + ((size_t)bz * Qn + q0 + row) * Nk + kc + c4);
            As[row][c4] = av.x; As[row][c4 + 1] = av.y; As[row][c4 + 2] = av.z; As[row][c4 + 3] = av.w;
            float4 vv = *(const float4*)(vb + ((size_t)(b * Nk + kc + row)) * 256 + h * 64 + c4);
            Vs[row][c4] = vv.x; Vs[row][c4 + 1] = vv.y; Vs[row][c4 + 2] = vv.z; Vs[row][c4 + 3] = vv.w;
        }
        __syncthreads();
#pragma unroll 4
        for (int kk = 0; kk < 64; kk++) {
            float a0 = As[(ty << 2) + 0][kk], a1 = As[(ty << 2) + 1][kk];
            float a2 = As[(ty << 2) + 2][kk], a3 = As[(ty << 2) + 3][kk];
            float c0 = Vs[kk][(tx << 2) + 0], c1 = Vs[kk][(tx << 2) + 1];
            float c2 = Vs[kk][(tx << 2) + 2], c3 = Vs[kk][(tx << 2) + 3];
            acc[0][0] += a0 * c0; acc[0][1] += a0 * c1; acc[0][2] += a0 * c2; acc[0][3] += a0 * c3;
            acc[1][0] += a1 * c0; acc[1][1] += a1 * c1; acc[1][2] += a1 * c2; acc[1][3] += a1 * c3;
            acc[2][0] += a2 * c0; acc[2][1] += a2 * c1; acc[2][2] += a2 * c2; acc[2][3] += a2 * c3;
            acc[3][0] += a3 * c0; acc[3][1] += a3 * c1; acc[3][2] += a3 * c2; acc[3][3] += a3 * c3;
        }
    }

#pragma unroll
    for (int i = 0; i < 4; i++) {
        float4 o = make_float4(acc[i][0], acc[i][1], acc[i][2], acc[i][3]);
        *(float4*)(xcat + ((size_t)(b * Qn + q0 + (ty << 2) + i)) * 512 + coloff + h * 64 + (tx << 2)) = o;
    }
}

// ---------------------------------------------------------------------------
// Host launch sequence
// ---------------------------------------------------------------------------
extern "C" void kernel_launch(void* const* d_in, const int* in_sizes, int n_in,
                              void* d_out, int out_size)
{
    (void)in_sizes; (void)out_size;
    const int s = (n_in >= 24) ? 2 : 0;

    const float* query   = (const float*)d_in[0];
    const float* key     = (const float*)d_in[1];
    const float* value   = (const float*)d_in[2];
    const float* q_w     = (const float*)d_in[3 + s];
    const float* sr1_w   = (const float*)d_in[4 + s];
    const float* sr1_b   = (const float*)d_in[5 + s];
    const float* norm1_w = (const float*)d_in[6 + s];
    const float* norm1_b = (const float*)d_in[7 + s];
    const float* sr2_w   = (const float*)d_in[8 + s];
    const float* sr2_b   = (const float*)d_in[9 + s];
    const float* norm2_w = (const float*)d_in[10 + s];
    const float* norm2_b = (const float*)d_in[11 + s];
    const float* k1_w    = (const float*)d_in[12 + s];
    /* v1_w unused: reference applies k1_w to value_1 */
    const float* k2_w    = (const float*)d_in[14 + s];
    const float* v2_w    = (const float*)d_in[15 + s];
    const float* lc1_w   = (const float*)d_in[16 + s];
    const float* lc1_b   = (const float*)d_in[17 + s];
    const float* lc2_w   = (const float*)d_in[18 + s];
    const float* lc2_b   = (const float*)d_in[19 + s];
    const float* proj_w  = (const float*)d_in[20 + s];
    const float* proj_b  = (const float*)d_in[21 + s];
    float* out = (float*)d_out;

    float *qproj, *img, *kv1n, *kv2n, *kv1, *k2, *v2, *v1r, *v2r, *attn, *xcat;
    cudaGetSymbolAddress((void**)&qproj, g_qproj);
    cudaGetSymbolAddress((void**)&img,   g_img);
    cudaGetSymbolAddress((void**)&kv1n,  g_kv1n);
    cudaGetSymbolAddress((void**)&kv2n,  g_kv2n);
    cudaGetSymbolAddress((void**)&kv1,   g_kv1);
    cudaGetSymbolAddress((void**)&k2,    g_k2);
    cudaGetSymbolAddress((void**)&v2,    g_v2);
    cudaGetSymbolAddress((void**)&v1r,   g_v1r);
    cudaGetSymbolAddress((void**)&v2r,   g_v2r);
    cudaGetSymbolAddress((void**)&attn,  g_attn);
    cudaGetSymbolAddress((void**)&xcat,  g_xcat);

    const size_t IMG1 = (size_t)B_ * C_ * 64 * 64;
    float* k1 = kv1;
    float* v1 = kv1 + (size_t)B_ * N1_ * C2_;

    dim3 blk(256);

    // q projection
    hgemm_kernel<0><<<dim3(4, 128), blk>>>(query, q_w, nullptr, qproj, 16384, 512, 512);

    // images (K at 0, V at IMG1)
    to_image_kernel<<<4096, 256>>>(key, img);
    to_image_kernel<<<4096, 256>>>(value, img + IMG1);

    // SR convs as implicit-im2col GEMMs (K+V fused in M)
    hgemm_kernel<1><<<dim3(4, 64),  blk>>>(img, sr1_w, sr1_b, kv1n, 8192,  512, 8192);
    hgemm_kernel<2><<<dim3(4, 256), blk>>>(img, sr2_w, sr2_b, kv2n, 32768, 512, 2048);

    // LayerNorm + GELU
    ln_gelu_kernel<<<8192,  256>>>(kv1n, norm1_w, norm1_b);
    ln_gelu_kernel<<<32768, 256>>>(kv2n, norm2_w, norm2_b);

    // head projections (branch1 k/v fused through k1_w)
    hgemm_kernel<0><<<dim3(2, 64),  blk>>>(kv1n, k1_w, nullptr, kv1, 8192, 256, 512);
    hgemm_kernel<0><<<dim3(2, 128), blk>>>(kv2n, k2_w, nullptr, k2, 16384, 256, 512);
    hgemm_kernel<0><<<dim3(2, 128), blk>>>(kv2n + (size_t)16384 * 512, v2_w, nullptr, v2, 16384, 256, 512);

    // local depthwise 3x3 residual
    dwconv_res_kernel<<<(B_ * N1_ * C2_) / 256, 256>>>(v1, lc1_w, lc1_b, v1r, 16, 16);
    dwconv_res_kernel<<<(B_ * N2_ * C2_) / 256, 256>>>(v2, lc2_w, lc2_b, v2r, 32, 32);

    // attention branch 1 (heads 0..3, Nk=256)
    scores_kernel<<<dim3(N1_ / 64, Qn / 64, B_ * 4), blk>>>(qproj, k1, attn, N1_, 0);
    softmax_kernel<<<B_ * 4 * Qn, 256>>>(attn, N1_);
    pv_kernel<<<dim3(1, Qn / 64, B_ * 4), blk>>>(attn, v1r, xcat, N1_, 0);

    // attention branch 2 (heads 4..7, Nk=1024)
    scores_kernel<<<dim3(N2_ / 64, Qn / 64, B_ * 4), blk>>>(qproj, k2, attn, N2_, 4);
    softmax_kernel<<<B_ * 4 * Qn, 256>>>(attn, N2_);
    pv_kernel<<<dim3(1, Qn / 64, B_ * 4), blk>>>(attn, v2r, xcat, N2_, 256);

    // output projection
    hgemm_kernel<0><<<dim3(4, 128), blk>>>(xcat, proj_w, proj_b, out, 16384, 512, 512);
}

// round 4
// speedup vs baseline: 2.1657x; 1.2257x over previous
#include <cuda_runtime.h>
#include <cuda_bf16.h>
#include <math.h>
#include <stdint.h>

// ---------------------------------------------------------------------------
// Problem constants
// ---------------------------------------------------------------------------
constexpr int B_   = 16;
constexpr int C_   = 512;
constexpr int Qn   = 1024;
constexpr int C2_  = 256;
constexpr int N1_  = 256;
constexpr int N2_  = 1024;

// ---------------------------------------------------------------------------
// Device scratch
// ---------------------------------------------------------------------------
__device__ float g_qproj[(size_t)Qn * B_ * C_];
__device__ float g_kv1n [(size_t)2 * B_ * N1_ * C_];
__device__ float g_kv2n [(size_t)2 * B_ * N2_ * C_];
__device__ float g_kv1  [(size_t)2 * B_ * N1_ * C2_];
__device__ float g_k2   [(size_t)B_ * N2_ * C2_];
__device__ float g_v2   [(size_t)B_ * N2_ * C2_];
__device__ float g_v1r  [(size_t)B_ * N1_ * C2_];
__device__ float g_v2r  [(size_t)B_ * N2_ * C2_];
__device__ float g_attn [(size_t)B_ * 4 * Qn * N2_];
__device__ float g_xcat [(size_t)B_ * Qn * C_];

// bf16 hi/lo planes
__device__ __nv_bfloat16 g_qh  [(size_t)16384 * 512];
__device__ __nv_bfloat16 g_ql  [(size_t)16384 * 512];
__device__ __nv_bfloat16 g_imgh[(size_t)2 * B_ * C_ * 64 * 64];
__device__ __nv_bfloat16 g_imgl[(size_t)2 * B_ * C_ * 64 * 64];
__device__ __nv_bfloat16 g_kv1nh[(size_t)8192 * 512];
__device__ __nv_bfloat16 g_kv1nl[(size_t)8192 * 512];
__device__ __nv_bfloat16 g_kv2nh[(size_t)32768 * 512];
__device__ __nv_bfloat16 g_kv2nl[(size_t)32768 * 512];
__device__ __nv_bfloat16 g_xh  [(size_t)16384 * 512];
__device__ __nv_bfloat16 g_xl  [(size_t)16384 * 512];
// weight planes
__device__ __nv_bfloat16 g_qwh [262144],  g_qwl [262144];
__device__ __nv_bfloat16 g_s1wh[4194304], g_s1wl[4194304];
__device__ __nv_bfloat16 g_s2wh[1048576], g_s2wl[1048576];
__device__ __nv_bfloat16 g_k1wh[131072],  g_k1wl[131072];
__device__ __nv_bfloat16 g_k2wh[131072],  g_k2wl[131072];
__device__ __nv_bfloat16 g_v2wh[131072],  g_v2wl[131072];
__device__ __nv_bfloat16 g_pwh [262144],  g_pwl [262144];

// ---------------------------------------------------------------------------
// helpers
// ---------------------------------------------------------------------------
__device__ __forceinline__ uint32_t smem_u32(const void* p) {
    uint32_t a;
    asm("{ .reg .u64 t; cvta.to.shared.u64 t, %1; cvt.u32.u64 %0, t; }" : "=r"(a) : "l"(p));
    return a;
}
__device__ __forceinline__ void ldsm_x4(uint32_t& r0, uint32_t& r1, uint32_t& r2, uint32_t& r3,
                                        uint32_t addr) {
    asm volatile("ldmatrix.sync.aligned.m8n8.x4.shared.b16 {%0,%1,%2,%3}, [%4];"
                 : "=r"(r0), "=r"(r1), "=r"(r2), "=r"(r3) : "r"(addr));
}
__device__ __forceinline__ void mma_bf16(float* d,
                                         uint32_t a0, uint32_t a1, uint32_t a2, uint32_t a3,
                                         uint32_t b0, uint32_t b1) {
    asm volatile(
        "mma.sync.aligned.m16n8k16.row.col.f32.bf16.bf16.f32 "
        "{%0,%1,%2,%3}, {%4,%5,%6,%7}, {%8,%9}, {%0,%1,%2,%3};"
        : "+f"(d[0]), "+f"(d[1]), "+f"(d[2]), "+f"(d[3])
        : "r"(a0), "r"(a1), "r"(a2), "r"(a3), "r"(b0), "r"(b1));
}
__device__ __forceinline__ uint32_t pack_hi(float x, float y) {
    __nv_bfloat162 p(__float2bfloat16(x), __float2bfloat16(y));
    return *(uint32_t*)&p;
}
__device__ __forceinline__ uint32_t pack_lo(float x, float y) {
    float hx = __bfloat162float(__float2bfloat16(x));
    float hy = __bfloat162float(__float2bfloat16(y));
    __nv_bfloat162 p(__float2bfloat16(x - hx), __float2bfloat16(y - hy));
    return *(uint32_t*)&p;
}

// ---------------------------------------------------------------------------
// generic fp32 -> hi/lo bf16 planes (n multiple of 1024)
// ---------------------------------------------------------------------------
__global__ void split_kernel(const float* __restrict__ src,
                             __nv_bfloat16* __restrict__ h,
                             __nv_bfloat16* __restrict__ l)
{
    int i = blockIdx.x * 256 + threadIdx.x;
    float4 v = ((const float4*)src)[i];
    ((uint2*)h)[i] = make_uint2(pack_hi(v.x, v.y), pack_hi(v.z, v.w));
    ((uint2*)l)[i] = make_uint2(pack_lo(v.x, v.y), pack_lo(v.z, v.w));
}

// ---------------------------------------------------------------------------
// (N,B,C) -> raw-reshape image, split into bf16 hi/lo planes
// ---------------------------------------------------------------------------
__global__ void to_image_split_kernel(const float* __restrict__ src,
                                      __nv_bfloat16* __restrict__ h,
                                      __nv_bfloat16* __restrict__ l)
{
    __shared__ float sm[16][513];
    size_t base = (size_t)blockIdx.x * 8192;
    for (int j = threadIdx.x; j < 8192; j += 256) sm[j >> 9][j & 511] = src[base + j];
    __syncthreads();
    for (int r = threadIdx.x; r < 8192; r += 256) {
        float v = sm[r & 15][r >> 4];
        __nv_bfloat16 hv = __float2bfloat16(v);
        h[base + r] = hv;
        l[base + r] = __float2bfloat16(v - __bfloat162float(hv));
    }
}

// ---------------------------------------------------------------------------
// Split-bf16 HMMA GEMM, pipelined, operands pre-converted to bf16 planes.
// Block 128x128, 8 warps (4Mx2N), K-chunk 32. reg-prefetch + double smem buf.
// LOADER 0: row-major planes. LOADER 1: 4x4/s4 conv on image planes.
// LOADER 2: 2x2/s2 conv on image planes.
// ---------------------------------------------------------------------------
template <int LOADER>
__global__ __launch_bounds__(256) void hgemm2_kernel(
    const __nv_bfloat16* __restrict__ Ah, const __nv_bfloat16* __restrict__ Al,
    const __nv_bfloat16* __restrict__ Wh, const __nv_bfloat16* __restrict__ Wl,
    const float* __restrict__ bias, float* __restrict__ Cmat,
    int M, int N, int K)
{
    extern __shared__ char smc[];                  // 2 bufs x 4 tiles x 128 x 80B
    const uint32_t sb = smem_u32(smc);

    const int tid  = threadIdx.x;
    const int wid  = tid >> 5;
    const int lane = tid & 31;
    const int bm = blockIdx.y << 7;
    const int bn = blockIdx.x << 7;
    const int m0 = (wid & 3) << 5;
    const int n0 = (wid >> 2) << 6;

    // per-thread load slots: 4 per plane-operand; slot s: row r=s>>3, kcol (s&7)*4
    int rr[4], kk[4];
#pragma unroll
    for (int j = 0; j < 4; j++) {
        int s = tid + (j << 8);
        rr[j] = s >> 3;
        kk[j] = (s & 7) << 2;
    }

    // ldmatrix offsets (bytes within one tile; row stride 80B)
    const uint32_t lrow = (uint32_t)(lane & 15);
    const uint32_t lkq  = (uint32_t)(lane >> 4) * 16;
    const uint32_t aOff0 = (m0 + lrow) * 80 + lkq;
    const uint32_t aOff1 = aOff0 + 16 * 80;
    uint32_t bOff[4];
#pragma unroll
    for (int nt = 0; nt < 4; nt++) bOff[nt] = (n0 + nt * 16 + lrow) * 80 + lkq;

    float acc[2][8][4];
#pragma unroll
    for (int i = 0; i < 2; i++)
#pragma unroll
        for (int j = 0; j < 8; j++)
#pragma unroll
            for (int l = 0; l < 4; l++) acc[i][j][l] = 0.f;

    uint2 pre[16];

    auto fetchA = [&](const __nv_bfloat16* plane, int r, int k) -> uint2 {
        if (LOADER == 0) {
            return *(const uint2*)(plane + (size_t)(bm + r) * K + k);
        } else if (LOADER == 1) {
            int m = bm + r;
            int b = m >> 8, oy = (m >> 4) & 15, ox = m & 15;
            int ic = k >> 4, ky = (k >> 2) & 3;
            return *(const uint2*)(plane + (((size_t)(b * 512 + ic) * 64) + oy * 4 + ky) * 64 + ox * 4);
        } else {
            int m = bm + r;
            int b = m >> 10, oy = (m >> 5) & 31, ox = m & 31;
            int ic = k >> 2;
            const __nv_bfloat16* p = plane + (((size_t)(b * 512 + ic) * 64) + oy * 2) * 64 + ox * 2;
            return make_uint2(*(const uint32_t*)p, *(const uint32_t*)(p + 64));
        }
    };

    auto load_chunk = [&](int k0) {
#pragma unroll
        for (int j = 0; j < 4; j++) {
            pre[0  + j] = fetchA(Ah, rr[j], k0 + kk[j]);
            pre[4  + j] = fetchA(Al, rr[j], k0 + kk[j]);
            pre[8  + j] = *(const uint2*)(Wh + (size_t)(bn + rr[j]) * K + k0 + kk[j]);
            pre[12 + j] = *(const uint2*)(Wl + (size_t)(bn + rr[j]) * K + k0 + kk[j]);
        }
    };
    auto store_chunk = [&](int buf) {
        const uint32_t bb = sb + (uint32_t)buf * 40960;
#pragma unroll
        for (int p = 0; p < 4; p++)
#pragma unroll
            for (int j = 0; j < 4; j++) {
                uint32_t off = bb + (uint32_t)p * 10240 + (uint32_t)rr[j] * 80 + (uint32_t)(kk[j] << 1);
                asm volatile("st.shared.v2.u32 [%0], {%1, %2};"
                             :: "r"(off), "r"(pre[p * 4 + j].x), "r"(pre[p * 4 + j].y) : "memory");
            }
    };

    const int nchunks = K >> 5;
    load_chunk(0);
    store_chunk(0);
    __syncthreads();

    for (int c = 0; c < nchunks; c++) {
        const bool more = (c + 1) < nchunks;
        if (more) load_chunk((c + 1) << 5);

        // ---- MMA on buffer c&1 ----
        const uint32_t bb = sb + (uint32_t)(c & 1) * 40960;
        const uint32_t AhB = bb, AlB = bb + 10240, WhB = bb + 20480, WlB = bb + 30720;
#pragma unroll
        for (int s = 0; s < 3; s++) {
            const uint32_t ab = (s == 2) ? AlB : AhB;
            const uint32_t wb = (s == 1) ? WlB : WhB;
#pragma unroll
            for (int kh = 0; kh < 2; kh++) {
                const uint32_t ko = (uint32_t)kh * 32;
                uint32_t a0, a1, a2, a3, a4, a5, a6, a7;
                ldsm_x4(a0, a1, a2, a3, ab + aOff0 + ko);
                ldsm_x4(a4, a5, a6, a7, ab + aOff1 + ko);
#pragma unroll
                for (int nt = 0; nt < 4; nt++) {
                    uint32_t b0, b1, b2, b3;
                    ldsm_x4(b0, b1, b2, b3, wb + bOff[nt] + ko);
                    mma_bf16(acc[0][nt * 2 + 0], a0, a1, a2, a3, b0, b2);
                    mma_bf16(acc[0][nt * 2 + 1], a0, a1, a2, a3, b1, b3);
                    mma_bf16(acc[1][nt * 2 + 0], a4, a5, a6, a7, b0, b2);
                    mma_bf16(acc[1][nt * 2 + 1], a4, a5, a6, a7, b1, b3);
                }
            }
        }

        if (more) store_chunk((c + 1) & 1);
        __syncthreads();
    }

    // ---- epilogue ----
    const int gr = lane >> 2;
    const int gc = (lane & 3) * 2;
#pragma unroll
    for (int mt = 0; mt < 2; mt++) {
        const int row0 = bm + m0 + mt * 16 + gr;
#pragma unroll
        for (int nt = 0; nt < 8; nt++) {
            const int col = bn + n0 + nt * 8 + gc;
            float b0 = bias ? bias[col] : 0.f;
            float b1 = bias ? bias[col + 1] : 0.f;
            *(float2*)(Cmat + (size_t)row0 * N + col) =
                make_float2(acc[mt][nt][0] + b0, acc[mt][nt][1] + b1);
            *(float2*)(Cmat + (size_t)(row0 + 8) * N + col) =
                make_float2(acc[mt][nt][2] + b0, acc[mt][nt][3] + b1);
        }
    }
}

// ---------------------------------------------------------------------------
// LayerNorm(512) + exact GELU -> bf16 hi/lo planes
// ---------------------------------------------------------------------------
__global__ void ln_gelu_split_kernel(const float* __restrict__ x,
                                     const float* __restrict__ w,
                                     const float* __restrict__ b,
                                     __nv_bfloat16* __restrict__ hO,
                                     __nv_bfloat16* __restrict__ lO)
{
    __shared__ float sh[8];
    const float* row = x + (size_t)blockIdx.x * 512;
    int t = threadIdx.x;
    float2 v = *(const float2*)(row + t * 2);

    float s = v.x + v.y;
#pragma unroll
    for (int o = 16; o; o >>= 1) s += __shfl_xor_sync(0xffffffffu, s, o);
    if ((t & 31) == 0) sh[t >> 5] = s;
    __syncthreads();
    float tot = 0.f;
#pragma unroll
    for (int i = 0; i < 8; i++) tot += sh[i];
    float mu = tot * (1.f / 512.f);
    float d0 = v.x - mu, d1 = v.y - mu;
    __syncthreads();

    float ss = d0 * d0 + d1 * d1;
#pragma unroll
    for (int o = 16; o; o >>= 1) ss += __shfl_xor_sync(0xffffffffu, ss, o);
    if ((t & 31) == 0) sh[t >> 5] = ss;
    __syncthreads();
    float tot2 = 0.f;
#pragma unroll
    for (int i = 0; i < 8; i++) tot2 += sh[i];
    float inv = rsqrtf(tot2 * (1.f / 512.f) + 1e-5f);

    float y0 = d0 * inv * w[t * 2]     + b[t * 2];
    float y1 = d1 * inv * w[t * 2 + 1] + b[t * 2 + 1];
    y0 = 0.5f * y0 * (1.f + erff(y0 * 0.7071067811865476f));
    y1 = 0.5f * y1 * (1.f + erff(y1 * 0.7071067811865476f));

    size_t o = (size_t)blockIdx.x * 256 + t;
    ((uint32_t*)hO)[o] = pack_hi(y0, y1);
    ((uint32_t*)lO)[o] = pack_lo(y0, y1);
}

// ---------------------------------------------------------------------------
// Depthwise 3x3 (pad 1) residual
// ---------------------------------------------------------------------------
__global__ void dwconv_res_kernel(const float* __restrict__ v,
                                  const float* __restrict__ lw,
                                  const float* __restrict__ lb,
                                  float* __restrict__ out,
                                  int hh, int ww)
{
    int idx = blockIdx.x * 256 + threadIdx.x;
    int c = idx & 255;
    int sp = idx >> 8;
    int Nn = hh * ww;
    int bb = sp / Nn;
    int n = sp - bb * Nn;
    int y = n / ww;
    int x = n - y * ww;

    float acc = lb[c];
#pragma unroll
    for (int dy = -1; dy <= 1; dy++) {
        int yy = y + dy;
        if (yy < 0 || yy >= hh) continue;
#pragma unroll
        for (int dx = -1; dx <= 1; dx++) {
            int xx = x + dx;
            if (xx < 0 || xx >= ww) continue;
            acc += v[((size_t)(bb * Nn + yy * ww + xx) << 8) + c] * lw[c * 9 + (dy + 1) * 3 + (dx + 1)];
        }
    }
    out[idx] = v[idx] + acc;
}

// ---------------------------------------------------------------------------
// Scores (fp32)
// ---------------------------------------------------------------------------
__global__ __launch_bounds__(256) void scores_kernel(
    const float* __restrict__ qp, const float* __restrict__ kb,
    float* __restrict__ attn, int Nk, int hoff)
{
    __shared__ float Qs[64][65];
    __shared__ float Ks[64][65];
    int bz = blockIdx.z;
    int b = bz >> 2, h = bz & 3;
    int q0 = blockIdx.y << 6, k0 = blockIdx.x << 6;
    int tid = threadIdx.x;

    for (int i = tid; i < 1024; i += 256) {
        int row = i >> 4;
        int d4 = (i & 15) << 2;
        float4 qv = *(const float4*)(qp + ((size_t)(b * Qn + q0 + row)) * 512 + (hoff + h) * 64 + d4);
        Qs[row][d4] = qv.x; Qs[row][d4 + 1] = qv.y; Qs[row][d4 + 2] = qv.z; Qs[row][d4 + 3] = qv.w;
        float4 kv = *(const float4*)(kb + ((size_t)(b * Nk + k0 + row)) * 256 + h * 64 + d4);
        Ks[row][d4] = kv.x; Ks[row][d4 + 1] = kv.y; Ks[row][d4 + 2] = kv.z; Ks[row][d4 + 3] = kv.w;
    }
    __syncthreads();

    int tx = tid & 15, ty = tid >> 4;
    float acc[4][4];
#pragma unroll
    for (int i = 0; i < 4; i++)
#pragma unroll
        for (int j = 0; j < 4; j++) acc[i][j] = 0.f;

#pragma unroll 8
    for (int d = 0; d < 64; d++) {
        float a0 = Qs[(ty << 2) + 0][d], a1 = Qs[(ty << 2) + 1][d];
        float a2 = Qs[(ty << 2) + 2][d], a3 = Qs[(ty << 2) + 3][d];
        float c0 = Ks[(tx << 2) + 0][d], c1 = Ks[(tx << 2) + 1][d];
        float c2 = Ks[(tx << 2) + 2][d], c3 = Ks[(tx << 2) + 3][d];
        acc[0][0] += a0 * c0; acc[0][1] += a0 * c1; acc[0][2] += a0 * c2; acc[0][3] += a0 * c3;
        acc[1][0] += a1 * c0; acc[1][1] += a1 * c1; acc[1][2] += a1 * c2; acc[1][3] += a1 * c3;
        acc[2][0] += a2 * c0; acc[2][1] += a2 * c1; acc[2][2] += a2 * c2; acc[2][3] += a2 * c3;
        acc[3][0] += a3 * c0; acc[3][1] += a3 * c1; acc[3][2] += a3 * c2; acc[3][3] += a3 * c3;
    }

    const float scale = 0.125f;
#pragma unroll
    for (int i = 0; i < 4; i++) {
        float4 o = make_float4(acc[i][0] * scale, acc[i][1] * scale, acc[i][2] * scale, acc[i][3] * scale);
        *(float4*)(attn + ((size_t)bz * Qn + q0 + (ty << 2) + i) * Nk + k0 + (tx << 2)) = o;
    }
}

// ---------------------------------------------------------------------------
// Row softmax
// ---------------------------------------------------------------------------
__global__ void softmax_kernel(float* __restrict__ attn, int L) {
    __shared__ float sh[8];
    float* row = attn + (size_t)blockIdx.x * L;
    int t = threadIdx.x;

    float m = -1e30f;
    for (int i = t; i < L; i += 256) m = fmaxf(m, row[i]);
#pragma unroll
    for (int o = 16; o; o >>= 1) m = fmaxf(m, __shfl_xor_sync(0xffffffffu, m, o));
    if ((t & 31) == 0) sh[t >> 5] = m;
    __syncthreads();
    float mm = sh[0];
#pragma unroll
    for (int i = 1; i < 8; i++) mm = fmaxf(mm, sh[i]);
    __syncthreads();

    float s = 0.f;
    for (int i = t; i < L; i += 256) {
        float e = __expf(row[i] - mm);
        row[i] = e;
        s += e;
    }
#pragma unroll
    for (int o = 16; o; o >>= 1) s += __shfl_xor_sync(0xffffffffu, s, o);
    if ((t & 31) == 0) sh[t >> 5] = s;
    __syncthreads();
    float tot = 0.f;
#pragma unroll
    for (int i = 0; i < 8; i++) tot += sh[i];
    float inv = 1.f / tot;
    for (int i = t; i < L; i += 256) row[i] *= inv;
}

// ---------------------------------------------------------------------------
// PV (fp32)
// ---------------------------------------------------------------------------
__global__ __launch_bounds__(256) void pv_kernel(
    const float* __restrict__ attn, const float* __restrict__ vb,
    float* __restrict__ xcat, int Nk, int coloff)
{
    __shared__ float As[64][65];
    __shared__ float Vs[64][65];
    int bz = blockIdx.z;
    int b = bz >> 2, h = bz & 3;
    int q0 = blockIdx.y << 6;
    int tid = threadIdx.x;
    int tx = tid & 15, ty = tid >> 4;

    float acc[4][4];
#pragma unroll
    for (int i = 0; i < 4; i++)
#pragma unroll
        for (int j = 0; j < 4; j++) acc[i][j] = 0.f;

    for (int kc = 0; kc < Nk; kc += 64) {
        __syncthreads();
        for (int i = tid; i < 1024; i += 256) {
            int row = i >> 4;
            int c4 = (i & 15) << 2;
            float4 av = *(const float4*)(attn + ((size_t)bz * Qn + q0 + row) * Nk + kc + c4);
            As[row][c4] = av.x; As[row][c4 + 1] = av.y; As[row][c4 + 2] = av.z; As[row][c4 + 3] = av.w;
            float4 vv = *(const float4*)(vb + ((size_t)(b * Nk + kc + row)) * 256 + h * 64 + c4);
            Vs[row][c4] = vv.x; Vs[row][c4 + 1] = vv.y; Vs[row][c4 + 2] = vv.z; Vs[row][c4 + 3] = vv.w;
        }
        __syncthreads();
#pragma unroll 4
        for (int kk = 0; kk < 64; kk++) {
            float a0 = As[(ty << 2) + 0][kk], a1 = As[(ty << 2) + 1][kk];
            float a2 = As[(ty << 2) + 2][kk], a3 = As[(ty << 2) + 3][kk];
            float c0 = Vs[kk][(tx << 2) + 0], c1 = Vs[kk][(tx << 2) + 1];
            float c2 = Vs[kk][(tx << 2) + 2], c3 = Vs[kk][(tx << 2) + 3];
            acc[0][0] += a0 * c0; acc[0][1] += a0 * c1; acc[0][2] += a0 * c2; acc[0][3] += a0 * c3;
            acc[1][0] += a1 * c0; acc[1][1] += a1 * c1; acc[1][2] += a1 * c2; acc[1][3] += a1 * c3;
            acc[2][0] += a2 * c0; acc[2][1] += a2 * c1; acc[2][2] += a2 * c2; acc[2][3] += a2 * c3;
            acc[3][0] += a3 * c0; acc[3][1] += a3 * c1; acc[3][2] += a3 * c2; acc[3][3] += a3 * c3;
        }
    }

#pragma unroll
    for (int i = 0; i < 4; i++) {
        float4 o = make_float4(acc[i][0], acc[i][1], acc[i][2], acc[i][3]);
        *(float4*)(xcat + ((size_t)(b * Qn + q0 + (ty << 2) + i)) * 512 + coloff + h * 64 + (tx << 2)) = o;
    }
}

// ---------------------------------------------------------------------------
// Host launch sequence
// ---------------------------------------------------------------------------
extern "C" void kernel_launch(void* const* d_in, const int* in_sizes, int n_in,
                              void* d_out, int out_size)
{
    (void)in_sizes; (void)out_size;
    const int s = (n_in >= 24) ? 2 : 0;

    const float* query   = (const float*)d_in[0];
    const float* key     = (const float*)d_in[1];
    const float* value   = (const float*)d_in[2];
    const float* q_w     = (const float*)d_in[3 + s];
    const float* sr1_w   = (const float*)d_in[4 + s];
    const float* sr1_b   = (const float*)d_in[5 + s];
    const float* norm1_w = (const float*)d_in[6 + s];
    const float* norm1_b = (const float*)d_in[7 + s];
    const float* sr2_w   = (const float*)d_in[8 + s];
    const float* sr2_b   = (const float*)d_in[9 + s];
    const float* norm2_w = (const float*)d_in[10 + s];
    const float* norm2_b = (const float*)d_in[11 + s];
    const float* k1_w    = (const float*)d_in[12 + s];
    const float* k2_w    = (const float*)d_in[14 + s];
    const float* v2_w    = (const float*)d_in[15 + s];
    const float* lc1_w   = (const float*)d_in[16 + s];
    const float* lc1_b   = (const float*)d_in[17 + s];
    const float* lc2_w   = (const float*)d_in[18 + s];
    const float* lc2_b   = (const float*)d_in[19 + s];
    const float* proj_w  = (const float*)d_in[20 + s];
    const float* proj_b  = (const float*)d_in[21 + s];
    float* out = (float*)d_out;

    float *qproj, *kv1n, *kv2n, *kv1, *k2, *v2, *v1r, *v2r, *attn, *xcat;
    cudaGetSymbolAddress((void**)&qproj, g_qproj);
    cudaGetSymbolAddress((void**)&kv1n,  g_kv1n);
    cudaGetSymbolAddress((void**)&kv2n,  g_kv2n);
    cudaGetSymbolAddress((void**)&kv1,   g_kv1);
    cudaGetSymbolAddress((void**)&k2,    g_k2);
    cudaGetSymbolAddress((void**)&v2,    g_v2);
    cudaGetSymbolAddress((void**)&v1r,   g_v1r);
    cudaGetSymbolAddress((void**)&v2r,   g_v2r);
    cudaGetSymbolAddress((void**)&attn,  g_attn);
    cudaGetSymbolAddress((void**)&xcat,  g_xcat);

    __nv_bfloat16 *qh, *ql, *imgh, *imgl, *kv1nh, *kv1nl, *kv2nh, *kv2nl, *xh, *xl;
    __nv_bfloat16 *qwh, *qwl, *s1wh, *s1wl, *s2wh, *s2wl, *k1wh, *k1wl, *k2wh, *k2wl, *v2wh, *v2wl, *pwh, *pwl;
    cudaGetSymbolAddress((void**)&qh, g_qh);       cudaGetSymbolAddress((void**)&ql, g_ql);
    cudaGetSymbolAddress((void**)&imgh, g_imgh);   cudaGetSymbolAddress((void**)&imgl, g_imgl);
    cudaGetSymbolAddress((void**)&kv1nh, g_kv1nh); cudaGetSymbolAddress((void**)&kv1nl, g_kv1nl);
    cudaGetSymbolAddress((void**)&kv2nh, g_kv2nh); cudaGetSymbolAddress((void**)&kv2nl, g_kv2nl);
    cudaGetSymbolAddress((void**)&xh, g_xh);       cudaGetSymbolAddress((void**)&xl, g_xl);
    cudaGetSymbolAddress((void**)&qwh, g_qwh);     cudaGetSymbolAddress((void**)&qwl, g_qwl);
    cudaGetSymbolAddress((void**)&s1wh, g_s1wh);   cudaGetSymbolAddress((void**)&s1wl, g_s1wl);
    cudaGetSymbolAddress((void**)&s2wh, g_s2wh);   cudaGetSymbolAddress((void**)&s2wl, g_s2wl);
    cudaGetSymbolAddress((void**)&k1wh, g_k1wh);   cudaGetSymbolAddress((void**)&k1wl, g_k1wl);
    cudaGetSymbolAddress((void**)&k2wh, g_k2wh);   cudaGetSymbolAddress((void**)&k2wl, g_k2wl);
    cudaGetSymbolAddress((void**)&v2wh, g_v2wh);   cudaGetSymbolAddress((void**)&v2wl, g_v2wl);
    cudaGetSymbolAddress((void**)&pwh, g_pwh);     cudaGetSymbolAddress((void**)&pwl, g_pwl);

    const size_t IMG1 = (size_t)B_ * C_ * 64 * 64;
    float* k1 = kv1;
    float* v1 = kv1 + (size_t)B_ * N1_ * C2_;

    const int SMEM = 81920;
    cudaFuncSetAttribute(hgemm2_kernel<0>, cudaFuncAttributeMaxDynamicSharedMemorySize, SMEM);
    cudaFuncSetAttribute(hgemm2_kernel<1>, cudaFuncAttributeMaxDynamicSharedMemorySize, SMEM);
    cudaFuncSetAttribute(hgemm2_kernel<2>, cudaFuncAttributeMaxDynamicSharedMemorySize, SMEM);

    dim3 blk(256);

    // weight + input splits
    split_kernel<<<256, 256>>>(q_w, qwh, qwl);
    split_kernel<<<4096, 256>>>(sr1_w, s1wh, s1wl);
    split_kernel<<<1024, 256>>>(sr2_w, s2wh, s2wl);
    split_kernel<<<128, 256>>>(k1_w, k1wh, k1wl);
    split_kernel<<<128, 256>>>(k2_w, k2wh, k2wl);
    split_kernel<<<128, 256>>>(v2_w, v2wh, v2wl);
    split_kernel<<<256, 256>>>(proj_w, pwh, pwl);
    split_kernel<<<8192, 256>>>(query, qh, ql);

    // images -> bf16 planes (K at 0, V at IMG1)
    to_image_split_kernel<<<4096, 256>>>(key, imgh, imgl);
    to_image_split_kernel<<<4096, 256>>>(value, imgh + IMG1, imgl + IMG1);

    // q projection
    hgemm2_kernel<0><<<dim3(4, 128), blk, SMEM>>>(qh, ql, qwh, qwl, nullptr, qproj, 16384, 512, 512);

    // SR convs (K+V fused in M)
    hgemm2_kernel<1><<<dim3(4, 64),  blk, SMEM>>>(imgh, imgl, s1wh, s1wl, sr1_b, kv1n, 8192,  512, 8192);
    hgemm2_kernel<2><<<dim3(4, 256), blk, SMEM>>>(imgh, imgl, s2wh, s2wl, sr2_b, kv2n, 32768, 512, 2048);

    // LayerNorm + GELU -> bf16 planes
    ln_gelu_split_kernel<<<8192,  256>>>(kv1n, norm1_w, norm1_b, kv1nh, kv1nl);
    ln_gelu_split_kernel<<<32768, 256>>>(kv2n, norm2_w, norm2_b, kv2nh, kv2nl);

    // head projections (branch1 k/v fused through k1_w)
    hgemm2_kernel<0><<<dim3(2, 64),  blk, SMEM>>>(kv1nh, kv1nl, k1wh, k1wl, nullptr, kv1, 8192, 256, 512);
    hgemm2_kernel<0><<<dim3(2, 128), blk, SMEM>>>(kv2nh, kv2nl, k2wh, k2wl, nullptr, k2, 16384, 256, 512);
    hgemm2_kernel<0><<<dim3(2, 128), blk, SMEM>>>(kv2nh + (size_t)16384 * 512, kv2nl + (size_t)16384 * 512,
                                                  v2wh, v2wl, nullptr, v2, 16384, 256, 512);

    // local depthwise 3x3 residual
    dwconv_res_kernel<<<(B_ * N1_ * C2_) / 256, 256>>>(v1, lc1_w, lc1_b, v1r, 16, 16);
    dwconv_res_kernel<<<(B_ * N2_ * C2_) / 256, 256>>>(v2, lc2_w, lc2_b, v2r, 32, 32);

    // attention branch 1 (heads 0..3, Nk=256)
    scores_kernel<<<dim3(N1_ / 64, Qn / 64, B_ * 4), blk>>>(qproj, k1, attn, N1_, 0);
    softmax_kernel<<<B_ * 4 * Qn, 256>>>(attn, N1_);
    pv_kernel<<<dim3(1, Qn / 64, B_ * 4), blk>>>(attn, v1r, xcat, N1_, 0);

    // attention branch 2 (heads 4..7, Nk=1024)
    scores_kernel<<<dim3(N2_ / 64, Qn / 64, B_ * 4), blk>>>(qproj, k2, attn, N2_, 4);
    softmax_kernel<<<B_ * 4 * Qn, 256>>>(attn, N2_);
    pv_kernel<<<dim3(1, Qn / 64, B_ * 4), blk>>>(attn, v2r, xcat, N2_, 256);

    // split xcat, then output projection
    split_kernel<<<8192, 256>>>(xcat, xh, xl);
    hgemm2_kernel<0><<<dim3(4, 128), blk, SMEM>>>(xh, xl, pwh, pwl, proj_b, out, 16384, 512, 512);
}

// round 5
// speedup vs baseline: 2.6728x; 1.2342x over previous
#include <cuda_runtime.h>
#include <cuda_bf16.h>
#include <math.h>
#include <stdint.h>

// ---------------------------------------------------------------------------
// Problem constants
// ---------------------------------------------------------------------------
constexpr int B_   = 16;
constexpr int C_   = 512;
constexpr int Qn   = 1024;
constexpr int C2_  = 256;
constexpr int N1_  = 256;
constexpr int N2_  = 1024;

// ---------------------------------------------------------------------------
// Device scratch
// ---------------------------------------------------------------------------
__device__ float g_qproj_unused[1];
__device__ float g_kv1n [(size_t)2 * B_ * N1_ * C_];
__device__ float g_kv2n [(size_t)2 * B_ * N2_ * C_];
__device__ float g_kv1  [(size_t)2 * B_ * N1_ * C2_];   // fp32 k1|v1 (v1 -> dwconv)
__device__ float g_v2   [(size_t)B_ * N2_ * C2_];

// bf16 hi/lo planes
__device__ __nv_bfloat16 g_qh   [(size_t)16384 * 512];   // query input planes
__device__ __nv_bfloat16 g_ql   [(size_t)16384 * 512];
__device__ __nv_bfloat16 g_qph  [(size_t)16384 * 512];   // qproj planes
__device__ __nv_bfloat16 g_qpl  [(size_t)16384 * 512];
__device__ __nv_bfloat16 g_imgh [(size_t)2 * B_ * C_ * 64 * 64];
__device__ __nv_bfloat16 g_imgl [(size_t)2 * B_ * C_ * 64 * 64];
__device__ __nv_bfloat16 g_kv1nh[(size_t)8192 * 512];
__device__ __nv_bfloat16 g_kv1nl[(size_t)8192 * 512];
__device__ __nv_bfloat16 g_kv2nh[(size_t)32768 * 512];
__device__ __nv_bfloat16 g_kv2nl[(size_t)32768 * 512];
__device__ __nv_bfloat16 g_k1ph [(size_t)8192 * 256];    // k1 (and v1, unused) planes
__device__ __nv_bfloat16 g_k1pl [(size_t)8192 * 256];
__device__ __nv_bfloat16 g_k2ph [(size_t)16384 * 256];
__device__ __nv_bfloat16 g_k2pl [(size_t)16384 * 256];
__device__ __nv_bfloat16 g_vt1h [(size_t)B_ * C2_ * N1_]; // transposed V planes [b][c][n]
__device__ __nv_bfloat16 g_vt1l [(size_t)B_ * C2_ * N1_];
__device__ __nv_bfloat16 g_vt2h [(size_t)B_ * C2_ * N2_];
__device__ __nv_bfloat16 g_vt2l [(size_t)B_ * C2_ * N2_];
__device__ __nv_bfloat16 g_xh   [(size_t)16384 * 512];   // attention output planes
__device__ __nv_bfloat16 g_xl   [(size_t)16384 * 512];
// weight planes
__device__ __nv_bfloat16 g_qwh [262144],  g_qwl [262144];
__device__ __nv_bfloat16 g_s1wh[4194304], g_s1wl[4194304];
__device__ __nv_bfloat16 g_s2wh[1048576], g_s2wl[1048576];
__device__ __nv_bfloat16 g_k1wh[131072],  g_k1wl[131072];
__device__ __nv_bfloat16 g_k2wh[131072],  g_k2wl[131072];
__device__ __nv_bfloat16 g_v2wh[131072],  g_v2wl[131072];
__device__ __nv_bfloat16 g_pwh [262144],  g_pwl [262144];

// ---------------------------------------------------------------------------
// helpers
// ---------------------------------------------------------------------------
__device__ __forceinline__ uint32_t smem_u32(const void* p) {
    uint32_t a;
    asm("{ .reg .u64 t; cvta.to.shared.u64 t, %1; cvt.u32.u64 %0, t; }" : "=r"(a) : "l"(p));
    return a;
}
__device__ __forceinline__ void ldsm_x4(uint32_t& r0, uint32_t& r1, uint32_t& r2, uint32_t& r3,
                                        uint32_t addr) {
    asm volatile("ldmatrix.sync.aligned.m8n8.x4.shared.b16 {%0,%1,%2,%3}, [%4];"
                 : "=r"(r0), "=r"(r1), "=r"(r2), "=r"(r3) : "r"(addr));
}
__device__ __forceinline__ void mma_bf16(float* d,
                                         uint32_t a0, uint32_t a1, uint32_t a2, uint32_t a3,
                                         uint32_t b0, uint32_t b1) {
    asm volatile(
        "mma.sync.aligned.m16n8k16.row.col.f32.bf16.bf16.f32 "
        "{%0,%1,%2,%3}, {%4,%5,%6,%7}, {%8,%9}, {%0,%1,%2,%3};"
        : "+f"(d[0]), "+f"(d[1]), "+f"(d[2]), "+f"(d[3])
        : "r"(a0), "r"(a1), "r"(a2), "r"(a3), "r"(b0), "r"(b1));
}
__device__ __forceinline__ uint32_t pack_hi(float x, float y) {
    __nv_bfloat162 p(__float2bfloat16(x), __float2bfloat16(y));
    return *(uint32_t*)&p;
}
__device__ __forceinline__ uint32_t pack_lo(float x, float y) {
    float hx = __bfloat162float(__float2bfloat16(x));
    float hy = __bfloat162float(__float2bfloat16(y));
    __nv_bfloat162 p(__float2bfloat16(x - hx), __float2bfloat16(y - hy));
    return *(uint32_t*)&p;
}

// ---------------------------------------------------------------------------
// generic fp32 -> hi/lo bf16 planes
// ---------------------------------------------------------------------------
__global__ void split_kernel(const float* __restrict__ src,
                             __nv_bfloat16* __restrict__ h,
                             __nv_bfloat16* __restrict__ l)
{
    int i = blockIdx.x * 256 + threadIdx.x;
    float4 v = ((const float4*)src)[i];
    ((uint2*)h)[i] = make_uint2(pack_hi(v.x, v.y), pack_hi(v.z, v.w));
    ((uint2*)l)[i] = make_uint2(pack_lo(v.x, v.y), pack_lo(v.z, v.w));
}

// ---------------------------------------------------------------------------
// (N,B,C) -> raw-reshape image, split into bf16 hi/lo planes
// ---------------------------------------------------------------------------
__global__ void to_image_split_kernel(const float* __restrict__ src,
                                      __nv_bfloat16* __restrict__ h,
                                      __nv_bfloat16* __restrict__ l)
{
    __shared__ float sm[16][513];
    size_t base = (size_t)blockIdx.x * 8192;
    for (int j = threadIdx.x; j < 8192; j += 256) sm[j >> 9][j & 511] = src[base + j];
    __syncthreads();
    for (int r = threadIdx.x; r < 8192; r += 256) {
        float v = sm[r & 15][r >> 4];
        __nv_bfloat16 hv = __float2bfloat16(v);
        h[base + r] = hv;
        l[base + r] = __float2bfloat16(v - __bfloat162float(hv));
    }
}

// ---------------------------------------------------------------------------
// Split-bf16 HMMA GEMM (pipelined).  OUT bit0: fp32 Cmat; bit1: bf16 planes.
// ---------------------------------------------------------------------------
template <int LOADER, int OUT>
__global__ __launch_bounds__(256) void hgemm2_kernel(
    const __nv_bfloat16* __restrict__ Ah, const __nv_bfloat16* __restrict__ Al,
    const __nv_bfloat16* __restrict__ Wh, const __nv_bfloat16* __restrict__ Wl,
    const float* __restrict__ bias, float* __restrict__ Cmat,
    __nv_bfloat16* __restrict__ Ch, __nv_bfloat16* __restrict__ Cl,
    int M, int N, int K)
{
    extern __shared__ char smc[];
    const uint32_t sb = smem_u32(smc);

    const int tid  = threadIdx.x;
    const int wid  = tid >> 5;
    const int lane = tid & 31;
    const int bm = blockIdx.y << 7;
    const int bn = blockIdx.x << 7;
    const int m0 = (wid & 3) << 5;
    const int n0 = (wid >> 2) << 6;

    int rr[4], kk[4];
#pragma unroll
    for (int j = 0; j < 4; j++) {
        int s = tid + (j << 8);
        rr[j] = s >> 3;
        kk[j] = (s & 7) << 2;
    }

    const uint32_t lrow = (uint32_t)(lane & 15);
    const uint32_t lkq  = (uint32_t)(lane >> 4) * 16;
    const uint32_t aOff0 = (m0 + lrow) * 80 + lkq;
    const uint32_t aOff1 = aOff0 + 16 * 80;
    uint32_t bOff[4];
#pragma unroll
    for (int nt = 0; nt < 4; nt++) bOff[nt] = (n0 + nt * 16 + lrow) * 80 + lkq;

    float acc[2][8][4];
#pragma unroll
    for (int i = 0; i < 2; i++)
#pragma unroll
        for (int j = 0; j < 8; j++)
#pragma unroll
            for (int l = 0; l < 4; l++) acc[i][j][l] = 0.f;

    uint2 pre[16];

    auto fetchA = [&](const __nv_bfloat16* plane, int r, int k) -> uint2 {
        if (LOADER == 0) {
            return *(const uint2*)(plane + (size_t)(bm + r) * K + k);
        } else if (LOADER == 1) {
            int m = bm + r;
            int b = m >> 8, oy = (m >> 4) & 15, ox = m & 15;
            int ic = k >> 4, ky = (k >> 2) & 3;
            return *(const uint2*)(plane + (((size_t)(b * 512 + ic) * 64) + oy * 4 + ky) * 64 + ox * 4);
        } else {
            int m = bm + r;
            int b = m >> 10, oy = (m >> 5) & 31, ox = m & 31;
            int ic = k >> 2;
            const __nv_bfloat16* p = plane + (((size_t)(b * 512 + ic) * 64) + oy * 2) * 64 + ox * 2;
            return make_uint2(*(const uint32_t*)p, *(const uint32_t*)(p + 64));
        }
    };

    auto load_chunk = [&](int k0) {
#pragma unroll
        for (int j = 0; j < 4; j++) {
            pre[0  + j] = fetchA(Ah, rr[j], k0 + kk[j]);
            pre[4  + j] = fetchA(Al, rr[j], k0 + kk[j]);
            pre[8  + j] = *(const uint2*)(Wh + (size_t)(bn + rr[j]) * K + k0 + kk[j]);
            pre[12 + j] = *(const uint2*)(Wl + (size_t)(bn + rr[j]) * K + k0 + kk[j]);
        }
    };
    auto store_chunk = [&](int buf) {
        const uint32_t bb = sb + (uint32_t)buf * 40960;
#pragma unroll
        for (int p = 0; p < 4; p++)
#pragma unroll
            for (int j = 0; j < 4; j++) {
                uint32_t off = bb + (uint32_t)p * 10240 + (uint32_t)rr[j] * 80 + (uint32_t)(kk[j] << 1);
                asm volatile("st.shared.v2.u32 [%0], {%1, %2};"
                             :: "r"(off), "r"(pre[p * 4 + j].x), "r"(pre[p * 4 + j].y) : "memory");
            }
    };

    const int nchunks = K >> 5;
    load_chunk(0);
    store_chunk(0);
    __syncthreads();

    for (int c = 0; c < nchunks; c++) {
        const bool more = (c + 1) < nchunks;
        if (more) load_chunk((c + 1) << 5);

        const uint32_t bb = sb + (uint32_t)(c & 1) * 40960;
        const uint32_t AhB = bb, AlB = bb + 10240, WhB = bb + 20480, WlB = bb + 30720;
#pragma unroll
        for (int s = 0; s < 3; s++) {
            const uint32_t ab = (s == 2) ? AlB : AhB;
            const uint32_t wb = (s == 1) ? WlB : WhB;
#pragma unroll
            for (int kh = 0; kh < 2; kh++) {
                const uint32_t ko = (uint32_t)kh * 32;
                uint32_t a0, a1, a2, a3, a4, a5, a6, a7;
                ldsm_x4(a0, a1, a2, a3, ab + aOff0 + ko);
                ldsm_x4(a4, a5, a6, a7, ab + aOff1 + ko);
#pragma unroll
                for (int nt = 0; nt < 4; nt++) {
                    uint32_t b0, b1, b2, b3;
                    ldsm_x4(b0, b1, b2, b3, wb + bOff[nt] + ko);
                    mma_bf16(acc[0][nt * 2 + 0], a0, a1, a2, a3, b0, b2);
                    mma_bf16(acc[0][nt * 2 + 1], a0, a1, a2, a3, b1, b3);
                    mma_bf16(acc[1][nt * 2 + 0], a4, a5, a6, a7, b0, b2);
                    mma_bf16(acc[1][nt * 2 + 1], a4, a5, a6, a7, b1, b3);
                }
            }
        }

        if (more) store_chunk((c + 1) & 1);
        __syncthreads();
    }

    const int gr = lane >> 2;
    const int gc = (lane & 3) * 2;
#pragma unroll
    for (int mt = 0; mt < 2; mt++) {
        const int row0 = bm + m0 + mt * 16 + gr;
#pragma unroll
        for (int nt = 0; nt < 8; nt++) {
            const int col = bn + n0 + nt * 8 + gc;
            float b0 = bias ? bias[col] : 0.f;
            float b1 = bias ? bias[col + 1] : 0.f;
            float o0 = acc[mt][nt][0] + b0, o1 = acc[mt][nt][1] + b1;
            float o2 = acc[mt][nt][2] + b0, o3 = acc[mt][nt][3] + b1;
            if (OUT & 1) {
                *(float2*)(Cmat + (size_t)row0 * N + col) = make_float2(o0, o1);
                *(float2*)(Cmat + (size_t)(row0 + 8) * N + col) = make_float2(o2, o3);
            }
            if (OUT & 2) {
                size_t i0 = ((size_t)row0 * N + col) >> 1;
                size_t i1 = ((size_t)(row0 + 8) * N + col) >> 1;
                ((uint32_t*)Ch)[i0] = pack_hi(o0, o1);
                ((uint32_t*)Cl)[i0] = pack_lo(o0, o1);
                ((uint32_t*)Ch)[i1] = pack_hi(o2, o3);
                ((uint32_t*)Cl)[i1] = pack_lo(o2, o3);
            }
        }
    }
}

// ---------------------------------------------------------------------------
// LayerNorm(512) + exact GELU -> bf16 hi/lo planes
// ---------------------------------------------------------------------------
__global__ void ln_gelu_split_kernel(const float* __restrict__ x,
                                     const float* __restrict__ w,
                                     const float* __restrict__ b,
                                     __nv_bfloat16* __restrict__ hO,
                                     __nv_bfloat16* __restrict__ lO)
{
    __shared__ float sh[8];
    const float* row = x + (size_t)blockIdx.x * 512;
    int t = threadIdx.x;
    float2 v = *(const float2*)(row + t * 2);

    float s = v.x + v.y;
#pragma unroll
    for (int o = 16; o; o >>= 1) s += __shfl_xor_sync(0xffffffffu, s, o);
    if ((t & 31) == 0) sh[t >> 5] = s;
    __syncthreads();
    float tot = 0.f;
#pragma unroll
    for (int i = 0; i < 8; i++) tot += sh[i];
    float mu = tot * (1.f / 512.f);
    float d0 = v.x - mu, d1 = v.y - mu;
    __syncthreads();

    float ss = d0 * d0 + d1 * d1;
#pragma unroll
    for (int o = 16; o; o >>= 1) ss += __shfl_xor_sync(0xffffffffu, ss, o);
    if ((t & 31) == 0) sh[t >> 5] = ss;
    __syncthreads();
    float tot2 = 0.f;
#pragma unroll
    for (int i = 0; i < 8; i++) tot2 += sh[i];
    float inv = rsqrtf(tot2 * (1.f / 512.f) + 1e-5f);

    float y0 = d0 * inv * w[t * 2]     + b[t * 2];
    float y1 = d1 * inv * w[t * 2 + 1] + b[t * 2 + 1];
    y0 = 0.5f * y0 * (1.f + erff(y0 * 0.7071067811865476f));
    y1 = 0.5f * y1 * (1.f + erff(y1 * 0.7071067811865476f));

    size_t o = (size_t)blockIdx.x * 256 + t;
    ((uint32_t*)hO)[o] = pack_hi(y0, y1);
    ((uint32_t*)lO)[o] = pack_lo(y0, y1);
}

// ---------------------------------------------------------------------------
// Depthwise 3x3 (pad 1) residual -> TRANSPOSED bf16 hi/lo planes vt[b][c][n]
// ---------------------------------------------------------------------------
__global__ void dwconv_res_t_kernel(const float* __restrict__ v,
                                    const float* __restrict__ lw,
                                    const float* __restrict__ lb,
                                    __nv_bfloat16* __restrict__ vth,
                                    __nv_bfloat16* __restrict__ vtl,
                                    int hh, int ww)
{
    int idx = blockIdx.x * 256 + threadIdx.x;
    int c = idx & 255;
    int sp = idx >> 8;
    int Nn = hh * ww;
    int bb = sp / Nn;
    int n = sp - bb * Nn;
    int y = n / ww;
    int x = n - y * ww;

    float acc = lb[c];
#pragma unroll
    for (int dy = -1; dy <= 1; dy++) {
        int yy = y + dy;
        if (yy < 0 || yy >= hh) continue;
#pragma unroll
        for (int dx = -1; dx <= 1; dx++) {
            int xx = x + dx;
            if (xx < 0 || xx >= ww) continue;
            acc += v[((size_t)(bb * Nn + yy * ww + xx) << 8) + c] * lw[c * 9 + (dy + 1) * 3 + (dx + 1)];
        }
    }
    float val = v[idx] + acc;
    __nv_bfloat16 hv = __float2bfloat16(val);
    size_t o = ((size_t)(bb * 256 + c)) * Nn + n;
    vth[o] = hv;
    vtl[o] = __float2bfloat16(val - __bfloat162float(hv));
}

// ---------------------------------------------------------------------------
// Flash attention, split-bf16 HMMA both GEMMs.
// Block: 128 q rows x one (b,h). Warp w owns q rows w*16..w*16+15 (full rows).
// kv tiles of 64. Q/K/V(t) planes in smem, row stride 144B (72 bf16).
// ---------------------------------------------------------------------------
__global__ __launch_bounds__(256) void flash_kernel(
    const __nv_bfloat16* __restrict__ qph, const __nv_bfloat16* __restrict__ qpl, // [.,512]
    const __nv_bfloat16* __restrict__ kph, const __nv_bfloat16* __restrict__ kpl, // [b*Nk+kv, 256]
    const __nv_bfloat16* __restrict__ vth, const __nv_bfloat16* __restrict__ vtl, // [(b*256+c)*Nk + kv]
    __nv_bfloat16* __restrict__ xh, __nv_bfloat16* __restrict__ xl,               // [.,512]
    int Nk, int hoff, int coloff)
{
    extern __shared__ char smc[];
    const uint32_t sb = smem_u32(smc);
    // layout (bytes): Qh 0 (18432), Ql 18432, Kh 36864 (9216), Kl 46080,
    //                 Vh 55296, Vl 64512 ; total 73728
    const uint32_t QH = sb, QL = sb + 18432, KH = sb + 36864, KL = sb + 46080;
    const uint32_t VH = sb + 55296, VL = sb + 64512;

    const int tid  = threadIdx.x;
    const int wid  = tid >> 5;
    const int lane = tid & 31;
    const int b = blockIdx.y >> 2;
    const int h = blockIdx.y & 3;
    const int q0 = blockIdx.x << 7;

    // ---- load Q tile (128 x 64, hi+lo) ----
    {
        const size_t qbase = ((size_t)(b * Qn + q0)) * 512 + (size_t)(hoff + h) * 64;
#pragma unroll
        for (int it = 0; it < 8; it++) {
            int i = tid + (it << 8);           // 0..2047
            int row = i >> 4;
            int c4 = (i & 15) << 2;
            uint32_t dst = (uint32_t)row * 144 + (uint32_t)(c4 << 1);
            *(uint2*)(smc + (QH - sb) + dst) = *(const uint2*)(qph + qbase + (size_t)row * 512 + c4);
            *(uint2*)(smc + (QL - sb) + dst) = *(const uint2*)(qpl + qbase + (size_t)row * 512 + c4);
        }
    }
    __syncthreads();

    const uint32_t lrow = (uint32_t)(lane & 15);
    const uint32_t lkq  = (uint32_t)(lane >> 4) * 16;
    const uint32_t qOff = ((uint32_t)(wid * 16) + lrow) * 144 + lkq;
    const uint32_t kOff = lrow * 144 + lkq;

    const int gr = lane >> 2;

    float m0 = -1e30f, m1 = -1e30f, l0 = 0.f, l1 = 0.f;
    float Oacc[8][4];
#pragma unroll
    for (int j = 0; j < 8; j++)
#pragma unroll
        for (int l = 0; l < 4; l++) Oacc[j][l] = 0.f;

    const int ntiles = Nk >> 6;
    for (int t = 0; t < ntiles; t++) {
        const int kv0 = t << 6;
        // ---- load K tile (64x64) and Vt tile (64x64), hi+lo ----
#pragma unroll
        for (int it = 0; it < 4; it++) {
            int i = tid + (it << 8);           // 0..1023
            int row = i >> 4;
            int c4 = (i & 15) << 2;
            uint32_t dst = (uint32_t)row * 144 + (uint32_t)(c4 << 1);
            size_t kidx = ((size_t)(b * Nk + kv0 + row)) * 256 + h * 64 + c4;
            *(uint2*)(smc + (KH - sb) + dst) = *(const uint2*)(kph + kidx);
            *(uint2*)(smc + (KL - sb) + dst) = *(const uint2*)(kpl + kidx);
            size_t vidx = ((size_t)(b * 256 + h * 64 + row)) * Nk + kv0 + c4;
            *(uint2*)(smc + (VH - sb) + dst) = *(const uint2*)(vth + vidx);
            *(uint2*)(smc + (VL - sb) + dst) = *(const uint2*)(vtl + vidx);
        }
        __syncthreads();

        // ---- S = Q K^T (3-pass split) ----
        float S[8][4];
#pragma unroll
        for (int j = 0; j < 8; j++)
#pragma unroll
            for (int l = 0; l < 4; l++) S[j][l] = 0.f;

#pragma unroll
        for (int s = 0; s < 3; s++) {
            const uint32_t qb = (s == 2) ? QL : QH;
            const uint32_t kb = (s == 1) ? KL : KH;
#pragma unroll
            for (int ks = 0; ks < 4; ks++) {
                const uint32_t ko = (uint32_t)ks * 32;
                uint32_t a0, a1, a2, a3;
                ldsm_x4(a0, a1, a2, a3, qb + qOff + ko);
#pragma unroll
                for (int g = 0; g < 4; g++) {
                    uint32_t b0, b1, b2, b3;
                    ldsm_x4(b0, b1, b2, b3, kb + (uint32_t)g * 2304 + kOff + ko);
                    mma_bf16(S[2 * g + 0], a0, a1, a2, a3, b0, b2);
                    mma_bf16(S[2 * g + 1], a0, a1, a2, a3, b1, b3);
                }
            }
        }

        // ---- online softmax (rows gr and gr+8; stats across 4 quad lanes) ----
        const float sc = 0.125f;
        float mx0 = m0, mx1 = m1;
#pragma unroll
        for (int j = 0; j < 8; j++) {
            S[j][0] *= sc; S[j][1] *= sc; S[j][2] *= sc; S[j][3] *= sc;
            mx0 = fmaxf(mx0, fmaxf(S[j][0], S[j][1]));
            mx1 = fmaxf(mx1, fmaxf(S[j][2], S[j][3]));
        }
#pragma unroll
        for (int o = 1; o <= 2; o <<= 1) {
            mx0 = fmaxf(mx0, __shfl_xor_sync(0xffffffffu, mx0, o));
            mx1 = fmaxf(mx1, __shfl_xor_sync(0xffffffffu, mx1, o));
        }
        const float alpha0 = __expf(m0 - mx0);
        const float alpha1 = __expf(m1 - mx1);
        m0 = mx0; m1 = mx1;

        float rs0 = 0.f, rs1 = 0.f;
#pragma unroll
        for (int j = 0; j < 8; j++) {
            S[j][0] = __expf(S[j][0] - mx0);
            S[j][1] = __expf(S[j][1] - mx0);
            S[j][2] = __expf(S[j][2] - mx1);
            S[j][3] = __expf(S[j][3] - mx1);
            rs0 += S[j][0] + S[j][1];
            rs1 += S[j][2] + S[j][3];
        }
#pragma unroll
        for (int o = 1; o <= 2; o <<= 1) {
            rs0 += __shfl_xor_sync(0xffffffffu, rs0, o);
            rs1 += __shfl_xor_sync(0xffffffffu, rs1, o);
        }
        l0 = l0 * alpha0 + rs0;
        l1 = l1 * alpha1 + rs1;

#pragma unroll
        for (int j = 0; j < 8; j++) {
            Oacc[j][0] *= alpha0; Oacc[j][1] *= alpha0;
            Oacc[j][2] *= alpha1; Oacc[j][3] *= alpha1;
        }

        // ---- O += P V (3-pass split: PhVh, PhVl, PlVh) ----
#pragma unroll
        for (int t16 = 0; t16 < 4; t16++) {
            uint32_t ph0 = pack_hi(S[2 * t16][0],     S[2 * t16][1]);
            uint32_t ph1 = pack_hi(S[2 * t16][2],     S[2 * t16][3]);
            uint32_t ph2 = pack_hi(S[2 * t16 + 1][0], S[2 * t16 + 1][1]);
            uint32_t ph3 = pack_hi(S[2 * t16 + 1][2], S[2 * t16 + 1][3]);
            uint32_t pl0 = pack_lo(S[2 * t16][0],     S[2 * t16][1]);
            uint32_t pl1 = pack_lo(S[2 * t16][2],     S[2 * t16][3]);
            uint32_t pl2 = pack_lo(S[2 * t16 + 1][0], S[2 * t16 + 1][1]);
            uint32_t pl3 = pack_lo(S[2 * t16 + 1][2], S[2 * t16 + 1][3]);
            const uint32_t ko = (uint32_t)t16 * 32;
#pragma unroll
            for (int g = 0; g < 4; g++) {
                uint32_t vh0, vh1, vh2, vh3;
                ldsm_x4(vh0, vh1, vh2, vh3, VH + (uint32_t)g * 2304 + kOff + ko);
                mma_bf16(Oacc[2 * g + 0], ph0, ph1, ph2, ph3, vh0, vh2);
                mma_bf16(Oacc[2 * g + 1], ph0, ph1, ph2, ph3, vh1, vh3);
                mma_bf16(Oacc[2 * g + 0], pl0, pl1, pl2, pl3, vh0, vh2);
                mma_bf16(Oacc[2 * g + 1], pl0, pl1, pl2, pl3, vh1, vh3);
                uint32_t vl0, vl1, vl2, vl3;
                ldsm_x4(vl0, vl1, vl2, vl3, VL + (uint32_t)g * 2304 + kOff + ko);
                mma_bf16(Oacc[2 * g + 0], ph0, ph1, ph2, ph3, vl0, vl2);
                mma_bf16(Oacc[2 * g + 1], ph0, ph1, ph2, ph3, vl1, vl3);
            }
        }
        __syncthreads();
    }

    // ---- epilogue: O / l -> x planes ----
    const float inv0 = 1.f / l0;
    const float inv1 = 1.f / l1;
    const int gc = (lane & 3) * 2;
    const int row0 = b * Qn + q0 + wid * 16 + gr;
#pragma unroll
    for (int j = 0; j < 8; j++) {
        const int col = coloff + h * 64 + (j >> 1) * 16 + (j & 1) * 8 + gc;
        float o0 = Oacc[j][0] * inv0, o1 = Oacc[j][1] * inv0;
        float o2 = Oacc[j][2] * inv1, o3 = Oacc[j][3] * inv1;
        size_t i0 = ((size_t)row0 * 512 + col) >> 1;
        size_t i1 = ((size_t)(row0 + 8) * 512 + col) >> 1;
        ((uint32_t*)xh)[i0] = pack_hi(o0, o1);
        ((uint32_t*)xl)[i0] = pack_lo(o0, o1);
        ((uint32_t*)xh)[i1] = pack_hi(o2, o3);
        ((uint32_t*)xl)[i1] = pack_lo(o2, o3);
    }
}

// ---------------------------------------------------------------------------
// Host launch sequence
// ---------------------------------------------------------------------------
extern "C" void kernel_launch(void* const* d_in, const int* in_sizes, int n_in,
                              void* d_out, int out_size)
{
    (void)in_sizes; (void)out_size;
    const int s = (n_in >= 24) ? 2 : 0;

    const float* query   = (const float*)d_in[0];
    const float* key     = (const float*)d_in[1];
    const float* value   = (const float*)d_in[2];
    const float* q_w     = (const float*)d_in[3 + s];
    const float* sr1_w   = (const float*)d_in[4 + s];
    const float* sr1_b   = (const float*)d_in[5 + s];
    const float* norm1_w = (const float*)d_in[6 + s];
    const float* norm1_b = (const float*)d_in[7 + s];
    const float* sr2_w   = (const float*)d_in[8 + s];
    const float* sr2_b   = (const float*)d_in[9 + s];
    const float* norm2_w = (const float*)d_in[10 + s];
    const float* norm2_b = (const float*)d_in[11 + s];
    const float* k1_w    = (const float*)d_in[12 + s];
    const float* k2_w    = (const float*)d_in[14 + s];
    const float* v2_w    = (const float*)d_in[15 + s];
    const float* lc1_w   = (const float*)d_in[16 + s];
    const float* lc1_b   = (const float*)d_in[17 + s];
    const float* lc2_w   = (const float*)d_in[18 + s];
    const float* lc2_b   = (const float*)d_in[19 + s];
    const float* proj_w  = (const float*)d_in[20 + s];
    const float* proj_b  = (const float*)d_in[21 + s];
    float* out = (float*)d_out;

    float *kv1n, *kv2n, *kv1, *v2;
    cudaGetSymbolAddress((void**)&kv1n, g_kv1n);
    cudaGetSymbolAddress((void**)&kv2n, g_kv2n);
    cudaGetSymbolAddress((void**)&kv1,  g_kv1);
    cudaGetSymbolAddress((void**)&v2,   g_v2);

    __nv_bfloat16 *qh, *ql, *qph, *qpl, *imgh, *imgl, *kv1nh, *kv1nl, *kv2nh, *kv2nl;
    __nv_bfloat16 *k1ph, *k1pl, *k2ph, *k2pl, *vt1h, *vt1l, *vt2h, *vt2l, *xh, *xl;
    __nv_bfloat16 *qwh, *qwl, *s1wh, *s1wl, *s2wh, *s2wl, *k1wh, *k1wl, *k2wh, *k2wl, *v2wh, *v2wl, *pwh, *pwl;
    cudaGetSymbolAddress((void**)&qh, g_qh);       cudaGetSymbolAddress((void**)&ql, g_ql);
    cudaGetSymbolAddress((void**)&qph, g_qph);     cudaGetSymbolAddress((void**)&qpl, g_qpl);
    cudaGetSymbolAddress((void**)&imgh, g_imgh);   cudaGetSymbolAddress((void**)&imgl, g_imgl);
    cudaGetSymbolAddress((void**)&kv1nh, g_kv1nh); cudaGetSymbolAddress((void**)&kv1nl, g_kv1nl);
    cudaGetSymbolAddress((void**)&kv2nh, g_kv2nh); cudaGetSymbolAddress((void**)&kv2nl, g_kv2nl);
    cudaGetSymbolAddress((void**)&k1ph, g_k1ph);   cudaGetSymbolAddress((void**)&k1pl, g_k1pl);
    cudaGetSymbolAddress((void**)&k2ph, g_k2ph);   cudaGetSymbolAddress((void**)&k2pl, g_k2pl);
    cudaGetSymbolAddress((void**)&vt1h, g_vt1h);   cudaGetSymbolAddress((void**)&vt1l, g_vt1l);
    cudaGetSymbolAddress((void**)&vt2h, g_vt2h);   cudaGetSymbolAddress((void**)&vt2l, g_vt2l);
    cudaGetSymbolAddress((void**)&xh, g_xh);       cudaGetSymbolAddress((void**)&xl, g_xl);
    cudaGetSymbolAddress((void**)&qwh, g_qwh);     cudaGetSymbolAddress((void**)&qwl, g_qwl);
    cudaGetSymbolAddress((void**)&s1wh, g_s1wh);   cudaGetSymbolAddress((void**)&s1wl, g_s1wl);
    cudaGetSymbolAddress((void**)&s2wh, g_s2wh);   cudaGetSymbolAddress((void**)&s2wl, g_s2wl);
    cudaGetSymbolAddress((void**)&k1wh, g_k1wh);   cudaGetSymbolAddress((void**)&k1wl, g_k1wl);
    cudaGetSymbolAddress((void**)&k2wh, g_k2wh);   cudaGetSymbolAddress((void**)&k2wl, g_k2wl);
    cudaGetSymbolAddress((void**)&v2wh, g_v2wh);   cudaGetSymbolAddress((void**)&v2wl, g_v2wl);
    cudaGetSymbolAddress((void**)&pwh, g_pwh);     cudaGetSymbolAddress((void**)&pwl, g_pwl);

    const size_t IMG1 = (size_t)B_ * C_ * 64 * 64;
    float* v1 = kv1 + (size_t)B_ * N1_ * C2_;

    const int SMEM = 81920;
    cudaFuncSetAttribute(hgemm2_kernel<0, 1>, cudaFuncAttributeMaxDynamicSharedMemorySize, SMEM);
    cudaFuncSetAttribute(hgemm2_kernel<0, 2>, cudaFuncAttributeMaxDynamicSharedMemorySize, SMEM);
    cudaFuncSetAttribute(hgemm2_kernel<0, 3>, cudaFuncAttributeMaxDynamicSharedMemorySize, SMEM);
    cudaFuncSetAttribute(hgemm2_kernel<1, 1>, cudaFuncAttributeMaxDynamicSharedMemorySize, SMEM);
    cudaFuncSetAttribute(hgemm2_kernel<2, 1>, cudaFuncAttributeMaxDynamicSharedMemorySize, SMEM);
    const int FSMEM = 73728;
    cudaFuncSetAttribute(flash_kernel, cudaFuncAttributeMaxDynamicSharedMemorySize, FSMEM);

    dim3 blk(256);

    // weight + input splits
    split_kernel<<<256, 256>>>(q_w, qwh, qwl);
    split_kernel<<<4096, 256>>>(sr1_w, s1wh, s1wl);
    split_kernel<<<1024, 256>>>(sr2_w, s2wh, s2wl);
    split_kernel<<<128, 256>>>(k1_w, k1wh, k1wl);
    split_kernel<<<128, 256>>>(k2_w, k2wh, k2wl);
    split_kernel<<<128, 256>>>(v2_w, v2wh, v2wl);
    split_kernel<<<256, 256>>>(proj_w, pwh, pwl);
    split_kernel<<<8192, 256>>>(query, qh, ql);

    // images -> bf16 planes
    to_image_split_kernel<<<4096, 256>>>(key, imgh, imgl);
    to_image_split_kernel<<<4096, 256>>>(value, imgh + IMG1, imgl + IMG1);

    // q projection -> planes only
    hgemm2_kernel<0, 2><<<dim3(4, 128), blk, SMEM>>>(qh, ql, qwh, qwl, nullptr,
                                                     nullptr, qph, qpl, 16384, 512, 512);

    // SR convs (K+V fused in M) -> fp32
    hgemm2_kernel<1, 1><<<dim3(4, 64),  blk, SMEM>>>(imgh, imgl, s1wh, s1wl, sr1_b,
                                                     kv1n, nullptr, nullptr, 8192, 512, 8192);
    hgemm2_kernel<2, 1><<<dim3(4, 256), blk, SMEM>>>(imgh, imgl, s2wh, s2wl, sr2_b,
                                                     kv2n, nullptr, nullptr, 32768, 512, 2048);

    // LayerNorm + GELU -> bf16 planes
    ln_gelu_split_kernel<<<8192,  256>>>(kv1n, norm1_w, norm1_b, kv1nh, kv1nl);
    ln_gelu_split_kernel<<<32768, 256>>>(kv2n, norm2_w, norm2_b, kv2nh, kv2nl);

    // head projections
    // branch1 k|v through k1_w: fp32 (for dwconv) + planes (k used by flash)
    hgemm2_kernel<0, 3><<<dim3(2, 64),  blk, SMEM>>>(kv1nh, kv1nl, k1wh, k1wl, nullptr,
                                                     kv1, k1ph, k1pl, 8192, 256, 512);
    // k2: planes only
    hgemm2_kernel<0, 2><<<dim3(2, 128), blk, SMEM>>>(kv2nh, kv2nl, k2wh, k2wl, nullptr,
                                                     nullptr, k2ph, k2pl, 16384, 256, 512);
    // v2: fp32 only (feeds dwconv)
    hgemm2_kernel<0, 1><<<dim3(2, 128), blk, SMEM>>>(kv2nh + (size_t)16384 * 512,
                                                     kv2nl + (size_t)16384 * 512,
                                                     v2wh, v2wl, nullptr,
                                                     v2, nullptr, nullptr, 16384, 256, 512);

    // depthwise 3x3 residual -> transposed V planes
    dwconv_res_t_kernel<<<(B_ * N1_ * C2_) / 256, 256>>>(v1, lc1_w, lc1_b, vt1h, vt1l, 16, 16);
    dwconv_res_t_kernel<<<(B_ * N2_ * C2_) / 256, 256>>>(v2, lc2_w, lc2_b, vt2h, vt2l, 32, 32);

    // flash attention (branch1: heads 0..3, Nk=256 ; branch2: heads 4..7, Nk=1024)
    flash_kernel<<<dim3(8, 64), blk, FSMEM>>>(qph, qpl, k1ph, k1pl, vt1h, vt1l,
                                              xh, xl, N1_, 0, 0);
    flash_kernel<<<dim3(8, 64), blk, FSMEM>>>(qph, qpl, k2ph, k2pl, vt2h, vt2l,
                                              xh, xl, N2_, 4, 256);

    // output projection
    hgemm2_kernel<0, 1><<<dim3(4, 128), blk, SMEM>>>(xh, xl, pwh, pwl, proj_b,
                                                     out, nullptr, nullptr, 16384, 512, 512);
}

// round 6
// speedup vs baseline: 2.8038x; 1.0490x over previous
#include <cuda_runtime.h>
#include <cuda_bf16.h>
#include <math.h>
#include <stdint.h>

// ---------------------------------------------------------------------------
// Problem constants
// ---------------------------------------------------------------------------
constexpr int B_   = 16;
constexpr int C_   = 512;
constexpr int Qn   = 1024;
constexpr int C2_  = 256;
constexpr int N1_  = 256;
constexpr int N2_  = 1024;

// ---------------------------------------------------------------------------
// Device scratch
// ---------------------------------------------------------------------------
__device__ float g_kv1n [(size_t)2 * B_ * N1_ * C_];
__device__ float g_kv2n [(size_t)2 * B_ * N2_ * C_];
__device__ float g_kv1  [(size_t)2 * B_ * N1_ * C2_];   // fp32 k1|v1 (v1 -> dwconv)
__device__ float g_v2   [(size_t)B_ * N2_ * C2_];

// bf16 hi/lo planes
__device__ __nv_bfloat16 g_qh   [(size_t)16384 * 512];
__device__ __nv_bfloat16 g_ql   [(size_t)16384 * 512];
__device__ __nv_bfloat16 g_qph  [(size_t)16384 * 512];
__device__ __nv_bfloat16 g_qpl  [(size_t)16384 * 512];
__device__ __nv_bfloat16 g_imgh [(size_t)2 * B_ * C_ * 64 * 64];
__device__ __nv_bfloat16 g_imgl [(size_t)2 * B_ * C_ * 64 * 64];
__device__ __nv_bfloat16 g_kv1nh[(size_t)8192 * 512];
__device__ __nv_bfloat16 g_kv1nl[(size_t)8192 * 512];
__device__ __nv_bfloat16 g_kv2nh[(size_t)32768 * 512];
__device__ __nv_bfloat16 g_kv2nl[(size_t)32768 * 512];
__device__ __nv_bfloat16 g_k1ph [(size_t)8192 * 256];
__device__ __nv_bfloat16 g_k1pl [(size_t)8192 * 256];
__device__ __nv_bfloat16 g_k2ph [(size_t)16384 * 256];
__device__ __nv_bfloat16 g_k2pl [(size_t)16384 * 256];
__device__ __nv_bfloat16 g_vt1h [(size_t)B_ * C2_ * N1_];
__device__ __nv_bfloat16 g_vt1l [(size_t)B_ * C2_ * N1_];
__device__ __nv_bfloat16 g_vt2h [(size_t)B_ * C2_ * N2_];
__device__ __nv_bfloat16 g_vt2l [(size_t)B_ * C2_ * N2_];
__device__ __nv_bfloat16 g_xh   [(size_t)16384 * 512];
__device__ __nv_bfloat16 g_xl   [(size_t)16384 * 512];
// weight planes
__device__ __nv_bfloat16 g_qwh [262144],  g_qwl [262144];
__device__ __nv_bfloat16 g_s1wh[4194304], g_s1wl[4194304];
__device__ __nv_bfloat16 g_s2wh[1048576], g_s2wl[1048576];
__device__ __nv_bfloat16 g_k1wh[131072],  g_k1wl[131072];
__device__ __nv_bfloat16 g_k2wh[131072],  g_k2wl[131072];
__device__ __nv_bfloat16 g_v2wh[131072],  g_v2wl[131072];
__device__ __nv_bfloat16 g_pwh [262144],  g_pwl [262144];

// ---------------------------------------------------------------------------
// helpers
// ---------------------------------------------------------------------------
__device__ __forceinline__ uint32_t smem_u32(const void* p) {
    uint32_t a;
    asm("{ .reg .u64 t; cvta.to.shared.u64 t, %1; cvt.u32.u64 %0, t; }" : "=r"(a) : "l"(p));
    return a;
}
__device__ __forceinline__ void ldsm_x4(uint32_t& r0, uint32_t& r1, uint32_t& r2, uint32_t& r3,
                                        uint32_t addr) {
    asm volatile("ldmatrix.sync.aligned.m8n8.x4.shared.b16 {%0,%1,%2,%3}, [%4];"
                 : "=r"(r0), "=r"(r1), "=r"(r2), "=r"(r3) : "r"(addr));
}
__device__ __forceinline__ void mma_bf16(float* d,
                                         uint32_t a0, uint32_t a1, uint32_t a2, uint32_t a3,
                                         uint32_t b0, uint32_t b1) {
    asm volatile(
        "mma.sync.aligned.m16n8k16.row.col.f32.bf16.bf16.f32 "
        "{%0,%1,%2,%3}, {%4,%5,%6,%7}, {%8,%9}, {%0,%1,%2,%3};"
        : "+f"(d[0]), "+f"(d[1]), "+f"(d[2]), "+f"(d[3])
        : "r"(a0), "r"(a1), "r"(a2), "r"(a3), "r"(b0), "r"(b1));
}
__device__ __forceinline__ uint32_t pack_hi(float x, float y) {
    __nv_bfloat162 p(__float2bfloat16(x), __float2bfloat16(y));
    return *(uint32_t*)&p;
}
__device__ __forceinline__ uint32_t pack_lo(float x, float y) {
    float hx = __bfloat162float(__float2bfloat16(x));
    float hy = __bfloat162float(__float2bfloat16(y));
    __nv_bfloat162 p(__float2bfloat16(x - hx), __float2bfloat16(y - hy));
    return *(uint32_t*)&p;
}

#define CP_ASYNC8(dst, src) \
    asm volatile("cp.async.ca.shared.global [%0], [%1], 8;" :: "r"(dst), "l"(src) : "memory")
#define CP_ASYNC4(dst, src) \
    asm volatile("cp.async.ca.shared.global [%0], [%1], 4;" :: "r"(dst), "l"(src) : "memory")
#define CP_COMMIT() asm volatile("cp.async.commit_group;" ::: "memory")
#define CP_WAIT0()  asm volatile("cp.async.wait_group 0;" ::: "memory")
#define CP_WAIT1()  asm volatile("cp.async.wait_group 1;" ::: "memory")

// ---------------------------------------------------------------------------
// generic fp32 -> hi/lo bf16 planes
// ---------------------------------------------------------------------------
__global__ void split_kernel(const float* __restrict__ src,
                             __nv_bfloat16* __restrict__ h,
                             __nv_bfloat16* __restrict__ l)
{
    int i = blockIdx.x * 256 + threadIdx.x;
    float4 v = ((const float4*)src)[i];
    ((uint2*)h)[i] = make_uint2(pack_hi(v.x, v.y), pack_hi(v.z, v.w));
    ((uint2*)l)[i] = make_uint2(pack_lo(v.x, v.y), pack_lo(v.z, v.w));
}

// ---------------------------------------------------------------------------
// (N,B,C) -> raw-reshape image, split into bf16 hi/lo planes
// ---------------------------------------------------------------------------
__global__ void to_image_split_kernel(const float* __restrict__ src,
                                      __nv_bfloat16* __restrict__ h,
                                      __nv_bfloat16* __restrict__ l)
{
    __shared__ float sm[16][513];
    size_t base = (size_t)blockIdx.x * 8192;
    for (int j = threadIdx.x; j < 8192; j += 256) sm[j >> 9][j & 511] = src[base + j];
    __syncthreads();
    for (int r = threadIdx.x; r < 8192; r += 256) {
        float v = sm[r & 15][r >> 4];
        __nv_bfloat16 hv = __float2bfloat16(v);
        h[base + r] = hv;
        l[base + r] = __float2bfloat16(v - __bfloat162float(hv));
    }
}

// ---------------------------------------------------------------------------
// Split-bf16 HMMA GEMM, cp.async double-buffered, 2 CTAs/SM.
// OUT bit0: fp32 Cmat; bit1: bf16 planes.
// ---------------------------------------------------------------------------
template <int LOADER, int OUT>
__global__ __launch_bounds__(256, 2) void hgemm2_kernel(
    const __nv_bfloat16* __restrict__ Ah, const __nv_bfloat16* __restrict__ Al,
    const __nv_bfloat16* __restrict__ Wh, const __nv_bfloat16* __restrict__ Wl,
    const float* __restrict__ bias, float* __restrict__ Cmat,
    __nv_bfloat16* __restrict__ Ch, __nv_bfloat16* __restrict__ Cl,
    int M, int N, int K)
{
    extern __shared__ char smc[];
    const uint32_t sb = smem_u32(smc);

    const int tid  = threadIdx.x;
    const int wid  = tid >> 5;
    const int lane = tid & 31;
    const int bm = blockIdx.y << 7;
    const int bn = blockIdx.x << 7;
    const int m0 = (wid & 3) << 5;
    const int n0 = (wid >> 2) << 6;

    int rr[4], kk[4];
#pragma unroll
    for (int j = 0; j < 4; j++) {
        int s = tid + (j << 8);
        rr[j] = s >> 3;
        kk[j] = (s & 7) << 2;
    }

    const uint32_t lrow = (uint32_t)(lane & 15);
    const uint32_t lkq  = (uint32_t)(lane >> 4) * 16;
    const uint32_t aOff0 = (m0 + lrow) * 80 + lkq;
    const uint32_t aOff1 = aOff0 + 16 * 80;
    uint32_t bOff[4];
#pragma unroll
    for (int nt = 0; nt < 4; nt++) bOff[nt] = (n0 + nt * 16 + lrow) * 80 + lkq;

    float acc[2][8][4];
#pragma unroll
    for (int i = 0; i < 2; i++)
#pragma unroll
        for (int j = 0; j < 8; j++)
#pragma unroll
            for (int l = 0; l < 4; l++) acc[i][j][l] = 0.f;

    auto gaddrA = [&](const __nv_bfloat16* plane, int r, int k) -> const __nv_bfloat16* {
        if (LOADER == 0) {
            return plane + (size_t)(bm + r) * K + k;
        } else if (LOADER == 1) {
            int m = bm + r;
            int b = m >> 8, oy = (m >> 4) & 15, ox = m & 15;
            int ic = k >> 4, ky = (k >> 2) & 3;
            return plane + (((size_t)(b * 512 + ic) * 64) + oy * 4 + ky) * 64 + ox * 4;
        } else {
            int m = bm + r;
            int b = m >> 10, oy = (m >> 5) & 31, ox = m & 31;
            int ic = k >> 2;
            return plane + (((size_t)(b * 512 + ic) * 64) + oy * 2) * 64 + ox * 2;
        }
    };

    auto issue_chunk = [&](int buf, int k0) {
        const uint32_t bb = sb + (uint32_t)buf * 40960;
#pragma unroll
        for (int j = 0; j < 4; j++) {
            const uint32_t off = (uint32_t)rr[j] * 80 + (uint32_t)(kk[j] << 1);
            const int k = k0 + kk[j];
            const __nv_bfloat16* pah = gaddrA(Ah, rr[j], k);
            const __nv_bfloat16* pal = gaddrA(Al, rr[j], k);
            const __nv_bfloat16* pwh = Wh + (size_t)(bn + rr[j]) * K + k;
            const __nv_bfloat16* pwl = Wl + (size_t)(bn + rr[j]) * K + k;
            if (LOADER == 2) {
                CP_ASYNC4(bb + off,             pah);
                CP_ASYNC4(bb + off + 4,         pah + 64);
                CP_ASYNC4(bb + 10240 + off,     pal);
                CP_ASYNC4(bb + 10240 + off + 4, pal + 64);
            } else {
                CP_ASYNC8(bb + off,         pah);
                CP_ASYNC8(bb + 10240 + off, pal);
            }
            CP_ASYNC8(bb + 20480 + off, pwh);
            CP_ASYNC8(bb + 30720 + off, pwl);
        }
    };

    const int nchunks = K >> 5;
    issue_chunk(0, 0);
    CP_COMMIT();

    for (int c = 0; c < nchunks; c++) {
        const bool more = (c + 1) < nchunks;
        if (more) {
            issue_chunk((c + 1) & 1, (c + 1) << 5);
            CP_COMMIT();
            CP_WAIT1();
        } else {
            CP_WAIT0();
        }
        __syncthreads();

        const uint32_t bb = sb + (uint32_t)(c & 1) * 40960;
        const uint32_t AhB = bb, AlB = bb + 10240, WhB = bb + 20480, WlB = bb + 30720;
#pragma unroll
        for (int s = 0; s < 3; s++) {
            const uint32_t ab = (s == 2) ? AlB : AhB;
            const uint32_t wb = (s == 1) ? WlB : WhB;
#pragma unroll
            for (int kh = 0; kh < 2; kh++) {
                const uint32_t ko = (uint32_t)kh * 32;
                uint32_t a0, a1, a2, a3, a4, a5, a6, a7;
                ldsm_x4(a0, a1, a2, a3, ab + aOff0 + ko);
                ldsm_x4(a4, a5, a6, a7, ab + aOff1 + ko);
#pragma unroll
                for (int nt = 0; nt < 4; nt++) {
                    uint32_t b0, b1, b2, b3;
                    ldsm_x4(b0, b1, b2, b3, wb + bOff[nt] + ko);
                    mma_bf16(acc[0][nt * 2 + 0], a0, a1, a2, a3, b0, b2);
                    mma_bf16(acc[0][nt * 2 + 1], a0, a1, a2, a3, b1, b3);
                    mma_bf16(acc[1][nt * 2 + 0], a4, a5, a6, a7, b0, b2);
                    mma_bf16(acc[1][nt * 2 + 1], a4, a5, a6, a7, b1, b3);
                }
            }
        }
        __syncthreads();
    }

    const int gr = lane >> 2;
    const int gc = (lane & 3) * 2;
#pragma unroll
    for (int mt = 0; mt < 2; mt++) {
        const int row0 = bm + m0 + mt * 16 + gr;
#pragma unroll
        for (int nt = 0; nt < 8; nt++) {
            const int col = bn + n0 + nt * 8 + gc;
            float b0 = bias ? bias[col] : 0.f;
            float b1 = bias ? bias[col + 1] : 0.f;
            float o0 = acc[mt][nt][0] + b0, o1 = acc[mt][nt][1] + b1;
            float o2 = acc[mt][nt][2] + b0, o3 = acc[mt][nt][3] + b1;
            if (OUT & 1) {
                *(float2*)(Cmat + (size_t)row0 * N + col) = make_float2(o0, o1);
                *(float2*)(Cmat + (size_t)(row0 + 8) * N + col) = make_float2(o2, o3);
            }
            if (OUT & 2) {
                size_t i0 = ((size_t)row0 * N + col) >> 1;
                size_t i1 = ((size_t)(row0 + 8) * N + col) >> 1;
                ((uint32_t*)Ch)[i0] = pack_hi(o0, o1);
                ((uint32_t*)Cl)[i0] = pack_lo(o0, o1);
                ((uint32_t*)Ch)[i1] = pack_hi(o2, o3);
                ((uint32_t*)Cl)[i1] = pack_lo(o2, o3);
            }
        }
    }
}

// ---------------------------------------------------------------------------
// LayerNorm(512) + exact GELU -> bf16 hi/lo planes
// ---------------------------------------------------------------------------
__global__ void ln_gelu_split_kernel(const float* __restrict__ x,
                                     const float* __restrict__ w,
                                     const float* __restrict__ b,
                                     __nv_bfloat16* __restrict__ hO,
                                     __nv_bfloat16* __restrict__ lO)
{
    __shared__ float sh[8];
    const float* row = x + (size_t)blockIdx.x * 512;
    int t = threadIdx.x;
    float2 v = *(const float2*)(row + t * 2);

    float s = v.x + v.y;
#pragma unroll
    for (int o = 16; o; o >>= 1) s += __shfl_xor_sync(0xffffffffu, s, o);
    if ((t & 31) == 0) sh[t >> 5] = s;
    __syncthreads();
    float tot = 0.f;
#pragma unroll
    for (int i = 0; i < 8; i++) tot += sh[i];
    float mu = tot * (1.f / 512.f);
    float d0 = v.x - mu, d1 = v.y - mu;
    __syncthreads();

    float ss = d0 * d0 + d1 * d1;
#pragma unroll
    for (int o = 16; o; o >>= 1) ss += __shfl_xor_sync(0xffffffffu, ss, o);
    if ((t & 31) == 0) sh[t >> 5] = ss;
    __syncthreads();
    float tot2 = 0.f;
#pragma unroll
    for (int i = 0; i < 8; i++) tot2 += sh[i];
    float inv = rsqrtf(tot2 * (1.f / 512.f) + 1e-5f);

    float y0 = d0 * inv * w[t * 2]     + b[t * 2];
    float y1 = d1 * inv * w[t * 2 + 1] + b[t * 2 + 1];
    y0 = 0.5f * y0 * (1.f + erff(y0 * 0.7071067811865476f));
    y1 = 0.5f * y1 * (1.f + erff(y1 * 0.7071067811865476f));

    size_t o = (size_t)blockIdx.x * 256 + t;
    ((uint32_t*)hO)[o] = pack_hi(y0, y1);
    ((uint32_t*)lO)[o] = pack_lo(y0, y1);
}

// ---------------------------------------------------------------------------
// Depthwise 3x3 (pad 1) residual -> TRANSPOSED bf16 hi/lo planes vt[b][c][n]
// ---------------------------------------------------------------------------
__global__ void dwconv_res_t_kernel(const float* __restrict__ v,
                                    const float* __restrict__ lw,
                                    const float* __restrict__ lb,
                                    __nv_bfloat16* __restrict__ vth,
                                    __nv_bfloat16* __restrict__ vtl,
                                    int hh, int ww)
{
    int idx = blockIdx.x * 256 + threadIdx.x;
    int c = idx & 255;
    int sp = idx >> 8;
    int Nn = hh * ww;
    int bb = sp / Nn;
    int n = sp - bb * Nn;
    int y = n / ww;
    int x = n - y * ww;

    float acc = lb[c];
#pragma unroll
    for (int dy = -1; dy <= 1; dy++) {
        int yy = y + dy;
        if (yy < 0 || yy >= hh) continue;
#pragma unroll
        for (int dx = -1; dx <= 1; dx++) {
            int xx = x + dx;
            if (xx < 0 || xx >= ww) continue;
            acc += v[((size_t)(bb * Nn + yy * ww + xx) << 8) + c] * lw[c * 9 + (dy + 1) * 3 + (dx + 1)];
        }
    }
    float val = v[idx] + acc;
    __nv_bfloat16 hv = __float2bfloat16(val);
    size_t o = ((size_t)(bb * 256 + c)) * Nn + n;
    vth[o] = hv;
    vtl[o] = __float2bfloat16(val - __bfloat162float(hv));
}

// ---------------------------------------------------------------------------
// Flash attention, split-bf16 HMMA, 2 CTAs/SM.
// ---------------------------------------------------------------------------
__global__ __launch_bounds__(256, 2) void flash_kernel(
    const __nv_bfloat16* __restrict__ qph, const __nv_bfloat16* __restrict__ qpl,
    const __nv_bfloat16* __restrict__ kph, const __nv_bfloat16* __restrict__ kpl,
    const __nv_bfloat16* __restrict__ vth, const __nv_bfloat16* __restrict__ vtl,
    __nv_bfloat16* __restrict__ xh, __nv_bfloat16* __restrict__ xl,
    int Nk, int hoff, int coloff)
{
    extern __shared__ char smc[];
    const uint32_t sb = smem_u32(smc);
    const uint32_t QH = sb, QL = sb + 18432, KH = sb + 36864, KL = sb + 46080;
    const uint32_t VH = sb + 55296, VL = sb + 64512;

    const int tid  = threadIdx.x;
    const int wid  = tid >> 5;
    const int lane = tid & 31;
    const int b = blockIdx.y >> 2;
    const int h = blockIdx.y & 3;
    const int q0 = blockIdx.x << 7;

    // ---- load Q tile (128 x 64, hi+lo) via cp.async ----
    {
        const size_t qbase = ((size_t)(b * Qn + q0)) * 512 + (size_t)(hoff + h) * 64;
#pragma unroll
        for (int it = 0; it < 8; it++) {
            int i = tid + (it << 8);
            int row = i >> 4;
            int c4 = (i & 15) << 2;
            uint32_t dst = (uint32_t)row * 144 + (uint32_t)(c4 << 1);
            CP_ASYNC8(QH + dst, qph + qbase + (size_t)row * 512 + c4);
            CP_ASYNC8(QL + dst, qpl + qbase + (size_t)row * 512 + c4);
        }
        CP_COMMIT();
    }

    const uint32_t lrow = (uint32_t)(lane & 15);
    const uint32_t lkq  = (uint32_t)(lane >> 4) * 16;
    const uint32_t qOff = ((uint32_t)(wid * 16) + lrow) * 144 + lkq;
    const uint32_t kOff = lrow * 144 + lkq;

    const int gr = lane >> 2;

    float m0 = -1e30f, m1 = -1e30f, l0 = 0.f, l1 = 0.f;
    float Oacc[8][4];
#pragma unroll
    for (int j = 0; j < 8; j++)
#pragma unroll
        for (int l = 0; l < 4; l++) Oacc[j][l] = 0.f;

    const int ntiles = Nk >> 6;
    for (int t = 0; t < ntiles; t++) {
        const int kv0 = t << 6;
#pragma unroll
        for (int it = 0; it < 4; it++) {
            int i = tid + (it << 8);
            int row = i >> 4;
            int c4 = (i & 15) << 2;
            uint32_t dst = (uint32_t)row * 144 + (uint32_t)(c4 << 1);
            size_t kidx = ((size_t)(b * Nk + kv0 + row)) * 256 + h * 64 + c4;
            CP_ASYNC8(KH + dst, kph + kidx);
            CP_ASYNC8(KL + dst, kpl + kidx);
            size_t vidx = ((size_t)(b * 256 + h * 64 + row)) * Nk + kv0 + c4;
            CP_ASYNC8(VH + dst, vth + vidx);
            CP_ASYNC8(VL + dst, vtl + vidx);
        }
        CP_COMMIT();
        CP_WAIT0();
        __syncthreads();

        // ---- S = Q K^T (3-pass split) ----
        float S[8][4];
#pragma unroll
        for (int j = 0; j < 8; j++)
#pragma unroll
            for (int l = 0; l < 4; l++) S[j][l] = 0.f;

#pragma unroll
        for (int s = 0; s < 3; s++) {
            const uint32_t qb = (s == 2) ? QL : QH;
            const uint32_t kb = (s == 1) ? KL : KH;
#pragma unroll
            for (int ks = 0; ks < 4; ks++) {
                const uint32_t ko = (uint32_t)ks * 32;
                uint32_t a0, a1, a2, a3;
                ldsm_x4(a0, a1, a2, a3, qb + qOff + ko);
#pragma unroll
                for (int g = 0; g < 4; g++) {
                    uint32_t b0, b1, b2, b3;
                    ldsm_x4(b0, b1, b2, b3, kb + (uint32_t)g * 2304 + kOff + ko);
                    mma_bf16(S[2 * g + 0], a0, a1, a2, a3, b0, b2);
                    mma_bf16(S[2 * g + 1], a0, a1, a2, a3, b1, b3);
                }
            }
        }

        // ---- online softmax ----
        const float sc = 0.125f;
        float mx0 = m0, mx1 = m1;
#pragma unroll
        for (int j = 0; j < 8; j++) {
            S[j][0] *= sc; S[j][1] *= sc; S[j][2] *= sc; S[j][3] *= sc;
            mx0 = fmaxf(mx0, fmaxf(S[j][0], S[j][1]));
            mx1 = fmaxf(mx1, fmaxf(S[j][2], S[j][3]));
        }
#pragma unroll
        for (int o = 1; o <= 2; o <<= 1) {
            mx0 = fmaxf(mx0, __shfl_xor_sync(0xffffffffu, mx0, o));
            mx1 = fmaxf(mx1, __shfl_xor_sync(0xffffffffu, mx1, o));
        }
        const float alpha0 = __expf(m0 - mx0);
        const float alpha1 = __expf(m1 - mx1);
        m0 = mx0; m1 = mx1;

        float rs0 = 0.f, rs1 = 0.f;
#pragma unroll
        for (int j = 0; j < 8; j++) {
            S[j][0] = __expf(S[j][0] - mx0);
            S[j][1] = __expf(S[j][1] - mx0);
            S[j][2] = __expf(S[j][2] - mx1);
            S[j][3] = __expf(S[j][3] - mx1);
            rs0 += S[j][0] + S[j][1];
            rs1 += S[j][2] + S[j][3];
        }
#pragma unroll
        for (int o = 1; o <= 2; o <<= 1) {
            rs0 += __shfl_xor_sync(0xffffffffu, rs0, o);
            rs1 += __shfl_xor_sync(0xffffffffu, rs1, o);
        }
        l0 = l0 * alpha0 + rs0;
        l1 = l1 * alpha1 + rs1;

#pragma unroll
        for (int j = 0; j < 8; j++) {
            Oacc[j][0] *= alpha0; Oacc[j][1] *= alpha0;
            Oacc[j][2] *= alpha1; Oacc[j][3] *= alpha1;
        }

        // ---- O += P V (3-pass split) ----
#pragma unroll
        for (int t16 = 0; t16 < 4; t16++) {
            uint32_t ph0 = pack_hi(S[2 * t16][0],     S[2 * t16][1]);
            uint32_t ph1 = pack_hi(S[2 * t16][2],     S[2 * t16][3]);
            uint32_t ph2 = pack_hi(S[2 * t16 + 1][0], S[2 * t16 + 1][1]);
            uint32_t ph3 = pack_hi(S[2 * t16 + 1][2], S[2 * t16 + 1][3]);
            uint32_t pl0 = pack_lo(S[2 * t16][0],     S[2 * t16][1]);
            uint32_t pl1 = pack_lo(S[2 * t16][2],     S[2 * t16][3]);
            uint32_t pl2 = pack_lo(S[2 * t16 + 1][0], S[2 * t16 + 1][1]);
            uint32_t pl3 = pack_lo(S[2 * t16 + 1][2], S[2 * t16 + 1][3]);
            const uint32_t ko = (uint32_t)t16 * 32;
#pragma unroll
            for (int g = 0; g < 4; g++) {
                uint32_t vh0, vh1, vh2, vh3;
                ldsm_x4(vh0, vh1, vh2, vh3, VH + (uint32_t)g * 2304 + kOff + ko);
                mma_bf16(Oacc[2 * g + 0], ph0, ph1, ph2, ph3, vh0, vh2);
                mma_bf16(Oacc[2 * g + 1], ph0, ph1, ph2, ph3, vh1, vh3);
                mma_bf16(Oacc[2 * g + 0], pl0, pl1, pl2, pl3, vh0, vh2);
                mma_bf16(Oacc[2 * g + 1], pl0, pl1, pl2, pl3, vh1, vh3);
                uint32_t vl0, vl1, vl2, vl3;
                ldsm_x4(vl0, vl1, vl2, vl3, VL + (uint32_t)g * 2304 + kOff + ko);
                mma_bf16(Oacc[2 * g + 0], ph0, ph1, ph2, ph3, vl0, vl2);
                mma_bf16(Oacc[2 * g + 1], ph0, ph1, ph2, ph3, vl1, vl3);
            }
        }
        __syncthreads();
    }

    // ---- epilogue: O / l -> x planes ----
    const float inv0 = 1.f / l0;
    const float inv1 = 1.f / l1;
    const int gc = (lane & 3) * 2;
    const int row0 = b * Qn + q0 + wid * 16 + gr;
#pragma unroll
    for (int j = 0; j < 8; j++) {
        const int col = coloff + h * 64 + (j >> 1) * 16 + (j & 1) * 8 + gc;
        float o0 = Oacc[j][0] * inv0, o1 = Oacc[j][1] * inv0;
        float o2 = Oacc[j][2] * inv1, o3 = Oacc[j][3] * inv1;
        size_t i0 = ((size_t)row0 * 512 + col) >> 1;
        size_t i1 = ((size_t)(row0 + 8) * 512 + col) >> 1;
        ((uint32_t*)xh)[i0] = pack_hi(o0, o1);
        ((uint32_t*)xl)[i0] = pack_lo(o0, o1);
        ((uint32_t*)xh)[i1] = pack_hi(o2, o3);
        ((uint32_t*)xl)[i1] = pack_lo(o2, o3);
    }
}

// ---------------------------------------------------------------------------
// Host launch sequence
// ---------------------------------------------------------------------------
extern "C" void kernel_launch(void* const* d_in, const int* in_sizes, int n_in,
                              void* d_out, int out_size)
{
    (void)in_sizes; (void)out_size;
    const int s = (n_in >= 24) ? 2 : 0;

    const float* query   = (const float*)d_in[0];
    const float* key     = (const float*)d_in[1];
    const float* value   = (const float*)d_in[2];
    const float* q_w     = (const float*)d_in[3 + s];
    const float* sr1_w   = (const float*)d_in[4 + s];
    const float* sr1_b   = (const float*)d_in[5 + s];
    const float* norm1_w = (const float*)d_in[6 + s];
    const float* norm1_b = (const float*)d_in[7 + s];
    const float* sr2_w   = (const float*)d_in[8 + s];
    const float* sr2_b   = (const float*)d_in[9 + s];
    const float* norm2_w = (const float*)d_in[10 + s];
    const float* norm2_b = (const float*)d_in[11 + s];
    const float* k1_w    = (const float*)d_in[12 + s];
    const float* k2_w    = (const float*)d_in[14 + s];
    const float* v2_w    = (const float*)d_in[15 + s];
    const float* lc1_w   = (const float*)d_in[16 + s];
    const float* lc1_b   = (const float*)d_in[17 + s];
    const float* lc2_w   = (const float*)d_in[18 + s];
    const float* lc2_b   = (const float*)d_in[19 + s];
    const float* proj_w  = (const float*)d_in[20 + s];
    const float* proj_b  = (const float*)d_in[21 + s];
    float* out = (float*)d_out;

    float *kv1n, *kv2n, *kv1, *v2;
    cudaGetSymbolAddress((void**)&kv1n, g_kv1n);
    cudaGetSymbolAddress((void**)&kv2n, g_kv2n);
    cudaGetSymbolAddress((void**)&kv1,  g_kv1);
    cudaGetSymbolAddress((void**)&v2,   g_v2);

    __nv_bfloat16 *qh, *ql, *qph, *qpl, *imgh, *imgl, *kv1nh, *kv1nl, *kv2nh, *kv2nl;
    __nv_bfloat16 *k1ph, *k1pl, *k2ph, *k2pl, *vt1h, *vt1l, *vt2h, *vt2l, *xh, *xl;
    __nv_bfloat16 *qwh, *qwl, *s1wh, *s1wl, *s2wh, *s2wl, *k1wh, *k1wl, *k2wh, *k2wl, *v2wh, *v2wl, *pwh, *pwl;
    cudaGetSymbolAddress((void**)&qh, g_qh);       cudaGetSymbolAddress((void**)&ql, g_ql);
    cudaGetSymbolAddress((void**)&qph, g_qph);     cudaGetSymbolAddress((void**)&qpl, g_qpl);
    cudaGetSymbolAddress((void**)&imgh, g_imgh);   cudaGetSymbolAddress((void**)&imgl, g_imgl);
    cudaGetSymbolAddress((void**)&kv1nh, g_kv1nh); cudaGetSymbolAddress((void**)&kv1nl, g_kv1nl);
    cudaGetSymbolAddress((void**)&kv2nh, g_kv2nh); cudaGetSymbolAddress((void**)&kv2nl, g_kv2nl);
    cudaGetSymbolAddress((void**)&k1ph, g_k1ph);   cudaGetSymbolAddress((void**)&k1pl, g_k1pl);
    cudaGetSymbolAddress((void**)&k2ph, g_k2ph);   cudaGetSymbolAddress((void**)&k2pl, g_k2pl);
    cudaGetSymbolAddress((void**)&vt1h, g_vt1h);   cudaGetSymbolAddress((void**)&vt1l, g_vt1l);
    cudaGetSymbolAddress((void**)&vt2h, g_vt2h);   cudaGetSymbolAddress((void**)&vt2l, g_vt2l);
    cudaGetSymbolAddress((void**)&xh, g_xh);       cudaGetSymbolAddress((void**)&xl, g_xl);
    cudaGetSymbolAddress((void**)&qwh, g_qwh);     cudaGetSymbolAddress((void**)&qwl, g_qwl);
    cudaGetSymbolAddress((void**)&s1wh, g_s1wh);   cudaGetSymbolAddress((void**)&s1wl, g_s1wl);
    cudaGetSymbolAddress((void**)&s2wh, g_s2wh);   cudaGetSymbolAddress((void**)&s2wl, g_s2wl);
    cudaGetSymbolAddress((void**)&k1wh, g_k1wh);   cudaGetSymbolAddress((void**)&k1wl, g_k1wl);
    cudaGetSymbolAddress((void**)&k2wh, g_k2wh);   cudaGetSymbolAddress((void**)&k2wl, g_k2wl);
    cudaGetSymbolAddress((void**)&v2wh, g_v2wh);   cudaGetSymbolAddress((void**)&v2wl, g_v2wl);
    cudaGetSymbolAddress((void**)&pwh, g_pwh);     cudaGetSymbolAddress((void**)&pwl, g_pwl);

    const size_t IMG1 = (size_t)B_ * C_ * 64 * 64;
    float* v1 = kv1 + (size_t)B_ * N1_ * C2_;

    const int SMEM = 81920;
    cudaFuncSetAttribute(hgemm2_kernel<0, 1>, cudaFuncAttributeMaxDynamicSharedMemorySize, SMEM);
    cudaFuncSetAttribute(hgemm2_kernel<0, 2>, cudaFuncAttributeMaxDynamicSharedMemorySize, SMEM);
    cudaFuncSetAttribute(hgemm2_kernel<0, 3>, cudaFuncAttributeMaxDynamicSharedMemorySize, SMEM);
    cudaFuncSetAttribute(hgemm2_kernel<1, 1>, cudaFuncAttributeMaxDynamicSharedMemorySize, SMEM);
    cudaFuncSetAttribute(hgemm2_kernel<2, 1>, cudaFuncAttributeMaxDynamicSharedMemorySize, SMEM);
    const int FSMEM = 73728;
    cudaFuncSetAttribute(flash_kernel, cudaFuncAttributeMaxDynamicSharedMemorySize, FSMEM);

    dim3 blk(256);

    split_kernel<<<256, 256>>>(q_w, qwh, qwl);
    split_kernel<<<4096, 256>>>(sr1_w, s1wh, s1wl);
    split_kernel<<<1024, 256>>>(sr2_w, s2wh, s2wl);
    split_kernel<<<128, 256>>>(k1_w, k1wh, k1wl);
    split_kernel<<<128, 256>>>(k2_w, k2wh, k2wl);
    split_kernel<<<128, 256>>>(v2_w, v2wh, v2wl);
    split_kernel<<<256, 256>>>(proj_w, pwh, pwl);
    split_kernel<<<8192, 256>>>(query, qh, ql);

    to_image_split_kernel<<<4096, 256>>>(key, imgh, imgl);
    to_image_split_kernel<<<4096, 256>>>(value, imgh + IMG1, imgl + IMG1);

    hgemm2_kernel<0, 2><<<dim3(4, 128), blk, SMEM>>>(qh, ql, qwh, qwl, nullptr,
                                                     nullptr, qph, qpl, 16384, 512, 512);

    hgemm2_kernel<1, 1><<<dim3(4, 64),  blk, SMEM>>>(imgh, imgl, s1wh, s1wl, sr1_b,
                                                     kv1n, nullptr, nullptr, 8192, 512, 8192);
    hgemm2_kernel<2, 1><<<dim3(4, 256), blk, SMEM>>>(imgh, imgl, s2wh, s2wl, sr2_b,
                                                     kv2n, nullptr, nullptr, 32768, 512, 2048);

    ln_gelu_split_kernel<<<8192,  256>>>(kv1n, norm1_w, norm1_b, kv1nh, kv1nl);
    ln_gelu_split_kernel<<<32768, 256>>>(kv2n, norm2_w, norm2_b, kv2nh, kv2nl);

    hgemm2_kernel<0, 3><<<dim3(2, 64),  blk, SMEM>>>(kv1nh, kv1nl, k1wh, k1wl, nullptr,
                                                     kv1, k1ph, k1pl, 8192, 256, 512);
    hgemm2_kernel<0, 2><<<dim3(2, 128), blk, SMEM>>>(kv2nh, kv2nl, k2wh, k2wl, nullptr,
                                                     nullptr, k2ph, k2pl, 16384, 256, 512);
    hgemm2_kernel<0, 1><<<dim3(2, 128), blk, SMEM>>>(kv2nh + (size_t)16384 * 512,
                                                     kv2nl + (size_t)16384 * 512,
                                                     v2wh, v2wl, nullptr,
                                                     v2, nullptr, nullptr, 16384, 256, 512);

    dwconv_res_t_kernel<<<(B_ * N1_ * C2_) / 256, 256>>>(v1, lc1_w, lc1_b, vt1h, vt1l, 16, 16);
    dwconv_res_t_kernel<<<(B_ * N2_ * C2_) / 256, 256>>>(v2, lc2_w, lc2_b, vt2h, vt2l, 32, 32);

    flash_kernel<<<dim3(8, 64), blk, FSMEM>>>(qph, qpl, k1ph, k1pl, vt1h, vt1l,
                                              xh, xl, N1_, 0, 0);
    flash_kernel<<<dim3(8, 64), blk, FSMEM>>>(qph, qpl, k2ph, k2pl, vt2h, vt2l,
                                              xh, xl, N2_, 4, 256);

    hgemm2_kernel<0, 1><<<dim3(4, 128), blk, SMEM>>>(xh, xl, pwh, pwl, proj_b,
                                                     out, nullptr, nullptr, 16384, 512, 512);
}

// round 7
// speedup vs baseline: 2.8988x; 1.0339x over previous
#include <cuda_runtime.h>
#include <cuda_bf16.h>
#include <math.h>
#include <stdint.h>

// ---------------------------------------------------------------------------
// Problem constants
// ---------------------------------------------------------------------------
constexpr int B_   = 16;
constexpr int C_   = 512;
constexpr int Qn   = 1024;
constexpr int C2_  = 256;
constexpr int N1_  = 256;
constexpr int N2_  = 1024;

// ---------------------------------------------------------------------------
// Device scratch
// ---------------------------------------------------------------------------
__device__ float g_kv1n [(size_t)2 * B_ * N1_ * C_];
__device__ float g_kv2n [(size_t)2 * B_ * N2_ * C_];
__device__ float g_kv1  [(size_t)2 * B_ * N1_ * C2_];   // fp32 k1|v1 (v1 -> dwconv)
__device__ float g_v2   [(size_t)B_ * N2_ * C2_];

// bf16 hi/lo planes
__device__ __nv_bfloat16 g_qh   [(size_t)16384 * 512];
__device__ __nv_bfloat16 g_ql   [(size_t)16384 * 512];
__device__ __nv_bfloat16 g_qph  [(size_t)16384 * 512];
__device__ __nv_bfloat16 g_qpl  [(size_t)16384 * 512];
__device__ __nv_bfloat16 g_imgh [(size_t)2 * B_ * C_ * 64 * 64];
__device__ __nv_bfloat16 g_imgl [(size_t)2 * B_ * C_ * 64 * 64];
__device__ __nv_bfloat16 g_kv1nh[(size_t)8192 * 512];
__device__ __nv_bfloat16 g_kv1nl[(size_t)8192 * 512];
__device__ __nv_bfloat16 g_kv2nh[(size_t)32768 * 512];
__device__ __nv_bfloat16 g_kv2nl[(size_t)32768 * 512];
__device__ __nv_bfloat16 g_k1ph [(size_t)8192 * 256];
__device__ __nv_bfloat16 g_k1pl [(size_t)8192 * 256];
__device__ __nv_bfloat16 g_k2ph [(size_t)16384 * 256];
__device__ __nv_bfloat16 g_k2pl [(size_t)16384 * 256];
__device__ __nv_bfloat16 g_vt1h [(size_t)B_ * C2_ * N1_];
__device__ __nv_bfloat16 g_vt1l [(size_t)B_ * C2_ * N1_];
__device__ __nv_bfloat16 g_vt2h [(size_t)B_ * C2_ * N2_];
__device__ __nv_bfloat16 g_vt2l [(size_t)B_ * C2_ * N2_];
__device__ __nv_bfloat16 g_xh   [(size_t)16384 * 512];
__device__ __nv_bfloat16 g_xl   [(size_t)16384 * 512];
// weight planes
__device__ __nv_bfloat16 g_qwh [262144],  g_qwl [262144];
__device__ __nv_bfloat16 g_s1wh[4194304], g_s1wl[4194304];
__device__ __nv_bfloat16 g_s2wh[1048576], g_s2wl[1048576];
__device__ __nv_bfloat16 g_k1wh[131072],  g_k1wl[131072];
__device__ __nv_bfloat16 g_k2wh[131072],  g_k2wl[131072];
__device__ __nv_bfloat16 g_v2wh[131072],  g_v2wl[131072];
__device__ __nv_bfloat16 g_pwh [262144],  g_pwl [262144];

// ---------------------------------------------------------------------------
// helpers
// ---------------------------------------------------------------------------
__device__ __forceinline__ uint32_t smem_u32(const void* p) {
    uint32_t a;
    asm("{ .reg .u64 t; cvta.to.shared.u64 t, %1; cvt.u32.u64 %0, t; }" : "=r"(a) : "l"(p));
    return a;
}
__device__ __forceinline__ void ldsm_x4(uint32_t& r0, uint32_t& r1, uint32_t& r2, uint32_t& r3,
                                        uint32_t addr) {
    asm volatile("ldmatrix.sync.aligned.m8n8.x4.shared.b16 {%0,%1,%2,%3}, [%4];"
                 : "=r"(r0), "=r"(r1), "=r"(r2), "=r"(r3) : "r"(addr));
}
__device__ __forceinline__ void mma_bf16(float* d,
                                         uint32_t a0, uint32_t a1, uint32_t a2, uint32_t a3,
                                         uint32_t b0, uint32_t b1) {
    asm volatile(
        "mma.sync.aligned.m16n8k16.row.col.f32.bf16.bf16.f32 "
        "{%0,%1,%2,%3}, {%4,%5,%6,%7}, {%8,%9}, {%0,%1,%2,%3};"
        : "+f"(d[0]), "+f"(d[1]), "+f"(d[2]), "+f"(d[3])
        : "r"(a0), "r"(a1), "r"(a2), "r"(a3), "r"(b0), "r"(b1));
}
__device__ __forceinline__ uint32_t pack_hi(float x, float y) {
    __nv_bfloat162 p(__float2bfloat16(x), __float2bfloat16(y));
    return *(uint32_t*)&p;
}
__device__ __forceinline__ uint32_t pack_lo(float x, float y) {
    float hx = __bfloat162float(__float2bfloat16(x));
    float hy = __bfloat162float(__float2bfloat16(y));
    __nv_bfloat162 p(__float2bfloat16(x - hx), __float2bfloat16(y - hy));
    return *(uint32_t*)&p;
}

#define CP_ASYNC8(dst, src) \
    asm volatile("cp.async.ca.shared.global [%0], [%1], 8;" :: "r"(dst), "l"(src) : "memory")
#define CP_ASYNC4(dst, src) \
    asm volatile("cp.async.ca.shared.global [%0], [%1], 4;" :: "r"(dst), "l"(src) : "memory")
#define CP_COMMIT() asm volatile("cp.async.commit_group;" ::: "memory")
#define CP_WAIT0()  asm volatile("cp.async.wait_group 0;" ::: "memory")
#define CP_WAIT1()  asm volatile("cp.async.wait_group 1;" ::: "memory")

// ---------------------------------------------------------------------------
// generic fp32 -> hi/lo bf16 planes
// ---------------------------------------------------------------------------
__global__ void split_kernel(const float* __restrict__ src,
                             __nv_bfloat16* __restrict__ h,
                             __nv_bfloat16* __restrict__ l)
{
    int i = blockIdx.x * 256 + threadIdx.x;
    float4 v = ((const float4*)src)[i];
    ((uint2*)h)[i] = make_uint2(pack_hi(v.x, v.y), pack_hi(v.z, v.w));
    ((uint2*)l)[i] = make_uint2(pack_lo(v.x, v.y), pack_lo(v.z, v.w));
}

// ---------------------------------------------------------------------------
// (N,B,C) -> raw-reshape image, split into bf16 hi/lo planes
// ---------------------------------------------------------------------------
__global__ void to_image_split_kernel(const float* __restrict__ src,
                                      __nv_bfloat16* __restrict__ h,
                                      __nv_bfloat16* __restrict__ l)
{
    __shared__ float sm[16][513];
    size_t base = (size_t)blockIdx.x * 8192;
    for (int j = threadIdx.x; j < 8192; j += 256) sm[j >> 9][j & 511] = src[base + j];
    __syncthreads();
    for (int r = threadIdx.x; r < 8192; r += 256) {
        float v = sm[r & 15][r >> 4];
        __nv_bfloat16 hv = __float2bfloat16(v);
        h[base + r] = hv;
        l[base + r] = __float2bfloat16(v - __bfloat162float(hv));
    }
}

// ---------------------------------------------------------------------------
// Split-bf16 HMMA GEMM, cp.async double-buffered, 2 CTAs/SM.
// OUT bit0: fp32 Cmat; bit1: bf16 planes.
// ---------------------------------------------------------------------------
template <int LOADER, int OUT>
__global__ __launch_bounds__(256, 2) void hgemm2_kernel(
    const __nv_bfloat16* __restrict__ Ah, const __nv_bfloat16* __restrict__ Al,
    const __nv_bfloat16* __restrict__ Wh, const __nv_bfloat16* __restrict__ Wl,
    const float* __restrict__ bias, float* __restrict__ Cmat,
    __nv_bfloat16* __restrict__ Ch, __nv_bfloat16* __restrict__ Cl,
    int M, int N, int K)
{
    extern __shared__ char smc[];
    const uint32_t sb = smem_u32(smc);

    const int tid  = threadIdx.x;
    const int wid  = tid >> 5;
    const int lane = tid & 31;
    const int bm = blockIdx.y << 7;
    const int bn = blockIdx.x << 7;
    const int m0 = (wid & 3) << 5;
    const int n0 = (wid >> 2) << 6;

    int rr[4], kk[4];
#pragma unroll
    for (int j = 0; j < 4; j++) {
        int s = tid + (j << 8);
        rr[j] = s >> 3;
        kk[j] = (s & 7) << 2;
    }

    const uint32_t lrow = (uint32_t)(lane & 15);
    const uint32_t lkq  = (uint32_t)(lane >> 4) * 16;
    const uint32_t aOff0 = (m0 + lrow) * 80 + lkq;
    const uint32_t aOff1 = aOff0 + 16 * 80;
    uint32_t bOff[4];
#pragma unroll
    for (int nt = 0; nt < 4; nt++) bOff[nt] = (n0 + nt * 16 + lrow) * 80 + lkq;

    float acc[2][8][4];
#pragma unroll
    for (int i = 0; i < 2; i++)
#pragma unroll
        for (int j = 0; j < 8; j++)
#pragma unroll
            for (int l = 0; l < 4; l++) acc[i][j][l] = 0.f;

    auto gaddrA = [&](const __nv_bfloat16* plane, int r, int k) -> const __nv_bfloat16* {
        if (LOADER == 0) {
            return plane + (size_t)(bm + r) * K + k;
        } else if (LOADER == 1) {
            int m = bm + r;
            int b = m >> 8, oy = (m >> 4) & 15, ox = m & 15;
            int ic = k >> 4, ky = (k >> 2) & 3;
            return plane + (((size_t)(b * 512 + ic) * 64) + oy * 4 + ky) * 64 + ox * 4;
        } else {
            int m = bm + r;
            int b = m >> 10, oy = (m >> 5) & 31, ox = m & 31;
            int ic = k >> 2;
            return plane + (((size_t)(b * 512 + ic) * 64) + oy * 2) * 64 + ox * 2;
        }
    };

    auto issue_chunk = [&](int buf, int k0) {
        const uint32_t bb = sb + (uint32_t)buf * 40960;
#pragma unroll
        for (int j = 0; j < 4; j++) {
            const uint32_t off = (uint32_t)rr[j] * 80 + (uint32_t)(kk[j] << 1);
            const int k = k0 + kk[j];
            const __nv_bfloat16* pah = gaddrA(Ah, rr[j], k);
            const __nv_bfloat16* pal = gaddrA(Al, rr[j], k);
            const __nv_bfloat16* pwh = Wh + (size_t)(bn + rr[j]) * K + k;
            const __nv_bfloat16* pwl = Wl + (size_t)(bn + rr[j]) * K + k;
            if (LOADER == 2) {
                CP_ASYNC4(bb + off,             pah);
                CP_ASYNC4(bb + off + 4,         pah + 64);
                CP_ASYNC4(bb + 10240 + off,     pal);
                CP_ASYNC4(bb + 10240 + off + 4, pal + 64);
            } else {
                CP_ASYNC8(bb + off,         pah);
                CP_ASYNC8(bb + 10240 + off, pal);
            }
            CP_ASYNC8(bb + 20480 + off, pwh);
            CP_ASYNC8(bb + 30720 + off, pwl);
        }
    };

    const int nchunks = K >> 5;
    issue_chunk(0, 0);
    CP_COMMIT();

    for (int c = 0; c < nchunks; c++) {
        const bool more = (c + 1) < nchunks;
        if (more) {
            issue_chunk((c + 1) & 1, (c + 1) << 5);
            CP_COMMIT();
            CP_WAIT1();
        } else {
            CP_WAIT0();
        }
        __syncthreads();

        const uint32_t bb = sb + (uint32_t)(c & 1) * 40960;
        const uint32_t AhB = bb, AlB = bb + 10240, WhB = bb + 20480, WlB = bb + 30720;
#pragma unroll
        for (int s = 0; s < 3; s++) {
            const uint32_t ab = (s == 2) ? AlB : AhB;
            const uint32_t wb = (s == 1) ? WlB : WhB;
#pragma unroll
            for (int kh = 0; kh < 2; kh++) {
                const uint32_t ko = (uint32_t)kh * 32;
                uint32_t a0, a1, a2, a3, a4, a5, a6, a7;
                ldsm_x4(a0, a1, a2, a3, ab + aOff0 + ko);
                ldsm_x4(a4, a5, a6, a7, ab + aOff1 + ko);
#pragma unroll
                for (int nt = 0; nt < 4; nt++) {
                    uint32_t b0, b1, b2, b3;
                    ldsm_x4(b0, b1, b2, b3, wb + bOff[nt] + ko);
                    mma_bf16(acc[0][nt * 2 + 0], a0, a1, a2, a3, b0, b2);
                    mma_bf16(acc[0][nt * 2 + 1], a0, a1, a2, a3, b1, b3);
                    mma_bf16(acc[1][nt * 2 + 0], a4, a5, a6, a7, b0, b2);
                    mma_bf16(acc[1][nt * 2 + 1], a4, a5, a6, a7, b1, b3);
                }
            }
        }
        __syncthreads();
    }

    const int gr = lane >> 2;
    const int gc = (lane & 3) * 2;
#pragma unroll
    for (int mt = 0; mt < 2; mt++) {
        const int row0 = bm + m0 + mt * 16 + gr;
#pragma unroll
        for (int nt = 0; nt < 8; nt++) {
            const int col = bn + n0 + nt * 8 + gc;
            float b0 = bias ? bias[col] : 0.f;
            float b1 = bias ? bias[col + 1] : 0.f;
            float o0 = acc[mt][nt][0] + b0, o1 = acc[mt][nt][1] + b1;
            float o2 = acc[mt][nt][2] + b0, o3 = acc[mt][nt][3] + b1;
            if (OUT & 1) {
                *(float2*)(Cmat + (size_t)row0 * N + col) = make_float2(o0, o1);
                *(float2*)(Cmat + (size_t)(row0 + 8) * N + col) = make_float2(o2, o3);
            }
            if (OUT & 2) {
                size_t i0 = ((size_t)row0 * N + col) >> 1;
                size_t i1 = ((size_t)(row0 + 8) * N + col) >> 1;
                ((uint32_t*)Ch)[i0] = pack_hi(o0, o1);
                ((uint32_t*)Cl)[i0] = pack_lo(o0, o1);
                ((uint32_t*)Ch)[i1] = pack_hi(o2, o3);
                ((uint32_t*)Cl)[i1] = pack_lo(o2, o3);
            }
        }
    }
}

// ---------------------------------------------------------------------------
// Merged head-projection GEMM: three sub-problems in one launch.
// N=256, K=512 fixed. grid.y: [0,64) prob0, [64,192) prob1, [192,320) prob2.
// out mode: prob0 = fp32 + planes, prob1 = planes, prob2 = fp32.
// ---------------------------------------------------------------------------
struct ProjParams {
    const __nv_bfloat16 *Ah[3], *Al[3], *Wh[3], *Wl[3];
    float* Cf[3];
    __nv_bfloat16 *Ch[3], *Cl[3];
    int outm[3];
};

__global__ __launch_bounds__(256, 2) void projgemm_kernel(ProjParams P)
{
    extern __shared__ char smc[];
    const uint32_t sb = smem_u32(smc);
    constexpr int K = 512, N = 256;

    const int y = blockIdx.y;
    const int pi = (y < 64) ? 0 : (y < 192 ? 1 : 2);
    const int ylocal = y - ((pi == 0) ? 0 : (pi == 1) ? 64 : 192);

    const __nv_bfloat16* Ah = P.Ah[pi];
    const __nv_bfloat16* Al = P.Al[pi];
    const __nv_bfloat16* Wh = P.Wh[pi];
    const __nv_bfloat16* Wl = P.Wl[pi];
    float* Cmat = P.Cf[pi];
    __nv_bfloat16* Ch = P.Ch[pi];
    __nv_bfloat16* Cl = P.Cl[pi];
    const int OUT = P.outm[pi];

    const int tid  = threadIdx.x;
    const int wid  = tid >> 5;
    const int lane = tid & 31;
    const int bm = ylocal << 7;
    const int bn = blockIdx.x << 7;
    const int m0 = (wid & 3) << 5;
    const int n0 = (wid >> 2) << 6;

    int rr[4], kk[4];
#pragma unroll
    for (int j = 0; j < 4; j++) {
        int s = tid + (j << 8);
        rr[j] = s >> 3;
        kk[j] = (s & 7) << 2;
    }

    const uint32_t lrow = (uint32_t)(lane & 15);
    const uint32_t lkq  = (uint32_t)(lane >> 4) * 16;
    const uint32_t aOff0 = (m0 + lrow) * 80 + lkq;
    const uint32_t aOff1 = aOff0 + 16 * 80;
    uint32_t bOff[4];
#pragma unroll
    for (int nt = 0; nt < 4; nt++) bOff[nt] = (n0 + nt * 16 + lrow) * 80 + lkq;

    float acc[2][8][4];
#pragma unroll
    for (int i = 0; i < 2; i++)
#pragma unroll
        for (int j = 0; j < 8; j++)
#pragma unroll
            for (int l = 0; l < 4; l++) acc[i][j][l] = 0.f;

    auto issue_chunk = [&](int buf, int k0) {
        const uint32_t bb = sb + (uint32_t)buf * 40960;
#pragma unroll
        for (int j = 0; j < 4; j++) {
            const uint32_t off = (uint32_t)rr[j] * 80 + (uint32_t)(kk[j] << 1);
            const int k = k0 + kk[j];
            CP_ASYNC8(bb + off,         Ah + (size_t)(bm + rr[j]) * K + k);
            CP_ASYNC8(bb + 10240 + off, Al + (size_t)(bm + rr[j]) * K + k);
            CP_ASYNC8(bb + 20480 + off, Wh + (size_t)(bn + rr[j]) * K + k);
            CP_ASYNC8(bb + 30720 + off, Wl + (size_t)(bn + rr[j]) * K + k);
        }
    };

    const int nchunks = K >> 5;
    issue_chunk(0, 0);
    CP_COMMIT();

    for (int c = 0; c < nchunks; c++) {
        const bool more = (c + 1) < nchunks;
        if (more) {
            issue_chunk((c + 1) & 1, (c + 1) << 5);
            CP_COMMIT();
            CP_WAIT1();
        } else {
            CP_WAIT0();
        }
        __syncthreads();

        const uint32_t bb = sb + (uint32_t)(c & 1) * 40960;
        const uint32_t AhB = bb, AlB = bb + 10240, WhB = bb + 20480, WlB = bb + 30720;
#pragma unroll
        for (int s = 0; s < 3; s++) {
            const uint32_t ab = (s == 2) ? AlB : AhB;
            const uint32_t wb = (s == 1) ? WlB : WhB;
#pragma unroll
            for (int kh = 0; kh < 2; kh++) {
                const uint32_t ko = (uint32_t)kh * 32;
                uint32_t a0, a1, a2, a3, a4, a5, a6, a7;
                ldsm_x4(a0, a1, a2, a3, ab + aOff0 + ko);
                ldsm_x4(a4, a5, a6, a7, ab + aOff1 + ko);
#pragma unroll
                for (int nt = 0; nt < 4; nt++) {
                    uint32_t b0, b1, b2, b3;
                    ldsm_x4(b0, b1, b2, b3, wb + bOff[nt] + ko);
                    mma_bf16(acc[0][nt * 2 + 0], a0, a1, a2, a3, b0, b2);
                    mma_bf16(acc[0][nt * 2 + 1], a0, a1, a2, a3, b1, b3);
                    mma_bf16(acc[1][nt * 2 + 0], a4, a5, a6, a7, b0, b2);
                    mma_bf16(acc[1][nt * 2 + 1], a4, a5, a6, a7, b1, b3);
                }
            }
        }
        __syncthreads();
    }

    const int gr = lane >> 2;
    const int gc = (lane & 3) * 2;
#pragma unroll
    for (int mt = 0; mt < 2; mt++) {
        const int row0 = bm + m0 + mt * 16 + gr;
#pragma unroll
        for (int nt = 0; nt < 8; nt++) {
            const int col = bn + n0 + nt * 8 + gc;
            float o0 = acc[mt][nt][0], o1 = acc[mt][nt][1];
            float o2 = acc[mt][nt][2], o3 = acc[mt][nt][3];
            if (OUT & 1) {
                *(float2*)(Cmat + (size_t)row0 * N + col) = make_float2(o0, o1);
                *(float2*)(Cmat + (size_t)(row0 + 8) * N + col) = make_float2(o2, o3);
            }
            if (OUT & 2) {
                size_t i0 = ((size_t)row0 * N + col) >> 1;
                size_t i1 = ((size_t)(row0 + 8) * N + col) >> 1;
                ((uint32_t*)Ch)[i0] = pack_hi(o0, o1);
                ((uint32_t*)Cl)[i0] = pack_lo(o0, o1);
                ((uint32_t*)Ch)[i1] = pack_hi(o2, o3);
                ((uint32_t*)Cl)[i1] = pack_lo(o2, o3);
            }
        }
    }
}

// ---------------------------------------------------------------------------
// LayerNorm(512) + exact GELU -> bf16 hi/lo planes
// ---------------------------------------------------------------------------
__global__ void ln_gelu_split_kernel(const float* __restrict__ x,
                                     const float* __restrict__ w,
                                     const float* __restrict__ b,
                                     __nv_bfloat16* __restrict__ hO,
                                     __nv_bfloat16* __restrict__ lO)
{
    __shared__ float sh[8];
    const float* row = x + (size_t)blockIdx.x * 512;
    int t = threadIdx.x;
    float2 v = *(const float2*)(row + t * 2);

    float s = v.x + v.y;
#pragma unroll
    for (int o = 16; o; o >>= 1) s += __shfl_xor_sync(0xffffffffu, s, o);
    if ((t & 31) == 0) sh[t >> 5] = s;
    __syncthreads();
    float tot = 0.f;
#pragma unroll
    for (int i = 0; i < 8; i++) tot += sh[i];
    float mu = tot * (1.f / 512.f);
    float d0 = v.x - mu, d1 = v.y - mu;
    __syncthreads();

    float ss = d0 * d0 + d1 * d1;
#pragma unroll
    for (int o = 16; o; o >>= 1) ss += __shfl_xor_sync(0xffffffffu, ss, o);
    if ((t & 31) == 0) sh[t >> 5] = ss;
    __syncthreads();
    float tot2 = 0.f;
#pragma unroll
    for (int i = 0; i < 8; i++) tot2 += sh[i];
    float inv = rsqrtf(tot2 * (1.f / 512.f) + 1e-5f);

    float y0 = d0 * inv * w[t * 2]     + b[t * 2];
    float y1 = d1 * inv * w[t * 2 + 1] + b[t * 2 + 1];
    y0 = 0.5f * y0 * (1.f + erff(y0 * 0.7071067811865476f));
    y1 = 0.5f * y1 * (1.f + erff(y1 * 0.7071067811865476f));

    size_t o = (size_t)blockIdx.x * 256 + t;
    ((uint32_t*)hO)[o] = pack_hi(y0, y1);
    ((uint32_t*)lO)[o] = pack_lo(y0, y1);
}

// ---------------------------------------------------------------------------
// Depthwise 3x3 (pad 1) residual -> transposed planes, coalesced via smem tile.
// Block: 64c x 64n tile. grid.x = B * 4 * (Nn/64).
// ---------------------------------------------------------------------------
__global__ void dwconv_res_t2_kernel(const float* __restrict__ v,
                                     const float* __restrict__ lw,
                                     const float* __restrict__ lb,
                                     __nv_bfloat16* __restrict__ vth,
                                     __nv_bfloat16* __restrict__ vtl,
                                     int hh, int ww)
{
    __shared__ float sm[64][65];
    const int Nn = hh * ww;
    const int nt = Nn >> 6;
    int bz = blockIdx.x;
    const int ntile = bz % nt; bz /= nt;
    const int ct = bz & 3;
    const int bb = bz >> 2;
    const int c0 = ct << 6, n0 = ntile << 6;

    const int tid = threadIdx.x;
    const int tc = tid & 63;
    const int tn0 = tid >> 6;
    const int c = c0 + tc;

    float wreg[9];
#pragma unroll
    for (int i = 0; i < 9; i++) wreg[i] = lw[c * 9 + i];
    const float bias = lb[c];

    for (int nn = tn0; nn < 64; nn += 4) {
        const int n = n0 + nn;
        const int y = n / ww;
        const int x = n - y * ww;
        float acc = bias;
#pragma unroll
        for (int dy = -1; dy <= 1; dy++) {
            int yy = y + dy;
            if (yy < 0 || yy >= hh) continue;
#pragma unroll
            for (int dx = -1; dx <= 1; dx++) {
                int xx = x + dx;
                if (xx < 0 || xx >= ww) continue;
                acc += v[((size_t)(bb * Nn + yy * ww + xx) << 8) + c] * wreg[(dy + 1) * 3 + (dx + 1)];
            }
        }
        sm[nn][tc] = v[((size_t)(bb * Nn + n) << 8) + c] + acc;
    }
    __syncthreads();

    // write transposed: vt[b][c][n], n fastest, uint32 (2 bf16) per store
    const int wc = tid >> 5;            // 0..7
    const int wn = (tid & 31) << 1;     // 0..62 step 2
    for (int cc = wc; cc < 64; cc += 8) {
        float v0 = sm[wn][cc], v1 = sm[wn + 1][cc];
        size_t o = (((size_t)(bb * 256 + c0 + cc)) * Nn + n0 + wn) >> 1;
        ((uint32_t*)vth)[o] = pack_hi(v0, v1);
        ((uint32_t*)vtl)[o] = pack_lo(v0, v1);
    }
}

// ---------------------------------------------------------------------------
// Flash attention, split-bf16 HMMA, 2 CTAs/SM.
// ---------------------------------------------------------------------------
__global__ __launch_bounds__(256, 2) void flash_kernel(
    const __nv_bfloat16* __restrict__ qph, const __nv_bfloat16* __restrict__ qpl,
    const __nv_bfloat16* __restrict__ kph, const __nv_bfloat16* __restrict__ kpl,
    const __nv_bfloat16* __restrict__ vth, const __nv_bfloat16* __restrict__ vtl,
    __nv_bfloat16* __restrict__ xh, __nv_bfloat16* __restrict__ xl,
    int Nk, int hoff, int coloff)
{
    extern __shared__ char smc[];
    const uint32_t sb = smem_u32(smc);
    const uint32_t QH = sb, QL = sb + 18432, KH = sb + 36864, KL = sb + 46080;
    const uint32_t VH = sb + 55296, VL = sb + 64512;

    const int tid  = threadIdx.x;
    const int wid  = tid >> 5;
    const int lane = tid & 31;
    const int b = blockIdx.y >> 2;
    const int h = blockIdx.y & 3;
    const int q0 = blockIdx.x << 7;

    {
        const size_t qbase = ((size_t)(b * Qn + q0)) * 512 + (size_t)(hoff + h) * 64;
#pragma unroll
        for (int it = 0; it < 8; it++) {
            int i = tid + (it << 8);
            int row = i >> 4;
            int c4 = (i & 15) << 2;
            uint32_t dst = (uint32_t)row * 144 + (uint32_t)(c4 << 1);
            CP_ASYNC8(QH + dst, qph + qbase + (size_t)row * 512 + c4);
            CP_ASYNC8(QL + dst, qpl + qbase + (size_t)row * 512 + c4);
        }
        CP_COMMIT();
    }

    const uint32_t lrow = (uint32_t)(lane & 15);
    const uint32_t lkq  = (uint32_t)(lane >> 4) * 16;
    const uint32_t qOff = ((uint32_t)(wid * 16) + lrow) * 144 + lkq;
    const uint32_t kOff = lrow * 144 + lkq;

    const int gr = lane >> 2;

    float m0 = -1e30f, m1 = -1e30f, l0 = 0.f, l1 = 0.f;
    float Oacc[8][4];
#pragma unroll
    for (int j = 0; j < 8; j++)
#pragma unroll
        for (int l = 0; l < 4; l++) Oacc[j][l] = 0.f;

    const int ntiles = Nk >> 6;
    for (int t = 0; t < ntiles; t++) {
        const int kv0 = t << 6;
#pragma unroll
        for (int it = 0; it < 4; it++) {
            int i = tid + (it << 8);
            int row = i >> 4;
            int c4 = (i & 15) << 2;
            uint32_t dst = (uint32_t)row * 144 + (uint32_t)(c4 << 1);
            size_t kidx = ((size_t)(b * Nk + kv0 + row)) * 256 + h * 64 + c4;
            CP_ASYNC8(KH + dst, kph + kidx);
            CP_ASYNC8(KL + dst, kpl + kidx);
            size_t vidx = ((size_t)(b * 256 + h * 64 + row)) * Nk + kv0 + c4;
            CP_ASYNC8(VH + dst, vth + vidx);
            CP_ASYNC8(VL + dst, vtl + vidx);
        }
        CP_COMMIT();
        CP_WAIT0();
        __syncthreads();

        float S[8][4];
#pragma unroll
        for (int j = 0; j < 8; j++)
#pragma unroll
            for (int l = 0; l < 4; l++) S[j][l] = 0.f;

#pragma unroll
        for (int s = 0; s < 3; s++) {
            const uint32_t qb = (s == 2) ? QL : QH;
            const uint32_t kb = (s == 1) ? KL : KH;
#pragma unroll
            for (int ks = 0; ks < 4; ks++) {
                const uint32_t ko = (uint32_t)ks * 32;
                uint32_t a0, a1, a2, a3;
                ldsm_x4(a0, a1, a2, a3, qb + qOff + ko);
#pragma unroll
                for (int g = 0; g < 4; g++) {
                    uint32_t b0, b1, b2, b3;
                    ldsm_x4(b0, b1, b2, b3, kb + (uint32_t)g * 2304 + kOff + ko);
                    mma_bf16(S[2 * g + 0], a0, a1, a2, a3, b0, b2);
                    mma_bf16(S[2 * g + 1], a0, a1, a2, a3, b1, b3);
                }
            }
        }

        const float sc = 0.125f;
        float mx0 = m0, mx1 = m1;
#pragma unroll
        for (int j = 0; j < 8; j++) {
            S[j][0] *= sc; S[j][1] *= sc; S[j][2] *= sc; S[j][3] *= sc;
            mx0 = fmaxf(mx0, fmaxf(S[j][0], S[j][1]));
            mx1 = fmaxf(mx1, fmaxf(S[j][2], S[j][3]));
        }
#pragma unroll
        for (int o = 1; o <= 2; o <<= 1) {
            mx0 = fmaxf(mx0, __shfl_xor_sync(0xffffffffu, mx0, o));
            mx1 = fmaxf(mx1, __shfl_xor_sync(0xffffffffu, mx1, o));
        }
        const float alpha0 = __expf(m0 - mx0);
        const float alpha1 = __expf(m1 - mx1);
        m0 = mx0; m1 = mx1;

        float rs0 = 0.f, rs1 = 0.f;
#pragma unroll
        for (int j = 0; j < 8; j++) {
            S[j][0] = __expf(S[j][0] - mx0);
            S[j][1] = __expf(S[j][1] - mx0);
            S[j][2] = __expf(S[j][2] - mx1);
            S[j][3] = __expf(S[j][3] - mx1);
            rs0 += S[j][0] + S[j][1];
            rs1 += S[j][2] + S[j][3];
        }
#pragma unroll
        for (int o = 1; o <= 2; o <<= 1) {
            rs0 += __shfl_xor_sync(0xffffffffu, rs0, o);
            rs1 += __shfl_xor_sync(0xffffffffu, rs1, o);
        }
        l0 = l0 * alpha0 + rs0;
        l1 = l1 * alpha1 + rs1;

#pragma unroll
        for (int j = 0; j < 8; j++) {
            Oacc[j][0] *= alpha0; Oacc[j][1] *= alpha0;
            Oacc[j][2] *= alpha1; Oacc[j][3] *= alpha1;
        }

#pragma unroll
        for (int t16 = 0; t16 < 4; t16++) {
            uint32_t ph0 = pack_hi(S[2 * t16][0],     S[2 * t16][1]);
            uint32_t ph1 = pack_hi(S[2 * t16][2],     S[2 * t16][3]);
            uint32_t ph2 = pack_hi(S[2 * t16 + 1][0], S[2 * t16 + 1][1]);
            uint32_t ph3 = pack_hi(S[2 * t16 + 1][2], S[2 * t16 + 1][3]);
            uint32_t pl0 = pack_lo(S[2 * t16][0],     S[2 * t16][1]);
            uint32_t pl1 = pack_lo(S[2 * t16][2],     S[2 * t16][3]);
            uint32_t pl2 = pack_lo(S[2 * t16 + 1][0], S[2 * t16 + 1][1]);
            uint32_t pl3 = pack_lo(S[2 * t16 + 1][2], S[2 * t16 + 1][3]);
            const uint32_t ko = (uint32_t)t16 * 32;
#pragma unroll
            for (int g = 0; g < 4; g++) {
                uint32_t vh0, vh1, vh2, vh3;
                ldsm_x4(vh0, vh1, vh2, vh3, VH + (uint32_t)g * 2304 + kOff + ko);
                mma_bf16(Oacc[2 * g + 0], ph0, ph1, ph2, ph3, vh0, vh2);
                mma_bf16(Oacc[2 * g + 1], ph0, ph1, ph2, ph3, vh1, vh3);
                mma_bf16(Oacc[2 * g + 0], pl0, pl1, pl2, pl3, vh0, vh2);
                mma_bf16(Oacc[2 * g + 1], pl0, pl1, pl2, pl3, vh1, vh3);
                uint32_t vl0, vl1, vl2, vl3;
                ldsm_x4(vl0, vl1, vl2, vl3, VL + (uint32_t)g * 2304 + kOff + ko);
                mma_bf16(Oacc[2 * g + 0], ph0, ph1, ph2, ph3, vl0, vl2);
                mma_bf16(Oacc[2 * g + 1], ph0, ph1, ph2, ph3, vl1, vl3);
            }
        }
        __syncthreads();
    }

    const float inv0 = 1.f / l0;
    const float inv1 = 1.f / l1;
    const int gc = (lane & 3) * 2;
    const int row0 = b * Qn + q0 + wid * 16 + gr;
#pragma unroll
    for (int j = 0; j < 8; j++) {
        const int col = coloff + h * 64 + (j >> 1) * 16 + (j & 1) * 8 + gc;
        float o0 = Oacc[j][0] * inv0, o1 = Oacc[j][1] * inv0;
        float o2 = Oacc[j][2] * inv1, o3 = Oacc[j][3] * inv1;
        size_t i0 = ((size_t)row0 * 512 + col) >> 1;
        size_t i1 = ((size_t)(row0 + 8) * 512 + col) >> 1;
        ((uint32_t*)xh)[i0] = pack_hi(o0, o1);
        ((uint32_t*)xl)[i0] = pack_lo(o0, o1);
        ((uint32_t*)xh)[i1] = pack_hi(o2, o3);
        ((uint32_t*)xl)[i1] = pack_lo(o2, o3);
    }
}

// ---------------------------------------------------------------------------
// Host launch sequence
// ---------------------------------------------------------------------------
extern "C" void kernel_launch(void* const* d_in, const int* in_sizes, int n_in,
                              void* d_out, int out_size)
{
    (void)in_sizes; (void)out_size;
    const int s = (n_in >= 24) ? 2 : 0;

    const float* query   = (const float*)d_in[0];
    const float* key     = (const float*)d_in[1];
    const float* value   = (const float*)d_in[2];
    const float* q_w     = (const float*)d_in[3 + s];
    const float* sr1_w   = (const float*)d_in[4 + s];
    const float* sr1_b   = (const float*)d_in[5 + s];
    const float* norm1_w = (const float*)d_in[6 + s];
    const float* norm1_b = (const float*)d_in[7 + s];
    const float* sr2_w   = (const float*)d_in[8 + s];
    const float* sr2_b   = (const float*)d_in[9 + s];
    const float* norm2_w = (const float*)d_in[10 + s];
    const float* norm2_b = (const float*)d_in[11 + s];
    const float* k1_w    = (const float*)d_in[12 + s];
    const float* k2_w    = (const float*)d_in[14 + s];
    const float* v2_w    = (const float*)d_in[15 + s];
    const float* lc1_w   = (const float*)d_in[16 + s];
    const float* lc1_b   = (const float*)d_in[17 + s];
    const float* lc2_w   = (const float*)d_in[18 + s];
    const float* lc2_b   = (const float*)d_in[19 + s];
    const float* proj_w  = (const float*)d_in[20 + s];
    const float* proj_b  = (const float*)d_in[21 + s];
    float* out = (float*)d_out;

    float *kv1n, *kv2n, *kv1, *v2;
    cudaGetSymbolAddress((void**)&kv1n, g_kv1n);
    cudaGetSymbolAddress((void**)&kv2n, g_kv2n);
    cudaGetSymbolAddress((void**)&kv1,  g_kv1);
    cudaGetSymbolAddress((void**)&v2,   g_v2);

    __nv_bfloat16 *qh, *ql, *qph, *qpl, *imgh, *imgl, *kv1nh, *kv1nl, *kv2nh, *kv2nl;
    __nv_bfloat16 *k1ph, *k1pl, *k2ph, *k2pl, *vt1h, *vt1l, *vt2h, *vt2l, *xh, *xl;
    __nv_bfloat16 *qwh, *qwl, *s1wh, *s1wl, *s2wh, *s2wl, *k1wh, *k1wl, *k2wh, *k2wl, *v2wh, *v2wl, *pwh, *pwl;
    cudaGetSymbolAddress((void**)&qh, g_qh);       cudaGetSymbolAddress((void**)&ql, g_ql);
    cudaGetSymbolAddress((void**)&qph, g_qph);     cudaGetSymbolAddress((void**)&qpl, g_qpl);
    cudaGetSymbolAddress((void**)&imgh, g_imgh);   cudaGetSymbolAddress((void**)&imgl, g_imgl);
    cudaGetSymbolAddress((void**)&kv1nh, g_kv1nh); cudaGetSymbolAddress((void**)&kv1nl, g_kv1nl);
    cudaGetSymbolAddress((void**)&kv2nh, g_kv2nh); cudaGetSymbolAddress((void**)&kv2nl, g_kv2nl);
    cudaGetSymbolAddress((void**)&k1ph, g_k1ph);   cudaGetSymbolAddress((void**)&k1pl, g_k1pl);
    cudaGetSymbolAddress((void**)&k2ph, g_k2ph);   cudaGetSymbolAddress((void**)&k2pl, g_k2pl);
    cudaGetSymbolAddress((void**)&vt1h, g_vt1h);   cudaGetSymbolAddress((void**)&vt1l, g_vt1l);
    cudaGetSymbolAddress((void**)&vt2h, g_vt2h);   cudaGetSymbolAddress((void**)&vt2l, g_vt2l);
    cudaGetSymbolAddress((void**)&xh, g_xh);       cudaGetSymbolAddress((void**)&xl, g_xl);
    cudaGetSymbolAddress((void**)&qwh, g_qwh);     cudaGetSymbolAddress((void**)&qwl, g_qwl);
    cudaGetSymbolAddress((void**)&s1wh, g_s1wh);   cudaGetSymbolAddress((void**)&s1wl, g_s1wl);
    cudaGetSymbolAddress((void**)&s2wh, g_s2wh);   cudaGetSymbolAddress((void**)&s2wl, g_s2wl);
    cudaGetSymbolAddress((void**)&k1wh, g_k1wh);   cudaGetSymbolAddress((void**)&k1wl, g_k1wl);
    cudaGetSymbolAddress((void**)&k2wh, g_k2wh);   cudaGetSymbolAddress((void**)&k2wl, g_k2wl);
    cudaGetSymbolAddress((void**)&v2wh, g_v2wh);   cudaGetSymbolAddress((void**)&v2wl, g_v2wl);
    cudaGetSymbolAddress((void**)&pwh, g_pwh);     cudaGetSymbolAddress((void**)&pwl, g_pwl);

    const size_t IMG1 = (size_t)B_ * C_ * 64 * 64;
    float* v1 = kv1 + (size_t)B_ * N1_ * C2_;

    const int SMEM = 81920;
    cudaFuncSetAttribute(hgemm2_kernel<0, 1>, cudaFuncAttributeMaxDynamicSharedMemorySize, SMEM);
    cudaFuncSetAttribute(hgemm2_kernel<0, 2>, cudaFuncAttributeMaxDynamicSharedMemorySize, SMEM);
    cudaFuncSetAttribute(hgemm2_kernel<1, 1>, cudaFuncAttributeMaxDynamicSharedMemorySize, SMEM);
    cudaFuncSetAttribute(hgemm2_kernel<2, 1>, cudaFuncAttributeMaxDynamicSharedMemorySize, SMEM);
    cudaFuncSetAttribute(projgemm_kernel, cudaFuncAttributeMaxDynamicSharedMemorySize, SMEM);
    const int FSMEM = 73728;
    cudaFuncSetAttribute(flash_kernel, cudaFuncAttributeMaxDynamicSharedMemorySize, FSMEM);

    dim3 blk(256);

    // --- launches 1..5: the prerequisites of the sr1 conv GEMM ---
    split_kernel<<<256, 256>>>(q_w, qwh, qwl);                      // 1
    split_kernel<<<4096, 256>>>(sr1_w, s1wh, s1wl);                 // 2
    split_kernel<<<1024, 256>>>(sr2_w, s2wh, s2wl);                 // 3
    to_image_split_kernel<<<4096, 256>>>(key, imgh, imgl);          // 4
    to_image_split_kernel<<<4096, 256>>>(value, imgh + IMG1, imgl + IMG1); // 5

    // --- launch 6: sr1 conv GEMM (ncu -s 5 -c 1 profiles this) ---
    hgemm2_kernel<1, 1><<<dim3(4, 64),  blk, SMEM>>>(imgh, imgl, s1wh, s1wl, sr1_b,
                                                     kv1n, nullptr, nullptr, 8192, 512, 8192);

    // remaining splits
    split_kernel<<<128, 256>>>(k1_w, k1wh, k1wl);
    split_kernel<<<128, 256>>>(k2_w, k2wh, k2wl);
    split_kernel<<<128, 256>>>(v2_w, v2wh, v2wl);
    split_kernel<<<256, 256>>>(proj_w, pwh, pwl);
    split_kernel<<<8192, 256>>>(query, qh, ql);

    hgemm2_kernel<2, 1><<<dim3(4, 256), blk, SMEM>>>(imgh, imgl, s2wh, s2wl, sr2_b,
                                                     kv2n, nullptr, nullptr, 32768, 512, 2048);

    hgemm2_kernel<0, 2><<<dim3(4, 128), blk, SMEM>>>(qh, ql, qwh, qwl, nullptr,
                                                     nullptr, qph, qpl, 16384, 512, 512);

    ln_gelu_split_kernel<<<8192,  256>>>(kv1n, norm1_w, norm1_b, kv1nh, kv1nl);
    ln_gelu_split_kernel<<<32768, 256>>>(kv2n, norm2_w, norm2_b, kv2nh, kv2nl);

    // merged head projections (one launch)
    {
        ProjParams P;
        P.Ah[0] = kv1nh;  P.Al[0] = kv1nl;  P.Wh[0] = k1wh; P.Wl[0] = k1wl;
        P.Cf[0] = kv1;    P.Ch[0] = k1ph;   P.Cl[0] = k1pl; P.outm[0] = 3;
        P.Ah[1] = kv2nh;  P.Al[1] = kv2nl;  P.Wh[1] = k2wh; P.Wl[1] = k2wl;
        P.Cf[1] = nullptr; P.Ch[1] = k2ph;  P.Cl[1] = k2pl; P.outm[1] = 2;
        P.Ah[2] = kv2nh + (size_t)16384 * 512;
        P.Al[2] = kv2nl + (size_t)16384 * 512;
        P.Wh[2] = v2wh;   P.Wl[2] = v2wl;
        P.Cf[2] = v2;     P.Ch[2] = nullptr; P.Cl[2] = nullptr; P.outm[2] = 1;
        projgemm_kernel<<<dim3(2, 320), blk, SMEM>>>(P);
    }

    // depthwise 3x3 residual -> transposed V planes (coalesced writes)
    dwconv_res_t2_kernel<<<B_ * 4 * (N1_ / 64), 256>>>(v1, lc1_w, lc1_b, vt1h, vt1l, 16, 16);
    dwconv_res_t2_kernel<<<B_ * 4 * (N2_ / 64), 256>>>(v2, lc2_w, lc2_b, vt2h, vt2l, 32, 32);

    flash_kernel<<<dim3(8, 64), blk, FSMEM>>>(qph, qpl, k1ph, k1pl, vt1h, vt1l,
                                              xh, xl, N1_, 0, 0);
    flash_kernel<<<dim3(8, 64), blk, FSMEM>>>(qph, qpl, k2ph, k2pl, vt2h, vt2l,
                                              xh, xl, N2_, 4, 256);

    hgemm2_kernel<0, 1><<<dim3(4, 128), blk, SMEM>>>(xh, xl, pwh, pwl, proj_b,
                                                     out, nullptr, nullptr, 16384, 512, 512);
}

// round 8
// speedup vs baseline: 2.9392x; 1.0139x over previous
#include <cuda_runtime.h>
#include <cuda_bf16.h>
#include <math.h>
#include <stdint.h>

// ---------------------------------------------------------------------------
// Problem constants
// ---------------------------------------------------------------------------
constexpr int B_   = 16;
constexpr int C_   = 512;
constexpr int Qn   = 1024;
constexpr int C2_  = 256;
constexpr int N1_  = 256;
constexpr int N2_  = 1024;

// ---------------------------------------------------------------------------
// Device scratch
// ---------------------------------------------------------------------------
__device__ float g_kv1n [(size_t)2 * B_ * N1_ * C_];
__device__ float g_kv2n [(size_t)2 * B_ * N2_ * C_];
__device__ float g_kv1  [(size_t)2 * B_ * N1_ * C2_];   // fp32 k1|v1 (v1 -> dwconv)
__device__ float g_v2   [(size_t)B_ * N2_ * C2_];

// bf16 hi/lo planes
__device__ __nv_bfloat16 g_qh   [(size_t)16384 * 512];
__device__ __nv_bfloat16 g_ql   [(size_t)16384 * 512];
__device__ __nv_bfloat16 g_qph  [(size_t)16384 * 512];
__device__ __nv_bfloat16 g_qpl  [(size_t)16384 * 512];
__device__ __nv_bfloat16 g_imgh [(size_t)2 * B_ * C_ * 64 * 64];
__device__ __nv_bfloat16 g_imgl [(size_t)2 * B_ * C_ * 64 * 64];
__device__ __nv_bfloat16 g_kv1nh[(size_t)8192 * 512];
__device__ __nv_bfloat16 g_kv1nl[(size_t)8192 * 512];
__device__ __nv_bfloat16 g_kv2nh[(size_t)32768 * 512];
__device__ __nv_bfloat16 g_kv2nl[(size_t)32768 * 512];
__device__ __nv_bfloat16 g_k1ph [(size_t)8192 * 256];
__device__ __nv_bfloat16 g_k1pl [(size_t)8192 * 256];
__device__ __nv_bfloat16 g_k2ph [(size_t)16384 * 256];
__device__ __nv_bfloat16 g_k2pl [(size_t)16384 * 256];
__device__ __nv_bfloat16 g_vt1h [(size_t)B_ * C2_ * N1_];
__device__ __nv_bfloat16 g_vt1l [(size_t)B_ * C2_ * N1_];
__device__ __nv_bfloat16 g_vt2h [(size_t)B_ * C2_ * N2_];
__device__ __nv_bfloat16 g_vt2l [(size_t)B_ * C2_ * N2_];
__device__ __nv_bfloat16 g_xh   [(size_t)16384 * 512];
__device__ __nv_bfloat16 g_xl   [(size_t)16384 * 512];
// weight planes
__device__ __nv_bfloat16 g_qwh [262144],  g_qwl [262144];
__device__ __nv_bfloat16 g_s1wh[4194304], g_s1wl[4194304];
__device__ __nv_bfloat16 g_s2wh[1048576], g_s2wl[1048576];
__device__ __nv_bfloat16 g_k1wh[131072],  g_k1wl[131072];
__device__ __nv_bfloat16 g_k2wh[131072],  g_k2wl[131072];
__device__ __nv_bfloat16 g_v2wh[131072],  g_v2wl[131072];
__device__ __nv_bfloat16 g_pwh [262144],  g_pwl [262144];

// ---------------------------------------------------------------------------
// helpers
// ---------------------------------------------------------------------------
__device__ __forceinline__ uint32_t smem_u32(const void* p) {
    uint32_t a;
    asm("{ .reg .u64 t; cvta.to.shared.u64 t, %1; cvt.u32.u64 %0, t; }" : "=r"(a) : "l"(p));
    return a;
}
__device__ __forceinline__ void ldsm_x4(uint32_t& r0, uint32_t& r1, uint32_t& r2, uint32_t& r3,
                                        uint32_t addr) {
    asm volatile("ldmatrix.sync.aligned.m8n8.x4.shared.b16 {%0,%1,%2,%3}, [%4];"
                 : "=r"(r0), "=r"(r1), "=r"(r2), "=r"(r3) : "r"(addr));
}
__device__ __forceinline__ void mma_bf16(float* d,
                                         uint32_t a0, uint32_t a1, uint32_t a2, uint32_t a3,
                                         uint32_t b0, uint32_t b1) {
    asm volatile(
        "mma.sync.aligned.m16n8k16.row.col.f32.bf16.bf16.f32 "
        "{%0,%1,%2,%3}, {%4,%5,%6,%7}, {%8,%9}, {%0,%1,%2,%3};"
        : "+f"(d[0]), "+f"(d[1]), "+f"(d[2]), "+f"(d[3])
        : "r"(a0), "r"(a1), "r"(a2), "r"(a3), "r"(b0), "r"(b1));
}
__device__ __forceinline__ uint32_t pack_hi(float x, float y) {
    __nv_bfloat162 p(__float2bfloat16(x), __float2bfloat16(y));
    return *(uint32_t*)&p;
}
__device__ __forceinline__ uint32_t pack_lo(float x, float y) {
    float hx = __bfloat162float(__float2bfloat16(x));
    float hy = __bfloat162float(__float2bfloat16(y));
    __nv_bfloat162 p(__float2bfloat16(x - hx), __float2bfloat16(y - hy));
    return *(uint32_t*)&p;
}

#define CP_ASYNC8(dst, src) \
    asm volatile("cp.async.ca.shared.global [%0], [%1], 8;" :: "r"(dst), "l"(src) : "memory")
#define CP_ASYNC4(dst, src) \
    asm volatile("cp.async.ca.shared.global [%0], [%1], 4;" :: "r"(dst), "l"(src) : "memory")
#define CP_COMMIT() asm volatile("cp.async.commit_group;" ::: "memory")
#define CP_WAIT0()  asm volatile("cp.async.wait_group 0;" ::: "memory")
#define CP_WAIT1()  asm volatile("cp.async.wait_group 1;" ::: "memory")

// ---------------------------------------------------------------------------
// generic fp32 -> hi/lo bf16 planes
// ---------------------------------------------------------------------------
__global__ void split_kernel(const float* __restrict__ src,
                             __nv_bfloat16* __restrict__ h,
                             __nv_bfloat16* __restrict__ l)
{
    int i = blockIdx.x * 256 + threadIdx.x;
    float4 v = ((const float4*)src)[i];
    ((uint2*)h)[i] = make_uint2(pack_hi(v.x, v.y), pack_hi(v.z, v.w));
    ((uint2*)l)[i] = make_uint2(pack_lo(v.x, v.y), pack_lo(v.z, v.w));
}

// ---------------------------------------------------------------------------
// (N,B,C) -> raw-reshape image, split into bf16 hi/lo planes.
// One launch handles BOTH key and value: blocks [0,4096) key, [4096,8192) value.
// ---------------------------------------------------------------------------
__global__ void to_image_split2_kernel(const float* __restrict__ srcK,
                                       const float* __restrict__ srcV,
                                       __nv_bfloat16* __restrict__ h,
                                       __nv_bfloat16* __restrict__ l,
                                       size_t img1)
{
    __shared__ float sm[16][513];
    const int half = blockIdx.x >> 12;                 // 0 = key, 1 = value
    const float* src = half ? srcV : srcK;
    const size_t dofs = half ? img1 : 0;
    size_t base = (size_t)(blockIdx.x & 4095) * 8192;
    for (int j = threadIdx.x; j < 8192; j += 256) sm[j >> 9][j & 511] = src[base + j];
    __syncthreads();
    for (int r = threadIdx.x; r < 8192; r += 256) {
        float v = sm[r & 15][r >> 4];
        __nv_bfloat16 hv = __float2bfloat16(v);
        h[dofs + base + r] = hv;
        l[dofs + base + r] = __float2bfloat16(v - __bfloat162float(hv));
    }
}

// ---------------------------------------------------------------------------
// Split-bf16 HMMA GEMM, cp.async double-buffered, 2 CTAs/SM.
// OUT bit0: fp32 Cmat; bit1: bf16 planes.
// ---------------------------------------------------------------------------
template <int LOADER, int OUT>
__global__ __launch_bounds__(256, 2) void hgemm2_kernel(
    const __nv_bfloat16* __restrict__ Ah, const __nv_bfloat16* __restrict__ Al,
    const __nv_bfloat16* __restrict__ Wh, const __nv_bfloat16* __restrict__ Wl,
    const float* __restrict__ bias, float* __restrict__ Cmat,
    __nv_bfloat16* __restrict__ Ch, __nv_bfloat16* __restrict__ Cl,
    int M, int N, int K)
{
    extern __shared__ char smc[];
    const uint32_t sb = smem_u32(smc);

    const int tid  = threadIdx.x;
    const int wid  = tid >> 5;
    const int lane = tid & 31;
    const int bm = blockIdx.y << 7;
    const int bn = blockIdx.x << 7;
    const int m0 = (wid & 3) << 5;
    const int n0 = (wid >> 2) << 6;

    int rr[4], kk[4];
#pragma unroll
    for (int j = 0; j < 4; j++) {
        int s = tid + (j << 8);
        rr[j] = s >> 3;
        kk[j] = (s & 7) << 2;
    }

    const uint32_t lrow = (uint32_t)(lane & 15);
    const uint32_t lkq  = (uint32_t)(lane >> 4) * 16;
    const uint32_t aOff0 = (m0 + lrow) * 80 + lkq;
    const uint32_t aOff1 = aOff0 + 16 * 80;
    uint32_t bOff[4];
#pragma unroll
    for (int nt = 0; nt < 4; nt++) bOff[nt] = (n0 + nt * 16 + lrow) * 80 + lkq;

    float acc[2][8][4];
#pragma unroll
    for (int i = 0; i < 2; i++)
#pragma unroll
        for (int j = 0; j < 8; j++)
#pragma unroll
            for (int l = 0; l < 4; l++) acc[i][j][l] = 0.f;

    auto gaddrA = [&](const __nv_bfloat16* plane, int r, int k) -> const __nv_bfloat16* {
        if (LOADER == 0) {
            return plane + (size_t)(bm + r) * K + k;
        } else if (LOADER == 1) {
            int m = bm + r;
            int b = m >> 8, oy = (m >> 4) & 15, ox = m & 15;
            int ic = k >> 4, ky = (k >> 2) & 3;
            return plane + (((size_t)(b * 512 + ic) * 64) + oy * 4 + ky) * 64 + ox * 4;
        } else {
            int m = bm + r;
            int b = m >> 10, oy = (m >> 5) & 31, ox = m & 31;
            int ic = k >> 2;
            return plane + (((size_t)(b * 512 + ic) * 64) + oy * 2) * 64 + ox * 2;
        }
    };

    auto issue_chunk = [&](int buf, int k0) {
        const uint32_t bb = sb + (uint32_t)buf * 40960;
#pragma unroll
        for (int j = 0; j < 4; j++) {
            const uint32_t off = (uint32_t)rr[j] * 80 + (uint32_t)(kk[j] << 1);
            const int k = k0 + kk[j];
            const __nv_bfloat16* pah = gaddrA(Ah, rr[j], k);
            const __nv_bfloat16* pal = gaddrA(Al, rr[j], k);
            const __nv_bfloat16* pwh = Wh + (size_t)(bn + rr[j]) * K + k;
            const __nv_bfloat16* pwl = Wl + (size_t)(bn + rr[j]) * K + k;
            if (LOADER == 2) {
                CP_ASYNC4(bb + off,             pah);
                CP_ASYNC4(bb + off + 4,         pah + 64);
                CP_ASYNC4(bb + 10240 + off,     pal);
                CP_ASYNC4(bb + 10240 + off + 4, pal + 64);
            } else {
                CP_ASYNC8(bb + off,         pah);
                CP_ASYNC8(bb + 10240 + off, pal);
            }
            CP_ASYNC8(bb + 20480 + off, pwh);
            CP_ASYNC8(bb + 30720 + off, pwl);
        }
    };

    const int nchunks = K >> 5;
    issue_chunk(0, 0);
    CP_COMMIT();

    for (int c = 0; c < nchunks; c++) {
        const bool more = (c + 1) < nchunks;
        if (more) {
            issue_chunk((c + 1) & 1, (c + 1) << 5);
            CP_COMMIT();
            CP_WAIT1();
        } else {
            CP_WAIT0();
        }
        __syncthreads();

        const uint32_t bb = sb + (uint32_t)(c & 1) * 40960;
        const uint32_t AhB = bb, AlB = bb + 10240, WhB = bb + 20480, WlB = bb + 30720;
#pragma unroll
        for (int s = 0; s < 3; s++) {
            const uint32_t ab = (s == 2) ? AlB : AhB;
            const uint32_t wb = (s == 1) ? WlB : WhB;
#pragma unroll
            for (int kh = 0; kh < 2; kh++) {
                const uint32_t ko = (uint32_t)kh * 32;
                uint32_t a0, a1, a2, a3, a4, a5, a6, a7;
                ldsm_x4(a0, a1, a2, a3, ab + aOff0 + ko);
                ldsm_x4(a4, a5, a6, a7, ab + aOff1 + ko);
#pragma unroll
                for (int nt = 0; nt < 4; nt++) {
                    uint32_t b0, b1, b2, b3;
                    ldsm_x4(b0, b1, b2, b3, wb + bOff[nt] + ko);
                    mma_bf16(acc[0][nt * 2 + 0], a0, a1, a2, a3, b0, b2);
                    mma_bf16(acc[0][nt * 2 + 1], a0, a1, a2, a3, b1, b3);
                    mma_bf16(acc[1][nt * 2 + 0], a4, a5, a6, a7, b0, b2);
                    mma_bf16(acc[1][nt * 2 + 1], a4, a5, a6, a7, b1, b3);
                }
            }
        }
        __syncthreads();
    }

    const int gr = lane >> 2;
    const int gc = (lane & 3) * 2;
#pragma unroll
    for (int mt = 0; mt < 2; mt++) {
        const int row0 = bm + m0 + mt * 16 + gr;
#pragma unroll
        for (int nt = 0; nt < 8; nt++) {
            const int col = bn + n0 + nt * 8 + gc;
            float b0 = bias ? bias[col] : 0.f;
            float b1 = bias ? bias[col + 1] : 0.f;
            float o0 = acc[mt][nt][0] + b0, o1 = acc[mt][nt][1] + b1;
            float o2 = acc[mt][nt][2] + b0, o3 = acc[mt][nt][3] + b1;
            if (OUT & 1) {
                *(float2*)(Cmat + (size_t)row0 * N + col) = make_float2(o0, o1);
                *(float2*)(Cmat + (size_t)(row0 + 8) * N + col) = make_float2(o2, o3);
            }
            if (OUT & 2) {
                size_t i0 = ((size_t)row0 * N + col) >> 1;
                size_t i1 = ((size_t)(row0 + 8) * N + col) >> 1;
                ((uint32_t*)Ch)[i0] = pack_hi(o0, o1);
                ((uint32_t*)Cl)[i0] = pack_lo(o0, o1);
                ((uint32_t*)Ch)[i1] = pack_hi(o2, o3);
                ((uint32_t*)Cl)[i1] = pack_lo(o2, o3);
            }
        }
    }
}

// ---------------------------------------------------------------------------
// Merged head-projection GEMM (3 sub-problems, one launch).
// ---------------------------------------------------------------------------
struct ProjParams {
    const __nv_bfloat16 *Ah[3], *Al[3], *Wh[3], *Wl[3];
    float* Cf[3];
    __nv_bfloat16 *Ch[3], *Cl[3];
    int outm[3];
};

__global__ __launch_bounds__(256, 2) void projgemm_kernel(ProjParams P)
{
    extern __shared__ char smc[];
    const uint32_t sb = smem_u32(smc);
    constexpr int K = 512, N = 256;

    const int y = blockIdx.y;
    const int pi = (y < 64) ? 0 : (y < 192 ? 1 : 2);
    const int ylocal = y - ((pi == 0) ? 0 : (pi == 1) ? 64 : 192);

    const __nv_bfloat16* Ah = P.Ah[pi];
    const __nv_bfloat16* Al = P.Al[pi];
    const __nv_bfloat16* Wh = P.Wh[pi];
    const __nv_bfloat16* Wl = P.Wl[pi];
    float* Cmat = P.Cf[pi];
    __nv_bfloat16* Ch = P.Ch[pi];
    __nv_bfloat16* Cl = P.Cl[pi];
    const int OUT = P.outm[pi];

    const int tid  = threadIdx.x;
    const int wid  = tid >> 5;
    const int lane = tid & 31;
    const int bm = ylocal << 7;
    const int bn = blockIdx.x << 7;
    const int m0 = (wid & 3) << 5;
    const int n0 = (wid >> 2) << 6;

    int rr[4], kk[4];
#pragma unroll
    for (int j = 0; j < 4; j++) {
        int s = tid + (j << 8);
        rr[j] = s >> 3;
        kk[j] = (s & 7) << 2;
    }

    const uint32_t lrow = (uint32_t)(lane & 15);
    const uint32_t lkq  = (uint32_t)(lane >> 4) * 16;
    const uint32_t aOff0 = (m0 + lrow) * 80 + lkq;
    const uint32_t aOff1 = aOff0 + 16 * 80;
    uint32_t bOff[4];
#pragma unroll
    for (int nt = 0; nt < 4; nt++) bOff[nt] = (n0 + nt * 16 + lrow) * 80 + lkq;

    float acc[2][8][4];
#pragma unroll
    for (int i = 0; i < 2; i++)
#pragma unroll
        for (int j = 0; j < 8; j++)
#pragma unroll
            for (int l = 0; l < 4; l++) acc[i][j][l] = 0.f;

    auto issue_chunk = [&](int buf, int k0) {
        const uint32_t bb = sb + (uint32_t)buf * 40960;
#pragma unroll
        for (int j = 0; j < 4; j++) {
            const uint32_t off = (uint32_t)rr[j] * 80 + (uint32_t)(kk[j] << 1);
            const int k = k0 + kk[j];
            CP_ASYNC8(bb + off,         Ah + (size_t)(bm + rr[j]) * K + k);
            CP_ASYNC8(bb + 10240 + off, Al + (size_t)(bm + rr[j]) * K + k);
            CP_ASYNC8(bb + 20480 + off, Wh + (size_t)(bn + rr[j]) * K + k);
            CP_ASYNC8(bb + 30720 + off, Wl + (size_t)(bn + rr[j]) * K + k);
        }
    };

    const int nchunks = K >> 5;
    issue_chunk(0, 0);
    CP_COMMIT();

    for (int c = 0; c < nchunks; c++) {
        const bool more = (c + 1) < nchunks;
        if (more) {
            issue_chunk((c + 1) & 1, (c + 1) << 5);
            CP_COMMIT();
            CP_WAIT1();
        } else {
            CP_WAIT0();
        }
        __syncthreads();

        const uint32_t bb = sb + (uint32_t)(c & 1) * 40960;
        const uint32_t AhB = bb, AlB = bb + 10240, WhB = bb + 20480, WlB = bb + 30720;
#pragma unroll
        for (int s = 0; s < 3; s++) {
            const uint32_t ab = (s == 2) ? AlB : AhB;
            const uint32_t wb = (s == 1) ? WlB : WhB;
#pragma unroll
            for (int kh = 0; kh < 2; kh++) {
                const uint32_t ko = (uint32_t)kh * 32;
                uint32_t a0, a1, a2, a3, a4, a5, a6, a7;
                ldsm_x4(a0, a1, a2, a3, ab + aOff0 + ko);
                ldsm_x4(a4, a5, a6, a7, ab + aOff1 + ko);
#pragma unroll
                for (int nt = 0; nt < 4; nt++) {
                    uint32_t b0, b1, b2, b3;
                    ldsm_x4(b0, b1, b2, b3, wb + bOff[nt] + ko);
                    mma_bf16(acc[0][nt * 2 + 0], a0, a1, a2, a3, b0, b2);
                    mma_bf16(acc[0][nt * 2 + 1], a0, a1, a2, a3, b1, b3);
                    mma_bf16(acc[1][nt * 2 + 0], a4, a5, a6, a7, b0, b2);
                    mma_bf16(acc[1][nt * 2 + 1], a4, a5, a6, a7, b1, b3);
                }
            }
        }
        __syncthreads();
    }

    const int gr = lane >> 2;
    const int gc = (lane & 3) * 2;
#pragma unroll
    for (int mt = 0; mt < 2; mt++) {
        const int row0 = bm + m0 + mt * 16 + gr;
#pragma unroll
        for (int nt = 0; nt < 8; nt++) {
            const int col = bn + n0 + nt * 8 + gc;
            float o0 = acc[mt][nt][0], o1 = acc[mt][nt][1];
            float o2 = acc[mt][nt][2], o3 = acc[mt][nt][3];
            if (OUT & 1) {
                *(float2*)(Cmat + (size_t)row0 * N + col) = make_float2(o0, o1);
                *(float2*)(Cmat + (size_t)(row0 + 8) * N + col) = make_float2(o2, o3);
            }
            if (OUT & 2) {
                size_t i0 = ((size_t)row0 * N + col) >> 1;
                size_t i1 = ((size_t)(row0 + 8) * N + col) >> 1;
                ((uint32_t*)Ch)[i0] = pack_hi(o0, o1);
                ((uint32_t*)Cl)[i0] = pack_lo(o0, o1);
                ((uint32_t*)Ch)[i1] = pack_hi(o2, o3);
                ((uint32_t*)Cl)[i1] = pack_lo(o2, o3);
            }
        }
    }
}

// ---------------------------------------------------------------------------
// LayerNorm(512) + exact GELU -> bf16 hi/lo planes
// ---------------------------------------------------------------------------
__global__ void ln_gelu_split_kernel(const float* __restrict__ x,
                                     const float* __restrict__ w,
                                     const float* __restrict__ b,
                                     __nv_bfloat16* __restrict__ hO,
                                     __nv_bfloat16* __restrict__ lO)
{
    __shared__ float sh[8];
    const float* row = x + (size_t)blockIdx.x * 512;
    int t = threadIdx.x;
    float2 v = *(const float2*)(row + t * 2);

    float s = v.x + v.y;
#pragma unroll
    for (int o = 16; o; o >>= 1) s += __shfl_xor_sync(0xffffffffu, s, o);
    if ((t & 31) == 0) sh[t >> 5] = s;
    __syncthreads();
    float tot = 0.f;
#pragma unroll
    for (int i = 0; i < 8; i++) tot += sh[i];
    float mu = tot * (1.f / 512.f);
    float d0 = v.x - mu, d1 = v.y - mu;
    __syncthreads();

    float ss = d0 * d0 + d1 * d1;
#pragma unroll
    for (int o = 16; o; o >>= 1) ss += __shfl_xor_sync(0xffffffffu, ss, o);
    if ((t & 31) == 0) sh[t >> 5] = ss;
    __syncthreads();
    float tot2 = 0.f;
#pragma unroll
    for (int i = 0; i < 8; i++) tot2 += sh[i];
    float inv = rsqrtf(tot2 * (1.f / 512.f) + 1e-5f);

    float y0 = d0 * inv * w[t * 2]     + b[t * 2];
    float y1 = d1 * inv * w[t * 2 + 1] + b[t * 2 + 1];
    y0 = 0.5f * y0 * (1.f + erff(y0 * 0.7071067811865476f));
    y1 = 0.5f * y1 * (1.f + erff(y1 * 0.7071067811865476f));

    size_t o = (size_t)blockIdx.x * 256 + t;
    ((uint32_t*)hO)[o] = pack_hi(y0, y1);
    ((uint32_t*)lO)[o] = pack_lo(y0, y1);
}

// ---------------------------------------------------------------------------
// Depthwise 3x3 (pad 1) residual -> transposed planes, coalesced via smem tile.
// ---------------------------------------------------------------------------
__global__ void dwconv_res_t2_kernel(const float* __restrict__ v,
                                     const float* __restrict__ lw,
                                     const float* __restrict__ lb,
                                     __nv_bfloat16* __restrict__ vth,
                                     __nv_bfloat16* __restrict__ vtl,
                                     int hh, int ww)
{
    __shared__ float sm[64][65];
    const int Nn = hh * ww;
    const int nt = Nn >> 6;
    int bz = blockIdx.x;
    const int ntile = bz % nt; bz /= nt;
    const int ct = bz & 3;
    const int bb = bz >> 2;
    const int c0 = ct << 6, n0 = ntile << 6;

    const int tid = threadIdx.x;
    const int tc = tid & 63;
    const int tn0 = tid >> 6;
    const int c = c0 + tc;

    float wreg[9];
#pragma unroll
    for (int i = 0; i < 9; i++) wreg[i] = lw[c * 9 + i];
    const float bias = lb[c];

    for (int nn = tn0; nn < 64; nn += 4) {
        const int n = n0 + nn;
        const int y = n / ww;
        const int x = n - y * ww;
        float acc = bias;
#pragma unroll
        for (int dy = -1; dy <= 1; dy++) {
            int yy = y + dy;
            if (yy < 0 || yy >= hh) continue;
#pragma unroll
            for (int dx = -1; dx <= 1; dx++) {
                int xx = x + dx;
                if (xx < 0 || xx >= ww) continue;
                acc += v[((size_t)(bb * Nn + yy * ww + xx) << 8) + c] * wreg[(dy + 1) * 3 + (dx + 1)];
            }
        }
        sm[nn][tc] = v[((size_t)(bb * Nn + n) << 8) + c] + acc;
    }
    __syncthreads();

    const int wc = tid >> 5;
    const int wn = (tid & 31) << 1;
    for (int cc = wc; cc < 64; cc += 8) {
        float v0 = sm[wn][cc], v1 = sm[wn + 1][cc];
        size_t o = (((size_t)(bb * 256 + c0 + cc)) * Nn + n0 + wn) >> 1;
        ((uint32_t*)vth)[o] = pack_hi(v0, v1);
        ((uint32_t*)vtl)[o] = pack_lo(v0, v1);
    }
}

// ---------------------------------------------------------------------------
// Flash attention, split-bf16 HMMA, K/V double-buffered (cp.async), 2 CTAs/SM.
// smem: Q 36864 | KVbuf0 36864 | KVbuf1 36864 = 110592.
//   KV buf: KH +0, KL +9216, VH +18432, VL +27648 (each 64 rows x 144B).
// ---------------------------------------------------------------------------
__global__ __launch_bounds__(256, 2) void flash_kernel(
    const __nv_bfloat16* __restrict__ qph, const __nv_bfloat16* __restrict__ qpl,
    const __nv_bfloat16* __restrict__ kph, const __nv_bfloat16* __restrict__ kpl,
    const __nv_bfloat16* __restrict__ vth, const __nv_bfloat16* __restrict__ vtl,
    __nv_bfloat16* __restrict__ xh, __nv_bfloat16* __restrict__ xl,
    int Nk, int hoff, int coloff)
{
    extern __shared__ char smc[];
    const uint32_t sb = smem_u32(smc);
    const uint32_t QH = sb, QL = sb + 18432;

    const int tid  = threadIdx.x;
    const int wid  = tid >> 5;
    const int lane = tid & 31;
    const int b = blockIdx.y >> 2;
    const int h = blockIdx.y & 3;
    const int q0 = blockIdx.x << 7;

    // ---- Q tile load (group 0) ----
    {
        const size_t qbase = ((size_t)(b * Qn + q0)) * 512 + (size_t)(hoff + h) * 64;
#pragma unroll
        for (int it = 0; it < 8; it++) {
            int i = tid + (it << 8);
            int row = i >> 4;
            int c4 = (i & 15) << 2;
            uint32_t dst = (uint32_t)row * 144 + (uint32_t)(c4 << 1);
            CP_ASYNC8(QH + dst, qph + qbase + (size_t)row * 512 + c4);
            CP_ASYNC8(QL + dst, qpl + qbase + (size_t)row * 512 + c4);
        }
        CP_COMMIT();
    }

    auto issue_kv = [&](int buf, int kv0) {
        const uint32_t bb = sb + 36864 + (uint32_t)buf * 36864;
#pragma unroll
        for (int it = 0; it < 4; it++) {
            int i = tid + (it << 8);
            int row = i >> 4;
            int c4 = (i & 15) << 2;
            uint32_t dst = (uint32_t)row * 144 + (uint32_t)(c4 << 1);
            size_t kidx = ((size_t)(b * Nk + kv0 + row)) * 256 + h * 64 + c4;
            CP_ASYNC8(bb + dst,         kph + kidx);
            CP_ASYNC8(bb + 9216 + dst,  kpl + kidx);
            size_t vidx = ((size_t)(b * 256 + h * 64 + row)) * Nk + kv0 + c4;
            CP_ASYNC8(bb + 18432 + dst, vth + vidx);
            CP_ASYNC8(bb + 27648 + dst, vtl + vidx);
        }
    };

    const uint32_t lrow = (uint32_t)(lane & 15);
    const uint32_t lkq  = (uint32_t)(lane >> 4) * 16;
    const uint32_t qOff = ((uint32_t)(wid * 16) + lrow) * 144 + lkq;
    const uint32_t kOff = lrow * 144 + lkq;

    const int gr = lane >> 2;

    float m0 = -1e30f, m1 = -1e30f, l0 = 0.f, l1 = 0.f;
    float Oacc[8][4];
#pragma unroll
    for (int j = 0; j < 8; j++)
#pragma unroll
        for (int l = 0; l < 4; l++) Oacc[j][l] = 0.f;

    const int ntiles = Nk >> 6;
    issue_kv(0, 0);
    CP_COMMIT();

    for (int t = 0; t < ntiles; t++) {
        const bool more = (t + 1) < ntiles;
        if (more) {
            issue_kv((t + 1) & 1, (t + 1) << 6);
            CP_COMMIT();
            CP_WAIT1();          // tile t (and Q) complete
        } else {
            CP_WAIT0();
        }
        __syncthreads();

        const uint32_t bb = sb + 36864 + (uint32_t)(t & 1) * 36864;
        const uint32_t KH = bb, KL = bb + 9216, VH = bb + 18432, VL = bb + 27648;

        // ---- S = Q K^T (3-pass split) ----
        float S[8][4];
#pragma unroll
        for (int j = 0; j < 8; j++)
#pragma unroll
            for (int l = 0; l < 4; l++) S[j][l] = 0.f;

#pragma unroll
        for (int s = 0; s < 3; s++) {
            const uint32_t qb = (s == 2) ? QL : QH;
            const uint32_t kb = (s == 1) ? KL : KH;
#pragma unroll
            for (int ks = 0; ks < 4; ks++) {
                const uint32_t ko = (uint32_t)ks * 32;
                uint32_t a0, a1, a2, a3;
                ldsm_x4(a0, a1, a2, a3, qb + qOff + ko);
#pragma unroll
                for (int g = 0; g < 4; g++) {
                    uint32_t b0, b1, b2, b3;
                    ldsm_x4(b0, b1, b2, b3, kb + (uint32_t)g * 2304 + kOff + ko);
                    mma_bf16(S[2 * g + 0], a0, a1, a2, a3, b0, b2);
                    mma_bf16(S[2 * g + 1], a0, a1, a2, a3, b1, b3);
                }
            }
        }

        // ---- online softmax ----
        const float sc = 0.125f;
        float mx0 = m0, mx1 = m1;
#pragma unroll
        for (int j = 0; j < 8; j++) {
            S[j][0] *= sc; S[j][1] *= sc; S[j][2] *= sc; S[j][3] *= sc;
            mx0 = fmaxf(mx0, fmaxf(S[j][0], S[j][1]));
            mx1 = fmaxf(mx1, fmaxf(S[j][2], S[j][3]));
        }
#pragma unroll
        for (int o = 1; o <= 2; o <<= 1) {
            mx0 = fmaxf(mx0, __shfl_xor_sync(0xffffffffu, mx0, o));
            mx1 = fmaxf(mx1, __shfl_xor_sync(0xffffffffu, mx1, o));
        }
        const float alpha0 = __expf(m0 - mx0);
        const float alpha1 = __expf(m1 - mx1);
        m0 = mx0; m1 = mx1;

        float rs0 = 0.f, rs1 = 0.f;
#pragma unroll
        for (int j = 0; j < 8; j++) {
            S[j][0] = __expf(S[j][0] - mx0);
            S[j][1] = __expf(S[j][1] - mx0);
            S[j][2] = __expf(S[j][2] - mx1);
            S[j][3] = __expf(S[j][3] - mx1);
            rs0 += S[j][0] + S[j][1];
            rs1 += S[j][2] + S[j][3];
        }
#pragma unroll
        for (int o = 1; o <= 2; o <<= 1) {
            rs0 += __shfl_xor_sync(0xffffffffu, rs0, o);
            rs1 += __shfl_xor_sync(0xffffffffu, rs1, o);
        }
        l0 = l0 * alpha0 + rs0;
        l1 = l1 * alpha1 + rs1;

#pragma unroll
        for (int j = 0; j < 8; j++) {
            Oacc[j][0] *= alpha0; Oacc[j][1] *= alpha0;
            Oacc[j][2] *= alpha1; Oacc[j][3] *= alpha1;
        }

        // ---- O += P V (3-pass split) ----
#pragma unroll
        for (int t16 = 0; t16 < 4; t16++) {
            uint32_t ph0 = pack_hi(S[2 * t16][0],     S[2 * t16][1]);
            uint32_t ph1 = pack_hi(S[2 * t16][2],     S[2 * t16][3]);
            uint32_t ph2 = pack_hi(S[2 * t16 + 1][0], S[2 * t16 + 1][1]);
            uint32_t ph3 = pack_hi(S[2 * t16 + 1][2], S[2 * t16 + 1][3]);
            uint32_t pl0 = pack_lo(S[2 * t16][0],     S[2 * t16][1]);
            uint32_t pl1 = pack_lo(S[2 * t16][2],     S[2 * t16][3]);
            uint32_t pl2 = pack_lo(S[2 * t16 + 1][0], S[2 * t16 + 1][1]);
            uint32_t pl3 = pack_lo(S[2 * t16 + 1][2], S[2 * t16 + 1][3]);
            const uint32_t ko = (uint32_t)t16 * 32;
#pragma unroll
            for (int g = 0; g < 4; g++) {
                uint32_t vh0, vh1, vh2, vh3;
                ldsm_x4(vh0, vh1, vh2, vh3, VH + (uint32_t)g * 2304 + kOff + ko);
                mma_bf16(Oacc[2 * g + 0], ph0, ph1, ph2, ph3, vh0, vh2);
                mma_bf16(Oacc[2 * g + 1], ph0, ph1, ph2, ph3, vh1, vh3);
                mma_bf16(Oacc[2 * g + 0], pl0, pl1, pl2, pl3, vh0, vh2);
                mma_bf16(Oacc[2 * g + 1], pl0, pl1, pl2, pl3, vh1, vh3);
                uint32_t vl0, vl1, vl2, vl3;
                ldsm_x4(vl0, vl1, vl2, vl3, VL + (uint32_t)g * 2304 + kOff + ko);
                mma_bf16(Oacc[2 * g + 0], ph0, ph1, ph2, ph3, vl0, vl2);
                mma_bf16(Oacc[2 * g + 1], ph0, ph1, ph2, ph3, vl1, vl3);
            }
        }
        __syncthreads();
    }

    // ---- epilogue ----
    const float inv0 = 1.f / l0;
    const float inv1 = 1.f / l1;
    const int gc = (lane & 3) * 2;
    const int row0 = b * Qn + q0 + wid * 16 + gr;
#pragma unroll
    for (int j = 0; j < 8; j++) {
        const int col = coloff + h * 64 + (j >> 1) * 16 + (j & 1) * 8 + gc;
        float o0 = Oacc[j][0] * inv0, o1 = Oacc[j][1] * inv0;
        float o2 = Oacc[j][2] * inv1, o3 = Oacc[j][3] * inv1;
        size_t i0 = ((size_t)row0 * 512 + col) >> 1;
        size_t i1 = ((size_t)(row0 + 8) * 512 + col) >> 1;
        ((uint32_t*)xh)[i0] = pack_hi(o0, o1);
        ((uint32_t*)xl)[i0] = pack_lo(o0, o1);
        ((uint32_t*)xh)[i1] = pack_hi(o2, o3);
        ((uint32_t*)xl)[i1] = pack_lo(o2, o3);
    }
}

// ---------------------------------------------------------------------------
// Host launch sequence
// ---------------------------------------------------------------------------
extern "C" void kernel_launch(void* const* d_in, const int* in_sizes, int n_in,
                              void* d_out, int out_size)
{
    (void)in_sizes; (void)out_size;
    const int s = (n_in >= 24) ? 2 : 0;

    const float* query   = (const float*)d_in[0];
    const float* key     = (const float*)d_in[1];
    const float* value   = (const float*)d_in[2];
    const float* q_w     = (const float*)d_in[3 + s];
    const float* sr1_w   = (const float*)d_in[4 + s];
    const float* sr1_b   = (const float*)d_in[5 + s];
    const float* norm1_w = (const float*)d_in[6 + s];
    const float* norm1_b = (const float*)d_in[7 + s];
    const float* sr2_w   = (const float*)d_in[8 + s];
    const float* sr2_b   = (const float*)d_in[9 + s];
    const float* norm2_w = (const float*)d_in[10 + s];
    const float* norm2_b = (const float*)d_in[11 + s];
    const float* k1_w    = (const float*)d_in[12 + s];
    const float* k2_w    = (const float*)d_in[14 + s];
    const float* v2_w    = (const float*)d_in[15 + s];
    const float* lc1_w   = (const float*)d_in[16 + s];
    const float* lc1_b   = (const float*)d_in[17 + s];
    const float* lc2_w   = (const float*)d_in[18 + s];
    const float* lc2_b   = (const float*)d_in[19 + s];
    const float* proj_w  = (const float*)d_in[20 + s];
    const float* proj_b  = (const float*)d_in[21 + s];
    float* out = (float*)d_out;

    float *kv1n, *kv2n, *kv1, *v2;
    cudaGetSymbolAddress((void**)&kv1n, g_kv1n);
    cudaGetSymbolAddress((void**)&kv2n, g_kv2n);
    cudaGetSymbolAddress((void**)&kv1,  g_kv1);
    cudaGetSymbolAddress((void**)&v2,   g_v2);

    __nv_bfloat16 *qh, *ql, *qph, *qpl, *imgh, *imgl, *kv1nh, *kv1nl, *kv2nh, *kv2nl;
    __nv_bfloat16 *k1ph, *k1pl, *k2ph, *k2pl, *vt1h, *vt1l, *vt2h, *vt2l, *xh, *xl;
    __nv_bfloat16 *qwh, *qwl, *s1wh, *s1wl, *s2wh, *s2wl, *k1wh, *k1wl, *k2wh, *k2wl, *v2wh, *v2wl, *pwh, *pwl;
    cudaGetSymbolAddress((void**)&qh, g_qh);       cudaGetSymbolAddress((void**)&ql, g_ql);
    cudaGetSymbolAddress((void**)&qph, g_qph);     cudaGetSymbolAddress((void**)&qpl, g_qpl);
    cudaGetSymbolAddress((void**)&imgh, g_imgh);   cudaGetSymbolAddress((void**)&imgl, g_imgl);
    cudaGetSymbolAddress((void**)&kv1nh, g_kv1nh); cudaGetSymbolAddress((void**)&kv1nl, g_kv1nl);
    cudaGetSymbolAddress((void**)&kv2nh, g_kv2nh); cudaGetSymbolAddress((void**)&kv2nl, g_kv2nl);
    cudaGetSymbolAddress((void**)&k1ph, g_k1ph);   cudaGetSymbolAddress((void**)&k1pl, g_k1pl);
    cudaGetSymbolAddress((void**)&k2ph, g_k2ph);   cudaGetSymbolAddress((void**)&k2pl, g_k2pl);
    cudaGetSymbolAddress((void**)&vt1h, g_vt1h);   cudaGetSymbolAddress((void**)&vt1l, g_vt1l);
    cudaGetSymbolAddress((void**)&vt2h, g_vt2h);   cudaGetSymbolAddress((void**)&vt2l, g_vt2l);
    cudaGetSymbolAddress((void**)&xh, g_xh);       cudaGetSymbolAddress((void**)&xl, g_xl);
    cudaGetSymbolAddress((void**)&qwh, g_qwh);     cudaGetSymbolAddress((void**)&qwl, g_qwl);
    cudaGetSymbolAddress((void**)&s1wh, g_s1wh);   cudaGetSymbolAddress((void**)&s1wl, g_s1wl);
    cudaGetSymbolAddress((void**)&s2wh, g_s2wh);   cudaGetSymbolAddress((void**)&s2wl, g_s2wl);
    cudaGetSymbolAddress((void**)&k1wh, g_k1wh);   cudaGetSymbolAddress((void**)&k1wl, g_k1wl);
    cudaGetSymbolAddress((void**)&k2wh, g_k2wh);   cudaGetSymbolAddress((void**)&k2wl, g_k2wl);
    cudaGetSymbolAddress((void**)&v2wh, g_v2wh);   cudaGetSymbolAddress((void**)&v2wl, g_v2wl);
    cudaGetSymbolAddress((void**)&pwh, g_pwh);     cudaGetSymbolAddress((void**)&pwl, g_pwl);

    const size_t IMG1 = (size_t)B_ * C_ * 64 * 64;
    float* v1 = kv1 + (size_t)B_ * N1_ * C2_;

    const int SMEM = 81920;
    cudaFuncSetAttribute(hgemm2_kernel<0, 1>, cudaFuncAttributeMaxDynamicSharedMemorySize, SMEM);
    cudaFuncSetAttribute(hgemm2_kernel<0, 2>, cudaFuncAttributeMaxDynamicSharedMemorySize, SMEM);
    cudaFuncSetAttribute(hgemm2_kernel<1, 1>, cudaFuncAttributeMaxDynamicSharedMemorySize, SMEM);
    cudaFuncSetAttribute(hgemm2_kernel<2, 1>, cudaFuncAttributeMaxDynamicSharedMemorySize, SMEM);
    cudaFuncSetAttribute(projgemm_kernel, cudaFuncAttributeMaxDynamicSharedMemorySize, SMEM);
    const int FSMEM = 110592;
    cudaFuncSetAttribute(flash_kernel, cudaFuncAttributeMaxDynamicSharedMemorySize, FSMEM);

    dim3 blk(256);

    split_kernel<<<256, 256>>>(q_w, qwh, qwl);
    split_kernel<<<4096, 256>>>(sr1_w, s1wh, s1wl);
    split_kernel<<<1024, 256>>>(sr2_w, s2wh, s2wl);
    to_image_split2_kernel<<<8192, 256>>>(key, value, imgh, imgl, IMG1);

    // SR convs (K+V fused in M)
    hgemm2_kernel<1, 1><<<dim3(4, 64),  blk, SMEM>>>(imgh, imgl, s1wh, s1wl, sr1_b,
                                                     kv1n, nullptr, nullptr, 8192, 512, 8192);

    split_kernel<<<128, 256>>>(k1_w, k1wh, k1wl);
    split_kernel<<<128, 256>>>(k2_w, k2wh, k2wl);
    split_kernel<<<128, 256>>>(v2_w, v2wh, v2wl);
    split_kernel<<<256, 256>>>(proj_w, pwh, pwl);
    split_kernel<<<8192, 256>>>(query, qh, ql);

    hgemm2_kernel<2, 1><<<dim3(4, 256), blk, SMEM>>>(imgh, imgl, s2wh, s2wl, sr2_b,
                                                     kv2n, nullptr, nullptr, 32768, 512, 2048);

    hgemm2_kernel<0, 2><<<dim3(4, 128), blk, SMEM>>>(qh, ql, qwh, qwl, nullptr,
                                                     nullptr, qph, qpl, 16384, 512, 512);

    ln_gelu_split_kernel<<<8192,  256>>>(kv1n, norm1_w, norm1_b, kv1nh, kv1nl);
    ln_gelu_split_kernel<<<32768, 256>>>(kv2n, norm2_w, norm2_b, kv2nh, kv2nl);

    {
        ProjParams P;
        P.Ah[0] = kv1nh;  P.Al[0] = kv1nl;  P.Wh[0] = k1wh; P.Wl[0] = k1wl;
        P.Cf[0] = kv1;    P.Ch[0] = k1ph;   P.Cl[0] = k1pl; P.outm[0] = 3;
        P.Ah[1] = kv2nh;  P.Al[1] = kv2nl;  P.Wh[1] = k2wh; P.Wl[1] = k2wl;
        P.Cf[1] = nullptr; P.Ch[1] = k2ph;  P.Cl[1] = k2pl; P.outm[1] = 2;
        P.Ah[2] = kv2nh + (size_t)16384 * 512;
        P.Al[2] = kv2nl + (size_t)16384 * 512;
        P.Wh[2] = v2wh;   P.Wl[2] = v2wl;
        P.Cf[2] = v2;     P.Ch[2] = nullptr; P.Cl[2] = nullptr; P.outm[2] = 1;
        projgemm_kernel<<<dim3(2, 320), blk, SMEM>>>(P);
    }

    dwconv_res_t2_kernel<<<B_ * 4 * (N1_ / 64), 256>>>(v1, lc1_w, lc1_b, vt1h, vt1l, 16, 16);
    dwconv_res_t2_kernel<<<B_ * 4 * (N2_ / 64), 256>>>(v2, lc2_w, lc2_b, vt2h, vt2l, 32, 32);

    flash_kernel<<<dim3(8, 64), blk, FSMEM>>>(qph, qpl, k1ph, k1pl, vt1h, vt1l,
                                              xh, xl, N1_, 0, 0);
    flash_kernel<<<dim3(8, 64), blk, FSMEM>>>(qph, qpl, k2ph, k2pl, vt2h, vt2l,
                                              xh, xl, N2_, 4, 256);

    hgemm2_kernel<0, 1><<<dim3(4, 128), blk, SMEM>>>(xh, xl, pwh, pwl, proj_b,
                                                     out, nullptr, nullptr, 16384, 512, 512);
}

// round 9
// speedup vs baseline: 3.1342x; 1.0663x over previous
#include <cuda_runtime.h>
#include <cuda_bf16.h>
#include <math.h>
#include <stdint.h>

// ---------------------------------------------------------------------------
// Problem constants
// ---------------------------------------------------------------------------
constexpr int B_   = 16;
constexpr int C_   = 512;
constexpr int Qn   = 1024;
constexpr int C2_  = 256;
constexpr int N1_  = 256;
constexpr int N2_  = 1024;

// ---------------------------------------------------------------------------
// Device scratch
// ---------------------------------------------------------------------------
__device__ float g_kv1n [(size_t)2 * B_ * N1_ * C_];
__device__ float g_kv2n [(size_t)2 * B_ * N2_ * C_];
__device__ float g_kv1  [(size_t)2 * B_ * N1_ * C2_];   // fp32 k1|v1 (v1 -> dwconv)
__device__ float g_v2   [(size_t)B_ * N2_ * C2_];

// bf16 hi/lo planes
__device__ __nv_bfloat16 g_qh   [(size_t)16384 * 512];
__device__ __nv_bfloat16 g_ql   [(size_t)16384 * 512];
__device__ __nv_bfloat16 g_qph  [(size_t)16384 * 512];
__device__ __nv_bfloat16 g_qpl  [(size_t)16384 * 512];
__device__ __nv_bfloat16 g_imgh [(size_t)2 * B_ * C_ * 64 * 64];
__device__ __nv_bfloat16 g_imgl [(size_t)2 * B_ * C_ * 64 * 64];
__device__ __nv_bfloat16 g_kv1nh[(size_t)8192 * 512];
__device__ __nv_bfloat16 g_kv1nl[(size_t)8192 * 512];
__device__ __nv_bfloat16 g_kv2nh[(size_t)32768 * 512];
__device__ __nv_bfloat16 g_kv2nl[(size_t)32768 * 512];
__device__ __nv_bfloat16 g_k1ph [(size_t)8192 * 256];
__device__ __nv_bfloat16 g_k1pl [(size_t)8192 * 256];
__device__ __nv_bfloat16 g_k2ph [(size_t)16384 * 256];
__device__ __nv_bfloat16 g_k2pl [(size_t)16384 * 256];
__device__ __nv_bfloat16 g_vt1h [(size_t)B_ * C2_ * N1_];
__device__ __nv_bfloat16 g_vt1l [(size_t)B_ * C2_ * N1_];
__device__ __nv_bfloat16 g_vt2h [(size_t)B_ * C2_ * N2_];
__device__ __nv_bfloat16 g_vt2l [(size_t)B_ * C2_ * N2_];
__device__ __nv_bfloat16 g_xh   [(size_t)16384 * 512];
__device__ __nv_bfloat16 g_xl   [(size_t)16384 * 512];
// weight planes
__device__ __nv_bfloat16 g_qwh [262144],  g_qwl [262144];
__device__ __nv_bfloat16 g_s1wh[4194304], g_s1wl[4194304];
__device__ __nv_bfloat16 g_s2wh[1048576], g_s2wl[1048576];
__device__ __nv_bfloat16 g_k1wh[131072],  g_k1wl[131072];
__device__ __nv_bfloat16 g_k2wh[131072],  g_k2wl[131072];
__device__ __nv_bfloat16 g_v2wh[131072],  g_v2wl[131072];
__device__ __nv_bfloat16 g_pwh [262144],  g_pwl [262144];

// ---------------------------------------------------------------------------
// helpers
// ---------------------------------------------------------------------------
__device__ __forceinline__ uint32_t smem_u32(const void* p) {
    uint32_t a;
    asm("{ .reg .u64 t; cvta.to.shared.u64 t, %1; cvt.u32.u64 %0, t; }" : "=r"(a) : "l"(p));
    return a;
}
__device__ __forceinline__ void ldsm_x4(uint32_t& r0, uint32_t& r1, uint32_t& r2, uint32_t& r3,
                                        uint32_t addr) {
    asm volatile("ldmatrix.sync.aligned.m8n8.x4.shared.b16 {%0,%1,%2,%3}, [%4];"
                 : "=r"(r0), "=r"(r1), "=r"(r2), "=r"(r3) : "r"(addr));
}
__device__ __forceinline__ void mma_bf16(float* d,
                                         uint32_t a0, uint32_t a1, uint32_t a2, uint32_t a3,
                                         uint32_t b0, uint32_t b1) {
    asm volatile(
        "mma.sync.aligned.m16n8k16.row.col.f32.bf16.bf16.f32 "
        "{%0,%1,%2,%3}, {%4,%5,%6,%7}, {%8,%9}, {%0,%1,%2,%3};"
        : "+f"(d[0]), "+f"(d[1]), "+f"(d[2]), "+f"(d[3])
        : "r"(a0), "r"(a1), "r"(a2), "r"(a3), "r"(b0), "r"(b1));
}
__device__ __forceinline__ uint32_t pack_hi(float x, float y) {
    __nv_bfloat162 p(__float2bfloat16(x), __float2bfloat16(y));
    return *(uint32_t*)&p;
}
__device__ __forceinline__ uint32_t pack_lo(float x, float y) {
    float hx = __bfloat162float(__float2bfloat16(x));
    float hy = __bfloat162float(__float2bfloat16(y));
    __nv_bfloat162 p(__float2bfloat16(x - hx), __float2bfloat16(y - hy));
    return *(uint32_t*)&p;
}

#define CP_ASYNC8(dst, src) \
    asm volatile("cp.async.ca.shared.global [%0], [%1], 8;" :: "r"(dst), "l"(src) : "memory")
#define CP_ASYNC4(dst, src) \
    asm volatile("cp.async.ca.shared.global [%0], [%1], 4;" :: "r"(dst), "l"(src) : "memory")
#define CP_COMMIT() asm volatile("cp.async.commit_group;" ::: "memory")
#define CP_WAIT0()  asm volatile("cp.async.wait_group 0;" ::: "memory")
#define CP_WAIT1()  asm volatile("cp.async.wait_group 1;" ::: "memory")

// ---------------------------------------------------------------------------
// generic fp32 -> hi/lo bf16 planes
// ---------------------------------------------------------------------------
__global__ void split_kernel(const float* __restrict__ src,
                             __nv_bfloat16* __restrict__ h,
                             __nv_bfloat16* __restrict__ l)
{
    int i = blockIdx.x * 256 + threadIdx.x;
    float4 v = ((const float4*)src)[i];
    ((uint2*)h)[i] = make_uint2(pack_hi(v.x, v.y), pack_hi(v.z, v.w));
    ((uint2*)l)[i] = make_uint2(pack_lo(v.x, v.y), pack_lo(v.z, v.w));
}

// ---------------------------------------------------------------------------
// (N,B,C) -> raw-reshape image, split into bf16 hi/lo planes (K + V one launch)
// ---------------------------------------------------------------------------
__global__ void to_image_split2_kernel(const float* __restrict__ srcK,
                                       const float* __restrict__ srcV,
                                       __nv_bfloat16* __restrict__ h,
                                       __nv_bfloat16* __restrict__ l,
                                       size_t img1)
{
    __shared__ float sm[16][513];
    const int half = blockIdx.x >> 12;
    const float* src = half ? srcV : srcK;
    const size_t dofs = half ? img1 : 0;
    size_t base = (size_t)(blockIdx.x & 4095) * 8192;
    for (int j = threadIdx.x; j < 8192; j += 256) sm[j >> 9][j & 511] = src[base + j];
    __syncthreads();
    for (int r = threadIdx.x; r < 8192; r += 256) {
        float v = sm[r & 15][r >> 4];
        __nv_bfloat16 hv = __float2bfloat16(v);
        h[dofs + base + r] = hv;
        l[dofs + base + r] = __float2bfloat16(v - __bfloat162float(hv));
    }
}

// ---------------------------------------------------------------------------
// GEMM mainloop body: register-reuse restructured (24 ldsm / 96 MMA per chunk)
// ---------------------------------------------------------------------------
#define GEMM_CHUNK_MMA(AhB, AlB, WhB, WlB)                                      \
    _Pragma("unroll")                                                           \
    for (int kh = 0; kh < 2; kh++) {                                            \
        const uint32_t ko = (uint32_t)kh * 32;                                  \
        uint32_t ah[8], al8[8];                                                 \
        ldsm_x4(ah[0], ah[1], ah[2], ah[3], (AhB) + aOff0 + ko);                \
        ldsm_x4(ah[4], ah[5], ah[6], ah[7], (AhB) + aOff1 + ko);                \
        ldsm_x4(al8[0], al8[1], al8[2], al8[3], (AlB) + aOff0 + ko);            \
        ldsm_x4(al8[4], al8[5], al8[6], al8[7], (AlB) + aOff1 + ko);            \
        _Pragma("unroll")                                                       \
        for (int nt = 0; nt < 4; nt++) {                                        \
            uint32_t bh[4], bl[4];                                              \
            ldsm_x4(bh[0], bh[1], bh[2], bh[3], (WhB) + bOff[nt] + ko);         \
            ldsm_x4(bl[0], bl[1], bl[2], bl[3], (WlB) + bOff[nt] + ko);         \
            mma_bf16(acc[0][nt * 2 + 0], ah[0], ah[1], ah[2], ah[3], bh[0], bh[2]); \
            mma_bf16(acc[0][nt * 2 + 1], ah[0], ah[1], ah[2], ah[3], bh[1], bh[3]); \
            mma_bf16(acc[1][nt * 2 + 0], ah[4], ah[5], ah[6], ah[7], bh[0], bh[2]); \
            mma_bf16(acc[1][nt * 2 + 1], ah[4], ah[5], ah[6], ah[7], bh[1], bh[3]); \
            mma_bf16(acc[0][nt * 2 + 0], ah[0], ah[1], ah[2], ah[3], bl[0], bl[2]); \
            mma_bf16(acc[0][nt * 2 + 1], ah[0], ah[1], ah[2], ah[3], bl[1], bl[3]); \
            mma_bf16(acc[1][nt * 2 + 0], ah[4], ah[5], ah[6], ah[7], bl[0], bl[2]); \
            mma_bf16(acc[1][nt * 2 + 1], ah[4], ah[5], ah[6], ah[7], bl[1], bl[3]); \
            mma_bf16(acc[0][nt * 2 + 0], al8[0], al8[1], al8[2], al8[3], bh[0], bh[2]); \
            mma_bf16(acc[0][nt * 2 + 1], al8[0], al8[1], al8[2], al8[3], bh[1], bh[3]); \
            mma_bf16(acc[1][nt * 2 + 0], al8[4], al8[5], al8[6], al8[7], bh[0], bh[2]); \
            mma_bf16(acc[1][nt * 2 + 1], al8[4], al8[5], al8[6], al8[7], bh[1], bh[3]); \
        }                                                                       \
    }

// ---------------------------------------------------------------------------
// Split-bf16 HMMA GEMM, cp.async double-buffered, 2 CTAs/SM.
// OUT bit0: fp32 Cmat; bit1: bf16 planes.
// ---------------------------------------------------------------------------
template <int LOADER, int OUT>
__global__ __launch_bounds__(256, 2) void hgemm2_kernel(
    const __nv_bfloat16* __restrict__ Ah, const __nv_bfloat16* __restrict__ Al,
    const __nv_bfloat16* __restrict__ Wh, const __nv_bfloat16* __restrict__ Wl,
    const float* __restrict__ bias, float* __restrict__ Cmat,
    __nv_bfloat16* __restrict__ Ch, __nv_bfloat16* __restrict__ Cl,
    int M, int N, int K)
{
    extern __shared__ char smc[];
    const uint32_t sb = smem_u32(smc);

    const int tid  = threadIdx.x;
    const int wid  = tid >> 5;
    const int lane = tid & 31;
    const int bm = blockIdx.y << 7;
    const int bn = blockIdx.x << 7;
    const int m0 = (wid & 3) << 5;
    const int n0 = (wid >> 2) << 6;

    int rr[4], kk[4];
#pragma unroll
    for (int j = 0; j < 4; j++) {
        int s = tid + (j << 8);
        rr[j] = s >> 3;
        kk[j] = (s & 7) << 2;
    }

    const uint32_t lrow = (uint32_t)(lane & 15);
    const uint32_t lkq  = (uint32_t)(lane >> 4) * 16;
    const uint32_t aOff0 = (m0 + lrow) * 80 + lkq;
    const uint32_t aOff1 = aOff0 + 16 * 80;
    uint32_t bOff[4];
#pragma unroll
    for (int nt = 0; nt < 4; nt++) bOff[nt] = (n0 + nt * 16 + lrow) * 80 + lkq;

    float acc[2][8][4];
#pragma unroll
    for (int i = 0; i < 2; i++)
#pragma unroll
        for (int j = 0; j < 8; j++)
#pragma unroll
            for (int l = 0; l < 4; l++) acc[i][j][l] = 0.f;

    auto gaddrA = [&](const __nv_bfloat16* plane, int r, int k) -> const __nv_bfloat16* {
        if (LOADER == 0) {
            return plane + (size_t)(bm + r) * K + k;
        } else if (LOADER == 1) {
            int m = bm + r;
            int b = m >> 8, oy = (m >> 4) & 15, ox = m & 15;
            int ic = k >> 4, ky = (k >> 2) & 3;
            return plane + (((size_t)(b * 512 + ic) * 64) + oy * 4 + ky) * 64 + ox * 4;
        } else {
            int m = bm + r;
            int b = m >> 10, oy = (m >> 5) & 31, ox = m & 31;
            int ic = k >> 2;
            return plane + (((size_t)(b * 512 + ic) * 64) + oy * 2) * 64 + ox * 2;
        }
    };

    auto issue_chunk = [&](int buf, int k0) {
        const uint32_t bb = sb + (uint32_t)buf * 40960;
#pragma unroll
        for (int j = 0; j < 4; j++) {
            const uint32_t off = (uint32_t)rr[j] * 80 + (uint32_t)(kk[j] << 1);
            const int k = k0 + kk[j];
            const __nv_bfloat16* pah = gaddrA(Ah, rr[j], k);
            const __nv_bfloat16* pal = gaddrA(Al, rr[j], k);
            const __nv_bfloat16* pwh = Wh + (size_t)(bn + rr[j]) * K + k;
            const __nv_bfloat16* pwl = Wl + (size_t)(bn + rr[j]) * K + k;
            if (LOADER == 2) {
                CP_ASYNC4(bb + off,             pah);
                CP_ASYNC4(bb + off + 4,         pah + 64);
                CP_ASYNC4(bb + 10240 + off,     pal);
                CP_ASYNC4(bb + 10240 + off + 4, pal + 64);
            } else {
                CP_ASYNC8(bb + off,         pah);
                CP_ASYNC8(bb + 10240 + off, pal);
            }
            CP_ASYNC8(bb + 20480 + off, pwh);
            CP_ASYNC8(bb + 30720 + off, pwl);
        }
    };

    const int nchunks = K >> 5;
    issue_chunk(0, 0);
    CP_COMMIT();

    for (int c = 0; c < nchunks; c++) {
        const bool more = (c + 1) < nchunks;
        if (more) {
            issue_chunk((c + 1) & 1, (c + 1) << 5);
            CP_COMMIT();
            CP_WAIT1();
        } else {
            CP_WAIT0();
        }
        __syncthreads();

        const uint32_t bb = sb + (uint32_t)(c & 1) * 40960;
        const uint32_t AhB = bb, AlB = bb + 10240, WhB = bb + 20480, WlB = bb + 30720;
        GEMM_CHUNK_MMA(AhB, AlB, WhB, WlB)
        __syncthreads();
    }

    const int gr = lane >> 2;
    const int gc = (lane & 3) * 2;
#pragma unroll
    for (int mt = 0; mt < 2; mt++) {
        const int row0 = bm + m0 + mt * 16 + gr;
#pragma unroll
        for (int nt = 0; nt < 8; nt++) {
            const int col = bn + n0 + nt * 8 + gc;
            float b0 = bias ? bias[col] : 0.f;
            float b1 = bias ? bias[col + 1] : 0.f;
            float o0 = acc[mt][nt][0] + b0, o1 = acc[mt][nt][1] + b1;
            float o2 = acc[mt][nt][2] + b0, o3 = acc[mt][nt][3] + b1;
            if (OUT & 1) {
                *(float2*)(Cmat + (size_t)row0 * N + col) = make_float2(o0, o1);
                *(float2*)(Cmat + (size_t)(row0 + 8) * N + col) = make_float2(o2, o3);
            }
            if (OUT & 2) {
                size_t i0 = ((size_t)row0 * N + col) >> 1;
                size_t i1 = ((size_t)(row0 + 8) * N + col) >> 1;
                ((uint32_t*)Ch)[i0] = pack_hi(o0, o1);
                ((uint32_t*)Cl)[i0] = pack_lo(o0, o1);
                ((uint32_t*)Ch)[i1] = pack_hi(o2, o3);
                ((uint32_t*)Cl)[i1] = pack_lo(o2, o3);
            }
        }
    }
}

// ---------------------------------------------------------------------------
// Merged head-projection GEMM (3 sub-problems, one launch).
// ---------------------------------------------------------------------------
struct ProjParams {
    const __nv_bfloat16 *Ah[3], *Al[3], *Wh[3], *Wl[3];
    float* Cf[3];
    __nv_bfloat16 *Ch[3], *Cl[3];
    int outm[3];
};

__global__ __launch_bounds__(256, 2) void projgemm_kernel(ProjParams P)
{
    extern __shared__ char smc[];
    const uint32_t sb = smem_u32(smc);
    constexpr int K = 512, N = 256;

    const int y = blockIdx.y;
    const int pi = (y < 64) ? 0 : (y < 192 ? 1 : 2);
    const int ylocal = y - ((pi == 0) ? 0 : (pi == 1) ? 64 : 192);

    const __nv_bfloat16* Ah = P.Ah[pi];
    const __nv_bfloat16* Al = P.Al[pi];
    const __nv_bfloat16* Wh = P.Wh[pi];
    const __nv_bfloat16* Wl = P.Wl[pi];
    float* Cmat = P.Cf[pi];
    __nv_bfloat16* Ch = P.Ch[pi];
    __nv_bfloat16* Cl = P.Cl[pi];
    const int OUT = P.outm[pi];

    const int tid  = threadIdx.x;
    const int wid  = tid >> 5;
    const int lane = tid & 31;
    const int bm = ylocal << 7;
    const int bn = blockIdx.x << 7;
    const int m0 = (wid & 3) << 5;
    const int n0 = (wid >> 2) << 6;

    int rr[4], kk[4];
#pragma unroll
    for (int j = 0; j < 4; j++) {
        int s = tid + (j << 8);
        rr[j] = s >> 3;
        kk[j] = (s & 7) << 2;
    }

    const uint32_t lrow = (uint32_t)(lane & 15);
    const uint32_t lkq  = (uint32_t)(lane >> 4) * 16;
    const uint32_t aOff0 = (m0 + lrow) * 80 + lkq;
    const uint32_t aOff1 = aOff0 + 16 * 80;
    uint32_t bOff[4];
#pragma unroll
    for (int nt = 0; nt < 4; nt++) bOff[nt] = (n0 + nt * 16 + lrow) * 80 + lkq;

    float acc[2][8][4];
#pragma unroll
    for (int i = 0; i < 2; i++)
#pragma unroll
        for (int j = 0; j < 8; j++)
#pragma unroll
            for (int l = 0; l < 4; l++) acc[i][j][l] = 0.f;

    auto issue_chunk = [&](int buf, int k0) {
        const uint32_t bb = sb + (uint32_t)buf * 40960;
#pragma unroll
        for (int j = 0; j < 4; j++) {
            const uint32_t off = (uint32_t)rr[j] * 80 + (uint32_t)(kk[j] << 1);
            const int k = k0 + kk[j];
            CP_ASYNC8(bb + off,         Ah + (size_t)(bm + rr[j]) * K + k);
            CP_ASYNC8(bb + 10240 + off, Al + (size_t)(bm + rr[j]) * K + k);
            CP_ASYNC8(bb + 20480 + off, Wh + (size_t)(bn + rr[j]) * K + k);
            CP_ASYNC8(bb + 30720 + off, Wl + (size_t)(bn + rr[j]) * K + k);
        }
    };

    const int nchunks = K >> 5;
    issue_chunk(0, 0);
    CP_COMMIT();

    for (int c = 0; c < nchunks; c++) {
        const bool more = (c + 1) < nchunks;
        if (more) {
            issue_chunk((c + 1) & 1, (c + 1) << 5);
            CP_COMMIT();
            CP_WAIT1();
        } else {
            CP_WAIT0();
        }
        __syncthreads();

        const uint32_t bb = sb + (uint32_t)(c & 1) * 40960;
        const uint32_t AhB = bb, AlB = bb + 10240, WhB = bb + 20480, WlB = bb + 30720;
        GEMM_CHUNK_MMA(AhB, AlB, WhB, WlB)
        __syncthreads();
    }

    const int gr = lane >> 2;
    const int gc = (lane & 3) * 2;
#pragma unroll
    for (int mt = 0; mt < 2; mt++) {
        const int row0 = bm + m0 + mt * 16 + gr;
#pragma unroll
        for (int nt = 0; nt < 8; nt++) {
            const int col = bn + n0 + nt * 8 + gc;
            float o0 = acc[mt][nt][0], o1 = acc[mt][nt][1];
            float o2 = acc[mt][nt][2], o3 = acc[mt][nt][3];
            if (OUT & 1) {
                *(float2*)(Cmat + (size_t)row0 * N + col) = make_float2(o0, o1);
                *(float2*)(Cmat + (size_t)(row0 + 8) * N + col) = make_float2(o2, o3);
            }
            if (OUT & 2) {
                size_t i0 = ((size_t)row0 * N + col) >> 1;
                size_t i1 = ((size_t)(row0 + 8) * N + col) >> 1;
                ((uint32_t*)Ch)[i0] = pack_hi(o0, o1);
                ((uint32_t*)Cl)[i0] = pack_lo(o0, o1);
                ((uint32_t*)Ch)[i1] = pack_hi(o2, o3);
                ((uint32_t*)Cl)[i1] = pack_lo(o2, o3);
            }
        }
    }
}

// ---------------------------------------------------------------------------
// LayerNorm(512) + exact GELU -> bf16 hi/lo planes
// ---------------------------------------------------------------------------
__global__ void ln_gelu_split_kernel(const float* __restrict__ x,
                                     const float* __restrict__ w,
                                     const float* __restrict__ b,
                                     __nv_bfloat16* __restrict__ hO,
                                     __nv_bfloat16* __restrict__ lO)
{
    __shared__ float sh[8];
    const float* row = x + (size_t)blockIdx.x * 512;
    int t = threadIdx.x;
    float2 v = *(const float2*)(row + t * 2);

    float s = v.x + v.y;
#pragma unroll
    for (int o = 16; o; o >>= 1) s += __shfl_xor_sync(0xffffffffu, s, o);
    if ((t & 31) == 0) sh[t >> 5] = s;
    __syncthreads();
    float tot = 0.f;
#pragma unroll
    for (int i = 0; i < 8; i++) tot += sh[i];
    float mu = tot * (1.f / 512.f);
    float d0 = v.x - mu, d1 = v.y - mu;
    __syncthreads();

    float ss = d0 * d0 + d1 * d1;
#pragma unroll
    for (int o = 16; o; o >>= 1) ss += __shfl_xor_sync(0xffffffffu, ss, o);
    if ((t & 31) == 0) sh[t >> 5] = ss;
    __syncthreads();
    float tot2 = 0.f;
#pragma unroll
    for (int i = 0; i < 8; i++) tot2 += sh[i];
    float inv = rsqrtf(tot2 * (1.f / 512.f) + 1e-5f);

    float y0 = d0 * inv * w[t * 2]     + b[t * 2];
    float y1 = d1 * inv * w[t * 2 + 1] + b[t * 2 + 1];
    y0 = 0.5f * y0 * (1.f + erff(y0 * 0.7071067811865476f));
    y1 = 0.5f * y1 * (1.f + erff(y1 * 0.7071067811865476f));

    size_t o = (size_t)blockIdx.x * 256 + t;
    ((uint32_t*)hO)[o] = pack_hi(y0, y1);
    ((uint32_t*)lO)[o] = pack_lo(y0, y1);
}

// ---------------------------------------------------------------------------
// Depthwise 3x3 (pad 1) residual -> transposed planes, coalesced via smem tile.
// ---------------------------------------------------------------------------
__global__ void dwconv_res_t2_kernel(const float* __restrict__ v,
                                     const float* __restrict__ lw,
                                     const float* __restrict__ lb,
                                     __nv_bfloat16* __restrict__ vth,
                                     __nv_bfloat16* __restrict__ vtl,
                                     int hh, int ww)
{
    __shared__ float sm[64][65];
    const int Nn = hh * ww;
    const int nt = Nn >> 6;
    int bz = blockIdx.x;
    const int ntile = bz % nt; bz /= nt;
    const int ct = bz & 3;
    const int bb = bz >> 2;
    const int c0 = ct << 6, n0 = ntile << 6;

    const int tid = threadIdx.x;
    const int tc = tid & 63;
    const int tn0 = tid >> 6;
    const int c = c0 + tc;

    float wreg[9];
#pragma unroll
    for (int i = 0; i < 9; i++) wreg[i] = lw[c * 9 + i];
    const float bias = lb[c];

    for (int nn = tn0; nn < 64; nn += 4) {
        const int n = n0 + nn;
        const int y = n / ww;
        const int x = n - y * ww;
        float acc = bias;
#pragma unroll
        for (int dy = -1; dy <= 1; dy++) {
            int yy = y + dy;
            if (yy < 0 || yy >= hh) continue;
#pragma unroll
            for (int dx = -1; dx <= 1; dx++) {
                int xx = x + dx;
                if (xx < 0 || xx >= ww) continue;
                acc += v[((size_t)(bb * Nn + yy * ww + xx) << 8) + c] * wreg[(dy + 1) * 3 + (dx + 1)];
            }
        }
        sm[nn][tc] = v[((size_t)(bb * Nn + n) << 8) + c] + acc;
    }
    __syncthreads();

    const int wc = tid >> 5;
    const int wn = (tid & 31) << 1;
    for (int cc = wc; cc < 64; cc += 8) {
        float v0 = sm[wn][cc], v1 = sm[wn + 1][cc];
        size_t o = (((size_t)(bb * 256 + c0 + cc)) * Nn + n0 + wn) >> 1;
        ((uint32_t*)vth)[o] = pack_hi(v0, v1);
        ((uint32_t*)vtl)[o] = pack_lo(v0, v1);
    }
}

// ---------------------------------------------------------------------------
// Flash attention, split-bf16 HMMA, K/V double-buffered (cp.async), 2 CTAs/SM.
// smem: Q 36864 | KVbuf0 36864 | KVbuf1 36864 = 110592.
// ---------------------------------------------------------------------------
__global__ __launch_bounds__(256, 2) void flash_kernel(
    const __nv_bfloat16* __restrict__ qph, const __nv_bfloat16* __restrict__ qpl,
    const __nv_bfloat16* __restrict__ kph, const __nv_bfloat16* __restrict__ kpl,
    const __nv_bfloat16* __restrict__ vth, const __nv_bfloat16* __restrict__ vtl,
    __nv_bfloat16* __restrict__ xh, __nv_bfloat16* __restrict__ xl,
    int Nk, int hoff, int coloff)
{
    extern __shared__ char smc[];
    const uint32_t sb = smem_u32(smc);
    const uint32_t QH = sb, QL = sb + 18432;

    const int tid  = threadIdx.x;
    const int wid  = tid >> 5;
    const int lane = tid & 31;
    const int b = blockIdx.y >> 2;
    const int h = blockIdx.y & 3;
    const int q0 = blockIdx.x << 7;

    {
        const size_t qbase = ((size_t)(b * Qn + q0)) * 512 + (size_t)(hoff + h) * 64;
#pragma unroll
        for (int it = 0; it < 8; it++) {
            int i = tid + (it << 8);
            int row = i >> 4;
            int c4 = (i & 15) << 2;
            uint32_t dst = (uint32_t)row * 144 + (uint32_t)(c4 << 1);
            CP_ASYNC8(QH + dst, qph + qbase + (size_t)row * 512 + c4);
            CP_ASYNC8(QL + dst, qpl + qbase + (size_t)row * 512 + c4);
        }
        CP_COMMIT();
    }

    auto issue_kv = [&](int buf, int kv0) {
        const uint32_t bb = sb + 36864 + (uint32_t)buf * 36864;
#pragma unroll
        for (int it = 0; it < 4; it++) {
            int i = tid + (it << 8);
            int row = i >> 4;
            int c4 = (i & 15) << 2;
            uint32_t dst = (uint32_t)row * 144 + (uint32_t)(c4 << 1);
            size_t kidx = ((size_t)(b * Nk + kv0 + row)) * 256 + h * 64 + c4;
            CP_ASYNC8(bb + dst,         kph + kidx);
            CP_ASYNC8(bb + 9216 + dst,  kpl + kidx);
            size_t vidx = ((size_t)(b * 256 + h * 64 + row)) * Nk + kv0 + c4;
            CP_ASYNC8(bb + 18432 + dst, vth + vidx);
            CP_ASYNC8(bb + 27648 + dst, vtl + vidx);
        }
    };

    const uint32_t lrow = (uint32_t)(lane & 15);
    const uint32_t lkq  = (uint32_t)(lane >> 4) * 16;
    const uint32_t qOff = ((uint32_t)(wid * 16) + lrow) * 144 + lkq;
    const uint32_t kOff = lrow * 144 + lkq;

    const int gr = lane >> 2;

    float m0 = -1e30f, m1 = -1e30f, l0 = 0.f, l1 = 0.f;
    float Oacc[8][4];
#pragma unroll
    for (int j = 0; j < 8; j++)
#pragma unroll
        for (int l = 0; l < 4; l++) Oacc[j][l] = 0.f;

    const int ntiles = Nk >> 6;
    issue_kv(0, 0);
    CP_COMMIT();

    for (int t = 0; t < ntiles; t++) {
        const bool more = (t + 1) < ntiles;
        if (more) {
            issue_kv((t + 1) & 1, (t + 1) << 6);
            CP_COMMIT();
            CP_WAIT1();
        } else {
            CP_WAIT0();
        }
        __syncthreads();

        const uint32_t bb = sb + 36864 + (uint32_t)(t & 1) * 36864;
        const uint32_t KH = bb, KL = bb + 9216, VH = bb + 18432, VL = bb + 27648;

        // ---- S = Q K^T, register-reuse: 3 split passes per fragment set ----
        float S[8][4];
#pragma unroll
        for (int j = 0; j < 8; j++)
#pragma unroll
            for (int l = 0; l < 4; l++) S[j][l] = 0.f;

#pragma unroll
        for (int ks = 0; ks < 4; ks++) {
            const uint32_t ko = (uint32_t)ks * 32;
            uint32_t qh4[4], ql4[4];
            ldsm_x4(qh4[0], qh4[1], qh4[2], qh4[3], QH + qOff + ko);
            ldsm_x4(ql4[0], ql4[1], ql4[2], ql4[3], QL + qOff + ko);
#pragma unroll
            for (int g = 0; g < 4; g++) {
                uint32_t kh4[4], kl4[4];
                ldsm_x4(kh4[0], kh4[1], kh4[2], kh4[3], KH + (uint32_t)g * 2304 + kOff + ko);
                ldsm_x4(kl4[0], kl4[1], kl4[2], kl4[3], KL + (uint32_t)g * 2304 + kOff + ko);
                mma_bf16(S[2 * g + 0], qh4[0], qh4[1], qh4[2], qh4[3], kh4[0], kh4[2]);
                mma_bf16(S[2 * g + 1], qh4[0], qh4[1], qh4[2], qh4[3], kh4[1], kh4[3]);
                mma_bf16(S[2 * g + 0], qh4[0], qh4[1], qh4[2], qh4[3], kl4[0], kl4[2]);
                mma_bf16(S[2 * g + 1], qh4[0], qh4[1], qh4[2], qh4[3], kl4[1], kl4[3]);
                mma_bf16(S[2 * g + 0], ql4[0], ql4[1], ql4[2], ql4[3], kh4[0], kh4[2]);
                mma_bf16(S[2 * g + 1], ql4[0], ql4[1], ql4[2], ql4[3], kh4[1], kh4[3]);
            }
        }

        // ---- online softmax ----
        const float sc = 0.125f;
        float mx0 = m0, mx1 = m1;
#pragma unroll
        for (int j = 0; j < 8; j++) {
            S[j][0] *= sc; S[j][1] *= sc; S[j][2] *= sc; S[j][3] *= sc;
            mx0 = fmaxf(mx0, fmaxf(S[j][0], S[j][1]));
            mx1 = fmaxf(mx1, fmaxf(S[j][2], S[j][3]));
        }
#pragma unroll
        for (int o = 1; o <= 2; o <<= 1) {
            mx0 = fmaxf(mx0, __shfl_xor_sync(0xffffffffu, mx0, o));
            mx1 = fmaxf(mx1, __shfl_xor_sync(0xffffffffu, mx1, o));
        }
        const float alpha0 = __expf(m0 - mx0);
        const float alpha1 = __expf(m1 - mx1);
        m0 = mx0; m1 = mx1;

        float rs0 = 0.f, rs1 = 0.f;
#pragma unroll
        for (int j = 0; j < 8; j++) {
            S[j][0] = __expf(S[j][0] - mx0);
            S[j][1] = __expf(S[j][1] - mx0);
            S[j][2] = __expf(S[j][2] - mx1);
            S[j][3] = __expf(S[j][3] - mx1);
            rs0 += S[j][0] + S[j][1];
            rs1 += S[j][2] + S[j][3];
        }
#pragma unroll
        for (int o = 1; o <= 2; o <<= 1) {
            rs0 += __shfl_xor_sync(0xffffffffu, rs0, o);
            rs1 += __shfl_xor_sync(0xffffffffu, rs1, o);
        }
        l0 = l0 * alpha0 + rs0;
        l1 = l1 * alpha1 + rs1;

#pragma unroll
        for (int j = 0; j < 8; j++) {
            Oacc[j][0] *= alpha0; Oacc[j][1] *= alpha0;
            Oacc[j][2] *= alpha1; Oacc[j][3] *= alpha1;
        }

        // ---- O += P V (3-pass split) ----
#pragma unroll
        for (int t16 = 0; t16 < 4; t16++) {
            uint32_t ph0 = pack_hi(S[2 * t16][0],     S[2 * t16][1]);
            uint32_t ph1 = pack_hi(S[2 * t16][2],     S[2 * t16][3]);
            uint32_t ph2 = pack_hi(S[2 * t16 + 1][0], S[2 * t16 + 1][1]);
            uint32_t ph3 = pack_hi(S[2 * t16 + 1][2], S[2 * t16 + 1][3]);
            uint32_t pl0 = pack_lo(S[2 * t16][0],     S[2 * t16][1]);
            uint32_t pl1 = pack_lo(S[2 * t16][2],     S[2 * t16][3]);
            uint32_t pl2 = pack_lo(S[2 * t16 + 1][0], S[2 * t16 + 1][1]);
            uint32_t pl3 = pack_lo(S[2 * t16 + 1][2], S[2 * t16 + 1][3]);
            const uint32_t ko = (uint32_t)t16 * 32;
#pragma unroll
            for (int g = 0; g < 4; g++) {
                uint32_t vh0, vh1, vh2, vh3;
                ldsm_x4(vh0, vh1, vh2, vh3, VH + (uint32_t)g * 2304 + kOff + ko);
                mma_bf16(Oacc[2 * g + 0], ph0, ph1, ph2, ph3, vh0, vh2);
                mma_bf16(Oacc[2 * g + 1], ph0, ph1, ph2, ph3, vh1, vh3);
                mma_bf16(Oacc[2 * g + 0], pl0, pl1, pl2, pl3, vh0, vh2);
                mma_bf16(Oacc[2 * g + 1], pl0, pl1, pl2, pl3, vh1, vh3);
                uint32_t vl0, vl1, vl2, vl3;
                ldsm_x4(vl0, vl1, vl2, vl3, VL + (uint32_t)g * 2304 + kOff + ko);
                mma_bf16(Oacc[2 * g + 0], ph0, ph1, ph2, ph3, vl0, vl2);
                mma_bf16(Oacc[2 * g + 1], ph0, ph1, ph2, ph3, vl1, vl3);
            }
        }
        __syncthreads();
    }

    // ---- epilogue ----
    const float inv0 = 1.f / l0;
    const float inv1 = 1.f / l1;
    const int gc = (lane & 3) * 2;
    const int row0 = b * Qn + q0 + wid * 16 + gr;
#pragma unroll
    for (int j = 0; j < 8; j++) {
        const int col = coloff + h * 64 + (j >> 1) * 16 + (j & 1) * 8 + gc;
        float o0 = Oacc[j][0] * inv0, o1 = Oacc[j][1] * inv0;
        float o2 = Oacc[j][2] * inv1, o3 = Oacc[j][3] * inv1;
        size_t i0 = ((size_t)row0 * 512 + col) >> 1;
        size_t i1 = ((size_t)(row0 + 8) * 512 + col) >> 1;
        ((uint32_t*)xh)[i0] = pack_hi(o0, o1);
        ((uint32_t*)xl)[i0] = pack_lo(o0, o1);
        ((uint32_t*)xh)[i1] = pack_hi(o2, o3);
        ((uint32_t*)xl)[i1] = pack_lo(o2, o3);
    }
}

// ---------------------------------------------------------------------------
// Host launch sequence
// ---------------------------------------------------------------------------
extern "C" void kernel_launch(void* const* d_in, const int* in_sizes, int n_in,
                              void* d_out, int out_size)
{
    (void)in_sizes; (void)out_size;
    const int s = (n_in >= 24) ? 2 : 0;

    const float* query   = (const float*)d_in[0];
    const float* key     = (const float*)d_in[1];
    const float* value   = (const float*)d_in[2];
    const float* q_w     = (const float*)d_in[3 + s];
    const float* sr1_w   = (const float*)d_in[4 + s];
    const float* sr1_b   = (const float*)d_in[5 + s];
    const float* norm1_w = (const float*)d_in[6 + s];
    const float* norm1_b = (const float*)d_in[7 + s];
    const float* sr2_w   = (const float*)d_in[8 + s];
    const float* sr2_b   = (const float*)d_in[9 + s];
    const float* norm2_w = (const float*)d_in[10 + s];
    const float* norm2_b = (const float*)d_in[11 + s];
    const float* k1_w    = (const float*)d_in[12 + s];
    const float* k2_w    = (const float*)d_in[14 + s];
    const float* v2_w    = (const float*)d_in[15 + s];
    const float* lc1_w   = (const float*)d_in[16 + s];
    const float* lc1_b   = (const float*)d_in[17 + s];
    const float* lc2_w   = (const float*)d_in[18 + s];
    const float* lc2_b   = (const float*)d_in[19 + s];
    const float* proj_w  = (const float*)d_in[20 + s];
    const float* proj_b  = (const float*)d_in[21 + s];
    float* out = (float*)d_out;

    float *kv1n, *kv2n, *kv1, *v2;
    cudaGetSymbolAddress((void**)&kv1n, g_kv1n);
    cudaGetSymbolAddress((void**)&kv2n, g_kv2n);
    cudaGetSymbolAddress((void**)&kv1,  g_kv1);
    cudaGetSymbolAddress((void**)&v2,   g_v2);

    __nv_bfloat16 *qh, *ql, *qph, *qpl, *imgh, *imgl, *kv1nh, *kv1nl, *kv2nh, *kv2nl;
    __nv_bfloat16 *k1ph, *k1pl, *k2ph, *k2pl, *vt1h, *vt1l, *vt2h, *vt2l, *xh, *xl;
    __nv_bfloat16 *qwh, *qwl, *s1wh, *s1wl, *s2wh, *s2wl, *k1wh, *k1wl, *k2wh, *k2wl, *v2wh, *v2wl, *pwh, *pwl;
    cudaGetSymbolAddress((void**)&qh, g_qh);       cudaGetSymbolAddress((void**)&ql, g_ql);
    cudaGetSymbolAddress((void**)&qph, g_qph);     cudaGetSymbolAddress((void**)&qpl, g_qpl);
    cudaGetSymbolAddress((void**)&imgh, g_imgh);   cudaGetSymbolAddress((void**)&imgl, g_imgl);
    cudaGetSymbolAddress((void**)&kv1nh, g_kv1nh); cudaGetSymbolAddress((void**)&kv1nl, g_kv1nl);
    cudaGetSymbolAddress((void**)&kv2nh, g_kv2nh); cudaGetSymbolAddress((void**)&kv2nl, g_kv2nl);
    cudaGetSymbolAddress((void**)&k1ph, g_k1ph);   cudaGetSymbolAddress((void**)&k1pl, g_k1pl);
    cudaGetSymbolAddress((void**)&k2ph, g_k2ph);   cudaGetSymbolAddress((void**)&k2pl, g_k2pl);
    cudaGetSymbolAddress((void**)&vt1h, g_vt1h);   cudaGetSymbolAddress((void**)&vt1l, g_vt1l);
    cudaGetSymbolAddress((void**)&vt2h, g_vt2h);   cudaGetSymbolAddress((void**)&vt2l, g_vt2l);
    cudaGetSymbolAddress((void**)&xh, g_xh);       cudaGetSymbolAddress((void**)&xl, g_xl);
    cudaGetSymbolAddress((void**)&qwh, g_qwh);     cudaGetSymbolAddress((void**)&qwl, g_qwl);
    cudaGetSymbolAddress((void**)&s1wh, g_s1wh);   cudaGetSymbolAddress((void**)&s1wl, g_s1wl);
    cudaGetSymbolAddress((void**)&s2wh, g_s2wh);   cudaGetSymbolAddress((void**)&s2wl, g_s2wl);
    cudaGetSymbolAddress((void**)&k1wh, g_k1wh);   cudaGetSymbolAddress((void**)&k1wl, g_k1wl);
    cudaGetSymbolAddress((void**)&k2wh, g_k2wh);   cudaGetSymbolAddress((void**)&k2wl, g_k2wl);
    cudaGetSymbolAddress((void**)&v2wh, g_v2wh);   cudaGetSymbolAddress((void**)&v2wl, g_v2wl);
    cudaGetSymbolAddress((void**)&pwh, g_pwh);     cudaGetSymbolAddress((void**)&pwl, g_pwl);

    const size_t IMG1 = (size_t)B_ * C_ * 64 * 64;
    float* v1 = kv1 + (size_t)B_ * N1_ * C2_;

    const int SMEM = 81920;
    cudaFuncSetAttribute(hgemm2_kernel<0, 1>, cudaFuncAttributeMaxDynamicSharedMemorySize, SMEM);
    cudaFuncSetAttribute(hgemm2_kernel<0, 2>, cudaFuncAttributeMaxDynamicSharedMemorySize, SMEM);
    cudaFuncSetAttribute(hgemm2_kernel<1, 1>, cudaFuncAttributeMaxDynamicSharedMemorySize, SMEM);
    cudaFuncSetAttribute(hgemm2_kernel<2, 1>, cudaFuncAttributeMaxDynamicSharedMemorySize, SMEM);
    cudaFuncSetAttribute(projgemm_kernel, cudaFuncAttributeMaxDynamicSharedMemorySize, SMEM);
    const int FSMEM = 110592;
    cudaFuncSetAttribute(flash_kernel, cudaFuncAttributeMaxDynamicSharedMemorySize, FSMEM);

    dim3 blk(256);

    // launches ordered so my 4th launch (overall #6 under ncu -s 5) = sr1 GEMM
    split_kernel<<<4096, 256>>>(sr1_w, s1wh, s1wl);                         // 1
    to_image_split2_kernel<<<8192, 256>>>(key, value, imgh, imgl, IMG1);    // 2
    split_kernel<<<1024, 256>>>(sr2_w, s2wh, s2wl);                         // 3
    hgemm2_kernel<1, 1><<<dim3(4, 64), blk, SMEM>>>(imgh, imgl, s1wh, s1wl, sr1_b,
                                                    kv1n, nullptr, nullptr, 8192, 512, 8192); // 4 <- profiled

    split_kernel<<<256, 256>>>(q_w, qwh, qwl);
    split_kernel<<<128, 256>>>(k1_w, k1wh, k1wl);
    split_kernel<<<128, 256>>>(k2_w, k2wh, k2wl);
    split_kernel<<<128, 256>>>(v2_w, v2wh, v2wl);
    split_kernel<<<256, 256>>>(proj_w, pwh, pwl);
    split_kernel<<<8192, 256>>>(query, qh, ql);

    hgemm2_kernel<2, 1><<<dim3(4, 256), blk, SMEM>>>(imgh, imgl, s2wh, s2wl, sr2_b,
                                                     kv2n, nullptr, nullptr, 32768, 512, 2048);

    hgemm2_kernel<0, 2><<<dim3(4, 128), blk, SMEM>>>(qh, ql, qwh, qwl, nullptr,
                                                     nullptr, qph, qpl, 16384, 512, 512);

    ln_gelu_split_kernel<<<8192,  256>>>(kv1n, norm1_w, norm1_b, kv1nh, kv1nl);
    ln_gelu_split_kernel<<<32768, 256>>>(kv2n, norm2_w, norm2_b, kv2nh, kv2nl);

    {
        ProjParams P;
        P.Ah[0] = kv1nh;  P.Al[0] = kv1nl;  P.Wh[0] = k1wh; P.Wl[0] = k1wl;
        P.Cf[0] = kv1;    P.Ch[0] = k1ph;   P.Cl[0] = k1pl; P.outm[0] = 3;
        P.Ah[1] = kv2nh;  P.Al[1] = kv2nl;  P.Wh[1] = k2wh; P.Wl[1] = k2wl;
        P.Cf[1] = nullptr; P.Ch[1] = k2ph;  P.Cl[1] = k2pl; P.outm[1] = 2;
        P.Ah[2] = kv2nh + (size_t)16384 * 512;
        P.Al[2] = kv2nl + (size_t)16384 * 512;
        P.Wh[2] = v2wh;   P.Wl[2] = v2wl;
        P.Cf[2] = v2;     P.Ch[2] = nullptr; P.Cl[2] = nullptr; P.outm[2] = 1;
        projgemm_kernel<<<dim3(2, 320), blk, SMEM>>>(P);
    }

    dwconv_res_t2_kernel<<<B_ * 4 * (N1_ / 64), 256>>>(v1, lc1_w, lc1_b, vt1h, vt1l, 16, 16);
    dwconv_res_t2_kernel<<<B_ * 4 * (N2_ / 64), 256>>>(v2, lc2_w, lc2_b, vt2h, vt2l, 32, 32);

    flash_kernel<<<dim3(8, 64), blk, FSMEM>>>(qph, qpl, k1ph, k1pl, vt1h, vt1l,
                                              xh, xl, N1_, 0, 0);
    flash_kernel<<<dim3(8, 64), blk, FSMEM>>>(qph, qpl, k2ph, k2pl, vt2h, vt2l,
                                              xh, xl, N2_, 4, 256);

    hgemm2_kernel<0, 1><<<dim3(4, 128), blk, SMEM>>>(xh, xl, pwh, pwl, proj_b,
                                                     out, nullptr, nullptr, 16384, 512, 512);
}

// round 10
// speedup vs baseline: 3.2296x; 1.0304x over previous
#include <cuda_runtime.h>
#include <cuda_bf16.h>
#include <math.h>
#include <stdint.h>

// ---------------------------------------------------------------------------
// Problem constants
// ---------------------------------------------------------------------------
constexpr int B_   = 16;
constexpr int C_   = 512;
constexpr int Qn   = 1024;
constexpr int C2_  = 256;
constexpr int N1_  = 256;
constexpr int N2_  = 1024;

// ---------------------------------------------------------------------------
// Device scratch
// ---------------------------------------------------------------------------
__device__ float g_kv1n [(size_t)2 * B_ * N1_ * C_];
__device__ float g_kv2n [(size_t)2 * B_ * N2_ * C_];
__device__ float g_kv1  [(size_t)2 * B_ * N1_ * C2_];
__device__ float g_v2   [(size_t)B_ * N2_ * C2_];

// bf16 hi/lo planes
__device__ __nv_bfloat16 g_qh   [(size_t)16384 * 512];
__device__ __nv_bfloat16 g_ql   [(size_t)16384 * 512];
__device__ __nv_bfloat16 g_qph  [(size_t)16384 * 512];
__device__ __nv_bfloat16 g_qpl  [(size_t)16384 * 512];
__device__ __nv_bfloat16 g_imgh [(size_t)2 * B_ * C_ * 64 * 64];
__device__ __nv_bfloat16 g_imgl [(size_t)2 * B_ * C_ * 64 * 64];
__device__ __nv_bfloat16 g_kv1nh[(size_t)8192 * 512];
__device__ __nv_bfloat16 g_kv1nl[(size_t)8192 * 512];
__device__ __nv_bfloat16 g_kv2nh[(size_t)32768 * 512];
__device__ __nv_bfloat16 g_kv2nl[(size_t)32768 * 512];
__device__ __nv_bfloat16 g_k1ph [(size_t)8192 * 256];
__device__ __nv_bfloat16 g_k1pl [(size_t)8192 * 256];
__device__ __nv_bfloat16 g_k2ph [(size_t)16384 * 256];
__device__ __nv_bfloat16 g_k2pl [(size_t)16384 * 256];
__device__ __nv_bfloat16 g_vt1h [(size_t)B_ * C2_ * N1_];
__device__ __nv_bfloat16 g_vt1l [(size_t)B_ * C2_ * N1_];
__device__ __nv_bfloat16 g_vt2h [(size_t)B_ * C2_ * N2_];
__device__ __nv_bfloat16 g_vt2l [(size_t)B_ * C2_ * N2_];
__device__ __nv_bfloat16 g_xh   [(size_t)16384 * 512];
__device__ __nv_bfloat16 g_xl   [(size_t)16384 * 512];
// weight planes
__device__ __nv_bfloat16 g_qwh [262144],  g_qwl [262144];
__device__ __nv_bfloat16 g_s1wh[4194304], g_s1wl[4194304];
__device__ __nv_bfloat16 g_s2wh[1048576], g_s2wl[1048576];
__device__ __nv_bfloat16 g_k1wh[131072],  g_k1wl[131072];
__device__ __nv_bfloat16 g_k2wh[131072],  g_k2wl[131072];
__device__ __nv_bfloat16 g_v2wh[131072],  g_v2wl[131072];
__device__ __nv_bfloat16 g_pwh [262144],  g_pwl [262144];

// ---------------------------------------------------------------------------
// helpers
// ---------------------------------------------------------------------------
__device__ __forceinline__ uint32_t smem_u32(const void* p) {
    uint32_t a;
    asm("{ .reg .u64 t; cvta.to.shared.u64 t, %1; cvt.u32.u64 %0, t; }" : "=r"(a) : "l"(p));
    return a;
}
__device__ __forceinline__ void ldsm_x4(uint32_t& r0, uint32_t& r1, uint32_t& r2, uint32_t& r3,
                                        uint32_t addr) {
    asm volatile("ldmatrix.sync.aligned.m8n8.x4.shared.b16 {%0,%1,%2,%3}, [%4];"
                 : "=r"(r0), "=r"(r1), "=r"(r2), "=r"(r3) : "r"(addr));
}
__device__ __forceinline__ void mma_bf16(float* d,
                                         uint32_t a0, uint32_t a1, uint32_t a2, uint32_t a3,
                                         uint32_t b0, uint32_t b1) {
    asm volatile(
        "mma.sync.aligned.m16n8k16.row.col.f32.bf16.bf16.f32 "
        "{%0,%1,%2,%3}, {%4,%5,%6,%7}, {%8,%9}, {%0,%1,%2,%3};"
        : "+f"(d[0]), "+f"(d[1]), "+f"(d[2]), "+f"(d[3])
        : "r"(a0), "r"(a1), "r"(a2), "r"(a3), "r"(b0), "r"(b1));
}
__device__ __forceinline__ uint32_t pack_hi(float x, float y) {
    __nv_bfloat162 p(__float2bfloat16(x), __float2bfloat16(y));
    return *(uint32_t*)&p;
}
__device__ __forceinline__ uint32_t pack_lo(float x, float y) {
    float hx = __bfloat162float(__float2bfloat16(x));
    float hy = __bfloat162float(__float2bfloat16(y));
    __nv_bfloat162 p(__float2bfloat16(x - hx), __float2bfloat16(y - hy));
    return *(uint32_t*)&p;
}

#define CP_ASYNC8(dst, src) \
    asm volatile("cp.async.ca.shared.global [%0], [%1], 8;" :: "r"(dst), "l"(src) : "memory")
#define CP_ASYNC4(dst, src) \
    asm volatile("cp.async.ca.shared.global [%0], [%1], 4;" :: "r"(dst), "l"(src) : "memory")
#define CP_COMMIT() asm volatile("cp.async.commit_group;" ::: "memory")
#define CP_WAIT0()  asm volatile("cp.async.wait_group 0;" ::: "memory")
#define CP_WAIT1()  asm volatile("cp.async.wait_group 1;" ::: "memory")

// ---------------------------------------------------------------------------
// generic fp32 -> hi/lo bf16 planes
// ---------------------------------------------------------------------------
__global__ void split_kernel(const float* __restrict__ src,
                             __nv_bfloat16* __restrict__ h,
                             __nv_bfloat16* __restrict__ l)
{
    int i = blockIdx.x * 256 + threadIdx.x;
    float4 v = ((const float4*)src)[i];
    ((uint2*)h)[i] = make_uint2(pack_hi(v.x, v.y), pack_hi(v.z, v.w));
    ((uint2*)l)[i] = make_uint2(pack_lo(v.x, v.y), pack_lo(v.z, v.w));
}

// ---------------------------------------------------------------------------
// (N,B,C) -> raw-reshape image, split into bf16 hi/lo planes (K + V one launch)
// ---------------------------------------------------------------------------
__global__ void to_image_split2_kernel(const float* __restrict__ srcK,
                                       const float* __restrict__ srcV,
                                       __nv_bfloat16* __restrict__ h,
                                       __nv_bfloat16* __restrict__ l,
                                       size_t img1)
{
    __shared__ float sm[16][513];
    const int half = blockIdx.x >> 12;
    const float* src = half ? srcV : srcK;
    const size_t dofs = half ? img1 : 0;
    size_t base = (size_t)(blockIdx.x & 4095) * 8192;
    for (int j = threadIdx.x; j < 8192; j += 256) sm[j >> 9][j & 511] = src[base + j];
    __syncthreads();
    for (int r = threadIdx.x; r < 8192; r += 256) {
        float v = sm[r & 15][r >> 4];
        __nv_bfloat16 hv = __float2bfloat16(v);
        h[dofs + base + r] = hv;
        l[dofs + base + r] = __float2bfloat16(v - __bfloat162float(hv));
    }
}

// ---------------------------------------------------------------------------
// 64x64-warp-tile mainloop body (4 warps): 32 ldsm + 192 MMA per chunk/warp
// ---------------------------------------------------------------------------
#define GEMM3_CHUNK_MMA(AhB, AlB, WhB, WlB)                                     \
    _Pragma("unroll")                                                           \
    for (int kh = 0; kh < 2; kh++) {                                            \
        const uint32_t ko = (uint32_t)kh * 32;                                  \
        uint32_t AH[4][4], AL[4][4], BH[4][4], BL[4][4];                        \
        _Pragma("unroll")                                                       \
        for (int mt = 0; mt < 4; mt++) {                                        \
            ldsm_x4(AH[mt][0], AH[mt][1], AH[mt][2], AH[mt][3], (AhB) + aOffs[mt] + ko); \
            ldsm_x4(AL[mt][0], AL[mt][1], AL[mt][2], AL[mt][3], (AlB) + aOffs[mt] + ko); \
        }                                                                       \
        _Pragma("unroll")                                                       \
        for (int nt = 0; nt < 4; nt++) {                                        \
            ldsm_x4(BH[nt][0], BH[nt][1], BH[nt][2], BH[nt][3], (WhB) + bOffs[nt] + ko); \
            ldsm_x4(BL[nt][0], BL[nt][1], BL[nt][2], BL[nt][3], (WlB) + bOffs[nt] + ko); \
        }                                                                       \
        _Pragma("unroll")                                                       \
        for (int mt = 0; mt < 4; mt++)                                          \
        _Pragma("unroll")                                                       \
        for (int nt = 0; nt < 4; nt++) {                                        \
            mma_bf16(acc[mt][2 * nt + 0], AH[mt][0], AH[mt][1], AH[mt][2], AH[mt][3], BH[nt][0], BH[nt][2]); \
            mma_bf16(acc[mt][2 * nt + 1], AH[mt][0], AH[mt][1], AH[mt][2], AH[mt][3], BH[nt][1], BH[nt][3]); \
            mma_bf16(acc[mt][2 * nt + 0], AH[mt][0], AH[mt][1], AH[mt][2], AH[mt][3], BL[nt][0], BL[nt][2]); \
            mma_bf16(acc[mt][2 * nt + 1], AH[mt][0], AH[mt][1], AH[mt][2], AH[mt][3], BL[nt][1], BL[nt][3]); \
            mma_bf16(acc[mt][2 * nt + 0], AL[mt][0], AL[mt][1], AL[mt][2], AL[mt][3], BH[nt][0], BH[nt][2]); \
            mma_bf16(acc[mt][2 * nt + 1], AL[mt][0], AL[mt][1], AL[mt][2], AL[mt][3], BH[nt][1], BH[nt][3]); \
        }                                                                       \
    }

// ---------------------------------------------------------------------------
// Split-bf16 HMMA GEMM v3: 128 threads, 4 warps of 64x64, cp.async double buf.
// OUT bit0: fp32 Cmat; bit1: bf16 planes.
// ---------------------------------------------------------------------------
template <int LOADER, int OUT>
__global__ __launch_bounds__(128, 2) void hgemm3_kernel(
    const __nv_bfloat16* __restrict__ Ah, const __nv_bfloat16* __restrict__ Al,
    const __nv_bfloat16* __restrict__ Wh, const __nv_bfloat16* __restrict__ Wl,
    const float* __restrict__ bias, float* __restrict__ Cmat,
    __nv_bfloat16* __restrict__ Ch, __nv_bfloat16* __restrict__ Cl,
    int M, int N, int K)
{
    extern __shared__ char smc[];
    const uint32_t sb = smem_u32(smc);

    const int tid  = threadIdx.x;
    const int wid  = tid >> 5;
    const int lane = tid & 31;
    const int bm = blockIdx.y << 7;
    const int bn = blockIdx.x << 7;
    const int m0 = (wid & 1) << 6;
    const int n0 = (wid >> 1) << 6;

    int rr[8], kk[8];
#pragma unroll
    for (int j = 0; j < 8; j++) {
        int s = tid + (j << 7);
        rr[j] = s >> 3;
        kk[j] = (s & 7) << 2;
    }

    const uint32_t lrow = (uint32_t)(lane & 15);
    const uint32_t lkq  = (uint32_t)(lane >> 4) * 16;
    uint32_t aOffs[4], bOffs[4];
#pragma unroll
    for (int t = 0; t < 4; t++) {
        aOffs[t] = (uint32_t)(m0 + t * 16 + lrow) * 80 + lkq;
        bOffs[t] = (uint32_t)(n0 + t * 16 + lrow) * 80 + lkq;
    }

    float acc[4][8][4];
#pragma unroll
    for (int i = 0; i < 4; i++)
#pragma unroll
        for (int j = 0; j < 8; j++)
#pragma unroll
            for (int l = 0; l < 4; l++) acc[i][j][l] = 0.f;

    auto gaddrA = [&](const __nv_bfloat16* plane, int r, int k) -> const __nv_bfloat16* {
        if (LOADER == 0) {
            return plane + (size_t)(bm + r) * K + k;
        } else if (LOADER == 1) {
            int m = bm + r;
            int b = m >> 8, oy = (m >> 4) & 15, ox = m & 15;
            int ic = k >> 4, ky = (k >> 2) & 3;
            return plane + (((size_t)(b * 512 + ic) * 64) + oy * 4 + ky) * 64 + ox * 4;
        } else {
            int m = bm + r;
            int b = m >> 10, oy = (m >> 5) & 31, ox = m & 31;
            int ic = k >> 2;
            return plane + (((size_t)(b * 512 + ic) * 64) + oy * 2) * 64 + ox * 2;
        }
    };

    auto issue_chunk = [&](int buf, int k0) {
        const uint32_t bb = sb + (uint32_t)buf * 40960;
#pragma unroll
        for (int j = 0; j < 8; j++) {
            const uint32_t off = (uint32_t)rr[j] * 80 + (uint32_t)(kk[j] << 1);
            const int k = k0 + kk[j];
            const __nv_bfloat16* pah = gaddrA(Ah, rr[j], k);
            const __nv_bfloat16* pal = gaddrA(Al, rr[j], k);
            const __nv_bfloat16* pwh = Wh + (size_t)(bn + rr[j]) * K + k;
            const __nv_bfloat16* pwl = Wl + (size_t)(bn + rr[j]) * K + k;
            if (LOADER == 2) {
                CP_ASYNC4(bb + off,             pah);
                CP_ASYNC4(bb + off + 4,         pah + 64);
                CP_ASYNC4(bb + 10240 + off,     pal);
                CP_ASYNC4(bb + 10240 + off + 4, pal + 64);
            } else {
                CP_ASYNC8(bb + off,         pah);
                CP_ASYNC8(bb + 10240 + off, pal);
            }
            CP_ASYNC8(bb + 20480 + off, pwh);
            CP_ASYNC8(bb + 30720 + off, pwl);
        }
    };

    const int nchunks = K >> 5;
    issue_chunk(0, 0);
    CP_COMMIT();

    for (int c = 0; c < nchunks; c++) {
        const bool more = (c + 1) < nchunks;
        if (more) {
            issue_chunk((c + 1) & 1, (c + 1) << 5);
            CP_COMMIT();
            CP_WAIT1();
        } else {
            CP_WAIT0();
        }
        __syncthreads();

        const uint32_t bb = sb + (uint32_t)(c & 1) * 40960;
        const uint32_t AhB = bb, AlB = bb + 10240, WhB = bb + 20480, WlB = bb + 30720;
        GEMM3_CHUNK_MMA(AhB, AlB, WhB, WlB)
        __syncthreads();
    }

    const int gr = lane >> 2;
    const int gc = (lane & 3) * 2;
#pragma unroll
    for (int mt = 0; mt < 4; mt++) {
        const int row0 = bm + m0 + mt * 16 + gr;
#pragma unroll
        for (int nt = 0; nt < 8; nt++) {
            const int col = bn + n0 + nt * 8 + gc;
            float b0 = bias ? bias[col] : 0.f;
            float b1 = bias ? bias[col + 1] : 0.f;
            float o0 = acc[mt][nt][0] + b0, o1 = acc[mt][nt][1] + b1;
            float o2 = acc[mt][nt][2] + b0, o3 = acc[mt][nt][3] + b1;
            if (OUT & 1) {
                *(float2*)(Cmat + (size_t)row0 * N + col) = make_float2(o0, o1);
                *(float2*)(Cmat + (size_t)(row0 + 8) * N + col) = make_float2(o2, o3);
            }
            if (OUT & 2) {
                size_t i0 = ((size_t)row0 * N + col) >> 1;
                size_t i1 = ((size_t)(row0 + 8) * N + col) >> 1;
                ((uint32_t*)Ch)[i0] = pack_hi(o0, o1);
                ((uint32_t*)Cl)[i0] = pack_lo(o0, o1);
                ((uint32_t*)Ch)[i1] = pack_hi(o2, o3);
                ((uint32_t*)Cl)[i1] = pack_lo(o2, o3);
            }
        }
    }
}

// ---------------------------------------------------------------------------
// Merged head-projection GEMM v3 (3 sub-problems, one launch, 128 threads).
// ---------------------------------------------------------------------------
struct ProjParams {
    const __nv_bfloat16 *Ah[3], *Al[3], *Wh[3], *Wl[3];
    float* Cf[3];
    __nv_bfloat16 *Ch[3], *Cl[3];
    int outm[3];
};

__global__ __launch_bounds__(128, 2) void projgemm3_kernel(ProjParams P)
{
    extern __shared__ char smc[];
    const uint32_t sb = smem_u32(smc);
    constexpr int K = 512, N = 256;

    const int y = blockIdx.y;
    const int pi = (y < 64) ? 0 : (y < 192 ? 1 : 2);
    const int ylocal = y - ((pi == 0) ? 0 : (pi == 1) ? 64 : 192);

    const __nv_bfloat16* Ah = P.Ah[pi];
    const __nv_bfloat16* Al = P.Al[pi];
    const __nv_bfloat16* Wh = P.Wh[pi];
    const __nv_bfloat16* Wl = P.Wl[pi];
    float* Cmat = P.Cf[pi];
    __nv_bfloat16* Ch = P.Ch[pi];
    __nv_bfloat16* Cl = P.Cl[pi];
    const int OUT = P.outm[pi];

    const int tid  = threadIdx.x;
    const int wid  = tid >> 5;
    const int lane = tid & 31;
    const int bm = ylocal << 7;
    const int bn = blockIdx.x << 7;
    const int m0 = (wid & 1) << 6;
    const int n0 = (wid >> 1) << 6;

    int rr[8], kk[8];
#pragma unroll
    for (int j = 0; j < 8; j++) {
        int s = tid + (j << 7);
        rr[j] = s >> 3;
        kk[j] = (s & 7) << 2;
    }

    const uint32_t lrow = (uint32_t)(lane & 15);
    const uint32_t lkq  = (uint32_t)(lane >> 4) * 16;
    uint32_t aOffs[4], bOffs[4];
#pragma unroll
    for (int t = 0; t < 4; t++) {
        aOffs[t] = (uint32_t)(m0 + t * 16 + lrow) * 80 + lkq;
        bOffs[t] = (uint32_t)(n0 + t * 16 + lrow) * 80 + lkq;
    }

    float acc[4][8][4];
#pragma unroll
    for (int i = 0; i < 4; i++)
#pragma unroll
        for (int j = 0; j < 8; j++)
#pragma unroll
            for (int l = 0; l < 4; l++) acc[i][j][l] = 0.f;

    auto issue_chunk = [&](int buf, int k0) {
        const uint32_t bb = sb + (uint32_t)buf * 40960;
#pragma unroll
        for (int j = 0; j < 8; j++) {
            const uint32_t off = (uint32_t)rr[j] * 80 + (uint32_t)(kk[j] << 1);
            const int k = k0 + kk[j];
            CP_ASYNC8(bb + off,         Ah + (size_t)(bm + rr[j]) * K + k);
            CP_ASYNC8(bb + 10240 + off, Al + (size_t)(bm + rr[j]) * K + k);
            CP_ASYNC8(bb + 20480 + off, Wh + (size_t)(bn + rr[j]) * K + k);
            CP_ASYNC8(bb + 30720 + off, Wl + (size_t)(bn + rr[j]) * K + k);
        }
    };

    const int nchunks = K >> 5;
    issue_chunk(0, 0);
    CP_COMMIT();

    for (int c = 0; c < nchunks; c++) {
        const bool more = (c + 1) < nchunks;
        if (more) {
            issue_chunk((c + 1) & 1, (c + 1) << 5);
            CP_COMMIT();
            CP_WAIT1();
        } else {
            CP_WAIT0();
        }
        __syncthreads();

        const uint32_t bb = sb + (uint32_t)(c & 1) * 40960;
        const uint32_t AhB = bb, AlB = bb + 10240, WhB = bb + 20480, WlB = bb + 30720;
        GEMM3_CHUNK_MMA(AhB, AlB, WhB, WlB)
        __syncthreads();
    }

    const int gr = lane >> 2;
    const int gc = (lane & 3) * 2;
#pragma unroll
    for (int mt = 0; mt < 4; mt++) {
        const int row0 = bm + m0 + mt * 16 + gr;
#pragma unroll
        for (int nt = 0; nt < 8; nt++) {
            const int col = bn + n0 + nt * 8 + gc;
            float o0 = acc[mt][nt][0], o1 = acc[mt][nt][1];
            float o2 = acc[mt][nt][2], o3 = acc[mt][nt][3];
            if (OUT & 1) {
                *(float2*)(Cmat + (size_t)row0 * N + col) = make_float2(o0, o1);
                *(float2*)(Cmat + (size_t)(row0 + 8) * N + col) = make_float2(o2, o3);
            }
            if (OUT & 2) {
                size_t i0 = ((size_t)row0 * N + col) >> 1;
                size_t i1 = ((size_t)(row0 + 8) * N + col) >> 1;
                ((uint32_t*)Ch)[i0] = pack_hi(o0, o1);
                ((uint32_t*)Cl)[i0] = pack_lo(o0, o1);
                ((uint32_t*)Ch)[i1] = pack_hi(o2, o3);
                ((uint32_t*)Cl)[i1] = pack_lo(o2, o3);
            }
        }
    }
}

// ---------------------------------------------------------------------------
// LayerNorm(512) + exact GELU -> bf16 hi/lo planes
// ---------------------------------------------------------------------------
__global__ void ln_gelu_split_kernel(const float* __restrict__ x,
                                     const float* __restrict__ w,
                                     const float* __restrict__ b,
                                     __nv_bfloat16* __restrict__ hO,
                                     __nv_bfloat16* __restrict__ lO)
{
    __shared__ float sh[8];
    const float* row = x + (size_t)blockIdx.x * 512;
    int t = threadIdx.x;
    float2 v = *(const float2*)(row + t * 2);

    float s = v.x + v.y;
#pragma unroll
    for (int o = 16; o; o >>= 1) s += __shfl_xor_sync(0xffffffffu, s, o);
    if ((t & 31) == 0) sh[t >> 5] = s;
    __syncthreads();
    float tot = 0.f;
#pragma unroll
    for (int i = 0; i < 8; i++) tot += sh[i];
    float mu = tot * (1.f / 512.f);
    float d0 = v.x - mu, d1 = v.y - mu;
    __syncthreads();

    float ss = d0 * d0 + d1 * d1;
#pragma unroll
    for (int o = 16; o; o >>= 1) ss += __shfl_xor_sync(0xffffffffu, ss, o);
    if ((t & 31) == 0) sh[t >> 5] = ss;
    __syncthreads();
    float tot2 = 0.f;
#pragma unroll
    for (int i = 0; i < 8; i++) tot2 += sh[i];
    float inv = rsqrtf(tot2 * (1.f / 512.f) + 1e-5f);

    float y0 = d0 * inv * w[t * 2]     + b[t * 2];
    float y1 = d1 * inv * w[t * 2 + 1] + b[t * 2 + 1];
    y0 = 0.5f * y0 * (1.f + erff(y0 * 0.7071067811865476f));
    y1 = 0.5f * y1 * (1.f + erff(y1 * 0.7071067811865476f));

    size_t o = (size_t)blockIdx.x * 256 + t;
    ((uint32_t*)hO)[o] = pack_hi(y0, y1);
    ((uint32_t*)lO)[o] = pack_lo(y0, y1);
}

// ---------------------------------------------------------------------------
// Depthwise 3x3 (pad 1) residual -> transposed planes, coalesced via smem tile.
// ---------------------------------------------------------------------------
__global__ void dwconv_res_t2_kernel(const float* __restrict__ v,
                                     const float* __restrict__ lw,
                                     const float* __restrict__ lb,
                                     __nv_bfloat16* __restrict__ vth,
                                     __nv_bfloat16* __restrict__ vtl,
                                     int hh, int ww)
{
    __shared__ float sm[64][65];
    const int Nn = hh * ww;
    const int nt = Nn >> 6;
    int bz = blockIdx.x;
    const int ntile = bz % nt; bz /= nt;
    const int ct = bz & 3;
    const int bb = bz >> 2;
    const int c0 = ct << 6, n0 = ntile << 6;

    const int tid = threadIdx.x;
    const int tc = tid & 63;
    const int tn0 = tid >> 6;
    const int c = c0 + tc;

    float wreg[9];
#pragma unroll
    for (int i = 0; i < 9; i++) wreg[i] = lw[c * 9 + i];
    const float bias = lb[c];

    for (int nn = tn0; nn < 64; nn += 4) {
        const int n = n0 + nn;
        const int y = n / ww;
        const int x = n - y * ww;
        float acc = bias;
#pragma unroll
        for (int dy = -1; dy <= 1; dy++) {
            int yy = y + dy;
            if (yy < 0 || yy >= hh) continue;
#pragma unroll
            for (int dx = -1; dx <= 1; dx++) {
                int xx = x + dx;
                if (xx < 0 || xx >= ww) continue;
                acc += v[((size_t)(bb * Nn + yy * ww + xx) << 8) + c] * wreg[(dy + 1) * 3 + (dx + 1)];
            }
        }
        sm[nn][tc] = v[((size_t)(bb * Nn + n) << 8) + c] + acc;
    }
    __syncthreads();

    const int wc = tid >> 5;
    const int wn = (tid & 31) << 1;
    for (int cc = wc; cc < 64; cc += 8) {
        float v0 = sm[wn][cc], v1 = sm[wn + 1][cc];
        size_t o = (((size_t)(bb * 256 + c0 + cc)) * Nn + n0 + wn) >> 1;
        ((uint32_t*)vth)[o] = pack_hi(v0, v1);
        ((uint32_t*)vtl)[o] = pack_lo(v0, v1);
    }
}

// ---------------------------------------------------------------------------
// Flash attention, split-bf16 HMMA, K/V double-buffered, 2 CTAs/SM (unchanged).
// ---------------------------------------------------------------------------
__global__ __launch_bounds__(256, 2) void flash_kernel(
    const __nv_bfloat16* __restrict__ qph, const __nv_bfloat16* __restrict__ qpl,
    const __nv_bfloat16* __restrict__ kph, const __nv_bfloat16* __restrict__ kpl,
    const __nv_bfloat16* __restrict__ vth, const __nv_bfloat16* __restrict__ vtl,
    __nv_bfloat16* __restrict__ xh, __nv_bfloat16* __restrict__ xl,
    int Nk, int hoff, int coloff)
{
    extern __shared__ char smc[];
    const uint32_t sb = smem_u32(smc);
    const uint32_t QH = sb, QL = sb + 18432;

    const int tid  = threadIdx.x;
    const int wid  = tid >> 5;
    const int lane = tid & 31;
    const int b = blockIdx.y >> 2;
    const int h = blockIdx.y & 3;
    const int q0 = blockIdx.x << 7;

    {
        const size_t qbase = ((size_t)(b * Qn + q0)) * 512 + (size_t)(hoff + h) * 64;
#pragma unroll
        for (int it = 0; it < 8; it++) {
            int i = tid + (it << 8);
            int row = i >> 4;
            int c4 = (i & 15) << 2;
            uint32_t dst = (uint32_t)row * 144 + (uint32_t)(c4 << 1);
            CP_ASYNC8(QH + dst, qph + qbase + (size_t)row * 512 + c4);
            CP_ASYNC8(QL + dst, qpl + qbase + (size_t)row * 512 + c4);
        }
        CP_COMMIT();
    }

    auto issue_kv = [&](int buf, int kv0) {
        const uint32_t bb = sb + 36864 + (uint32_t)buf * 36864;
#pragma unroll
        for (int it = 0; it < 4; it++) {
            int i = tid + (it << 8);
            int row = i >> 4;
            int c4 = (i & 15) << 2;
            uint32_t dst = (uint32_t)row * 144 + (uint32_t)(c4 << 1);
            size_t kidx = ((size_t)(b * Nk + kv0 + row)) * 256 + h * 64 + c4;
            CP_ASYNC8(bb + dst,         kph + kidx);
            CP_ASYNC8(bb + 9216 + dst,  kpl + kidx);
            size_t vidx = ((size_t)(b * 256 + h * 64 + row)) * Nk + kv0 + c4;
            CP_ASYNC8(bb + 18432 + dst, vth + vidx);
            CP_ASYNC8(bb + 27648 + dst, vtl + vidx);
        }
    };

    const uint32_t lrow = (uint32_t)(lane & 15);
    const uint32_t lkq  = (uint32_t)(lane >> 4) * 16;
    const uint32_t qOff = ((uint32_t)(wid * 16) + lrow) * 144 + lkq;
    const uint32_t kOff = lrow * 144 + lkq;

    const int gr = lane >> 2;

    float m0 = -1e30f, m1 = -1e30f, l0 = 0.f, l1 = 0.f;
    float Oacc[8][4];
#pragma unroll
    for (int j = 0; j < 8; j++)
#pragma unroll
        for (int l = 0; l < 4; l++) Oacc[j][l] = 0.f;

    const int ntiles = Nk >> 6;
    issue_kv(0, 0);
    CP_COMMIT();

    for (int t = 0; t < ntiles; t++) {
        const bool more = (t + 1) < ntiles;
        if (more) {
            issue_kv((t + 1) & 1, (t + 1) << 6);
            CP_COMMIT();
            CP_WAIT1();
        } else {
            CP_WAIT0();
        }
        __syncthreads();

        const uint32_t bb = sb + 36864 + (uint32_t)(t & 1) * 36864;
        const uint32_t KH = bb, KL = bb + 9216, VH = bb + 18432, VL = bb + 27648;

        float S[8][4];
#pragma unroll
        for (int j = 0; j < 8; j++)
#pragma unroll
            for (int l = 0; l < 4; l++) S[j][l] = 0.f;

#pragma unroll
        for (int ks = 0; ks < 4; ks++) {
            const uint32_t ko = (uint32_t)ks * 32;
            uint32_t qh4[4], ql4[4];
            ldsm_x4(qh4[0], qh4[1], qh4[2], qh4[3], QH + qOff + ko);
            ldsm_x4(ql4[0], ql4[1], ql4[2], ql4[3], QL + qOff + ko);
#pragma unroll
            for (int g = 0; g < 4; g++) {
                uint32_t kh4[4], kl4[4];
                ldsm_x4(kh4[0], kh4[1], kh4[2], kh4[3], KH + (uint32_t)g * 2304 + kOff + ko);
                ldsm_x4(kl4[0], kl4[1], kl4[2], kl4[3], KL + (uint32_t)g * 2304 + kOff + ko);
                mma_bf16(S[2 * g + 0], qh4[0], qh4[1], qh4[2], qh4[3], kh4[0], kh4[2]);
                mma_bf16(S[2 * g + 1], qh4[0], qh4[1], qh4[2], qh4[3], kh4[1], kh4[3]);
                mma_bf16(S[2 * g + 0], qh4[0], qh4[1], qh4[2], qh4[3], kl4[0], kl4[2]);
                mma_bf16(S[2 * g + 1], qh4[0], qh4[1], qh4[2], qh4[3], kl4[1], kl4[3]);
                mma_bf16(S[2 * g + 0], ql4[0], ql4[1], ql4[2], ql4[3], kh4[0], kh4[2]);
                mma_bf16(S[2 * g + 1], ql4[0], ql4[1], ql4[2], ql4[3], kh4[1], kh4[3]);
            }
        }

        const float sc = 0.125f;
        float mx0 = m0, mx1 = m1;
#pragma unroll
        for (int j = 0; j < 8; j++) {
            S[j][0] *= sc; S[j][1] *= sc; S[j][2] *= sc; S[j][3] *= sc;
            mx0 = fmaxf(mx0, fmaxf(S[j][0], S[j][1]));
            mx1 = fmaxf(mx1, fmaxf(S[j][2], S[j][3]));
        }
#pragma unroll
        for (int o = 1; o <= 2; o <<= 1) {
            mx0 = fmaxf(mx0, __shfl_xor_sync(0xffffffffu, mx0, o));
            mx1 = fmaxf(mx1, __shfl_xor_sync(0xffffffffu, mx1, o));
        }
        const float alpha0 = __expf(m0 - mx0);
        const float alpha1 = __expf(m1 - mx1);
        m0 = mx0; m1 = mx1;

        float rs0 = 0.f, rs1 = 0.f;
#pragma unroll
        for (int j = 0; j < 8; j++) {
            S[j][0] = __expf(S[j][0] - mx0);
            S[j][1] = __expf(S[j][1] - mx0);
            S[j][2] = __expf(S[j][2] - mx1);
            S[j][3] = __expf(S[j][3] - mx1);
            rs0 += S[j][0] + S[j][1];
            rs1 += S[j][2] + S[j][3];
        }
#pragma unroll
        for (int o = 1; o <= 2; o <<= 1) {
            rs0 += __shfl_xor_sync(0xffffffffu, rs0, o);
            rs1 += __shfl_xor_sync(0xffffffffu, rs1, o);
        }
        l0 = l0 * alpha0 + rs0;
        l1 = l1 * alpha1 + rs1;

#pragma unroll
        for (int j = 0; j < 8; j++) {
            Oacc[j][0] *= alpha0; Oacc[j][1] *= alpha0;
            Oacc[j][2] *= alpha1; Oacc[j][3] *= alpha1;
        }

#pragma unroll
        for (int t16 = 0; t16 < 4; t16++) {
            uint32_t ph0 = pack_hi(S[2 * t16][0],     S[2 * t16][1]);
            uint32_t ph1 = pack_hi(S[2 * t16][2],     S[2 * t16][3]);
            uint32_t ph2 = pack_hi(S[2 * t16 + 1][0], S[2 * t16 + 1][1]);
            uint32_t ph3 = pack_hi(S[2 * t16 + 1][2], S[2 * t16 + 1][3]);
            uint32_t pl0 = pack_lo(S[2 * t16][0],     S[2 * t16][1]);
            uint32_t pl1 = pack_lo(S[2 * t16][2],     S[2 * t16][3]);
            uint32_t pl2 = pack_lo(S[2 * t16 + 1][0], S[2 * t16 + 1][1]);
            uint32_t pl3 = pack_lo(S[2 * t16 + 1][2], S[2 * t16 + 1][3]);
            const uint32_t ko = (uint32_t)t16 * 32;
#pragma unroll
            for (int g = 0; g < 4; g++) {
                uint32_t vh0, vh1, vh2, vh3;
                ldsm_x4(vh0, vh1, vh2, vh3, VH + (uint32_t)g * 2304 + kOff + ko);
                mma_bf16(Oacc[2 * g + 0], ph0, ph1, ph2, ph3, vh0, vh2);
                mma_bf16(Oacc[2 * g + 1], ph0, ph1, ph2, ph3, vh1, vh3);
                mma_bf16(Oacc[2 * g + 0], pl0, pl1, pl2, pl3, vh0, vh2);
                mma_bf16(Oacc[2 * g + 1], pl0, pl1, pl2, pl3, vh1, vh3);
                uint32_t vl0, vl1, vl2, vl3;
                ldsm_x4(vl0, vl1, vl2, vl3, VL + (uint32_t)g * 2304 + kOff + ko);
                mma_bf16(Oacc[2 * g + 0], ph0, ph1, ph2, ph3, vl0, vl2);
                mma_bf16(Oacc[2 * g + 1], ph0, ph1, ph2, ph3, vl1, vl3);
            }
        }
        __syncthreads();
    }

    const float inv0 = 1.f / l0;
    const float inv1 = 1.f / l1;
    const int gc = (lane & 3) * 2;
    const int row0 = b * Qn + q0 + wid * 16 + gr;
#pragma unroll
    for (int j = 0; j < 8; j++) {
        const int col = coloff + h * 64 + (j >> 1) * 16 + (j & 1) * 8 + gc;
        float o0 = Oacc[j][0] * inv0, o1 = Oacc[j][1] * inv0;
        float o2 = Oacc[j][2] * inv1, o3 = Oacc[j][3] * inv1;
        size_t i0 = ((size_t)row0 * 512 + col) >> 1;
        size_t i1 = ((size_t)(row0 + 8) * 512 + col) >> 1;
        ((uint32_t*)xh)[i0] = pack_hi(o0, o1);
        ((uint32_t*)xl)[i0] = pack_lo(o0, o1);
        ((uint32_t*)xh)[i1] = pack_hi(o2, o3);
        ((uint32_t*)xl)[i1] = pack_lo(o2, o3);
    }
}

// ---------------------------------------------------------------------------
// Host launch sequence
// ---------------------------------------------------------------------------
extern "C" void kernel_launch(void* const* d_in, const int* in_sizes, int n_in,
                              void* d_out, int out_size)
{
    (void)in_sizes; (void)out_size;
    const int s = (n_in >= 24) ? 2 : 0;

    const float* query   = (const float*)d_in[0];
    const float* key     = (const float*)d_in[1];
    const float* value   = (const float*)d_in[2];
    const float* q_w     = (const float*)d_in[3 + s];
    const float* sr1_w   = (const float*)d_in[4 + s];
    const float* sr1_b   = (const float*)d_in[5 + s];
    const float* norm1_w = (const float*)d_in[6 + s];
    const float* norm1_b = (const float*)d_in[7 + s];
    const float* sr2_w   = (const float*)d_in[8 + s];
    const float* sr2_b   = (const float*)d_in[9 + s];
    const float* norm2_w = (const float*)d_in[10 + s];
    const float* norm2_b = (const float*)d_in[11 + s];
    const float* k1_w    = (const float*)d_in[12 + s];
    const float* k2_w    = (const float*)d_in[14 + s];
    const float* v2_w    = (const float*)d_in[15 + s];
    const float* lc1_w   = (const float*)d_in[16 + s];
    const float* lc1_b   = (const float*)d_in[17 + s];
    const float* lc2_w   = (const float*)d_in[18 + s];
    const float* lc2_b   = (const float*)d_in[19 + s];
    const float* proj_w  = (const float*)d_in[20 + s];
    const float* proj_b  = (const float*)d_in[21 + s];
    float* out = (float*)d_out;

    float *kv1n, *kv2n, *kv1, *v2;
    cudaGetSymbolAddress((void**)&kv1n, g_kv1n);
    cudaGetSymbolAddress((void**)&kv2n, g_kv2n);
    cudaGetSymbolAddress((void**)&kv1,  g_kv1);
    cudaGetSymbolAddress((void**)&v2,   g_v2);

    __nv_bfloat16 *qh, *ql, *qph, *qpl, *imgh, *imgl, *kv1nh, *kv1nl, *kv2nh, *kv2nl;
    __nv_bfloat16 *k1ph, *k1pl, *k2ph, *k2pl, *vt1h, *vt1l, *vt2h, *vt2l, *xh, *xl;
    __nv_bfloat16 *qwh, *qwl, *s1wh, *s1wl, *s2wh, *s2wl, *k1wh, *k1wl, *k2wh, *k2wl, *v2wh, *v2wl, *pwh, *pwl;
    cudaGetSymbolAddress((void**)&qh, g_qh);       cudaGetSymbolAddress((void**)&ql, g_ql);
    cudaGetSymbolAddress((void**)&qph, g_qph);     cudaGetSymbolAddress((void**)&qpl, g_qpl);
    cudaGetSymbolAddress((void**)&imgh, g_imgh);   cudaGetSymbolAddress((void**)&imgl, g_imgl);
    cudaGetSymbolAddress((void**)&kv1nh, g_kv1nh); cudaGetSymbolAddress((void**)&kv1nl, g_kv1nl);
    cudaGetSymbolAddress((void**)&kv2nh, g_kv2nh); cudaGetSymbolAddress((void**)&kv2nl, g_kv2nl);
    cudaGetSymbolAddress((void**)&k1ph, g_k1ph);   cudaGetSymbolAddress((void**)&k1pl, g_k1pl);
    cudaGetSymbolAddress((void**)&k2ph, g_k2ph);   cudaGetSymbolAddress((void**)&k2pl, g_k2pl);
    cudaGetSymbolAddress((void**)&vt1h, g_vt1h);   cudaGetSymbolAddress((void**)&vt1l, g_vt1l);
    cudaGetSymbolAddress((void**)&vt2h, g_vt2h);   cudaGetSymbolAddress((void**)&vt2l, g_vt2l);
    cudaGetSymbolAddress((void**)&xh, g_xh);       cudaGetSymbolAddress((void**)&xl, g_xl);
    cudaGetSymbolAddress((void**)&qwh, g_qwh);     cudaGetSymbolAddress((void**)&qwl, g_qwl);
    cudaGetSymbolAddress((void**)&s1wh, g_s1wh);   cudaGetSymbolAddress((void**)&s1wl, g_s1wl);
    cudaGetSymbolAddress((void**)&s2wh, g_s2wh);   cudaGetSymbolAddress((void**)&s2wl, g_s2wl);
    cudaGetSymbolAddress((void**)&k1wh, g_k1wh);   cudaGetSymbolAddress((void**)&k1wl, g_k1wl);
    cudaGetSymbolAddress((void**)&k2wh, g_k2wh);   cudaGetSymbolAddress((void**)&k2wl, g_k2wl);
    cudaGetSymbolAddress((void**)&v2wh, g_v2wh);   cudaGetSymbolAddress((void**)&v2wl, g_v2wl);
    cudaGetSymbolAddress((void**)&pwh, g_pwh);     cudaGetSymbolAddress((void**)&pwl, g_pwl);

    const size_t IMG1 = (size_t)B_ * C_ * 64 * 64;
    float* v1 = kv1 + (size_t)B_ * N1_ * C2_;

    const int SMEM = 81920;
    cudaFuncSetAttribute(hgemm3_kernel<0, 1>, cudaFuncAttributeMaxDynamicSharedMemorySize, SMEM);
    cudaFuncSetAttribute(hgemm3_kernel<0, 2>, cudaFuncAttributeMaxDynamicSharedMemorySize, SMEM);
    cudaFuncSetAttribute(hgemm3_kernel<1, 1>, cudaFuncAttributeMaxDynamicSharedMemorySize, SMEM);
    cudaFuncSetAttribute(hgemm3_kernel<2, 1>, cudaFuncAttributeMaxDynamicSharedMemorySize, SMEM);
    cudaFuncSetAttribute(projgemm3_kernel, cudaFuncAttributeMaxDynamicSharedMemorySize, SMEM);
    const int FSMEM = 110592;
    cudaFuncSetAttribute(flash_kernel, cudaFuncAttributeMaxDynamicSharedMemorySize, FSMEM);

    dim3 gblk(128);
    dim3 blk(256);

    // launches ordered so my 4th launch (#6 under ncu -s 5) = sr1 GEMM
    split_kernel<<<4096, 256>>>(sr1_w, s1wh, s1wl);                         // 1
    to_image_split2_kernel<<<8192, 256>>>(key, value, imgh, imgl, IMG1);    // 2
    split_kernel<<<1024, 256>>>(sr2_w, s2wh, s2wl);                         // 3
    hgemm3_kernel<1, 1><<<dim3(4, 64), gblk, SMEM>>>(imgh, imgl, s1wh, s1wl, sr1_b,
                                                     kv1n, nullptr, nullptr, 8192, 512, 8192); // 4 <- profiled

    split_kernel<<<256, 256>>>(q_w, qwh, qwl);
    split_kernel<<<128, 256>>>(k1_w, k1wh, k1wl);
    split_kernel<<<128, 256>>>(k2_w, k2wh, k2wl);
    split_kernel<<<128, 256>>>(v2_w, v2wh, v2wl);
    split_kernel<<<256, 256>>>(proj_w, pwh, pwl);
    split_kernel<<<8192, 256>>>(query, qh, ql);

    hgemm3_kernel<2, 1><<<dim3(4, 256), gblk, SMEM>>>(imgh, imgl, s2wh, s2wl, sr2_b,
                                                      kv2n, nullptr, nullptr, 32768, 512, 2048);

    hgemm3_kernel<0, 2><<<dim3(4, 128), gblk, SMEM>>>(qh, ql, qwh, qwl, nullptr,
                                                      nullptr, qph, qpl, 16384, 512, 512);

    ln_gelu_split_kernel<<<8192,  256>>>(kv1n, norm1_w, norm1_b, kv1nh, kv1nl);
    ln_gelu_split_kernel<<<32768, 256>>>(kv2n, norm2_w, norm2_b, kv2nh, kv2nl);

    {
        ProjParams P;
        P.Ah[0] = kv1nh;  P.Al[0] = kv1nl;  P.Wh[0] = k1wh; P.Wl[0] = k1wl;
        P.Cf[0] = kv1;    P.Ch[0] = k1ph;   P.Cl[0] = k1pl; P.outm[0] = 3;
        P.Ah[1] = kv2nh;  P.Al[1] = kv2nl;  P.Wh[1] = k2wh; P.Wl[1] = k2wl;
        P.Cf[1] = nullptr; P.Ch[1] = k2ph;  P.Cl[1] = k2pl; P.outm[1] = 2;
        P.Ah[2] = kv2nh + (size_t)16384 * 512;
        P.Al[2] = kv2nl + (size_t)16384 * 512;
        P.Wh[2] = v2wh;   P.Wl[2] = v2wl;
        P.Cf[2] = v2;     P.Ch[2] = nullptr; P.Cl[2] = nullptr; P.outm[2] = 1;
        projgemm3_kernel<<<dim3(2, 320), gblk, SMEM>>>(P);
    }

    dwconv_res_t2_kernel<<<B_ * 4 * (N1_ / 64), 256>>>(v1, lc1_w, lc1_b, vt1h, vt1l, 16, 16);
    dwconv_res_t2_kernel<<<B_ * 4 * (N2_ / 64), 256>>>(v2, lc2_w, lc2_b, vt2h, vt2l, 32, 32);

    flash_kernel<<<dim3(8, 64), blk, FSMEM>>>(qph, qpl, k1ph, k1pl, vt1h, vt1l,
                                              xh, xl, N1_, 0, 0);
    flash_kernel<<<dim3(8, 64), blk, FSMEM>>>(qph, qpl, k2ph, k2pl, vt2h, vt2l,
                                              xh, xl, N2_, 4, 256);

    hgemm3_kernel<0, 1><<<dim3(4, 128), gblk, SMEM>>>(xh, xl, pwh, pwl, proj_b,
                                                      out, nullptr, nullptr, 16384, 512, 512);
}

// round 11
// speedup vs baseline: 3.2319x; 1.0007x over previous
#include <cuda_runtime.h>
#include <cuda_bf16.h>
#include <math.h>
#include <stdint.h>

// ---------------------------------------------------------------------------
// Problem constants
// ---------------------------------------------------------------------------
constexpr int B_   = 16;
constexpr int C_   = 512;
constexpr int Qn   = 1024;
constexpr int C2_  = 256;
constexpr int N1_  = 256;
constexpr int N2_  = 1024;

// ---------------------------------------------------------------------------
// Device scratch
// ---------------------------------------------------------------------------
__device__ float g_kv1n [(size_t)2 * B_ * N1_ * C_];
__device__ float g_kv2n [(size_t)2 * B_ * N2_ * C_];
__device__ float g_kv1  [(size_t)2 * B_ * N1_ * C2_];
__device__ float g_v2   [(size_t)B_ * N2_ * C2_];

// bf16 hi/lo planes
__device__ __nv_bfloat16 g_qh   [(size_t)16384 * 512];
__device__ __nv_bfloat16 g_ql   [(size_t)16384 * 512];
__device__ __nv_bfloat16 g_qph  [(size_t)16384 * 512];
__device__ __nv_bfloat16 g_qpl  [(size_t)16384 * 512];
__device__ __nv_bfloat16 g_imgh [(size_t)2 * B_ * C_ * 64 * 64];
__device__ __nv_bfloat16 g_imgl [(size_t)2 * B_ * C_ * 64 * 64];
__device__ __nv_bfloat16 g_kv1nh[(size_t)8192 * 512];
__device__ __nv_bfloat16 g_kv1nl[(size_t)8192 * 512];
__device__ __nv_bfloat16 g_kv2nh[(size_t)32768 * 512];
__device__ __nv_bfloat16 g_kv2nl[(size_t)32768 * 512];
__device__ __nv_bfloat16 g_k1ph [(size_t)8192 * 256];
__device__ __nv_bfloat16 g_k1pl [(size_t)8192 * 256];
__device__ __nv_bfloat16 g_k2ph [(size_t)16384 * 256];
__device__ __nv_bfloat16 g_k2pl [(size_t)16384 * 256];
__device__ __nv_bfloat16 g_vt1h [(size_t)B_ * C2_ * N1_];
__device__ __nv_bfloat16 g_vt1l [(size_t)B_ * C2_ * N1_];
__device__ __nv_bfloat16 g_vt2h [(size_t)B_ * C2_ * N2_];
__device__ __nv_bfloat16 g_vt2l [(size_t)B_ * C2_ * N2_];
__device__ __nv_bfloat16 g_xh   [(size_t)16384 * 512];
__device__ __nv_bfloat16 g_xl   [(size_t)16384 * 512];
// weight planes
__device__ __nv_bfloat16 g_qwh [262144],  g_qwl [262144];
__device__ __nv_bfloat16 g_s1wh[4194304], g_s1wl[4194304];
__device__ __nv_bfloat16 g_s2wh[1048576], g_s2wl[1048576];
__device__ __nv_bfloat16 g_k1wh[131072],  g_k1wl[131072];
__device__ __nv_bfloat16 g_k2wh[131072],  g_k2wl[131072];
__device__ __nv_bfloat16 g_v2wh[131072],  g_v2wl[131072];
__device__ __nv_bfloat16 g_pwh [262144],  g_pwl [262144];

// ---------------------------------------------------------------------------
// helpers
// ---------------------------------------------------------------------------
__device__ __forceinline__ uint32_t smem_u32(const void* p) {
    uint32_t a;
    asm("{ .reg .u64 t; cvta.to.shared.u64 t, %1; cvt.u32.u64 %0, t; }" : "=r"(a) : "l"(p));
    return a;
}
__device__ __forceinline__ void ldsm_x4(uint32_t& r0, uint32_t& r1, uint32_t& r2, uint32_t& r3,
                                        uint32_t addr) {
    asm volatile("ldmatrix.sync.aligned.m8n8.x4.shared.b16 {%0,%1,%2,%3}, [%4];"
                 : "=r"(r0), "=r"(r1), "=r"(r2), "=r"(r3) : "r"(addr));
}
__device__ __forceinline__ void mma_bf16(float* d,
                                         uint32_t a0, uint32_t a1, uint32_t a2, uint32_t a3,
                                         uint32_t b0, uint32_t b1) {
    asm volatile(
        "mma.sync.aligned.m16n8k16.row.col.f32.bf16.bf16.f32 "
        "{%0,%1,%2,%3}, {%4,%5,%6,%7}, {%8,%9}, {%0,%1,%2,%3};"
        : "+f"(d[0]), "+f"(d[1]), "+f"(d[2]), "+f"(d[3])
        : "r"(a0), "r"(a1), "r"(a2), "r"(a3), "r"(b0), "r"(b1));
}
__device__ __forceinline__ uint32_t pack_hi(float x, float y) {
    __nv_bfloat162 p(__float2bfloat16(x), __float2bfloat16(y));
    return *(uint32_t*)&p;
}
__device__ __forceinline__ uint32_t pack_lo(float x, float y) {
    float hx = __bfloat162float(__float2bfloat16(x));
    float hy = __bfloat162float(__float2bfloat16(y));
    __nv_bfloat162 p(__float2bfloat16(x - hx), __float2bfloat16(y - hy));
    return *(uint32_t*)&p;
}

#define CP_ASYNC16(dst, src) \
    asm volatile("cp.async.cg.shared.global [%0], [%1], 16;" :: "r"(dst), "l"(src) : "memory")
#define CP_ASYNC8(dst, src) \
    asm volatile("cp.async.ca.shared.global [%0], [%1], 8;" :: "r"(dst), "l"(src) : "memory")
#define CP_ASYNC4(dst, src) \
    asm volatile("cp.async.ca.shared.global [%0], [%1], 4;" :: "r"(dst), "l"(src) : "memory")
#define CP_COMMIT() asm volatile("cp.async.commit_group;" ::: "memory")
#define CP_WAIT0()  asm volatile("cp.async.wait_group 0;" ::: "memory")
#define CP_WAIT1()  asm volatile("cp.async.wait_group 1;" ::: "memory")

// ---------------------------------------------------------------------------
// generic fp32 -> hi/lo bf16 planes
// ---------------------------------------------------------------------------
__global__ void split_kernel(const float* __restrict__ src,
                             __nv_bfloat16* __restrict__ h,
                             __nv_bfloat16* __restrict__ l)
{
    int i = blockIdx.x * 256 + threadIdx.x;
    float4 v = ((const float4*)src)[i];
    ((uint2*)h)[i] = make_uint2(pack_hi(v.x, v.y), pack_hi(v.z, v.w));
    ((uint2*)l)[i] = make_uint2(pack_lo(v.x, v.y), pack_lo(v.z, v.w));
}

// ---------------------------------------------------------------------------
// (N,B,C) -> raw-reshape image, split into bf16 hi/lo planes (K + V one launch)
// ---------------------------------------------------------------------------
__global__ void to_image_split2_kernel(const float* __restrict__ srcK,
                                       const float* __restrict__ srcV,
                                       __nv_bfloat16* __restrict__ h,
                                       __nv_bfloat16* __restrict__ l,
                                       size_t img1)
{
    __shared__ float sm[16][513];
    const int half = blockIdx.x >> 12;
    const float* src = half ? srcV : srcK;
    const size_t dofs = half ? img1 : 0;
    size_t base = (size_t)(blockIdx.x & 4095) * 8192;
    for (int j = threadIdx.x; j < 8192; j += 256) sm[j >> 9][j & 511] = src[base + j];
    __syncthreads();
    for (int r = threadIdx.x; r < 8192; r += 256) {
        float v = sm[r & 15][r >> 4];
        __nv_bfloat16 hv = __float2bfloat16(v);
        h[dofs + base + r] = hv;
        l[dofs + base + r] = __float2bfloat16(v - __bfloat162float(hv));
    }
}

// ---------------------------------------------------------------------------
// 64x64-warp-tile mainloop body (4 warps)
// ---------------------------------------------------------------------------
#define GEMM3_CHUNK_MMA(AhB, AlB, WhB, WlB)                                     \
    _Pragma("unroll")                                                           \
    for (int kh = 0; kh < 2; kh++) {                                            \
        const uint32_t ko = (uint32_t)kh * 32;                                  \
        uint32_t AH[4][4], AL[4][4], BH[4][4], BL[4][4];                        \
        _Pragma("unroll")                                                       \
        for (int mt = 0; mt < 4; mt++) {                                        \
            ldsm_x4(AH[mt][0], AH[mt][1], AH[mt][2], AH[mt][3], (AhB) + aOffs[mt] + ko); \
            ldsm_x4(AL[mt][0], AL[mt][1], AL[mt][2], AL[mt][3], (AlB) + aOffs[mt] + ko); \
        }                                                                       \
        _Pragma("unroll")                                                       \
        for (int nt = 0; nt < 4; nt++) {                                        \
            ldsm_x4(BH[nt][0], BH[nt][1], BH[nt][2], BH[nt][3], (WhB) + bOffs[nt] + ko); \
            ldsm_x4(BL[nt][0], BL[nt][1], BL[nt][2], BL[nt][3], (WlB) + bOffs[nt] + ko); \
        }                                                                       \
        _Pragma("unroll")                                                       \
        for (int mt = 0; mt < 4; mt++)                                          \
        _Pragma("unroll")                                                       \
        for (int nt = 0; nt < 4; nt++) {                                        \
            mma_bf16(acc[mt][2 * nt + 0], AH[mt][0], AH[mt][1], AH[mt][2], AH[mt][3], BH[nt][0], BH[nt][2]); \
            mma_bf16(acc[mt][2 * nt + 1], AH[mt][0], AH[mt][1], AH[mt][2], AH[mt][3], BH[nt][1], BH[nt][3]); \
            mma_bf16(acc[mt][2 * nt + 0], AH[mt][0], AH[mt][1], AH[mt][2], AH[mt][3], BL[nt][0], BL[nt][2]); \
            mma_bf16(acc[mt][2 * nt + 1], AH[mt][0], AH[mt][1], AH[mt][2], AH[mt][3], BL[nt][1], BL[nt][3]); \
            mma_bf16(acc[mt][2 * nt + 0], AL[mt][0], AL[mt][1], AL[mt][2], AL[mt][3], BH[nt][0], BH[nt][2]); \
            mma_bf16(acc[mt][2 * nt + 1], AL[mt][0], AL[mt][1], AL[mt][2], AL[mt][3], BH[nt][1], BH[nt][3]); \
        }                                                                       \
    }

// ---------------------------------------------------------------------------
// Split-bf16 HMMA GEMM v3: 128 threads, 4 warps of 64x64, cp.async double buf.
// 16B cp.async for W (all loaders) and A (loader 0).
// ---------------------------------------------------------------------------
template <int LOADER, int OUT>
__global__ __launch_bounds__(128, 2) void hgemm3_kernel(
    const __nv_bfloat16* __restrict__ Ah, const __nv_bfloat16* __restrict__ Al,
    const __nv_bfloat16* __restrict__ Wh, const __nv_bfloat16* __restrict__ Wl,
    const float* __restrict__ bias, float* __restrict__ Cmat,
    __nv_bfloat16* __restrict__ Ch, __nv_bfloat16* __restrict__ Cl,
    int M, int N, int K)
{
    extern __shared__ char smc[];
    const uint32_t sb = smem_u32(smc);

    const int tid  = threadIdx.x;
    const int wid  = tid >> 5;
    const int lane = tid & 31;
    const int bm = blockIdx.y << 7;
    const int bn = blockIdx.x << 7;
    const int m0 = (wid & 1) << 6;
    const int n0 = (wid >> 1) << 6;

    // 8B slots (A, loaders 1/2)
    int rr[8], kk[8];
#pragma unroll
    for (int j = 0; j < 8; j++) {
        int s = tid + (j << 7);
        rr[j] = s >> 3;
        kk[j] = (s & 7) << 2;
    }
    // 16B slots (W always; A loader 0)
    int rw[4], kw[4];
#pragma unroll
    for (int j = 0; j < 4; j++) {
        int s = tid + (j << 7);
        rw[j] = s >> 2;
        kw[j] = (s & 3) << 3;
    }

    const uint32_t lrow = (uint32_t)(lane & 15);
    const uint32_t lkq  = (uint32_t)(lane >> 4) * 16;
    uint32_t aOffs[4], bOffs[4];
#pragma unroll
    for (int t = 0; t < 4; t++) {
        aOffs[t] = (uint32_t)(m0 + t * 16 + lrow) * 80 + lkq;
        bOffs[t] = (uint32_t)(n0 + t * 16 + lrow) * 80 + lkq;
    }

    float acc[4][8][4];
#pragma unroll
    for (int i = 0; i < 4; i++)
#pragma unroll
        for (int j = 0; j < 8; j++)
#pragma unroll
            for (int l = 0; l < 4; l++) acc[i][j][l] = 0.f;

    auto gaddrA = [&](const __nv_bfloat16* plane, int r, int k) -> const __nv_bfloat16* {
        if (LOADER == 1) {
            int m = bm + r;
            int b = m >> 8, oy = (m >> 4) & 15, ox = m & 15;
            int ic = k >> 4, ky = (k >> 2) & 3;
            return plane + (((size_t)(b * 512 + ic) * 64) + oy * 4 + ky) * 64 + ox * 4;
        } else {
            int m = bm + r;
            int b = m >> 10, oy = (m >> 5) & 31, ox = m & 31;
            int ic = k >> 2;
            return plane + (((size_t)(b * 512 + ic) * 64) + oy * 2) * 64 + ox * 2;
        }
    };

    auto issue_chunk = [&](int buf, int k0) {
        const uint32_t bb = sb + (uint32_t)buf * 40960;
        if (LOADER == 0) {
#pragma unroll
            for (int j = 0; j < 4; j++) {
                const uint32_t off = (uint32_t)rw[j] * 80 + (uint32_t)(kw[j] << 1);
                const int k = k0 + kw[j];
                CP_ASYNC16(bb + off,         Ah + (size_t)(bm + rw[j]) * K + k);
                CP_ASYNC16(bb + 10240 + off, Al + (size_t)(bm + rw[j]) * K + k);
            }
        } else {
#pragma unroll
            for (int j = 0; j < 8; j++) {
                const uint32_t off = (uint32_t)rr[j] * 80 + (uint32_t)(kk[j] << 1);
                const int k = k0 + kk[j];
                const __nv_bfloat16* pah = gaddrA(Ah, rr[j], k);
                const __nv_bfloat16* pal = gaddrA(Al, rr[j], k);
                if (LOADER == 2) {
                    CP_ASYNC4(bb + off,             pah);
                    CP_ASYNC4(bb + off + 4,         pah + 64);
                    CP_ASYNC4(bb + 10240 + off,     pal);
                    CP_ASYNC4(bb + 10240 + off + 4, pal + 64);
                } else {
                    CP_ASYNC8(bb + off,         pah);
                    CP_ASYNC8(bb + 10240 + off, pal);
                }
            }
        }
#pragma unroll
        for (int j = 0; j < 4; j++) {
            const uint32_t off = (uint32_t)rw[j] * 80 + (uint32_t)(kw[j] << 1);
            const int k = k0 + kw[j];
            CP_ASYNC16(bb + 20480 + off, Wh + (size_t)(bn + rw[j]) * K + k);
            CP_ASYNC16(bb + 30720 + off, Wl + (size_t)(bn + rw[j]) * K + k);
        }
    };

    const int nchunks = K >> 5;
    issue_chunk(0, 0);
    CP_COMMIT();

    for (int c = 0; c < nchunks; c++) {
        const bool more = (c + 1) < nchunks;
        if (more) {
            issue_chunk((c + 1) & 1, (c + 1) << 5);
            CP_COMMIT();
            CP_WAIT1();
        } else {
            CP_WAIT0();
        }
        __syncthreads();

        const uint32_t bb = sb + (uint32_t)(c & 1) * 40960;
        const uint32_t AhB = bb, AlB = bb + 10240, WhB = bb + 20480, WlB = bb + 30720;
        GEMM3_CHUNK_MMA(AhB, AlB, WhB, WlB)
        __syncthreads();
    }

    const int gr = lane >> 2;
    const int gc = (lane & 3) * 2;
#pragma unroll
    for (int mt = 0; mt < 4; mt++) {
        const int row0 = bm + m0 + mt * 16 + gr;
#pragma unroll
        for (int nt = 0; nt < 8; nt++) {
            const int col = bn + n0 + nt * 8 + gc;
            float b0 = bias ? bias[col] : 0.f;
            float b1 = bias ? bias[col + 1] : 0.f;
            float o0 = acc[mt][nt][0] + b0, o1 = acc[mt][nt][1] + b1;
            float o2 = acc[mt][nt][2] + b0, o3 = acc[mt][nt][3] + b1;
            if (OUT & 1) {
                *(float2*)(Cmat + (size_t)row0 * N + col) = make_float2(o0, o1);
                *(float2*)(Cmat + (size_t)(row0 + 8) * N + col) = make_float2(o2, o3);
            }
            if (OUT & 2) {
                size_t i0 = ((size_t)row0 * N + col) >> 1;
                size_t i1 = ((size_t)(row0 + 8) * N + col) >> 1;
                ((uint32_t*)Ch)[i0] = pack_hi(o0, o1);
                ((uint32_t*)Cl)[i0] = pack_lo(o0, o1);
                ((uint32_t*)Ch)[i1] = pack_hi(o2, o3);
                ((uint32_t*)Cl)[i1] = pack_lo(o2, o3);
            }
        }
    }
}

// ---------------------------------------------------------------------------
// Merged head-projection GEMM v3 (3 sub-problems, one launch, 128 threads).
// ---------------------------------------------------------------------------
struct ProjParams {
    const __nv_bfloat16 *Ah[3], *Al[3], *Wh[3], *Wl[3];
    float* Cf[3];
    __nv_bfloat16 *Ch[3], *Cl[3];
    int outm[3];
};

__global__ __launch_bounds__(128, 2) void projgemm3_kernel(ProjParams P)
{
    extern __shared__ char smc[];
    const uint32_t sb = smem_u32(smc);
    constexpr int K = 512, N = 256;

    const int y = blockIdx.y;
    const int pi = (y < 64) ? 0 : (y < 192 ? 1 : 2);
    const int ylocal = y - ((pi == 0) ? 0 : (pi == 1) ? 64 : 192);

    const __nv_bfloat16* Ah = P.Ah[pi];
    const __nv_bfloat16* Al = P.Al[pi];
    const __nv_bfloat16* Wh = P.Wh[pi];
    const __nv_bfloat16* Wl = P.Wl[pi];
    float* Cmat = P.Cf[pi];
    __nv_bfloat16* Ch = P.Ch[pi];
    __nv_bfloat16* Cl = P.Cl[pi];
    const int OUT = P.outm[pi];

    const int tid  = threadIdx.x;
    const int wid  = tid >> 5;
    const int lane = tid & 31;
    const int bm = ylocal << 7;
    const int bn = blockIdx.x << 7;
    const int m0 = (wid & 1) << 6;
    const int n0 = (wid >> 1) << 6;

    int rw[4], kw[4];
#pragma unroll
    for (int j = 0; j < 4; j++) {
        int s = tid + (j << 7);
        rw[j] = s >> 2;
        kw[j] = (s & 3) << 3;
    }

    const uint32_t lrow = (uint32_t)(lane & 15);
    const uint32_t lkq  = (uint32_t)(lane >> 4) * 16;
    uint32_t aOffs[4], bOffs[4];
#pragma unroll
    for (int t = 0; t < 4; t++) {
        aOffs[t] = (uint32_t)(m0 + t * 16 + lrow) * 80 + lkq;
        bOffs[t] = (uint32_t)(n0 + t * 16 + lrow) * 80 + lkq;
    }

    float acc[4][8][4];
#pragma unroll
    for (int i = 0; i < 4; i++)
#pragma unroll
        for (int j = 0; j < 8; j++)
#pragma unroll
            for (int l = 0; l < 4; l++) acc[i][j][l] = 0.f;

    auto issue_chunk = [&](int buf, int k0) {
        const uint32_t bb = sb + (uint32_t)buf * 40960;
#pragma unroll
        for (int j = 0; j < 4; j++) {
            const uint32_t off = (uint32_t)rw[j] * 80 + (uint32_t)(kw[j] << 1);
            const int k = k0 + kw[j];
            CP_ASYNC16(bb + off,         Ah + (size_t)(bm + rw[j]) * K + k);
            CP_ASYNC16(bb + 10240 + off, Al + (size_t)(bm + rw[j]) * K + k);
            CP_ASYNC16(bb + 20480 + off, Wh + (size_t)(bn + rw[j]) * K + k);
            CP_ASYNC16(bb + 30720 + off, Wl + (size_t)(bn + rw[j]) * K + k);
        }
    };

    const int nchunks = K >> 5;
    issue_chunk(0, 0);
    CP_COMMIT();

    for (int c = 0; c < nchunks; c++) {
        const bool more = (c + 1) < nchunks;
        if (more) {
            issue_chunk((c + 1) & 1, (c + 1) << 5);
            CP_COMMIT();
            CP_WAIT1();
        } else {
            CP_WAIT0();
        }
        __syncthreads();

        const uint32_t bb = sb + (uint32_t)(c & 1) * 40960;
        const uint32_t AhB = bb, AlB = bb + 10240, WhB = bb + 20480, WlB = bb + 30720;
        GEMM3_CHUNK_MMA(AhB, AlB, WhB, WlB)
        __syncthreads();
    }

    const int gr = lane >> 2;
    const int gc = (lane & 3) * 2;
#pragma unroll
    for (int mt = 0; mt < 4; mt++) {
        const int row0 = bm + m0 + mt * 16 + gr;
#pragma unroll
        for (int nt = 0; nt < 8; nt++) {
            const int col = bn + n0 + nt * 8 + gc;
            float o0 = acc[mt][nt][0], o1 = acc[mt][nt][1];
            float o2 = acc[mt][nt][2], o3 = acc[mt][nt][3];
            if (OUT & 1) {
                *(float2*)(Cmat + (size_t)row0 * N + col) = make_float2(o0, o1);
                *(float2*)(Cmat + (size_t)(row0 + 8) * N + col) = make_float2(o2, o3);
            }
            if (OUT & 2) {
                size_t i0 = ((size_t)row0 * N + col) >> 1;
                size_t i1 = ((size_t)(row0 + 8) * N + col) >> 1;
                ((uint32_t*)Ch)[i0] = pack_hi(o0, o1);
                ((uint32_t*)Cl)[i0] = pack_lo(o0, o1);
                ((uint32_t*)Ch)[i1] = pack_hi(o2, o3);
                ((uint32_t*)Cl)[i1] = pack_lo(o2, o3);
            }
        }
    }
}

// ---------------------------------------------------------------------------
// LayerNorm(512) + exact GELU -> bf16 hi/lo planes
// ---------------------------------------------------------------------------
__global__ void ln_gelu_split_kernel(const float* __restrict__ x,
                                     const float* __restrict__ w,
                                     const float* __restrict__ b,
                                     __nv_bfloat16* __restrict__ hO,
                                     __nv_bfloat16* __restrict__ lO)
{
    __shared__ float sh[8];
    const float* row = x + (size_t)blockIdx.x * 512;
    int t = threadIdx.x;
    float2 v = *(const float2*)(row + t * 2);

    float s = v.x + v.y;
#pragma unroll
    for (int o = 16; o; o >>= 1) s += __shfl_xor_sync(0xffffffffu, s, o);
    if ((t & 31) == 0) sh[t >> 5] = s;
    __syncthreads();
    float tot = 0.f;
#pragma unroll
    for (int i = 0; i < 8; i++) tot += sh[i];
    float mu = tot * (1.f / 512.f);
    float d0 = v.x - mu, d1 = v.y - mu;
    __syncthreads();

    float ss = d0 * d0 + d1 * d1;
#pragma unroll
    for (int o = 16; o; o >>= 1) ss += __shfl_xor_sync(0xffffffffu, ss, o);
    if ((t & 31) == 0) sh[t >> 5] = ss;
    __syncthreads();
    float tot2 = 0.f;
#pragma unroll
    for (int i = 0; i < 8; i++) tot2 += sh[i];
    float inv = rsqrtf(tot2 * (1.f / 512.f) + 1e-5f);

    float y0 = d0 * inv * w[t * 2]     + b[t * 2];
    float y1 = d1 * inv * w[t * 2 + 1] + b[t * 2 + 1];
    y0 = 0.5f * y0 * (1.f + erff(y0 * 0.7071067811865476f));
    y1 = 0.5f * y1 * (1.f + erff(y1 * 0.7071067811865476f));

    size_t o = (size_t)blockIdx.x * 256 + t;
    ((uint32_t*)hO)[o] = pack_hi(y0, y1);
    ((uint32_t*)lO)[o] = pack_lo(y0, y1);
}

// ---------------------------------------------------------------------------
// Depthwise 3x3 (pad 1) residual -> transposed planes, coalesced via smem tile.
// ---------------------------------------------------------------------------
__global__ void dwconv_res_t2_kernel(const float* __restrict__ v,
                                     const float* __restrict__ lw,
                                     const float* __restrict__ lb,
                                     __nv_bfloat16* __restrict__ vth,
                                     __nv_bfloat16* __restrict__ vtl,
                                     int hh, int ww)
{
    __shared__ float sm[64][65];
    const int Nn = hh * ww;
    const int nt = Nn >> 6;
    int bz = blockIdx.x;
    const int ntile = bz % nt; bz /= nt;
    const int ct = bz & 3;
    const int bb = bz >> 2;
    const int c0 = ct << 6, n0 = ntile << 6;

    const int tid = threadIdx.x;
    const int tc = tid & 63;
    const int tn0 = tid >> 6;
    const int c = c0 + tc;

    float wreg[9];
#pragma unroll
    for (int i = 0; i < 9; i++) wreg[i] = lw[c * 9 + i];
    const float bias = lb[c];

    for (int nn = tn0; nn < 64; nn += 4) {
        const int n = n0 + nn;
        const int y = n / ww;
        const int x = n - y * ww;
        float acc = bias;
#pragma unroll
        for (int dy = -1; dy <= 1; dy++) {
            int yy = y + dy;
            if (yy < 0 || yy >= hh) continue;
#pragma unroll
            for (int dx = -1; dx <= 1; dx++) {
                int xx = x + dx;
                if (xx < 0 || xx >= ww) continue;
                acc += v[((size_t)(bb * Nn + yy * ww + xx) << 8) + c] * wreg[(dy + 1) * 3 + (dx + 1)];
            }
        }
        sm[nn][tc] = v[((size_t)(bb * Nn + n) << 8) + c] + acc;
    }
    __syncthreads();

    const int wc = tid >> 5;
    const int wn = (tid & 31) << 1;
    for (int cc = wc; cc < 64; cc += 8) {
        float v0 = sm[wn][cc], v1 = sm[wn + 1][cc];
        size_t o = (((size_t)(bb * 256 + c0 + cc)) * Nn + n0 + wn) >> 1;
        ((uint32_t*)vth)[o] = pack_hi(v0, v1);
        ((uint32_t*)vtl)[o] = pack_lo(v0, v1);
    }
}

// ---------------------------------------------------------------------------
// Flash attention v2: 128 threads, 4 warps x 32 q-rows (m32 warp tile).
// Both branches in one launch (grid.y [0,64) = branch1, [64,128) = branch2).
// smem: Q 36864 | KVbuf0 36864 | KVbuf1 36864 = 110592.
// ---------------------------------------------------------------------------
struct FlashB {
    const __nv_bfloat16 *kph, *kpl, *vth, *vtl;
    int Nk, hoff, coloff;
};

__global__ __launch_bounds__(128, 2) void flash2_kernel(
    const __nv_bfloat16* __restrict__ qph, const __nv_bfloat16* __restrict__ qpl,
    __nv_bfloat16* __restrict__ xh, __nv_bfloat16* __restrict__ xl,
    FlashB P0, FlashB P1)
{
    extern __shared__ char smc[];
    const uint32_t sb = smem_u32(smc);
    const uint32_t QH = sb, QL = sb + 18432;

    const int tid  = threadIdx.x;
    const int wid  = tid >> 5;
    const int lane = tid & 31;
    const int y = blockIdx.y;
    const FlashB P = (y < 64) ? P0 : P1;
    const int yl = y & 63;
    const int b = yl >> 2;
    const int h = yl & 3;
    const int q0 = blockIdx.x << 7;

    // ---- Q tile load (128 x 64, hi+lo) ----
    {
        const size_t qbase = ((size_t)(b * Qn + q0)) * 512 + (size_t)(P.hoff + h) * 64;
#pragma unroll
        for (int it = 0; it < 16; it++) {
            int i = tid + (it << 7);
            int row = i >> 4;
            int c4 = (i & 15) << 2;
            uint32_t dst = (uint32_t)row * 144 + (uint32_t)(c4 << 1);
            CP_ASYNC8(QH + dst, qph + qbase + (size_t)row * 512 + c4);
            CP_ASYNC8(QL + dst, qpl + qbase + (size_t)row * 512 + c4);
        }
        CP_COMMIT();
    }

    auto issue_kv = [&](int buf, int kv0) {
        const uint32_t bb = sb + 36864 + (uint32_t)buf * 36864;
#pragma unroll
        for (int it = 0; it < 8; it++) {
            int i = tid + (it << 7);
            int row = i >> 4;
            int c4 = (i & 15) << 2;
            uint32_t dst = (uint32_t)row * 144 + (uint32_t)(c4 << 1);
            size_t kidx = ((size_t)(b * P.Nk + kv0 + row)) * 256 + h * 64 + c4;
            CP_ASYNC8(bb + dst,         P.kph + kidx);
            CP_ASYNC8(bb + 9216 + dst,  P.kpl + kidx);
            size_t vidx = ((size_t)(b * 256 + h * 64 + row)) * P.Nk + kv0 + c4;
            CP_ASYNC8(bb + 18432 + dst, P.vth + vidx);
            CP_ASYNC8(bb + 27648 + dst, P.vtl + vidx);
        }
    };

    const uint32_t lrow = (uint32_t)(lane & 15);
    const uint32_t lkq  = (uint32_t)(lane >> 4) * 16;
    uint32_t qOff[2];
    qOff[0] = ((uint32_t)(wid * 32) + lrow) * 144 + lkq;
    qOff[1] = qOff[0] + 16 * 144;
    const uint32_t kOff = lrow * 144 + lkq;
    const int gr = lane >> 2;

    float m[2][2], l[2][2];
#pragma unroll
    for (int i = 0; i < 2; i++) { m[i][0] = -1e30f; m[i][1] = -1e30f; l[i][0] = 0.f; l[i][1] = 0.f; }
    float Oacc[2][8][4];
#pragma unroll
    for (int i = 0; i < 2; i++)
#pragma unroll
        for (int j = 0; j < 8; j++)
#pragma unroll
            for (int q = 0; q < 4; q++) Oacc[i][j][q] = 0.f;

    const int ntiles = P.Nk >> 6;
    issue_kv(0, 0);
    CP_COMMIT();

    for (int t = 0; t < ntiles; t++) {
        const bool more = (t + 1) < ntiles;
        if (more) {
            issue_kv((t + 1) & 1, (t + 1) << 6);
            CP_COMMIT();
            CP_WAIT1();
        } else {
            CP_WAIT0();
        }
        __syncthreads();

        const uint32_t bb = sb + 36864 + (uint32_t)(t & 1) * 36864;
        const uint32_t KH = bb, KL = bb + 9216, VH = bb + 18432, VL = bb + 27648;

        // ---- S = Q K^T ----
        float S[2][8][4];
#pragma unroll
        for (int i = 0; i < 2; i++)
#pragma unroll
            for (int j = 0; j < 8; j++)
#pragma unroll
                for (int q = 0; q < 4; q++) S[i][j][q] = 0.f;

#pragma unroll
        for (int ks = 0; ks < 4; ks++) {
            const uint32_t ko = (uint32_t)ks * 32;
            uint32_t qh4[2][4], ql4[2][4];
#pragma unroll
            for (int mt = 0; mt < 2; mt++) {
                ldsm_x4(qh4[mt][0], qh4[mt][1], qh4[mt][2], qh4[mt][3], QH + qOff[mt] + ko);
                ldsm_x4(ql4[mt][0], ql4[mt][1], ql4[mt][2], ql4[mt][3], QL + qOff[mt] + ko);
            }
#pragma unroll
            for (int g = 0; g < 4; g++) {
                uint32_t kh4[4], kl4[4];
                ldsm_x4(kh4[0], kh4[1], kh4[2], kh4[3], KH + (uint32_t)g * 2304 + kOff + ko);
                ldsm_x4(kl4[0], kl4[1], kl4[2], kl4[3], KL + (uint32_t)g * 2304 + kOff + ko);
#pragma unroll
                for (int mt = 0; mt < 2; mt++) {
                    mma_bf16(S[mt][2 * g + 0], qh4[mt][0], qh4[mt][1], qh4[mt][2], qh4[mt][3], kh4[0], kh4[2]);
                    mma_bf16(S[mt][2 * g + 1], qh4[mt][0], qh4[mt][1], qh4[mt][2], qh4[mt][3], kh4[1], kh4[3]);
                    mma_bf16(S[mt][2 * g + 0], qh4[mt][0], qh4[mt][1], qh4[mt][2], qh4[mt][3], kl4[0], kl4[2]);
                    mma_bf16(S[mt][2 * g + 1], qh4[mt][0], qh4[mt][1], qh4[mt][2], qh4[mt][3], kl4[1], kl4[3]);
                    mma_bf16(S[mt][2 * g + 0], ql4[mt][0], ql4[mt][1], ql4[mt][2], ql4[mt][3], kh4[0], kh4[2]);
                    mma_bf16(S[mt][2 * g + 1], ql4[mt][0], ql4[mt][1], ql4[mt][2], ql4[mt][3], kh4[1], kh4[3]);
                }
            }
        }

        // ---- online softmax per m-tile ----
        const float sc = 0.125f;
#pragma unroll
        for (int mt = 0; mt < 2; mt++) {
            float mx0 = m[mt][0], mx1 = m[mt][1];
#pragma unroll
            for (int j = 0; j < 8; j++) {
                S[mt][j][0] *= sc; S[mt][j][1] *= sc; S[mt][j][2] *= sc; S[mt][j][3] *= sc;
                mx0 = fmaxf(mx0, fmaxf(S[mt][j][0], S[mt][j][1]));
                mx1 = fmaxf(mx1, fmaxf(S[mt][j][2], S[mt][j][3]));
            }
#pragma unroll
            for (int o = 1; o <= 2; o <<= 1) {
                mx0 = fmaxf(mx0, __shfl_xor_sync(0xffffffffu, mx0, o));
                mx1 = fmaxf(mx1, __shfl_xor_sync(0xffffffffu, mx1, o));
            }
            const float alpha0 = __expf(m[mt][0] - mx0);
            const float alpha1 = __expf(m[mt][1] - mx1);
            m[mt][0] = mx0; m[mt][1] = mx1;

            float rs0 = 0.f, rs1 = 0.f;
#pragma unroll
            for (int j = 0; j < 8; j++) {
                S[mt][j][0] = __expf(S[mt][j][0] - mx0);
                S[mt][j][1] = __expf(S[mt][j][1] - mx0);
                S[mt][j][2] = __expf(S[mt][j][2] - mx1);
                S[mt][j][3] = __expf(S[mt][j][3] - mx1);
                rs0 += S[mt][j][0] + S[mt][j][1];
                rs1 += S[mt][j][2] + S[mt][j][3];
            }
#pragma unroll
            for (int o = 1; o <= 2; o <<= 1) {
                rs0 += __shfl_xor_sync(0xffffffffu, rs0, o);
                rs1 += __shfl_xor_sync(0xffffffffu, rs1, o);
            }
            l[mt][0] = l[mt][0] * alpha0 + rs0;
            l[mt][1] = l[mt][1] * alpha1 + rs1;

#pragma unroll
            for (int j = 0; j < 8; j++) {
                Oacc[mt][j][0] *= alpha0; Oacc[mt][j][1] *= alpha0;
                Oacc[mt][j][2] *= alpha1; Oacc[mt][j][3] *= alpha1;
            }
        }

        // ---- O += P V ;  V fragments shared across both m-tiles ----
#pragma unroll
        for (int t16 = 0; t16 < 4; t16++) {
            uint32_t ph[2][4], pl[2][4];
#pragma unroll
            for (int mt = 0; mt < 2; mt++) {
                ph[mt][0] = pack_hi(S[mt][2 * t16][0],     S[mt][2 * t16][1]);
                ph[mt][1] = pack_hi(S[mt][2 * t16][2],     S[mt][2 * t16][3]);
                ph[mt][2] = pack_hi(S[mt][2 * t16 + 1][0], S[mt][2 * t16 + 1][1]);
                ph[mt][3] = pack_hi(S[mt][2 * t16 + 1][2], S[mt][2 * t16 + 1][3]);
                pl[mt][0] = pack_lo(S[mt][2 * t16][0],     S[mt][2 * t16][1]);
                pl[mt][1] = pack_lo(S[mt][2 * t16][2],     S[mt][2 * t16][3]);
                pl[mt][2] = pack_lo(S[mt][2 * t16 + 1][0], S[mt][2 * t16 + 1][1]);
                pl[mt][3] = pack_lo(S[mt][2 * t16 + 1][2], S[mt][2 * t16 + 1][3]);
            }
            const uint32_t ko = (uint32_t)t16 * 32;
#pragma unroll
            for (int g = 0; g < 4; g++) {
                uint32_t vh[4], vl[4];
                ldsm_x4(vh[0], vh[1], vh[2], vh[3], VH + (uint32_t)g * 2304 + kOff + ko);
                ldsm_x4(vl[0], vl[1], vl[2], vl[3], VL + (uint32_t)g * 2304 + kOff + ko);
#pragma unroll
                for (int mt = 0; mt < 2; mt++) {
                    mma_bf16(Oacc[mt][2 * g + 0], ph[mt][0], ph[mt][1], ph[mt][2], ph[mt][3], vh[0], vh[2]);
                    mma_bf16(Oacc[mt][2 * g + 1], ph[mt][0], ph[mt][1], ph[mt][2], ph[mt][3], vh[1], vh[3]);
                    mma_bf16(Oacc[mt][2 * g + 0], pl[mt][0], pl[mt][1], pl[mt][2], pl[mt][3], vh[0], vh[2]);
                    mma_bf16(Oacc[mt][2 * g + 1], pl[mt][0], pl[mt][1], pl[mt][2], pl[mt][3], vh[1], vh[3]);
                    mma_bf16(Oacc[mt][2 * g + 0], ph[mt][0], ph[mt][1], ph[mt][2], ph[mt][3], vl[0], vl[2]);
                    mma_bf16(Oacc[mt][2 * g + 1], ph[mt][0], ph[mt][1], ph[mt][2], ph[mt][3], vl[1], vl[3]);
                }
            }
        }
        __syncthreads();
    }

    // ---- epilogue ----
    const int gc = (lane & 3) * 2;
#pragma unroll
    for (int mt = 0; mt < 2; mt++) {
        const float inv0 = 1.f / l[mt][0];
        const float inv1 = 1.f / l[mt][1];
        const int row0 = b * Qn + q0 + wid * 32 + mt * 16 + gr;
#pragma unroll
        for (int j = 0; j < 8; j++) {
            const int col = P.coloff + h * 64 + (j >> 1) * 16 + (j & 1) * 8 + gc;
            float o0 = Oacc[mt][j][0] * inv0, o1 = Oacc[mt][j][1] * inv0;
            float o2 = Oacc[mt][j][2] * inv1, o3 = Oacc[mt][j][3] * inv1;
            size_t i0 = ((size_t)row0 * 512 + col) >> 1;
            size_t i1 = ((size_t)(row0 + 8) * 512 + col) >> 1;
            ((uint32_t*)xh)[i0] = pack_hi(o0, o1);
            ((uint32_t*)xl)[i0] = pack_lo(o0, o1);
            ((uint32_t*)xh)[i1] = pack_hi(o2, o3);
            ((uint32_t*)xl)[i1] = pack_lo(o2, o3);
        }
    }
}

// ---------------------------------------------------------------------------
// Host launch sequence
// ---------------------------------------------------------------------------
extern "C" void kernel_launch(void* const* d_in, const int* in_sizes, int n_in,
                              void* d_out, int out_size)
{
    (void)in_sizes; (void)out_size;
    const int s = (n_in >= 24) ? 2 : 0;

    const float* query   = (const float*)d_in[0];
    const float* key     = (const float*)d_in[1];
    const float* value   = (const float*)d_in[2];
    const float* q_w     = (const float*)d_in[3 + s];
    const float* sr1_w   = (const float*)d_in[4 + s];
    const float* sr1_b   = (const float*)d_in[5 + s];
    const float* norm1_w = (const float*)d_in[6 + s];
    const float* norm1_b = (const float*)d_in[7 + s];
    const float* sr2_w   = (const float*)d_in[8 + s];
    const float* sr2_b   = (const float*)d_in[9 + s];
    const float* norm2_w = (const float*)d_in[10 + s];
    const float* norm2_b = (const float*)d_in[11 + s];
    const float* k1_w    = (const float*)d_in[12 + s];
    const float* k2_w    = (const float*)d_in[14 + s];
    const float* v2_w    = (const float*)d_in[15 + s];
    const float* lc1_w   = (const float*)d_in[16 + s];
    const float* lc1_b   = (const float*)d_in[17 + s];
    const float* lc2_w   = (const float*)d_in[18 + s];
    const float* lc2_b   = (const float*)d_in[19 + s];
    const float* proj_w  = (const float*)d_in[20 + s];
    const float* proj_b  = (const float*)d_in[21 + s];
    float* out = (float*)d_out;

    float *kv1n, *kv2n, *kv1, *v2;
    cudaGetSymbolAddress((void**)&kv1n, g_kv1n);
    cudaGetSymbolAddress((void**)&kv2n, g_kv2n);
    cudaGetSymbolAddress((void**)&kv1,  g_kv1);
    cudaGetSymbolAddress((void**)&v2,   g_v2);

    __nv_bfloat16 *qh, *ql, *qph, *qpl, *imgh, *imgl, *kv1nh, *kv1nl, *kv2nh, *kv2nl;
    __nv_bfloat16 *k1ph, *k1pl, *k2ph, *k2pl, *vt1h, *vt1l, *vt2h, *vt2l, *xh, *xl;
    __nv_bfloat16 *qwh, *qwl, *s1wh, *s1wl, *s2wh, *s2wl, *k1wh, *k1wl, *k2wh, *k2wl, *v2wh, *v2wl, *pwh, *pwl;
    cudaGetSymbolAddress((void**)&qh, g_qh);       cudaGetSymbolAddress((void**)&ql, g_ql);
    cudaGetSymbolAddress((void**)&qph, g_qph);     cudaGetSymbolAddress((void**)&qpl, g_qpl);
    cudaGetSymbolAddress((void**)&imgh, g_imgh);   cudaGetSymbolAddress((void**)&imgl, g_imgl);
    cudaGetSymbolAddress((void**)&kv1nh, g_kv1nh); cudaGetSymbolAddress((void**)&kv1nl, g_kv1nl);
    cudaGetSymbolAddress((void**)&kv2nh, g_kv2nh); cudaGetSymbolAddress((void**)&kv2nl, g_kv2nl);
    cudaGetSymbolAddress((void**)&k1ph, g_k1ph);   cudaGetSymbolAddress((void**)&k1pl, g_k1pl);
    cudaGetSymbolAddress((void**)&k2ph, g_k2ph);   cudaGetSymbolAddress((void**)&k2pl, g_k2pl);
    cudaGetSymbolAddress((void**)&vt1h, g_vt1h);   cudaGetSymbolAddress((void**)&vt1l, g_vt1l);
    cudaGetSymbolAddress((void**)&vt2h, g_vt2h);   cudaGetSymbolAddress((void**)&vt2l, g_vt2l);
    cudaGetSymbolAddress((void**)&xh, g_xh);       cudaGetSymbolAddress((void**)&xl, g_xl);
    cudaGetSymbolAddress((void**)&qwh, g_qwh);     cudaGetSymbolAddress((void**)&qwl, g_qwl);
    cudaGetSymbolAddress((void**)&s1wh, g_s1wh);   cudaGetSymbolAddress((void**)&s1wl, g_s1wl);
    cudaGetSymbolAddress((void**)&s2wh, g_s2wh);   cudaGetSymbolAddress((void**)&s2wl, g_s2wl);
    cudaGetSymbolAddress((void**)&k1wh, g_k1wh);   cudaGetSymbolAddress((void**)&k1wl, g_k1wl);
    cudaGetSymbolAddress((void**)&k2wh, g_k2wh);   cudaGetSymbolAddress((void**)&k2wl, g_k2wl);
    cudaGetSymbolAddress((void**)&v2wh, g_v2wh);   cudaGetSymbolAddress((void**)&v2wl, g_v2wl);
    cudaGetSymbolAddress((void**)&pwh, g_pwh);     cudaGetSymbolAddress((void**)&pwl, g_pwl);

    const size_t IMG1 = (size_t)B_ * C_ * 64 * 64;
    float* v1 = kv1 + (size_t)B_ * N1_ * C2_;

    const int SMEM = 81920;
    cudaFuncSetAttribute(hgemm3_kernel<0, 1>, cudaFuncAttributeMaxDynamicSharedMemorySize, SMEM);
    cudaFuncSetAttribute(hgemm3_kernel<0, 2>, cudaFuncAttributeMaxDynamicSharedMemorySize, SMEM);
    cudaFuncSetAttribute(hgemm3_kernel<1, 1>, cudaFuncAttributeMaxDynamicSharedMemorySize, SMEM);
    cudaFuncSetAttribute(hgemm3_kernel<2, 1>, cudaFuncAttributeMaxDynamicSharedMemorySize, SMEM);
    cudaFuncSetAttribute(projgemm3_kernel, cudaFuncAttributeMaxDynamicSharedMemorySize, SMEM);
    const int FSMEM = 110592;
    cudaFuncSetAttribute(flash2_kernel, cudaFuncAttributeMaxDynamicSharedMemorySize, FSMEM);

    dim3 gblk(128);

    // launches ordered so my 4th launch (#6 under ncu -s 5) = sr1 GEMM
    split_kernel<<<4096, 256>>>(sr1_w, s1wh, s1wl);                         // 1
    to_image_split2_kernel<<<8192, 256>>>(key, value, imgh, imgl, IMG1);    // 2
    split_kernel<<<1024, 256>>>(sr2_w, s2wh, s2wl);                         // 3
    hgemm3_kernel<1, 1><<<dim3(4, 64), gblk, SMEM>>>(imgh, imgl, s1wh, s1wl, sr1_b,
                                                     kv1n, nullptr, nullptr, 8192, 512, 8192); // 4 <- profiled

    split_kernel<<<256, 256>>>(q_w, qwh, qwl);
    split_kernel<<<128, 256>>>(k1_w, k1wh, k1wl);
    split_kernel<<<128, 256>>>(k2_w, k2wh, k2wl);
    split_kernel<<<128, 256>>>(v2_w, v2wh, v2wl);
    split_kernel<<<256, 256>>>(proj_w, pwh, pwl);
    split_kernel<<<8192, 256>>>(query, qh, ql);

    hgemm3_kernel<2, 1><<<dim3(4, 256), gblk, SMEM>>>(imgh, imgl, s2wh, s2wl, sr2_b,
                                                      kv2n, nullptr, nullptr, 32768, 512, 2048);

    hgemm3_kernel<0, 2><<<dim3(4, 128), gblk, SMEM>>>(qh, ql, qwh, qwl, nullptr,
                                                      nullptr, qph, qpl, 16384, 512, 512);

    ln_gelu_split_kernel<<<8192,  256>>>(kv1n, norm1_w, norm1_b, kv1nh, kv1nl);
    ln_gelu_split_kernel<<<32768, 256>>>(kv2n, norm2_w, norm2_b, kv2nh, kv2nl);

    {
        ProjParams P;
        P.Ah[0] = kv1nh;  P.Al[0] = kv1nl;  P.Wh[0] = k1wh; P.Wl[0] = k1wl;
        P.Cf[0] = kv1;    P.Ch[0] = k1ph;   P.Cl[0] = k1pl; P.outm[0] = 3;
        P.Ah[1] = kv2nh;  P.Al[1] = kv2nl;  P.Wh[1] = k2wh; P.Wl[1] = k2wl;
        P.Cf[1] = nullptr; P.Ch[1] = k2ph;  P.Cl[1] = k2pl; P.outm[1] = 2;
        P.Ah[2] = kv2nh + (size_t)16384 * 512;
        P.Al[2] = kv2nl + (size_t)16384 * 512;
        P.Wh[2] = v2wh;   P.Wl[2] = v2wl;
        P.Cf[2] = v2;     P.Ch[2] = nullptr; P.Cl[2] = nullptr; P.outm[2] = 1;
        projgemm3_kernel<<<dim3(2, 320), gblk, SMEM>>>(P);
    }

    dwconv_res_t2_kernel<<<B_ * 4 * (N1_ / 64), 256>>>(v1, lc1_w, lc1_b, vt1h, vt1l, 16, 16);
    dwconv_res_t2_kernel<<<B_ * 4 * (N2_ / 64), 256>>>(v2, lc2_w, lc2_b, vt2h, vt2l, 32, 32);

    {
        FlashB P0, P1;
        P0.kph = k1ph; P0.kpl = k1pl; P0.vth = vt1h; P0.vtl = vt1l;
        P0.Nk = N1_; P0.hoff = 0; P0.coloff = 0;
        P1.kph = k2ph; P1.kpl = k2pl; P1.vth = vt2h; P1.vtl = vt2l;
        P1.Nk = N2_; P1.hoff = 4; P1.coloff = 256;
        flash2_kernel<<<dim3(8, 128), gblk, FSMEM>>>(qph, qpl, xh, xl, P0, P1);
    }

    hgemm3_kernel<0, 1><<<dim3(4, 128), gblk, SMEM>>>(xh, xl, pwh, pwl, proj_b,
                                                      out, nullptr, nullptr, 16384, 512, 512);
}

// round 12
// speedup vs baseline: 3.2574x; 1.0079x over previous
#include <cuda_runtime.h>
#include <cuda_bf16.h>
#include <math.h>
#include <stdint.h>

// ---------------------------------------------------------------------------
// Problem constants
// ---------------------------------------------------------------------------
constexpr int B_   = 16;
constexpr int C_   = 512;
constexpr int Qn   = 1024;
constexpr int C2_  = 256;
constexpr int N1_  = 256;
constexpr int N2_  = 1024;

// ---------------------------------------------------------------------------
// Device scratch
// ---------------------------------------------------------------------------
__device__ float g_kv1n [(size_t)2 * B_ * N1_ * C_];
__device__ float g_kv2n [(size_t)2 * B_ * N2_ * C_];
__device__ float g_kv1  [(size_t)2 * B_ * N1_ * C2_];
__device__ float g_v2   [(size_t)B_ * N2_ * C2_];

// bf16 hi/lo planes
__device__ __nv_bfloat16 g_qh   [(size_t)16384 * 512];
__device__ __nv_bfloat16 g_ql   [(size_t)16384 * 512];
__device__ __nv_bfloat16 g_qph  [(size_t)16384 * 512];
__device__ __nv_bfloat16 g_qpl  [(size_t)16384 * 512];
__device__ __nv_bfloat16 g_imgh [(size_t)2 * B_ * C_ * 64 * 64];
__device__ __nv_bfloat16 g_imgl [(size_t)2 * B_ * C_ * 64 * 64];
__device__ __nv_bfloat16 g_kv1nh[(size_t)8192 * 512];
__device__ __nv_bfloat16 g_kv1nl[(size_t)8192 * 512];
__device__ __nv_bfloat16 g_kv2nh[(size_t)32768 * 512];
__device__ __nv_bfloat16 g_kv2nl[(size_t)32768 * 512];
__device__ __nv_bfloat16 g_k1ph [(size_t)8192 * 256];
__device__ __nv_bfloat16 g_k1pl [(size_t)8192 * 256];
__device__ __nv_bfloat16 g_k2ph [(size_t)16384 * 256];
__device__ __nv_bfloat16 g_k2pl [(size_t)16384 * 256];
__device__ __nv_bfloat16 g_vt1h [(size_t)B_ * C2_ * N1_];
__device__ __nv_bfloat16 g_vt1l [(size_t)B_ * C2_ * N1_];
__device__ __nv_bfloat16 g_vt2h [(size_t)B_ * C2_ * N2_];
__device__ __nv_bfloat16 g_vt2l [(size_t)B_ * C2_ * N2_];
__device__ __nv_bfloat16 g_xh   [(size_t)16384 * 512];
__device__ __nv_bfloat16 g_xl   [(size_t)16384 * 512];
// weight planes
__device__ __nv_bfloat16 g_qwh [262144],  g_qwl [262144];
__device__ __nv_bfloat16 g_s1wh[4194304], g_s1wl[4194304];
__device__ __nv_bfloat16 g_s2wh[1048576], g_s2wl[1048576];
__device__ __nv_bfloat16 g_k1wh[131072],  g_k1wl[131072];
__device__ __nv_bfloat16 g_k2wh[131072],  g_k2wl[131072];
__device__ __nv_bfloat16 g_v2wh[131072],  g_v2wl[131072];
__device__ __nv_bfloat16 g_pwh [262144],  g_pwl [262144];

// ---------------------------------------------------------------------------
// helpers
// ---------------------------------------------------------------------------
__device__ __forceinline__ uint32_t smem_u32(const void* p) {
    uint32_t a;
    asm("{ .reg .u64 t; cvta.to.shared.u64 t, %1; cvt.u32.u64 %0, t; }" : "=r"(a) : "l"(p));
    return a;
}
__device__ __forceinline__ void ldsm_x4(uint32_t& r0, uint32_t& r1, uint32_t& r2, uint32_t& r3,
                                        uint32_t addr) {
    asm volatile("ldmatrix.sync.aligned.m8n8.x4.shared.b16 {%0,%1,%2,%3}, [%4];"
                 : "=r"(r0), "=r"(r1), "=r"(r2), "=r"(r3) : "r"(addr));
}
__device__ __forceinline__ void mma_bf16(float* d,
                                         uint32_t a0, uint32_t a1, uint32_t a2, uint32_t a3,
                                         uint32_t b0, uint32_t b1) {
    asm volatile(
        "mma.sync.aligned.m16n8k16.row.col.f32.bf16.bf16.f32 "
        "{%0,%1,%2,%3}, {%4,%5,%6,%7}, {%8,%9}, {%0,%1,%2,%3};"
        : "+f"(d[0]), "+f"(d[1]), "+f"(d[2]), "+f"(d[3])
        : "r"(a0), "r"(a1), "r"(a2), "r"(a3), "r"(b0), "r"(b1));
}
__device__ __forceinline__ uint32_t pack_hi(float x, float y) {
    __nv_bfloat162 p(__float2bfloat16(x), __float2bfloat16(y));
    return *(uint32_t*)&p;
}
__device__ __forceinline__ uint32_t pack_lo(float x, float y) {
    float hx = __bfloat162float(__float2bfloat16(x));
    float hy = __bfloat162float(__float2bfloat16(y));
    __nv_bfloat162 p(__float2bfloat16(x - hx), __float2bfloat16(y - hy));
    return *(uint32_t*)&p;
}

#define CP_ASYNC16(dst, src) \
    asm volatile("cp.async.cg.shared.global [%0], [%1], 16;" :: "r"(dst), "l"(src) : "memory")
#define CP_ASYNC8(dst, src) \
    asm volatile("cp.async.ca.shared.global [%0], [%1], 8;" :: "r"(dst), "l"(src) : "memory")
#define CP_ASYNC4(dst, src) \
    asm volatile("cp.async.ca.shared.global [%0], [%1], 4;" :: "r"(dst), "l"(src) : "memory")
#define CP_COMMIT() asm volatile("cp.async.commit_group;" ::: "memory")
#define CP_WAIT0()  asm volatile("cp.async.wait_group 0;" ::: "memory")
#define CP_WAIT1()  asm volatile("cp.async.wait_group 1;" ::: "memory")

// ---------------------------------------------------------------------------
// generic fp32 -> hi/lo bf16 planes
// ---------------------------------------------------------------------------
__global__ void split_kernel(const float* __restrict__ src,
                             __nv_bfloat16* __restrict__ h,
                             __nv_bfloat16* __restrict__ l)
{
    int i = blockIdx.x * 256 + threadIdx.x;
    float4 v = ((const float4*)src)[i];
    ((uint2*)h)[i] = make_uint2(pack_hi(v.x, v.y), pack_hi(v.z, v.w));
    ((uint2*)l)[i] = make_uint2(pack_lo(v.x, v.y), pack_lo(v.z, v.w));
}

// ---------------------------------------------------------------------------
// (N,B,C) -> raw-reshape image, split into bf16 hi/lo planes (K + V one launch)
// ---------------------------------------------------------------------------
__global__ void to_image_split2_kernel(const float* __restrict__ srcK,
                                       const float* __restrict__ srcV,
                                       __nv_bfloat16* __restrict__ h,
                                       __nv_bfloat16* __restrict__ l,
                                       size_t img1)
{
    __shared__ float sm[16][513];
    const int half = blockIdx.x >> 12;
    const float* src = half ? srcV : srcK;
    const size_t dofs = half ? img1 : 0;
    size_t base = (size_t)(blockIdx.x & 4095) * 8192;
    for (int j = threadIdx.x; j < 8192; j += 256) sm[j >> 9][j & 511] = src[base + j];
    __syncthreads();
    for (int r = threadIdx.x; r < 8192; r += 256) {
        float v = sm[r & 15][r >> 4];
        __nv_bfloat16 hv = __float2bfloat16(v);
        h[dofs + base + r] = hv;
        l[dofs + base + r] = __float2bfloat16(v - __bfloat162float(hv));
    }
}

// ---------------------------------------------------------------------------
// 64x64-warp-tile mainloop body (4 warps).
// PASS-MAJOR MMA order: each accumulator written once per pass
// (RAW reuse distance 32 MMAs instead of 2).
// ---------------------------------------------------------------------------
#define GEMM3_CHUNK_MMA(AhB, AlB, WhB, WlB)                                     \
    _Pragma("unroll")                                                           \
    for (int kh = 0; kh < 2; kh++) {                                            \
        const uint32_t ko = (uint32_t)kh * 32;                                  \
        uint32_t AH[4][4], AL[4][4], BH[4][4], BL[4][4];                        \
        _Pragma("unroll")                                                       \
        for (int mt = 0; mt < 4; mt++) {                                        \
            ldsm_x4(AH[mt][0], AH[mt][1], AH[mt][2], AH[mt][3], (AhB) + aOffs[mt] + ko); \
            ldsm_x4(AL[mt][0], AL[mt][1], AL[mt][2], AL[mt][3], (AlB) + aOffs[mt] + ko); \
        }                                                                       \
        _Pragma("unroll")                                                       \
        for (int nt = 0; nt < 4; nt++) {                                        \
            ldsm_x4(BH[nt][0], BH[nt][1], BH[nt][2], BH[nt][3], (WhB) + bOffs[nt] + ko); \
            ldsm_x4(BL[nt][0], BL[nt][1], BL[nt][2], BL[nt][3], (WlB) + bOffs[nt] + ko); \
        }                                                                       \
        _Pragma("unroll")                                                       \
        for (int mt = 0; mt < 4; mt++)                                          \
        _Pragma("unroll")                                                       \
        for (int nt = 0; nt < 4; nt++) {                                        \
            mma_bf16(acc[mt][2 * nt + 0], AH[mt][0], AH[mt][1], AH[mt][2], AH[mt][3], BH[nt][0], BH[nt][2]); \
            mma_bf16(acc[mt][2 * nt + 1], AH[mt][0], AH[mt][1], AH[mt][2], AH[mt][3], BH[nt][1], BH[nt][3]); \
        }                                                                       \
        _Pragma("unroll")                                                       \
        for (int mt = 0; mt < 4; mt++)                                          \
        _Pragma("unroll")                                                       \
        for (int nt = 0; nt < 4; nt++) {                                        \
            mma_bf16(acc[mt][2 * nt + 0], AH[mt][0], AH[mt][1], AH[mt][2], AH[mt][3], BL[nt][0], BL[nt][2]); \
            mma_bf16(acc[mt][2 * nt + 1], AH[mt][0], AH[mt][1], AH[mt][2], AH[mt][3], BL[nt][1], BL[nt][3]); \
        }                                                                       \
        _Pragma("unroll")                                                       \
        for (int mt = 0; mt < 4; mt++)                                          \
        _Pragma("unroll")                                                       \
        for (int nt = 0; nt < 4; nt++) {                                        \
            mma_bf16(acc[mt][2 * nt + 0], AL[mt][0], AL[mt][1], AL[mt][2], AL[mt][3], BH[nt][0], BH[nt][2]); \
            mma_bf16(acc[mt][2 * nt + 1], AL[mt][0], AL[mt][1], AL[mt][2], AL[mt][3], BH[nt][1], BH[nt][3]); \
        }                                                                       \
    }

// ---------------------------------------------------------------------------
// Split-bf16 HMMA GEMM v3: 128 threads, 4 warps of 64x64, cp.async double buf.
// ---------------------------------------------------------------------------
template <int LOADER, int OUT>
__global__ __launch_bounds__(128, 2) void hgemm3_kernel(
    const __nv_bfloat16* __restrict__ Ah, const __nv_bfloat16* __restrict__ Al,
    const __nv_bfloat16* __restrict__ Wh, const __nv_bfloat16* __restrict__ Wl,
    const float* __restrict__ bias, float* __restrict__ Cmat,
    __nv_bfloat16* __restrict__ Ch, __nv_bfloat16* __restrict__ Cl,
    int M, int N, int K)
{
    extern __shared__ char smc[];
    const uint32_t sb = smem_u32(smc);

    const int tid  = threadIdx.x;
    const int wid  = tid >> 5;
    const int lane = tid & 31;
    const int bm = blockIdx.y << 7;
    const int bn = blockIdx.x << 7;
    const int m0 = (wid & 1) << 6;
    const int n0 = (wid >> 1) << 6;

    int rr[8], kk[8];
#pragma unroll
    for (int j = 0; j < 8; j++) {
        int s = tid + (j << 7);
        rr[j] = s >> 3;
        kk[j] = (s & 7) << 2;
    }
    int rw[4], kw[4];
#pragma unroll
    for (int j = 0; j < 4; j++) {
        int s = tid + (j << 7);
        rw[j] = s >> 2;
        kw[j] = (s & 3) << 3;
    }

    const uint32_t lrow = (uint32_t)(lane & 15);
    const uint32_t lkq  = (uint32_t)(lane >> 4) * 16;
    uint32_t aOffs[4], bOffs[4];
#pragma unroll
    for (int t = 0; t < 4; t++) {
        aOffs[t] = (uint32_t)(m0 + t * 16 + lrow) * 80 + lkq;
        bOffs[t] = (uint32_t)(n0 + t * 16 + lrow) * 80 + lkq;
    }

    float acc[4][8][4];
#pragma unroll
    for (int i = 0; i < 4; i++)
#pragma unroll
        for (int j = 0; j < 8; j++)
#pragma unroll
            for (int l = 0; l < 4; l++) acc[i][j][l] = 0.f;

    auto gaddrA = [&](const __nv_bfloat16* plane, int r, int k) -> const __nv_bfloat16* {
        if (LOADER == 1) {
            int m = bm + r;
            int b = m >> 8, oy = (m >> 4) & 15, ox = m & 15;
            int ic = k >> 4, ky = (k >> 2) & 3;
            return plane + (((size_t)(b * 512 + ic) * 64) + oy * 4 + ky) * 64 + ox * 4;
        } else {
            int m = bm + r;
            int b = m >> 10, oy = (m >> 5) & 31, ox = m & 31;
            int ic = k >> 2;
            return plane + (((size_t)(b * 512 + ic) * 64) + oy * 2) * 64 + ox * 2;
        }
    };

    auto issue_chunk = [&](int buf, int k0) {
        const uint32_t bb = sb + (uint32_t)buf * 40960;
        if (LOADER == 0) {
#pragma unroll
            for (int j = 0; j < 4; j++) {
                const uint32_t off = (uint32_t)rw[j] * 80 + (uint32_t)(kw[j] << 1);
                const int k = k0 + kw[j];
                CP_ASYNC16(bb + off,         Ah + (size_t)(bm + rw[j]) * K + k);
                CP_ASYNC16(bb + 10240 + off, Al + (size_t)(bm + rw[j]) * K + k);
            }
        } else {
#pragma unroll
            for (int j = 0; j < 8; j++) {
                const uint32_t off = (uint32_t)rr[j] * 80 + (uint32_t)(kk[j] << 1);
                const int k = k0 + kk[j];
                const __nv_bfloat16* pah = gaddrA(Ah, rr[j], k);
                const __nv_bfloat16* pal = gaddrA(Al, rr[j], k);
                if (LOADER == 2) {
                    CP_ASYNC4(bb + off,             pah);
                    CP_ASYNC4(bb + off + 4,         pah + 64);
                    CP_ASYNC4(bb + 10240 + off,     pal);
                    CP_ASYNC4(bb + 10240 + off + 4, pal + 64);
                } else {
                    CP_ASYNC8(bb + off,         pah);
                    CP_ASYNC8(bb + 10240 + off, pal);
                }
            }
        }
#pragma unroll
        for (int j = 0; j < 4; j++) {
            const uint32_t off = (uint32_t)rw[j] * 80 + (uint32_t)(kw[j] << 1);
            const int k = k0 + kw[j];
            CP_ASYNC16(bb + 20480 + off, Wh + (size_t)(bn + rw[j]) * K + k);
            CP_ASYNC16(bb + 30720 + off, Wl + (size_t)(bn + rw[j]) * K + k);
        }
    };

    const int nchunks = K >> 5;
    issue_chunk(0, 0);
    CP_COMMIT();

    for (int c = 0; c < nchunks; c++) {
        const bool more = (c + 1) < nchunks;
        if (more) {
            issue_chunk((c + 1) & 1, (c + 1) << 5);
            CP_COMMIT();
            CP_WAIT1();
        } else {
            CP_WAIT0();
        }
        __syncthreads();

        const uint32_t bb = sb + (uint32_t)(c & 1) * 40960;
        const uint32_t AhB = bb, AlB = bb + 10240, WhB = bb + 20480, WlB = bb + 30720;
        GEMM3_CHUNK_MMA(AhB, AlB, WhB, WlB)
        __syncthreads();
    }

    const int gr = lane >> 2;
    const int gc = (lane & 3) * 2;
#pragma unroll
    for (int mt = 0; mt < 4; mt++) {
        const int row0 = bm + m0 + mt * 16 + gr;
#pragma unroll
        for (int nt = 0; nt < 8; nt++) {
            const int col = bn + n0 + nt * 8 + gc;
            float b0 = bias ? bias[col] : 0.f;
            float b1 = bias ? bias[col + 1] : 0.f;
            float o0 = acc[mt][nt][0] + b0, o1 = acc[mt][nt][1] + b1;
            float o2 = acc[mt][nt][2] + b0, o3 = acc[mt][nt][3] + b1;
            if (OUT & 1) {
                *(float2*)(Cmat + (size_t)row0 * N + col) = make_float2(o0, o1);
                *(float2*)(Cmat + (size_t)(row0 + 8) * N + col) = make_float2(o2, o3);
            }
            if (OUT & 2) {
                size_t i0 = ((size_t)row0 * N + col) >> 1;
                size_t i1 = ((size_t)(row0 + 8) * N + col) >> 1;
                ((uint32_t*)Ch)[i0] = pack_hi(o0, o1);
                ((uint32_t*)Cl)[i0] = pack_lo(o0, o1);
                ((uint32_t*)Ch)[i1] = pack_hi(o2, o3);
                ((uint32_t*)Cl)[i1] = pack_lo(o2, o3);
            }
        }
    }
}

// ---------------------------------------------------------------------------
// Merged head-projection GEMM v3 (3 sub-problems, one launch, 128 threads).
// ---------------------------------------------------------------------------
struct ProjParams {
    const __nv_bfloat16 *Ah[3], *Al[3], *Wh[3], *Wl[3];
    float* Cf[3];
    __nv_bfloat16 *Ch[3], *Cl[3];
    int outm[3];
};

__global__ __launch_bounds__(128, 2) void projgemm3_kernel(ProjParams P)
{
    extern __shared__ char smc[];
    const uint32_t sb = smem_u32(smc);
    constexpr int K = 512, N = 256;

    const int y = blockIdx.y;
    const int pi = (y < 64) ? 0 : (y < 192 ? 1 : 2);
    const int ylocal = y - ((pi == 0) ? 0 : (pi == 1) ? 64 : 192);

    const __nv_bfloat16* Ah = P.Ah[pi];
    const __nv_bfloat16* Al = P.Al[pi];
    const __nv_bfloat16* Wh = P.Wh[pi];
    const __nv_bfloat16* Wl = P.Wl[pi];
    float* Cmat = P.Cf[pi];
    __nv_bfloat16* Ch = P.Ch[pi];
    __nv_bfloat16* Cl = P.Cl[pi];
    const int OUT = P.outm[pi];

    const int tid  = threadIdx.x;
    const int wid  = tid >> 5;
    const int lane = tid & 31;
    const int bm = ylocal << 7;
    const int bn = blockIdx.x << 7;
    const int m0 = (wid & 1) << 6;
    const int n0 = (wid >> 1) << 6;

    int rw[4], kw[4];
#pragma unroll
    for (int j = 0; j < 4; j++) {
        int s = tid + (j << 7);
        rw[j] = s >> 2;
        kw[j] = (s & 3) << 3;
    }

    const uint32_t lrow = (uint32_t)(lane & 15);
    const uint32_t lkq  = (uint32_t)(lane >> 4) * 16;
    uint32_t aOffs[4], bOffs[4];
#pragma unroll
    for (int t = 0; t < 4; t++) {
        aOffs[t] = (uint32_t)(m0 + t * 16 + lrow) * 80 + lkq;
        bOffs[t] = (uint32_t)(n0 + t * 16 + lrow) * 80 + lkq;
    }

    float acc[4][8][4];
#pragma unroll
    for (int i = 0; i < 4; i++)
#pragma unroll
        for (int j = 0; j < 8; j++)
#pragma unroll
            for (int l = 0; l < 4; l++) acc[i][j][l] = 0.f;

    auto issue_chunk = [&](int buf, int k0) {
        const uint32_t bb = sb + (uint32_t)buf * 40960;
#pragma unroll
        for (int j = 0; j < 4; j++) {
            const uint32_t off = (uint32_t)rw[j] * 80 + (uint32_t)(kw[j] << 1);
            const int k = k0 + kw[j];
            CP_ASYNC16(bb + off,         Ah + (size_t)(bm + rw[j]) * K + k);
            CP_ASYNC16(bb + 10240 + off, Al + (size_t)(bm + rw[j]) * K + k);
            CP_ASYNC16(bb + 20480 + off, Wh + (size_t)(bn + rw[j]) * K + k);
            CP_ASYNC16(bb + 30720 + off, Wl + (size_t)(bn + rw[j]) * K + k);
        }
    };

    const int nchunks = K >> 5;
    issue_chunk(0, 0);
    CP_COMMIT();

    for (int c = 0; c < nchunks; c++) {
        const bool more = (c + 1) < nchunks;
        if (more) {
            issue_chunk((c + 1) & 1, (c + 1) << 5);
            CP_COMMIT();
            CP_WAIT1();
        } else {
            CP_WAIT0();
        }
        __syncthreads();

        const uint32_t bb = sb + (uint32_t)(c & 1) * 40960;
        const uint32_t AhB = bb, AlB = bb + 10240, WhB = bb + 20480, WlB = bb + 30720;
        GEMM3_CHUNK_MMA(AhB, AlB, WhB, WlB)
        __syncthreads();
    }

    const int gr = lane >> 2;
    const int gc = (lane & 3) * 2;
#pragma unroll
    for (int mt = 0; mt < 4; mt++) {
        const int row0 = bm + m0 + mt * 16 + gr;
#pragma unroll
        for (int nt = 0; nt < 8; nt++) {
            const int col = bn + n0 + nt * 8 + gc;
            float o0 = acc[mt][nt][0], o1 = acc[mt][nt][1];
            float o2 = acc[mt][nt][2], o3 = acc[mt][nt][3];
            if (OUT & 1) {
                *(float2*)(Cmat + (size_t)row0 * N + col) = make_float2(o0, o1);
                *(float2*)(Cmat + (size_t)(row0 + 8) * N + col) = make_float2(o2, o3);
            }
            if (OUT & 2) {
                size_t i0 = ((size_t)row0 * N + col) >> 1;
                size_t i1 = ((size_t)(row0 + 8) * N + col) >> 1;
                ((uint32_t*)Ch)[i0] = pack_hi(o0, o1);
                ((uint32_t*)Cl)[i0] = pack_lo(o0, o1);
                ((uint32_t*)Ch)[i1] = pack_hi(o2, o3);
                ((uint32_t*)Cl)[i1] = pack_lo(o2, o3);
            }
        }
    }
}

// ---------------------------------------------------------------------------
// LayerNorm(512) + exact GELU -> bf16 hi/lo planes
// ---------------------------------------------------------------------------
__global__ void ln_gelu_split_kernel(const float* __restrict__ x,
                                     const float* __restrict__ w,
                                     const float* __restrict__ b,
                                     __nv_bfloat16* __restrict__ hO,
                                     __nv_bfloat16* __restrict__ lO)
{
    __shared__ float sh[8];
    const float* row = x + (size_t)blockIdx.x * 512;
    int t = threadIdx.x;
    float2 v = *(const float2*)(row + t * 2);

    float s = v.x + v.y;
#pragma unroll
    for (int o = 16; o; o >>= 1) s += __shfl_xor_sync(0xffffffffu, s, o);
    if ((t & 31) == 0) sh[t >> 5] = s;
    __syncthreads();
    float tot = 0.f;
#pragma unroll
    for (int i = 0; i < 8; i++) tot += sh[i];
    float mu = tot * (1.f / 512.f);
    float d0 = v.x - mu, d1 = v.y - mu;
    __syncthreads();

    float ss = d0 * d0 + d1 * d1;
#pragma unroll
    for (int o = 16; o; o >>= 1) ss += __shfl_xor_sync(0xffffffffu, ss, o);
    if ((t & 31) == 0) sh[t >> 5] = ss;
    __syncthreads();
    float tot2 = 0.f;
#pragma unroll
    for (int i = 0; i < 8; i++) tot2 += sh[i];
    float inv = rsqrtf(tot2 * (1.f / 512.f) + 1e-5f);

    float y0 = d0 * inv * w[t * 2]     + b[t * 2];
    float y1 = d1 * inv * w[t * 2 + 1] + b[t * 2 + 1];
    y0 = 0.5f * y0 * (1.f + erff(y0 * 0.7071067811865476f));
    y1 = 0.5f * y1 * (1.f + erff(y1 * 0.7071067811865476f));

    size_t o = (size_t)blockIdx.x * 256 + t;
    ((uint32_t*)hO)[o] = pack_hi(y0, y1);
    ((uint32_t*)lO)[o] = pack_lo(y0, y1);
}

// ---------------------------------------------------------------------------
// Depthwise 3x3 (pad 1) residual -> transposed planes, coalesced via smem tile.
// ---------------------------------------------------------------------------
__global__ void dwconv_res_t2_kernel(const float* __restrict__ v,
                                     const float* __restrict__ lw,
                                     const float* __restrict__ lb,
                                     __nv_bfloat16* __restrict__ vth,
                                     __nv_bfloat16* __restrict__ vtl,
                                     int hh, int ww)
{
    __shared__ float sm[64][65];
    const int Nn = hh * ww;
    const int nt = Nn >> 6;
    int bz = blockIdx.x;
    const int ntile = bz % nt; bz /= nt;
    const int ct = bz & 3;
    const int bb = bz >> 2;
    const int c0 = ct << 6, n0 = ntile << 6;

    const int tid = threadIdx.x;
    const int tc = tid & 63;
    const int tn0 = tid >> 6;
    const int c = c0 + tc;

    float wreg[9];
#pragma unroll
    for (int i = 0; i < 9; i++) wreg[i] = lw[c * 9 + i];
    const float bias = lb[c];

    for (int nn = tn0; nn < 64; nn += 4) {
        const int n = n0 + nn;
        const int y = n / ww;
        const int x = n - y * ww;
        float acc = bias;
#pragma unroll
        for (int dy = -1; dy <= 1; dy++) {
            int yy = y + dy;
            if (yy < 0 || yy >= hh) continue;
#pragma unroll
            for (int dx = -1; dx <= 1; dx++) {
                int xx = x + dx;
                if (xx < 0 || xx >= ww) continue;
                acc += v[((size_t)(bb * Nn + yy * ww + xx) << 8) + c] * wreg[(dy + 1) * 3 + (dx + 1)];
            }
        }
        sm[nn][tc] = v[((size_t)(bb * Nn + n) << 8) + c] + acc;
    }
    __syncthreads();

    const int wc = tid >> 5;
    const int wn = (tid & 31) << 1;
    for (int cc = wc; cc < 64; cc += 8) {
        float v0 = sm[wn][cc], v1 = sm[wn + 1][cc];
        size_t o = (((size_t)(bb * 256 + c0 + cc)) * Nn + n0 + wn) >> 1;
        ((uint32_t*)vth)[o] = pack_hi(v0, v1);
        ((uint32_t*)vtl)[o] = pack_lo(v0, v1);
    }
}

// ---------------------------------------------------------------------------
// Flash attention v2: 128 threads, 4 warps x 32 q-rows.
// Pass-major MMA ordering inside each (ks,g)/(t16,g) block (RAW distance 4).
// ---------------------------------------------------------------------------
struct FlashB {
    const __nv_bfloat16 *kph, *kpl, *vth, *vtl;
    int Nk, hoff, coloff;
};

__global__ __launch_bounds__(128, 2) void flash2_kernel(
    const __nv_bfloat16* __restrict__ qph, const __nv_bfloat16* __restrict__ qpl,
    __nv_bfloat16* __restrict__ xh, __nv_bfloat16* __restrict__ xl,
    FlashB P0, FlashB P1)
{
    extern __shared__ char smc[];
    const uint32_t sb = smem_u32(smc);
    const uint32_t QH = sb, QL = sb + 18432;

    const int tid  = threadIdx.x;
    const int wid  = tid >> 5;
    const int lane = tid & 31;
    const int y = blockIdx.y;
    const FlashB P = (y < 64) ? P0 : P1;
    const int yl = y & 63;
    const int b = yl >> 2;
    const int h = yl & 3;
    const int q0 = blockIdx.x << 7;

    {
        const size_t qbase = ((size_t)(b * Qn + q0)) * 512 + (size_t)(P.hoff + h) * 64;
#pragma unroll
        for (int it = 0; it < 16; it++) {
            int i = tid + (it << 7);
            int row = i >> 4;
            int c4 = (i & 15) << 2;
            uint32_t dst = (uint32_t)row * 144 + (uint32_t)(c4 << 1);
            CP_ASYNC8(QH + dst, qph + qbase + (size_t)row * 512 + c4);
            CP_ASYNC8(QL + dst, qpl + qbase + (size_t)row * 512 + c4);
        }
        CP_COMMIT();
    }

    auto issue_kv = [&](int buf, int kv0) {
        const uint32_t bb = sb + 36864 + (uint32_t)buf * 36864;
#pragma unroll
        for (int it = 0; it < 8; it++) {
            int i = tid + (it << 7);
            int row = i >> 4;
            int c4 = (i & 15) << 2;
            uint32_t dst = (uint32_t)row * 144 + (uint32_t)(c4 << 1);
            size_t kidx = ((size_t)(b * P.Nk + kv0 + row)) * 256 + h * 64 + c4;
            CP_ASYNC8(bb + dst,         P.kph + kidx);
            CP_ASYNC8(bb + 9216 + dst,  P.kpl + kidx);
            size_t vidx = ((size_t)(b * 256 + h * 64 + row)) * P.Nk + kv0 + c4;
            CP_ASYNC8(bb + 18432 + dst, P.vth + vidx);
            CP_ASYNC8(bb + 27648 + dst, P.vtl + vidx);
        }
    };

    const uint32_t lrow = (uint32_t)(lane & 15);
    const uint32_t lkq  = (uint32_t)(lane >> 4) * 16;
    uint32_t qOff[2];
    qOff[0] = ((uint32_t)(wid * 32) + lrow) * 144 + lkq;
    qOff[1] = qOff[0] + 16 * 144;
    const uint32_t kOff = lrow * 144 + lkq;
    const int gr = lane >> 2;

    float m[2][2], l[2][2];
#pragma unroll
    for (int i = 0; i < 2; i++) { m[i][0] = -1e30f; m[i][1] = -1e30f; l[i][0] = 0.f; l[i][1] = 0.f; }
    float Oacc[2][8][4];
#pragma unroll
    for (int i = 0; i < 2; i++)
#pragma unroll
        for (int j = 0; j < 8; j++)
#pragma unroll
            for (int q = 0; q < 4; q++) Oacc[i][j][q] = 0.f;

    const int ntiles = P.Nk >> 6;
    issue_kv(0, 0);
    CP_COMMIT();

    for (int t = 0; t < ntiles; t++) {
        const bool more = (t + 1) < ntiles;
        if (more) {
            issue_kv((t + 1) & 1, (t + 1) << 6);
            CP_COMMIT();
            CP_WAIT1();
        } else {
            CP_WAIT0();
        }
        __syncthreads();

        const uint32_t bb = sb + 36864 + (uint32_t)(t & 1) * 36864;
        const uint32_t KH = bb, KL = bb + 9216, VH = bb + 18432, VL = bb + 27648;

        float S[2][8][4];
#pragma unroll
        for (int i = 0; i < 2; i++)
#pragma unroll
            for (int j = 0; j < 8; j++)
#pragma unroll
                for (int q = 0; q < 4; q++) S[i][j][q] = 0.f;

#pragma unroll
        for (int ks = 0; ks < 4; ks++) {
            const uint32_t ko = (uint32_t)ks * 32;
            uint32_t qh4[2][4], ql4[2][4];
#pragma unroll
            for (int mt = 0; mt < 2; mt++) {
                ldsm_x4(qh4[mt][0], qh4[mt][1], qh4[mt][2], qh4[mt][3], QH + qOff[mt] + ko);
                ldsm_x4(ql4[mt][0], ql4[mt][1], ql4[mt][2], ql4[mt][3], QL + qOff[mt] + ko);
            }
#pragma unroll
            for (int g = 0; g < 4; g++) {
                uint32_t kh4[4], kl4[4];
                ldsm_x4(kh4[0], kh4[1], kh4[2], kh4[3], KH + (uint32_t)g * 2304 + kOff + ko);
                ldsm_x4(kl4[0], kl4[1], kl4[2], kl4[3], KL + (uint32_t)g * 2304 + kOff + ko);
                // pass-major: hh (both mt), then hl, then lh
#pragma unroll
                for (int mt = 0; mt < 2; mt++) {
                    mma_bf16(S[mt][2 * g + 0], qh4[mt][0], qh4[mt][1], qh4[mt][2], qh4[mt][3], kh4[0], kh4[2]);
                    mma_bf16(S[mt][2 * g + 1], qh4[mt][0], qh4[mt][1], qh4[mt][2], qh4[mt][3], kh4[1], kh4[3]);
                }
#pragma unroll
                for (int mt = 0; mt < 2; mt++) {
                    mma_bf16(S[mt][2 * g + 0], qh4[mt][0], qh4[mt][1], qh4[mt][2], qh4[mt][3], kl4[0], kl4[2]);
                    mma_bf16(S[mt][2 * g + 1], qh4[mt][0], qh4[mt][1], qh4[mt][2], qh4[mt][3], kl4[1], kl4[3]);
                }
#pragma unroll
                for (int mt = 0; mt < 2; mt++) {
                    mma_bf16(S[mt][2 * g + 0], ql4[mt][0], ql4[mt][1], ql4[mt][2], ql4[mt][3], kh4[0], kh4[2]);
                    mma_bf16(S[mt][2 * g + 1], ql4[mt][0], ql4[mt][1], ql4[mt][2], ql4[mt][3], kh4[1], kh4[3]);
                }
            }
        }

        const float sc = 0.125f;
#pragma unroll
        for (int mt = 0; mt < 2; mt++) {
            float mx0 = m[mt][0], mx1 = m[mt][1];
#pragma unroll
            for (int j = 0; j < 8; j++) {
                S[mt][j][0] *= sc; S[mt][j][1] *= sc; S[mt][j][2] *= sc; S[mt][j][3] *= sc;
                mx0 = fmaxf(mx0, fmaxf(S[mt][j][0], S[mt][j][1]));
                mx1 = fmaxf(mx1, fmaxf(S[mt][j][2], S[mt][j][3]));
            }
#pragma unroll
            for (int o = 1; o <= 2; o <<= 1) {
                mx0 = fmaxf(mx0, __shfl_xor_sync(0xffffffffu, mx0, o));
                mx1 = fmaxf(mx1, __shfl_xor_sync(0xffffffffu, mx1, o));
            }
            const float alpha0 = __expf(m[mt][0] - mx0);
            const float alpha1 = __expf(m[mt][1] - mx1);
            m[mt][0] = mx0; m[mt][1] = mx1;

            float rs0 = 0.f, rs1 = 0.f;
#pragma unroll
            for (int j = 0; j < 8; j++) {
                S[mt][j][0] = __expf(S[mt][j][0] - mx0);
                S[mt][j][1] = __expf(S[mt][j][1] - mx0);
                S[mt][j][2] = __expf(S[mt][j][2] - mx1);
                S[mt][j][3] = __expf(S[mt][j][3] - mx1);
                rs0 += S[mt][j][0] + S[mt][j][1];
                rs1 += S[mt][j][2] + S[mt][j][3];
            }
#pragma unroll
            for (int o = 1; o <= 2; o <<= 1) {
                rs0 += __shfl_xor_sync(0xffffffffu, rs0, o);
                rs1 += __shfl_xor_sync(0xffffffffu, rs1, o);
            }
            l[mt][0] = l[mt][0] * alpha0 + rs0;
            l[mt][1] = l[mt][1] * alpha1 + rs1;

#pragma unroll
            for (int j = 0; j < 8; j++) {
                Oacc[mt][j][0] *= alpha0; Oacc[mt][j][1] *= alpha0;
                Oacc[mt][j][2] *= alpha1; Oacc[mt][j][3] *= alpha1;
            }
        }

#pragma unroll
        for (int t16 = 0; t16 < 4; t16++) {
            uint32_t ph[2][4], pl[2][4];
#pragma unroll
            for (int mt = 0; mt < 2; mt++) {
                ph[mt][0] = pack_hi(S[mt][2 * t16][0],     S[mt][2 * t16][1]);
                ph[mt][1] = pack_hi(S[mt][2 * t16][2],     S[mt][2 * t16][3]);
                ph[mt][2] = pack_hi(S[mt][2 * t16 + 1][0], S[mt][2 * t16 + 1][1]);
                ph[mt][3] = pack_hi(S[mt][2 * t16 + 1][2], S[mt][2 * t16 + 1][3]);
                pl[mt][0] = pack_lo(S[mt][2 * t16][0],     S[mt][2 * t16][1]);
                pl[mt][1] = pack_lo(S[mt][2 * t16][2],     S[mt][2 * t16][3]);
                pl[mt][2] = pack_lo(S[mt][2 * t16 + 1][0], S[mt][2 * t16 + 1][1]);
                pl[mt][3] = pack_lo(S[mt][2 * t16 + 1][2], S[mt][2 * t16 + 1][3]);
            }
            const uint32_t ko = (uint32_t)t16 * 32;
#pragma unroll
            for (int g = 0; g < 4; g++) {
                uint32_t vh[4], vl[4];
                ldsm_x4(vh[0], vh[1], vh[2], vh[3], VH + (uint32_t)g * 2304 + kOff + ko);
                ldsm_x4(vl[0], vl[1], vl[2], vl[3], VL + (uint32_t)g * 2304 + kOff + ko);
                // pass-major
#pragma unroll
                for (int mt = 0; mt < 2; mt++) {
                    mma_bf16(Oacc[mt][2 * g + 0], ph[mt][0], ph[mt][1], ph[mt][2], ph[mt][3], vh[0], vh[2]);
                    mma_bf16(Oacc[mt][2 * g + 1], ph[mt][0], ph[mt][1], ph[mt][2], ph[mt][3], vh[1], vh[3]);
                }
#pragma unroll
                for (int mt = 0; mt < 2; mt++) {
                    mma_bf16(Oacc[mt][2 * g + 0], pl[mt][0], pl[mt][1], pl[mt][2], pl[mt][3], vh[0], vh[2]);
                    mma_bf16(Oacc[mt][2 * g + 1], pl[mt][0], pl[mt][1], pl[mt][2], pl[mt][3], vh[1], vh[3]);
                }
#pragma unroll
                for (int mt = 0; mt < 2; mt++) {
                    mma_bf16(Oacc[mt][2 * g + 0], ph[mt][0], ph[mt][1], ph[mt][2], ph[mt][3], vl[0], vl[2]);
                    mma_bf16(Oacc[mt][2 * g + 1], ph[mt][0], ph[mt][1], ph[mt][2], ph[mt][3], vl[1], vl[3]);
                }
            }
        }
        __syncthreads();
    }

    const int gc = (lane & 3) * 2;
#pragma unroll
    for (int mt = 0; mt < 2; mt++) {
        const float inv0 = 1.f / l[mt][0];
        const float inv1 = 1.f / l[mt][1];
        const int row0 = b * Qn + q0 + wid * 32 + mt * 16 + gr;
#pragma unroll
        for (int j = 0; j < 8; j++) {
            const int col = P.coloff + h * 64 + (j >> 1) * 16 + (j & 1) * 8 + gc;
            float o0 = Oacc[mt][j][0] * inv0, o1 = Oacc[mt][j][1] * inv0;
            float o2 = Oacc[mt][j][2] * inv1, o3 = Oacc[mt][j][3] * inv1;
            size_t i0 = ((size_t)row0 * 512 + col) >> 1;
            size_t i1 = ((size_t)(row0 + 8) * 512 + col) >> 1;
            ((uint32_t*)xh)[i0] = pack_hi(o0, o1);
            ((uint32_t*)xl)[i0] = pack_lo(o0, o1);
            ((uint32_t*)xh)[i1] = pack_hi(o2, o3);
            ((uint32_t*)xl)[i1] = pack_lo(o2, o3);
        }
    }
}

// ---------------------------------------------------------------------------
// Host launch sequence
// ---------------------------------------------------------------------------
extern "C" void kernel_launch(void* const* d_in, const int* in_sizes, int n_in,
                              void* d_out, int out_size)
{
    (void)in_sizes; (void)out_size;
    const int s = (n_in >= 24) ? 2 : 0;

    const float* query   = (const float*)d_in[0];
    const float* key     = (const float*)d_in[1];
    const float* value   = (const float*)d_in[2];
    const float* q_w     = (const float*)d_in[3 + s];
    const float* sr1_w   = (const float*)d_in[4 + s];
    const float* sr1_b   = (const float*)d_in[5 + s];
    const float* norm1_w = (const float*)d_in[6 + s];
    const float* norm1_b = (const float*)d_in[7 + s];
    const float* sr2_w   = (const float*)d_in[8 + s];
    const float* sr2_b   = (const float*)d_in[9 + s];
    const float* norm2_w = (const float*)d_in[10 + s];
    const float* norm2_b = (const float*)d_in[11 + s];
    const float* k1_w    = (const float*)d_in[12 + s];
    const float* k2_w    = (const float*)d_in[14 + s];
    const float* v2_w    = (const float*)d_in[15 + s];
    const float* lc1_w   = (const float*)d_in[16 + s];
    const float* lc1_b   = (const float*)d_in[17 + s];
    const float* lc2_w   = (const float*)d_in[18 + s];
    const float* lc2_b   = (const float*)d_in[19 + s];
    const float* proj_w  = (const float*)d_in[20 + s];
    const float* proj_b  = (const float*)d_in[21 + s];
    float* out = (float*)d_out;

    float *kv1n, *kv2n, *kv1, *v2;
    cudaGetSymbolAddress((void**)&kv1n, g_kv1n);
    cudaGetSymbolAddress((void**)&kv2n, g_kv2n);
    cudaGetSymbolAddress((void**)&kv1,  g_kv1);
    cudaGetSymbolAddress((void**)&v2,   g_v2);

    __nv_bfloat16 *qh, *ql, *qph, *qpl, *imgh, *imgl, *kv1nh, *kv1nl, *kv2nh, *kv2nl;
    __nv_bfloat16 *k1ph, *k1pl, *k2ph, *k2pl, *vt1h, *vt1l, *vt2h, *vt2l, *xh, *xl;
    __nv_bfloat16 *qwh, *qwl, *s1wh, *s1wl, *s2wh, *s2wl, *k1wh, *k1wl, *k2wh, *k2wl, *v2wh, *v2wl, *pwh, *pwl;
    cudaGetSymbolAddress((void**)&qh, g_qh);       cudaGetSymbolAddress((void**)&ql, g_ql);
    cudaGetSymbolAddress((void**)&qph, g_qph);     cudaGetSymbolAddress((void**)&qpl, g_qpl);
    cudaGetSymbolAddress((void**)&imgh, g_imgh);   cudaGetSymbolAddress((void**)&imgl, g_imgl);
    cudaGetSymbolAddress((void**)&kv1nh, g_kv1nh); cudaGetSymbolAddress((void**)&kv1nl, g_kv1nl);
    cudaGetSymbolAddress((void**)&kv2nh, g_kv2nh); cudaGetSymbolAddress((void**)&kv2nl, g_kv2nl);
    cudaGetSymbolAddress((void**)&k1ph, g_k1ph);   cudaGetSymbolAddress((void**)&k1pl, g_k1pl);
    cudaGetSymbolAddress((void**)&k2ph, g_k2ph);   cudaGetSymbolAddress((void**)&k2pl, g_k2pl);
    cudaGetSymbolAddress((void**)&vt1h, g_vt1h);   cudaGetSymbolAddress((void**)&vt1l, g_vt1l);
    cudaGetSymbolAddress((void**)&vt2h, g_vt2h);   cudaGetSymbolAddress((void**)&vt2l, g_vt2l);
    cudaGetSymbolAddress((void**)&xh, g_xh);       cudaGetSymbolAddress((void**)&xl, g_xl);
    cudaGetSymbolAddress((void**)&qwh, g_qwh);     cudaGetSymbolAddress((void**)&qwl, g_qwl);
    cudaGetSymbolAddress((void**)&s1wh, g_s1wh);   cudaGetSymbolAddress((void**)&s1wl, g_s1wl);
    cudaGetSymbolAddress((void**)&s2wh, g_s2wh);   cudaGetSymbolAddress((void**)&s2wl, g_s2wl);
    cudaGetSymbolAddress((void**)&k1wh, g_k1wh);   cudaGetSymbolAddress((void**)&k1wl, g_k1wl);
    cudaGetSymbolAddress((void**)&k2wh, g_k2wh);   cudaGetSymbolAddress((void**)&k2wl, g_k2wl);
    cudaGetSymbolAddress((void**)&v2wh, g_v2wh);   cudaGetSymbolAddress((void**)&v2wl, g_v2wl);
    cudaGetSymbolAddress((void**)&pwh, g_pwh);     cudaGetSymbolAddress((void**)&pwl, g_pwl);

    const size_t IMG1 = (size_t)B_ * C_ * 64 * 64;
    float* v1 = kv1 + (size_t)B_ * N1_ * C2_;

    const int SMEM = 81920;
    cudaFuncSetAttribute(hgemm3_kernel<0, 1>, cudaFuncAttributeMaxDynamicSharedMemorySize, SMEM);
    cudaFuncSetAttribute(hgemm3_kernel<0, 2>, cudaFuncAttributeMaxDynamicSharedMemorySize, SMEM);
    cudaFuncSetAttribute(hgemm3_kernel<1, 1>, cudaFuncAttributeMaxDynamicSharedMemorySize, SMEM);
    cudaFuncSetAttribute(hgemm3_kernel<2, 1>, cudaFuncAttributeMaxDynamicSharedMemorySize, SMEM);
    cudaFuncSetAttribute(projgemm3_kernel, cudaFuncAttributeMaxDynamicSharedMemorySize, SMEM);
    const int FSMEM = 110592;
    cudaFuncSetAttribute(flash2_kernel, cudaFuncAttributeMaxDynamicSharedMemorySize, FSMEM);

    dim3 gblk(128);

    // launches ordered so my 4th launch (#6 under ncu -s 5) = sr1 GEMM
    split_kernel<<<4096, 256>>>(sr1_w, s1wh, s1wl);                         // 1
    to_image_split2_kernel<<<8192, 256>>>(key, value, imgh, imgl, IMG1);    // 2
    split_kernel<<<1024, 256>>>(sr2_w, s2wh, s2wl);                         // 3
    hgemm3_kernel<1, 1><<<dim3(4, 64), gblk, SMEM>>>(imgh, imgl, s1wh, s1wl, sr1_b,
                                                     kv1n, nullptr, nullptr, 8192, 512, 8192); // 4 <- profiled

    split_kernel<<<256, 256>>>(q_w, qwh, qwl);
    split_kernel<<<128, 256>>>(k1_w, k1wh, k1wl);
    split_kernel<<<128, 256>>>(k2_w, k2wh, k2wl);
    split_kernel<<<128, 256>>>(v2_w, v2wh, v2wl);
    split_kernel<<<256, 256>>>(proj_w, pwh, pwl);
    split_kernel<<<8192, 256>>>(query, qh, ql);

    hgemm3_kernel<2, 1><<<dim3(4, 256), gblk, SMEM>>>(imgh, imgl, s2wh, s2wl, sr2_b,
                                                      kv2n, nullptr, nullptr, 32768, 512, 2048);

    hgemm3_kernel<0, 2><<<dim3(4, 128), gblk, SMEM>>>(qh, ql, qwh, qwl, nullptr,
                                                      nullptr, qph, qpl, 16384, 512, 512);

    ln_gelu_split_kernel<<<8192,  256>>>(kv1n, norm1_w, norm1_b, kv1nh, kv1nl);
    ln_gelu_split_kernel<<<32768, 256>>>(kv2n, norm2_w, norm2_b, kv2nh, kv2nl);

    {
        ProjParams P;
        P.Ah[0] = kv1nh;  P.Al[0] = kv1nl;  P.Wh[0] = k1wh; P.Wl[0] = k1wl;
        P.Cf[0] = kv1;    P.Ch[0] = k1ph;   P.Cl[0] = k1pl; P.outm[0] = 3;
        P.Ah[1] = kv2nh;  P.Al[1] = kv2nl;  P.Wh[1] = k2wh; P.Wl[1] = k2wl;
        P.Cf[1] = nullptr; P.Ch[1] = k2ph;  P.Cl[1] = k2pl; P.outm[1] = 2;
        P.Ah[2] = kv2nh + (size_t)16384 * 512;
        P.Al[2] = kv2nl + (size_t)16384 * 512;
        P.Wh[2] = v2wh;   P.Wl[2] = v2wl;
        P.Cf[2] = v2;     P.Ch[2] = nullptr; P.Cl[2] = nullptr; P.outm[2] = 1;
        projgemm3_kernel<<<dim3(2, 320), gblk, SMEM>>>(P);
    }

    dwconv_res_t2_kernel<<<B_ * 4 * (N1_ / 64), 256>>>(v1, lc1_w, lc1_b, vt1h, vt1l, 16, 16);
    dwconv_res_t2_kernel<<<B_ * 4 * (N2_ / 64), 256>>>(v2, lc2_w, lc2_b, vt2h, vt2l, 32, 32);

    {
        FlashB P0, P1;
        P0.kph = k1ph; P0.kpl = k1pl; P0.vth = vt1h; P0.vtl = vt1l;
        P0.Nk = N1_; P0.hoff = 0; P0.coloff = 0;
        P1.kph = k2ph; P1.kpl = k2pl; P1.vth = vt2h; P1.vtl = vt2l;
        P1.Nk = N2_; P1.hoff = 4; P1.coloff = 256;
        flash2_kernel<<<dim3(8, 128), gblk, FSMEM>>>(qph, qpl, xh, xl, P0, P1);
    }

    hgemm3_kernel<0, 1><<<dim3(4, 128), gblk, SMEM>>>(xh, xl, pwh, pwl, proj_b,
                                                      out, nullptr, nullptr, 16384, 512, 512);
}

// round 13
// speedup vs baseline: 5.2484x; 1.6112x over previous
#include <cuda_runtime.h>
#include <cuda_bf16.h>
#include <cuda_fp16.h>
#include <math.h>
#include <stdint.h>

// ---------------------------------------------------------------------------
// Problem constants
// ---------------------------------------------------------------------------
constexpr int B_   = 16;
constexpr int C_   = 512;
constexpr int Qn   = 1024;
constexpr int C2_  = 256;
constexpr int N1_  = 256;
constexpr int N2_  = 1024;

// ---------------------------------------------------------------------------
// Device scratch
// ---------------------------------------------------------------------------
__device__ float g_kv1n [(size_t)2 * B_ * N1_ * C_];
__device__ float g_kv2n [(size_t)2 * B_ * N2_ * C_];
__device__ float g_kv1  [(size_t)2 * B_ * N1_ * C2_];
__device__ float g_v2   [(size_t)B_ * N2_ * C2_];

// bf16 hi/lo planes (imgh reused as fp16 single plane; imgl unused)
__device__ __nv_bfloat16 g_qh   [(size_t)16384 * 512];
__device__ __nv_bfloat16 g_ql   [(size_t)16384 * 512];
__device__ __nv_bfloat16 g_qph  [(size_t)16384 * 512];
__device__ __nv_bfloat16 g_qpl  [(size_t)16384 * 512];
__device__ __nv_bfloat16 g_imgh [(size_t)2 * B_ * C_ * 64 * 64];   // fp16 plane (cast)
__device__ __nv_bfloat16 g_kv1nh[(size_t)8192 * 512];
__device__ __nv_bfloat16 g_kv1nl[(size_t)8192 * 512];
__device__ __nv_bfloat16 g_kv2nh[(size_t)32768 * 512];
__device__ __nv_bfloat16 g_kv2nl[(size_t)32768 * 512];
__device__ __nv_bfloat16 g_k1ph [(size_t)8192 * 256];
__device__ __nv_bfloat16 g_k1pl [(size_t)8192 * 256];
__device__ __nv_bfloat16 g_k2ph [(size_t)16384 * 256];
__device__ __nv_bfloat16 g_k2pl [(size_t)16384 * 256];
__device__ __nv_bfloat16 g_vt1h [(size_t)B_ * C2_ * N1_];
__device__ __nv_bfloat16 g_vt1l [(size_t)B_ * C2_ * N1_];
__device__ __nv_bfloat16 g_vt2h [(size_t)B_ * C2_ * N2_];
__device__ __nv_bfloat16 g_vt2l [(size_t)B_ * C2_ * N2_];
__device__ __nv_bfloat16 g_xh   [(size_t)16384 * 512];
__device__ __nv_bfloat16 g_xl   [(size_t)16384 * 512];
// weight planes (s1wh/s2wh reused as fp16 single planes)
__device__ __nv_bfloat16 g_qwh [262144],  g_qwl [262144];
__device__ __nv_bfloat16 g_s1wh[4194304];
__device__ __nv_bfloat16 g_s2wh[1048576];
__device__ __nv_bfloat16 g_k1wh[131072],  g_k1wl[131072];
__device__ __nv_bfloat16 g_k2wh[131072],  g_k2wl[131072];
__device__ __nv_bfloat16 g_v2wh[131072],  g_v2wl[131072];
__device__ __nv_bfloat16 g_pwh [262144],  g_pwl [262144];

// ---------------------------------------------------------------------------
// helpers
// ---------------------------------------------------------------------------
__device__ __forceinline__ uint32_t smem_u32(const void* p) {
    uint32_t a;
    asm("{ .reg .u64 t; cvta.to.shared.u64 t, %1; cvt.u32.u64 %0, t; }" : "=r"(a) : "l"(p));
    return a;
}
__device__ __forceinline__ void ldsm_x4(uint32_t& r0, uint32_t& r1, uint32_t& r2, uint32_t& r3,
                                        uint32_t addr) {
    asm volatile("ldmatrix.sync.aligned.m8n8.x4.shared.b16 {%0,%1,%2,%3}, [%4];"
                 : "=r"(r0), "=r"(r1), "=r"(r2), "=r"(r3) : "r"(addr));
}
__device__ __forceinline__ void mma_bf16(float* d,
                                         uint32_t a0, uint32_t a1, uint32_t a2, uint32_t a3,
                                         uint32_t b0, uint32_t b1) {
    asm volatile(
        "mma.sync.aligned.m16n8k16.row.col.f32.bf16.bf16.f32 "
        "{%0,%1,%2,%3}, {%4,%5,%6,%7}, {%8,%9}, {%0,%1,%2,%3};"
        : "+f"(d[0]), "+f"(d[1]), "+f"(d[2]), "+f"(d[3])
        : "r"(a0), "r"(a1), "r"(a2), "r"(a3), "r"(b0), "r"(b1));
}
__device__ __forceinline__ void mma_f16(float* d,
                                        uint32_t a0, uint32_t a1, uint32_t a2, uint32_t a3,
                                        uint32_t b0, uint32_t b1) {
    asm volatile(
        "mma.sync.aligned.m16n8k16.row.col.f32.f16.f16.f32 "
        "{%0,%1,%2,%3}, {%4,%5,%6,%7}, {%8,%9}, {%0,%1,%2,%3};"
        : "+f"(d[0]), "+f"(d[1]), "+f"(d[2]), "+f"(d[3])
        : "r"(a0), "r"(a1), "r"(a2), "r"(a3), "r"(b0), "r"(b1));
}
__device__ __forceinline__ uint32_t pack_hi(float x, float y) {
    __nv_bfloat162 p(__float2bfloat16(x), __float2bfloat16(y));
    return *(uint32_t*)&p;
}
__device__ __forceinline__ uint32_t pack_lo(float x, float y) {
    float hx = __bfloat162float(__float2bfloat16(x));
    float hy = __bfloat162float(__float2bfloat16(y));
    __nv_bfloat162 p(__float2bfloat16(x - hx), __float2bfloat16(y - hy));
    return *(uint32_t*)&p;
}
__device__ __forceinline__ uint32_t pack_f16(float x, float y) {
    __half2 p = __floats2half2_rn(x, y);
    return *(uint32_t*)&p;
}

#define CP_ASYNC16(dst, src) \
    asm volatile("cp.async.cg.shared.global [%0], [%1], 16;" :: "r"(dst), "l"(src) : "memory")
#define CP_ASYNC8(dst, src) \
    asm volatile("cp.async.ca.shared.global [%0], [%1], 8;" :: "r"(dst), "l"(src) : "memory")
#define CP_ASYNC4(dst, src) \
    asm volatile("cp.async.ca.shared.global [%0], [%1], 4;" :: "r"(dst), "l"(src) : "memory")
#define CP_COMMIT() asm volatile("cp.async.commit_group;" ::: "memory")
#define CP_WAIT0()  asm volatile("cp.async.wait_group 0;" ::: "memory")
#define CP_WAIT1()  asm volatile("cp.async.wait_group 1;" ::: "memory")

// ---------------------------------------------------------------------------
// fp32 -> hi/lo bf16 planes
// ---------------------------------------------------------------------------
__global__ void split_kernel(const float* __restrict__ src,
                             __nv_bfloat16* __restrict__ h,
                             __nv_bfloat16* __restrict__ l)
{
    int i = blockIdx.x * 256 + threadIdx.x;
    float4 v = ((const float4*)src)[i];
    ((uint2*)h)[i] = make_uint2(pack_hi(v.x, v.y), pack_hi(v.z, v.w));
    ((uint2*)l)[i] = make_uint2(pack_lo(v.x, v.y), pack_lo(v.z, v.w));
}

// fp32 -> single fp16 plane
__global__ void split_h_kernel(const float* __restrict__ src,
                               __half* __restrict__ h)
{
    int i = blockIdx.x * 256 + threadIdx.x;
    float4 v = ((const float4*)src)[i];
    ((uint2*)h)[i] = make_uint2(pack_f16(v.x, v.y), pack_f16(v.z, v.w));
}

// ---------------------------------------------------------------------------
// (N,B,C) -> raw-reshape image, single fp16 plane (K + V one launch)
// ---------------------------------------------------------------------------
__global__ void to_image_h_kernel(const float* __restrict__ srcK,
                                  const float* __restrict__ srcV,
                                  __half* __restrict__ h,
                                  size_t img1)
{
    __shared__ float sm[16][513];
    const int half_ = blockIdx.x >> 12;
    const float* src = half_ ? srcV : srcK;
    const size_t dofs = half_ ? img1 : 0;
    size_t base = (size_t)(blockIdx.x & 4095) * 8192;
    for (int j = threadIdx.x; j < 8192; j += 256) sm[j >> 9][j & 511] = src[base + j];
    __syncthreads();
    for (int r = threadIdx.x; r < 8192; r += 256) {
        h[dofs + base + r] = __float2half(sm[r & 15][r >> 4]);
    }
}

// ---------------------------------------------------------------------------
// Single-pass fp16 HMMA conv GEMM: 128 threads, 4 warps of 64x64.
// smem: buf = A(10240) + W(10240) = 20480; double buffered = 40960.
// LOADER 1: 4x4/s4 conv im2col. LOADER 2: 2x2/s2.
// ---------------------------------------------------------------------------
template <int LOADER>
__global__ __launch_bounds__(128, 2) void hgemm4_kernel(
    const __half* __restrict__ A, const __half* __restrict__ W,
    const float* __restrict__ bias, float* __restrict__ Cmat,
    int M, int N, int K)
{
    extern __shared__ char smc[];
    const uint32_t sb = smem_u32(smc);

    const int tid  = threadIdx.x;
    const int wid  = tid >> 5;
    const int lane = tid & 31;
    const int bm = blockIdx.y << 7;
    const int bn = blockIdx.x << 7;
    const int m0 = (wid & 1) << 6;
    const int n0 = (wid >> 1) << 6;

    int rr[8], kk[8];
#pragma unroll
    for (int j = 0; j < 8; j++) {
        int s = tid + (j << 7);
        rr[j] = s >> 3;
        kk[j] = (s & 7) << 2;
    }
    int rw[4], kw[4];
#pragma unroll
    for (int j = 0; j < 4; j++) {
        int s = tid + (j << 7);
        rw[j] = s >> 2;
        kw[j] = (s & 3) << 3;
    }

    const uint32_t lrow = (uint32_t)(lane & 15);
    const uint32_t lkq  = (uint32_t)(lane >> 4) * 16;
    uint32_t aOffs[4], bOffs[4];
#pragma unroll
    for (int t = 0; t < 4; t++) {
        aOffs[t] = (uint32_t)(m0 + t * 16 + lrow) * 80 + lkq;
        bOffs[t] = (uint32_t)(n0 + t * 16 + lrow) * 80 + lkq;
    }

    float acc[4][8][4];
#pragma unroll
    for (int i = 0; i < 4; i++)
#pragma unroll
        for (int j = 0; j < 8; j++)
#pragma unroll
            for (int l = 0; l < 4; l++) acc[i][j][l] = 0.f;

    auto gaddrA = [&](int r, int k) -> const __half* {
        if (LOADER == 1) {
            int m = bm + r;
            int b = m >> 8, oy = (m >> 4) & 15, ox = m & 15;
            int ic = k >> 4, ky = (k >> 2) & 3;
            return A + (((size_t)(b * 512 + ic) * 64) + oy * 4 + ky) * 64 + ox * 4;
        } else {
            int m = bm + r;
            int b = m >> 10, oy = (m >> 5) & 31, ox = m & 31;
            int ic = k >> 2;
            return A + (((size_t)(b * 512 + ic) * 64) + oy * 2) * 64 + ox * 2;
        }
    };

    auto issue_chunk = [&](int buf, int k0) {
        const uint32_t bb = sb + (uint32_t)buf * 20480;
#pragma unroll
        for (int j = 0; j < 8; j++) {
            const uint32_t off = (uint32_t)rr[j] * 80 + (uint32_t)(kk[j] << 1);
            const int k = k0 + kk[j];
            const __half* pa = gaddrA(rr[j], k);
            if (LOADER == 2) {
                CP_ASYNC4(bb + off,     pa);
                CP_ASYNC4(bb + off + 4, pa + 64);
            } else {
                CP_ASYNC8(bb + off, pa);
            }
        }
#pragma unroll
        for (int j = 0; j < 4; j++) {
            const uint32_t off = (uint32_t)rw[j] * 80 + (uint32_t)(kw[j] << 1);
            const int k = k0 + kw[j];
            CP_ASYNC16(bb + 10240 + off, W + (size_t)(bn + rw[j]) * K + k);
        }
    };

    const int nchunks = K >> 5;
    issue_chunk(0, 0);
    CP_COMMIT();

    for (int c = 0; c < nchunks; c++) {
        const bool more = (c + 1) < nchunks;
        if (more) {
            issue_chunk((c + 1) & 1, (c + 1) << 5);
            CP_COMMIT();
            CP_WAIT1();
        } else {
            CP_WAIT0();
        }
        __syncthreads();

        const uint32_t bb = sb + (uint32_t)(c & 1) * 20480;
        const uint32_t AB = bb, WB = bb + 10240;
#pragma unroll
        for (int kh = 0; kh < 2; kh++) {
            const uint32_t ko = (uint32_t)kh * 32;
            uint32_t AA[4][4], BB[4][4];
#pragma unroll
            for (int mt = 0; mt < 4; mt++)
                ldsm_x4(AA[mt][0], AA[mt][1], AA[mt][2], AA[mt][3], AB + aOffs[mt] + ko);
#pragma unroll
            for (int nt = 0; nt < 4; nt++)
                ldsm_x4(BB[nt][0], BB[nt][1], BB[nt][2], BB[nt][3], WB + bOffs[nt] + ko);
#pragma unroll
            for (int mt = 0; mt < 4; mt++)
#pragma unroll
                for (int nt = 0; nt < 4; nt++) {
                    mma_f16(acc[mt][2 * nt + 0], AA[mt][0], AA[mt][1], AA[mt][2], AA[mt][3], BB[nt][0], BB[nt][2]);
                    mma_f16(acc[mt][2 * nt + 1], AA[mt][0], AA[mt][1], AA[mt][2], AA[mt][3], BB[nt][1], BB[nt][3]);
                }
        }
        __syncthreads();
    }

    const int gr = lane >> 2;
    const int gc = (lane & 3) * 2;
#pragma unroll
    for (int mt = 0; mt < 4; mt++) {
        const int row0 = bm + m0 + mt * 16 + gr;
#pragma unroll
        for (int nt = 0; nt < 8; nt++) {
            const int col = bn + n0 + nt * 8 + gc;
            float b0 = bias[col], b1 = bias[col + 1];
            *(float2*)(Cmat + (size_t)row0 * N + col) =
                make_float2(acc[mt][nt][0] + b0, acc[mt][nt][1] + b1);
            *(float2*)(Cmat + (size_t)(row0 + 8) * N + col) =
                make_float2(acc[mt][nt][2] + b0, acc[mt][nt][3] + b1);
        }
    }
}

// ---------------------------------------------------------------------------
// 64x64-warp-tile split-bf16 mainloop body (pass-major)
// ---------------------------------------------------------------------------
#define GEMM3_CHUNK_MMA(AhB, AlB, WhB, WlB)                                     \
    _Pragma("unroll")                                                           \
    for (int kh = 0; kh < 2; kh++) {                                            \
        const uint32_t ko = (uint32_t)kh * 32;                                  \
        uint32_t AH[4][4], AL[4][4], BH[4][4], BL[4][4];                        \
        _Pragma("unroll")                                                       \
        for (int mt = 0; mt < 4; mt++) {                                        \
            ldsm_x4(AH[mt][0], AH[mt][1], AH[mt][2], AH[mt][3], (AhB) + aOffs[mt] + ko); \
            ldsm_x4(AL[mt][0], AL[mt][1], AL[mt][2], AL[mt][3], (AlB) + aOffs[mt] + ko); \
        }                                                                       \
        _Pragma("unroll")                                                       \
        for (int nt = 0; nt < 4; nt++) {                                        \
            ldsm_x4(BH[nt][0], BH[nt][1], BH[nt][2], BH[nt][3], (WhB) + bOffs[nt] + ko); \
            ldsm_x4(BL[nt][0], BL[nt][1], BL[nt][2], BL[nt][3], (WlB) + bOffs[nt] + ko); \
        }                                                                       \
        _Pragma("unroll")                                                       \
        for (int mt = 0; mt < 4; mt++)                                          \
        _Pragma("unroll")                                                       \
        for (int nt = 0; nt < 4; nt++) {                                        \
            mma_bf16(acc[mt][2 * nt + 0], AH[mt][0], AH[mt][1], AH[mt][2], AH[mt][3], BH[nt][0], BH[nt][2]); \
            mma_bf16(acc[mt][2 * nt + 1], AH[mt][0], AH[mt][1], AH[mt][2], AH[mt][3], BH[nt][1], BH[nt][3]); \
        }                                                                       \
        _Pragma("unroll")                                                       \
        for (int mt = 0; mt < 4; mt++)                                          \
        _Pragma("unroll")                                                       \
        for (int nt = 0; nt < 4; nt++) {                                        \
            mma_bf16(acc[mt][2 * nt + 0], AH[mt][0], AH[mt][1], AH[mt][2], AH[mt][3], BL[nt][0], BL[nt][2]); \
            mma_bf16(acc[mt][2 * nt + 1], AH[mt][0], AH[mt][1], AH[mt][2], AH[mt][3], BL[nt][1], BL[nt][3]); \
        }                                                                       \
        _Pragma("unroll")                                                       \
        for (int mt = 0; mt < 4; mt++)                                          \
        _Pragma("unroll")                                                       \
        for (int nt = 0; nt < 4; nt++) {                                        \
            mma_bf16(acc[mt][2 * nt + 0], AL[mt][0], AL[mt][1], AL[mt][2], AL[mt][3], BH[nt][0], BH[nt][2]); \
            mma_bf16(acc[mt][2 * nt + 1], AL[mt][0], AL[mt][1], AL[mt][2], AL[mt][3], BH[nt][1], BH[nt][3]); \
        }                                                                       \
    }

// ---------------------------------------------------------------------------
// Split-bf16 HMMA GEMM v3 (row-major planes only), used for q/out projections.
// ---------------------------------------------------------------------------
template <int OUT>
__global__ __launch_bounds__(128, 2) void hgemm3_kernel(
    const __nv_bfloat16* __restrict__ Ah, const __nv_bfloat16* __restrict__ Al,
    const __nv_bfloat16* __restrict__ Wh, const __nv_bfloat16* __restrict__ Wl,
    const float* __restrict__ bias, float* __restrict__ Cmat,
    __nv_bfloat16* __restrict__ Ch, __nv_bfloat16* __restrict__ Cl,
    int M, int N, int K)
{
    extern __shared__ char smc[];
    const uint32_t sb = smem_u32(smc);

    const int tid  = threadIdx.x;
    const int wid  = tid >> 5;
    const int lane = tid & 31;
    const int bm = blockIdx.y << 7;
    const int bn = blockIdx.x << 7;
    const int m0 = (wid & 1) << 6;
    const int n0 = (wid >> 1) << 6;

    int rw[4], kw[4];
#pragma unroll
    for (int j = 0; j < 4; j++) {
        int s = tid + (j << 7);
        rw[j] = s >> 2;
        kw[j] = (s & 3) << 3;
    }

    const uint32_t lrow = (uint32_t)(lane & 15);
    const uint32_t lkq  = (uint32_t)(lane >> 4) * 16;
    uint32_t aOffs[4], bOffs[4];
#pragma unroll
    for (int t = 0; t < 4; t++) {
        aOffs[t] = (uint32_t)(m0 + t * 16 + lrow) * 80 + lkq;
        bOffs[t] = (uint32_t)(n0 + t * 16 + lrow) * 80 + lkq;
    }

    float acc[4][8][4];
#pragma unroll
    for (int i = 0; i < 4; i++)
#pragma unroll
        for (int j = 0; j < 8; j++)
#pragma unroll
            for (int l = 0; l < 4; l++) acc[i][j][l] = 0.f;

    auto issue_chunk = [&](int buf, int k0) {
        const uint32_t bb = sb + (uint32_t)buf * 40960;
#pragma unroll
        for (int j = 0; j < 4; j++) {
            const uint32_t off = (uint32_t)rw[j] * 80 + (uint32_t)(kw[j] << 1);
            const int k = k0 + kw[j];
            CP_ASYNC16(bb + off,         Ah + (size_t)(bm + rw[j]) * K + k);
            CP_ASYNC16(bb + 10240 + off, Al + (size_t)(bm + rw[j]) * K + k);
            CP_ASYNC16(bb + 20480 + off, Wh + (size_t)(bn + rw[j]) * K + k);
            CP_ASYNC16(bb + 30720 + off, Wl + (size_t)(bn + rw[j]) * K + k);
        }
    };

    const int nchunks = K >> 5;
    issue_chunk(0, 0);
    CP_COMMIT();

    for (int c = 0; c < nchunks; c++) {
        const bool more = (c + 1) < nchunks;
        if (more) {
            issue_chunk((c + 1) & 1, (c + 1) << 5);
            CP_COMMIT();
            CP_WAIT1();
        } else {
            CP_WAIT0();
        }
        __syncthreads();

        const uint32_t bb = sb + (uint32_t)(c & 1) * 40960;
        const uint32_t AhB = bb, AlB = bb + 10240, WhB = bb + 20480, WlB = bb + 30720;
        GEMM3_CHUNK_MMA(AhB, AlB, WhB, WlB)
        __syncthreads();
    }

    const int gr = lane >> 2;
    const int gc = (lane & 3) * 2;
#pragma unroll
    for (int mt = 0; mt < 4; mt++) {
        const int row0 = bm + m0 + mt * 16 + gr;
#pragma unroll
        for (int nt = 0; nt < 8; nt++) {
            const int col = bn + n0 + nt * 8 + gc;
            float b0 = bias ? bias[col] : 0.f;
            float b1 = bias ? bias[col + 1] : 0.f;
            float o0 = acc[mt][nt][0] + b0, o1 = acc[mt][nt][1] + b1;
            float o2 = acc[mt][nt][2] + b0, o3 = acc[mt][nt][3] + b1;
            if (OUT & 1) {
                *(float2*)(Cmat + (size_t)row0 * N + col) = make_float2(o0, o1);
                *(float2*)(Cmat + (size_t)(row0 + 8) * N + col) = make_float2(o2, o3);
            }
            if (OUT & 2) {
                size_t i0 = ((size_t)row0 * N + col) >> 1;
                size_t i1 = ((size_t)(row0 + 8) * N + col) >> 1;
                ((uint32_t*)Ch)[i0] = pack_hi(o0, o1);
                ((uint32_t*)Cl)[i0] = pack_lo(o0, o1);
                ((uint32_t*)Ch)[i1] = pack_hi(o2, o3);
                ((uint32_t*)Cl)[i1] = pack_lo(o2, o3);
            }
        }
    }
}

// ---------------------------------------------------------------------------
// Merged head-projection GEMM v3 (3 sub-problems, one launch, 128 threads).
// ---------------------------------------------------------------------------
struct ProjParams {
    const __nv_bfloat16 *Ah[3], *Al[3], *Wh[3], *Wl[3];
    float* Cf[3];
    __nv_bfloat16 *Ch[3], *Cl[3];
    int outm[3];
};

__global__ __launch_bounds__(128, 2) void projgemm3_kernel(ProjParams P)
{
    extern __shared__ char smc[];
    const uint32_t sb = smem_u32(smc);
    constexpr int K = 512, N = 256;

    const int y = blockIdx.y;
    const int pi = (y < 64) ? 0 : (y < 192 ? 1 : 2);
    const int ylocal = y - ((pi == 0) ? 0 : (pi == 1) ? 64 : 192);

    const __nv_bfloat16* Ah = P.Ah[pi];
    const __nv_bfloat16* Al = P.Al[pi];
    const __nv_bfloat16* Wh = P.Wh[pi];
    const __nv_bfloat16* Wl = P.Wl[pi];
    float* Cmat = P.Cf[pi];
    __nv_bfloat16* Ch = P.Ch[pi];
    __nv_bfloat16* Cl = P.Cl[pi];
    const int OUT = P.outm[pi];

    const int tid  = threadIdx.x;
    const int wid  = tid >> 5;
    const int lane = tid & 31;
    const int bm = ylocal << 7;
    const int bn = blockIdx.x << 7;
    const int m0 = (wid & 1) << 6;
    const int n0 = (wid >> 1) << 6;

    int rw[4], kw[4];
#pragma unroll
    for (int j = 0; j < 4; j++) {
        int s = tid + (j << 7);
        rw[j] = s >> 2;
        kw[j] = (s & 3) << 3;
    }

    const uint32_t lrow = (uint32_t)(lane & 15);
    const uint32_t lkq  = (uint32_t)(lane >> 4) * 16;
    uint32_t aOffs[4], bOffs[4];
#pragma unroll
    for (int t = 0; t < 4; t++) {
        aOffs[t] = (uint32_t)(m0 + t * 16 + lrow) * 80 + lkq;
        bOffs[t] = (uint32_t)(n0 + t * 16 + lrow) * 80 + lkq;
    }

    float acc[4][8][4];
#pragma unroll
    for (int i = 0; i < 4; i++)
#pragma unroll
        for (int j = 0; j < 8; j++)
#pragma unroll
            for (int l = 0; l < 4; l++) acc[i][j][l] = 0.f;

    auto issue_chunk = [&](int buf, int k0) {
        const uint32_t bb = sb + (uint32_t)buf * 40960;
#pragma unroll
        for (int j = 0; j < 4; j++) {
            const uint32_t off = (uint32_t)rw[j] * 80 + (uint32_t)(kw[j] << 1);
            const int k = k0 + kw[j];
            CP_ASYNC16(bb + off,         Ah + (size_t)(bm + rw[j]) * K + k);
            CP_ASYNC16(bb + 10240 + off, Al + (size_t)(bm + rw[j]) * K + k);
            CP_ASYNC16(bb + 20480 + off, Wh + (size_t)(bn + rw[j]) * K + k);
            CP_ASYNC16(bb + 30720 + off, Wl + (size_t)(bn + rw[j]) * K + k);
        }
    };

    const int nchunks = K >> 5;
    issue_chunk(0, 0);
    CP_COMMIT();

    for (int c = 0; c < nchunks; c++) {
        const bool more = (c + 1) < nchunks;
        if (more) {
            issue_chunk((c + 1) & 1, (c + 1) << 5);
            CP_COMMIT();
            CP_WAIT1();
        } else {
            CP_WAIT0();
        }
        __syncthreads();

        const uint32_t bb = sb + (uint32_t)(c & 1) * 40960;
        const uint32_t AhB = bb, AlB = bb + 10240, WhB = bb + 20480, WlB = bb + 30720;
        GEMM3_CHUNK_MMA(AhB, AlB, WhB, WlB)
        __syncthreads();
    }

    const int gr = lane >> 2;
    const int gc = (lane & 3) * 2;
#pragma unroll
    for (int mt = 0; mt < 4; mt++) {
        const int row0 = bm + m0 + mt * 16 + gr;
#pragma unroll
        for (int nt = 0; nt < 8; nt++) {
            const int col = bn + n0 + nt * 8 + gc;
            float o0 = acc[mt][nt][0], o1 = acc[mt][nt][1];
            float o2 = acc[mt][nt][2], o3 = acc[mt][nt][3];
            if (OUT & 1) {
                *(float2*)(Cmat + (size_t)row0 * N + col) = make_float2(o0, o1);
                *(float2*)(Cmat + (size_t)(row0 + 8) * N + col) = make_float2(o2, o3);
            }
            if (OUT & 2) {
                size_t i0 = ((size_t)row0 * N + col) >> 1;
                size_t i1 = ((size_t)(row0 + 8) * N + col) >> 1;
                ((uint32_t*)Ch)[i0] = pack_hi(o0, o1);
                ((uint32_t*)Cl)[i0] = pack_lo(o0, o1);
                ((uint32_t*)Ch)[i1] = pack_hi(o2, o3);
                ((uint32_t*)Cl)[i1] = pack_lo(o2, o3);
            }
        }
    }
}

// ---------------------------------------------------------------------------
// LayerNorm(512) + exact GELU -> bf16 hi/lo planes
// ---------------------------------------------------------------------------
__global__ void ln_gelu_split_kernel(const float* __restrict__ x,
                                     const float* __restrict__ w,
                                     const float* __restrict__ b,
                                     __nv_bfloat16* __restrict__ hO,
                                     __nv_bfloat16* __restrict__ lO)
{
    __shared__ float sh[8];
    const float* row = x + (size_t)blockIdx.x * 512;
    int t = threadIdx.x;
    float2 v = *(const float2*)(row + t * 2);

    float s = v.x + v.y;
#pragma unroll
    for (int o = 16; o; o >>= 1) s += __shfl_xor_sync(0xffffffffu, s, o);
    if ((t & 31) == 0) sh[t >> 5] = s;
    __syncthreads();
    float tot = 0.f;
#pragma unroll
    for (int i = 0; i < 8; i++) tot += sh[i];
    float mu = tot * (1.f / 512.f);
    float d0 = v.x - mu, d1 = v.y - mu;
    __syncthreads();

    float ss = d0 * d0 + d1 * d1;
#pragma unroll
    for (int o = 16; o; o >>= 1) ss += __shfl_xor_sync(0xffffffffu, ss, o);
    if ((t & 31) == 0) sh[t >> 5] = ss;
    __syncthreads();
    float tot2 = 0.f;
#pragma unroll
    for (int i = 0; i < 8; i++) tot2 += sh[i];
    float inv = rsqrtf(tot2 * (1.f / 512.f) + 1e-5f);

    float y0 = d0 * inv * w[t * 2]     + b[t * 2];
    float y1 = d1 * inv * w[t * 2 + 1] + b[t * 2 + 1];
    y0 = 0.5f * y0 * (1.f + erff(y0 * 0.7071067811865476f));
    y1 = 0.5f * y1 * (1.f + erff(y1 * 0.7071067811865476f));

    size_t o = (size_t)blockIdx.x * 256 + t;
    ((uint32_t*)hO)[o] = pack_hi(y0, y1);
    ((uint32_t*)lO)[o] = pack_lo(y0, y1);
}

// ---------------------------------------------------------------------------
// Depthwise 3x3 (pad 1) residual -> transposed planes, coalesced via smem tile.
// ---------------------------------------------------------------------------
__global__ void dwconv_res_t2_kernel(const float* __restrict__ v,
                                     const float* __restrict__ lw,
                                     const float* __restrict__ lb,
                                     __nv_bfloat16* __restrict__ vth,
                                     __nv_bfloat16* __restrict__ vtl,
                                     int hh, int ww)
{
    __shared__ float sm[64][65];
    const int Nn = hh * ww;
    const int nt = Nn >> 6;
    int bz = blockIdx.x;
    const int ntile = bz % nt; bz /= nt;
    const int ct = bz & 3;
    const int bb = bz >> 2;
    const int c0 = ct << 6, n0 = ntile << 6;

    const int tid = threadIdx.x;
    const int tc = tid & 63;
    const int tn0 = tid >> 6;
    const int c = c0 + tc;

    float wreg[9];
#pragma unroll
    for (int i = 0; i < 9; i++) wreg[i] = lw[c * 9 + i];
    const float bias = lb[c];

    for (int nn = tn0; nn < 64; nn += 4) {
        const int n = n0 + nn;
        const int y = n / ww;
        const int x = n - y * ww;
        float acc = bias;
#pragma unroll
        for (int dy = -1; dy <= 1; dy++) {
            int yy = y + dy;
            if (yy < 0 || yy >= hh) continue;
#pragma unroll
            for (int dx = -1; dx <= 1; dx++) {
                int xx = x + dx;
                if (xx < 0 || xx >= ww) continue;
                acc += v[((size_t)(bb * Nn + yy * ww + xx) << 8) + c] * wreg[(dy + 1) * 3 + (dx + 1)];
            }
        }
        sm[nn][tc] = v[((size_t)(bb * Nn + n) << 8) + c] + acc;
    }
    __syncthreads();

    const int wc = tid >> 5;
    const int wn = (tid & 31) << 1;
    for (int cc = wc; cc < 64; cc += 8) {
        float v0 = sm[wn][cc], v1 = sm[wn + 1][cc];
        size_t o = (((size_t)(bb * 256 + c0 + cc)) * Nn + n0 + wn) >> 1;
        ((uint32_t*)vth)[o] = pack_hi(v0, v1);
        ((uint32_t*)vtl)[o] = pack_lo(v0, v1);
    }
}

// ---------------------------------------------------------------------------
// Flash attention v2 (split-bf16, unchanged)
// ---------------------------------------------------------------------------
struct FlashB {
    const __nv_bfloat16 *kph, *kpl, *vth, *vtl;
    int Nk, hoff, coloff;
};

__global__ __launch_bounds__(128, 2) void flash2_kernel(
    const __nv_bfloat16* __restrict__ qph, const __nv_bfloat16* __restrict__ qpl,
    __nv_bfloat16* __restrict__ xh, __nv_bfloat16* __restrict__ xl,
    FlashB P0, FlashB P1)
{
    extern __shared__ char smc[];
    const uint32_t sb = smem_u32(smc);
    const uint32_t QH = sb, QL = sb + 18432;

    const int tid  = threadIdx.x;
    const int wid  = tid >> 5;
    const int lane = tid & 31;
    const int y = blockIdx.y;
    const FlashB P = (y < 64) ? P0 : P1;
    const int yl = y & 63;
    const int b = yl >> 2;
    const int h = yl & 3;
    const int q0 = blockIdx.x << 7;

    {
        const size_t qbase = ((size_t)(b * Qn + q0)) * 512 + (size_t)(P.hoff + h) * 64;
#pragma unroll
        for (int it = 0; it < 16; it++) {
            int i = tid + (it << 7);
            int row = i >> 4;
            int c4 = (i & 15) << 2;
            uint32_t dst = (uint32_t)row * 144 + (uint32_t)(c4 << 1);
            CP_ASYNC8(QH + dst, qph + qbase + (size_t)row * 512 + c4);
            CP_ASYNC8(QL + dst, qpl + qbase + (size_t)row * 512 + c4);
        }
        CP_COMMIT();
    }

    auto issue_kv = [&](int buf, int kv0) {
        const uint32_t bb = sb + 36864 + (uint32_t)buf * 36864;
#pragma unroll
        for (int it = 0; it < 8; it++) {
            int i = tid + (it << 7);
            int row = i >> 4;
            int c4 = (i & 15) << 2;
            uint32_t dst = (uint32_t)row * 144 + (uint32_t)(c4 << 1);
            size_t kidx = ((size_t)(b * P.Nk + kv0 + row)) * 256 + h * 64 + c4;
            CP_ASYNC8(bb + dst,         P.kph + kidx);
            CP_ASYNC8(bb + 9216 + dst,  P.kpl + kidx);
            size_t vidx = ((size_t)(b * 256 + h * 64 + row)) * P.Nk + kv0 + c4;
            CP_ASYNC8(bb + 18432 + dst, P.vth + vidx);
            CP_ASYNC8(bb + 27648 + dst, P.vtl + vidx);
        }
    };

    const uint32_t lrow = (uint32_t)(lane & 15);
    const uint32_t lkq  = (uint32_t)(lane >> 4) * 16;
    uint32_t qOff[2];
    qOff[0] = ((uint32_t)(wid * 32) + lrow) * 144 + lkq;
    qOff[1] = qOff[0] + 16 * 144;
    const uint32_t kOff = lrow * 144 + lkq;
    const int gr = lane >> 2;

    float m[2][2], l[2][2];
#pragma unroll
    for (int i = 0; i < 2; i++) { m[i][0] = -1e30f; m[i][1] = -1e30f; l[i][0] = 0.f; l[i][1] = 0.f; }
    float Oacc[2][8][4];
#pragma unroll
    for (int i = 0; i < 2; i++)
#pragma unroll
        for (int j = 0; j < 8; j++)
#pragma unroll
            for (int q = 0; q < 4; q++) Oacc[i][j][q] = 0.f;

    const int ntiles = P.Nk >> 6;
    issue_kv(0, 0);
    CP_COMMIT();

    for (int t = 0; t < ntiles; t++) {
        const bool more = (t + 1) < ntiles;
        if (more) {
            issue_kv((t + 1) & 1, (t + 1) << 6);
            CP_COMMIT();
            CP_WAIT1();
        } else {
            CP_WAIT0();
        }
        __syncthreads();

        const uint32_t bb = sb + 36864 + (uint32_t)(t & 1) * 36864;
        const uint32_t KH = bb, KL = bb + 9216, VH = bb + 18432, VL = bb + 27648;

        float S[2][8][4];
#pragma unroll
        for (int i = 0; i < 2; i++)
#pragma unroll
            for (int j = 0; j < 8; j++)
#pragma unroll
                for (int q = 0; q < 4; q++) S[i][j][q] = 0.f;

#pragma unroll
        for (int ks = 0; ks < 4; ks++) {
            const uint32_t ko = (uint32_t)ks * 32;
            uint32_t qh4[2][4], ql4[2][4];
#pragma unroll
            for (int mt = 0; mt < 2; mt++) {
                ldsm_x4(qh4[mt][0], qh4[mt][1], qh4[mt][2], qh4[mt][3], QH + qOff[mt] + ko);
                ldsm_x4(ql4[mt][0], ql4[mt][1], ql4[mt][2], ql4[mt][3], QL + qOff[mt] + ko);
            }
#pragma unroll
            for (int g = 0; g < 4; g++) {
                uint32_t kh4[4], kl4[4];
                ldsm_x4(kh4[0], kh4[1], kh4[2], kh4[3], KH + (uint32_t)g * 2304 + kOff + ko);
                ldsm_x4(kl4[0], kl4[1], kl4[2], kl4[3], KL + (uint32_t)g * 2304 + kOff + ko);
#pragma unroll
                for (int mt = 0; mt < 2; mt++) {
                    mma_bf16(S[mt][2 * g + 0], qh4[mt][0], qh4[mt][1], qh4[mt][2], qh4[mt][3], kh4[0], kh4[2]);
                    mma_bf16(S[mt][2 * g + 1], qh4[mt][0], qh4[mt][1], qh4[mt][2], qh4[mt][3], kh4[1], kh4[3]);
                }
#pragma unroll
                for (int mt = 0; mt < 2; mt++) {
                    mma_bf16(S[mt][2 * g + 0], qh4[mt][0], qh4[mt][1], qh4[mt][2], qh4[mt][3], kl4[0], kl4[2]);
                    mma_bf16(S[mt][2 * g + 1], qh4[mt][0], qh4[mt][1], qh4[mt][2], qh4[mt][3], kl4[1], kl4[3]);
                }
#pragma unroll
                for (int mt = 0; mt < 2; mt++) {
                    mma_bf16(S[mt][2 * g + 0], ql4[mt][0], ql4[mt][1], ql4[mt][2], ql4[mt][3], kh4[0], kh4[2]);
                    mma_bf16(S[mt][2 * g + 1], ql4[mt][0], ql4[mt][1], ql4[mt][2], ql4[mt][3], kh4[1], kh4[3]);
                }
            }
        }

        const float sc = 0.125f;
#pragma unroll
        for (int mt = 0; mt < 2; mt++) {
            float mx0 = m[mt][0], mx1 = m[mt][1];
#pragma unroll
            for (int j = 0; j < 8; j++) {
                S[mt][j][0] *= sc; S[mt][j][1] *= sc; S[mt][j][2] *= sc; S[mt][j][3] *= sc;
                mx0 = fmaxf(mx0, fmaxf(S[mt][j][0], S[mt][j][1]));
                mx1 = fmaxf(mx1, fmaxf(S[mt][j][2], S[mt][j][3]));
            }
#pragma unroll
            for (int o = 1; o <= 2; o <<= 1) {
                mx0 = fmaxf(mx0, __shfl_xor_sync(0xffffffffu, mx0, o));
                mx1 = fmaxf(mx1, __shfl_xor_sync(0xffffffffu, mx1, o));
            }
            const float alpha0 = __expf(m[mt][0] - mx0);
            const float alpha1 = __expf(m[mt][1] - mx1);
            m[mt][0] = mx0; m[mt][1] = mx1;

            float rs0 = 0.f, rs1 = 0.f;
#pragma unroll
            for (int j = 0; j < 8; j++) {
                S[mt][j][0] = __expf(S[mt][j][0] - mx0);
                S[mt][j][1] = __expf(S[mt][j][1] - mx0);
                S[mt][j][2] = __expf(S[mt][j][2] - mx1);
                S[mt][j][3] = __expf(S[mt][j][3] - mx1);
                rs0 += S[mt][j][0] + S[mt][j][1];
                rs1 += S[mt][j][2] + S[mt][j][3];
            }
#pragma unroll
            for (int o = 1; o <= 2; o <<= 1) {
                rs0 += __shfl_xor_sync(0xffffffffu, rs0, o);
                rs1 += __shfl_xor_sync(0xffffffffu, rs1, o);
            }
            l[mt][0] = l[mt][0] * alpha0 + rs0;
            l[mt][1] = l[mt][1] * alpha1 + rs1;

#pragma unroll
            for (int j = 0; j < 8; j++) {
                Oacc[mt][j][0] *= alpha0; Oacc[mt][j][1] *= alpha0;
                Oacc[mt][j][2] *= alpha1; Oacc[mt][j][3] *= alpha1;
            }
        }

#pragma unroll
        for (int t16 = 0; t16 < 4; t16++) {
            uint32_t ph[2][4], pl[2][4];
#pragma unroll
            for (int mt = 0; mt < 2; mt++) {
                ph[mt][0] = pack_hi(S[mt][2 * t16][0],     S[mt][2 * t16][1]);
                ph[mt][1] = pack_hi(S[mt][2 * t16][2],     S[mt][2 * t16][3]);
                ph[mt][2] = pack_hi(S[mt][2 * t16 + 1][0], S[mt][2 * t16 + 1][1]);
                ph[mt][3] = pack_hi(S[mt][2 * t16 + 1][2], S[mt][2 * t16 + 1][3]);
                pl[mt][0] = pack_lo(S[mt][2 * t16][0],     S[mt][2 * t16][1]);
                pl[mt][1] = pack_lo(S[mt][2 * t16][2],     S[mt][2 * t16][3]);
                pl[mt][2] = pack_lo(S[mt][2 * t16 + 1][0], S[mt][2 * t16 + 1][1]);
                pl[mt][3] = pack_lo(S[mt][2 * t16 + 1][2], S[mt][2 * t16 + 1][3]);
            }
            const uint32_t ko = (uint32_t)t16 * 32;
#pragma unroll
            for (int g = 0; g < 4; g++) {
                uint32_t vh[4], vl[4];
                ldsm_x4(vh[0], vh[1], vh[2], vh[3], VH + (uint32_t)g * 2304 + kOff + ko);
                ldsm_x4(vl[0], vl[1], vl[2], vl[3], VL + (uint32_t)g * 2304 + kOff + ko);
#pragma unroll
                for (int mt = 0; mt < 2; mt++) {
                    mma_bf16(Oacc[mt][2 * g + 0], ph[mt][0], ph[mt][1], ph[mt][2], ph[mt][3], vh[0], vh[2]);
                    mma_bf16(Oacc[mt][2 * g + 1], ph[mt][0], ph[mt][1], ph[mt][2], ph[mt][3], vh[1], vh[3]);
                }
#pragma unroll
                for (int mt = 0; mt < 2; mt++) {
                    mma_bf16(Oacc[mt][2 * g + 0], pl[mt][0], pl[mt][1], pl[mt][2], pl[mt][3], vh[0], vh[2]);
                    mma_bf16(Oacc[mt][2 * g + 1], pl[mt][0], pl[mt][1], pl[mt][2], pl[mt][3], vh[1], vh[3]);
                }
#pragma unroll
                for (int mt = 0; mt < 2; mt++) {
                    mma_bf16(Oacc[mt][2 * g + 0], ph[mt][0], ph[mt][1], ph[mt][2], ph[mt][3], vl[0], vl[2]);
                    mma_bf16(Oacc[mt][2 * g + 1], ph[mt][0], ph[mt][1], ph[mt][2], ph[mt][3], vl[1], vl[3]);
                }
            }
        }
        __syncthreads();
    }

    const int gc = (lane & 3) * 2;
#pragma unroll
    for (int mt = 0; mt < 2; mt++) {
        const float inv0 = 1.f / l[mt][0];
        const float inv1 = 1.f / l[mt][1];
        const int row0 = b * Qn + q0 + wid * 32 + mt * 16 + gr;
#pragma unroll
        for (int j = 0; j < 8; j++) {
            const int col = P.coloff + h * 64 + (j >> 1) * 16 + (j & 1) * 8 + gc;
            float o0 = Oacc[mt][j][0] * inv0, o1 = Oacc[mt][j][1] * inv0;
            float o2 = Oacc[mt][j][2] * inv1, o3 = Oacc[mt][j][3] * inv1;
            size_t i0 = ((size_t)row0 * 512 + col) >> 1;
            size_t i1 = ((size_t)(row0 + 8) * 512 + col) >> 1;
            ((uint32_t*)xh)[i0] = pack_hi(o0, o1);
            ((uint32_t*)xl)[i0] = pack_lo(o0, o1);
            ((uint32_t*)xh)[i1] = pack_hi(o2, o3);
            ((uint32_t*)xl)[i1] = pack_lo(o2, o3);
        }
    }
}

// ---------------------------------------------------------------------------
// Host launch sequence
// ---------------------------------------------------------------------------
extern "C" void kernel_launch(void* const* d_in, const int* in_sizes, int n_in,
                              void* d_out, int out_size)
{
    (void)in_sizes; (void)out_size;
    const int s = (n_in >= 24) ? 2 : 0;

    const float* query   = (const float*)d_in[0];
    const float* key     = (const float*)d_in[1];
    const float* value   = (const float*)d_in[2];
    const float* q_w     = (const float*)d_in[3 + s];
    const float* sr1_w   = (const float*)d_in[4 + s];
    const float* sr1_b   = (const float*)d_in[5 + s];
    const float* norm1_w = (const float*)d_in[6 + s];
    const float* norm1_b = (const float*)d_in[7 + s];
    const float* sr2_w   = (const float*)d_in[8 + s];
    const float* sr2_b   = (const float*)d_in[9 + s];
    const float* norm2_w = (const float*)d_in[10 + s];
    const float* norm2_b = (const float*)d_in[11 + s];
    const float* k1_w    = (const float*)d_in[12 + s];
    const float* k2_w    = (const float*)d_in[14 + s];
    const float* v2_w    = (const float*)d_in[15 + s];
    const float* lc1_w   = (const float*)d_in[16 + s];
    const float* lc1_b   = (const float*)d_in[17 + s];
    const float* lc2_w   = (const float*)d_in[18 + s];
    const float* lc2_b   = (const float*)d_in[19 + s];
    const float* proj_w  = (const float*)d_in[20 + s];
    const float* proj_b  = (const float*)d_in[21 + s];
    float* out = (float*)d_out;

    float *kv1n, *kv2n, *kv1, *v2;
    cudaGetSymbolAddress((void**)&kv1n, g_kv1n);
    cudaGetSymbolAddress((void**)&kv2n, g_kv2n);
    cudaGetSymbolAddress((void**)&kv1,  g_kv1);
    cudaGetSymbolAddress((void**)&v2,   g_v2);

    __nv_bfloat16 *qh, *ql, *qph, *qpl, *kv1nh, *kv1nl, *kv2nh, *kv2nl;
    __nv_bfloat16 *k1ph, *k1pl, *k2ph, *k2pl, *vt1h, *vt1l, *vt2h, *vt2l, *xh, *xl;
    __nv_bfloat16 *qwh, *qwl, *k1wh, *k1wl, *k2wh, *k2wl, *v2wh, *v2wl, *pwh, *pwl;
    __half *imgf, *s1wf, *s2wf;
    cudaGetSymbolAddress((void**)&qh, g_qh);       cudaGetSymbolAddress((void**)&ql, g_ql);
    cudaGetSymbolAddress((void**)&qph, g_qph);     cudaGetSymbolAddress((void**)&qpl, g_qpl);
    cudaGetSymbolAddress((void**)&imgf, g_imgh);
    cudaGetSymbolAddress((void**)&s1wf, g_s1wh);
    cudaGetSymbolAddress((void**)&s2wf, g_s2wh);
    cudaGetSymbolAddress((void**)&kv1nh, g_kv1nh); cudaGetSymbolAddress((void**)&kv1nl, g_kv1nl);
    cudaGetSymbolAddress((void**)&kv2nh, g_kv2nh); cudaGetSymbolAddress((void**)&kv2nl, g_kv2nl);
    cudaGetSymbolAddress((void**)&k1ph, g_k1ph);   cudaGetSymbolAddress((void**)&k1pl, g_k1pl);
    cudaGetSymbolAddress((void**)&k2ph, g_k2ph);   cudaGetSymbolAddress((void**)&k2pl, g_k2pl);
    cudaGetSymbolAddress((void**)&vt1h, g_vt1h);   cudaGetSymbolAddress((void**)&vt1l, g_vt1l);
    cudaGetSymbolAddress((void**)&vt2h, g_vt2h);   cudaGetSymbolAddress((void**)&vt2l, g_vt2l);
    cudaGetSymbolAddress((void**)&xh, g_xh);       cudaGetSymbolAddress((void**)&xl, g_xl);
    cudaGetSymbolAddress((void**)&qwh, g_qwh);     cudaGetSymbolAddress((void**)&qwl, g_qwl);
    cudaGetSymbolAddress((void**)&k1wh, g_k1wh);   cudaGetSymbolAddress((void**)&k1wl, g_k1wl);
    cudaGetSymbolAddress((void**)&k2wh, g_k2wh);   cudaGetSymbolAddress((void**)&k2wl, g_k2wl);
    cudaGetSymbolAddress((void**)&v2wh, g_v2wh);   cudaGetSymbolAddress((void**)&v2wl, g_v2wl);
    cudaGetSymbolAddress((void**)&pwh, g_pwh);     cudaGetSymbolAddress((void**)&pwl, g_pwl);

    const size_t IMG1 = (size_t)B_ * C_ * 64 * 64;
    float* v1 = kv1 + (size_t)B_ * N1_ * C2_;

    const int SMEM = 81920;
    const int SMEM4 = 40960;
    cudaFuncSetAttribute(hgemm3_kernel<1>, cudaFuncAttributeMaxDynamicSharedMemorySize, SMEM);
    cudaFuncSetAttribute(hgemm3_kernel<2>, cudaFuncAttributeMaxDynamicSharedMemorySize, SMEM);
    cudaFuncSetAttribute(hgemm4_kernel<1>, cudaFuncAttributeMaxDynamicSharedMemorySize, SMEM4);
    cudaFuncSetAttribute(hgemm4_kernel<2>, cudaFuncAttributeMaxDynamicSharedMemorySize, SMEM4);
    cudaFuncSetAttribute(projgemm3_kernel, cudaFuncAttributeMaxDynamicSharedMemorySize, SMEM);
    const int FSMEM = 110592;
    cudaFuncSetAttribute(flash2_kernel, cudaFuncAttributeMaxDynamicSharedMemorySize, FSMEM);

    dim3 gblk(128);

    // launches ordered so my 4th launch (#6 under ncu -s 5) = sr1 GEMM
    split_h_kernel<<<4096, 256>>>(sr1_w, s1wf);                             // 1
    to_image_h_kernel<<<8192, 256>>>(key, value, imgf, IMG1);               // 2
    split_h_kernel<<<1024, 256>>>(sr2_w, s2wf);                             // 3
    hgemm4_kernel<1><<<dim3(4, 64), gblk, SMEM4>>>(imgf, s1wf, sr1_b,
                                                   kv1n, 8192, 512, 8192);  // 4 <- profiled

    split_kernel<<<256, 256>>>(q_w, qwh, qwl);
    split_kernel<<<128, 256>>>(k1_w, k1wh, k1wl);
    split_kernel<<<128, 256>>>(k2_w, k2wh, k2wl);
    split_kernel<<<128, 256>>>(v2_w, v2wh, v2wl);
    split_kernel<<<256, 256>>>(proj_w, pwh, pwl);
    split_kernel<<<8192, 256>>>(query, qh, ql);

    hgemm4_kernel<2><<<dim3(4, 256), gblk, SMEM4>>>(imgf, s2wf, sr2_b,
                                                    kv2n, 32768, 512, 2048);

    hgemm3_kernel<2><<<dim3(4, 128), gblk, SMEM>>>(qh, ql, qwh, qwl, nullptr,
                                                   nullptr, qph, qpl, 16384, 512, 512);

    ln_gelu_split_kernel<<<8192,  256>>>(kv1n, norm1_w, norm1_b, kv1nh, kv1nl);
    ln_gelu_split_kernel<<<32768, 256>>>(kv2n, norm2_w, norm2_b, kv2nh, kv2nl);

    {
        ProjParams P;
        P.Ah[0] = kv1nh;  P.Al[0] = kv1nl;  P.Wh[0] = k1wh; P.Wl[0] = k1wl;
        P.Cf[0] = kv1;    P.Ch[0] = k1ph;   P.Cl[0] = k1pl; P.outm[0] = 3;
        P.Ah[1] = kv2nh;  P.Al[1] = kv2nl;  P.Wh[1] = k2wh; P.Wl[1] = k2wl;
        P.Cf[1] = nullptr; P.Ch[1] = k2ph;  P.Cl[1] = k2pl; P.outm[1] = 2;
        P.Ah[2] = kv2nh + (size_t)16384 * 512;
        P.Al[2] = kv2nl + (size_t)16384 * 512;
        P.Wh[2] = v2wh;   P.Wl[2] = v2wl;
        P.Cf[2] = v2;     P.Ch[2] = nullptr; P.Cl[2] = nullptr; P.outm[2] = 1;
        projgemm3_kernel<<<dim3(2, 320), gblk, SMEM>>>(P);
    }

    dwconv_res_t2_kernel<<<B_ * 4 * (N1_ / 64), 256>>>(v1, lc1_w, lc1_b, vt1h, vt1l, 16, 16);
    dwconv_res_t2_kernel<<<B_ * 4 * (N2_ / 64), 256>>>(v2, lc2_w, lc2_b, vt2h, vt2l, 32, 32);

    {
        FlashB P0, P1;
        P0.kph = k1ph; P0.kpl = k1pl; P0.vth = vt1h; P0.vtl = vt1l;
        P0.Nk = N1_; P0.hoff = 0; P0.coloff = 0;
        P1.kph = k2ph; P1.kpl = k2pl; P1.vth = vt2h; P1.vtl = vt2l;
        P1.Nk = N2_; P1.hoff = 4; P1.coloff = 256;
        flash2_kernel<<<dim3(8, 128), gblk, FSMEM>>>(qph, qpl, xh, xl, P0, P1);
    }

    hgemm3_kernel<1><<<dim3(4, 128), gblk, SMEM>>>(xh, xl, pwh, pwl, proj_b,
                                                   out, nullptr, nullptr, 16384, 512, 512);
}